// round 2
// baseline (speedup 1.0000x reference)
#include <cuda_runtime.h>
#include <cstdint>

// Problem constants
#define BB 4
#define SS 2048
#define DD 1024
#define HH 16
#define DKV 64
#define MM (BB*SS)          // 8192 rows

// Scratch (device globals: allocation-free)
__device__ float g_Q[MM * DD];
__device__ float g_K[MM * DD];
__device__ float g_V[MM * DD];
__device__ float g_O[MM * DD];

// ---------------------------------------------------------------------------
// Tiled SGEMM: C[M,N] = A[M,K] * W[K,N] + bias[N]   (optionally * qmask[row])
// BM=BN=128, BK=16, 256 threads, 8x8 register micro-tile per thread.
// ---------------------------------------------------------------------------
template<bool QMASK>
__global__ __launch_bounds__(256, 2)
void sgemm_bias(const float* __restrict__ A, const float* __restrict__ W,
                const float* __restrict__ bias, const int* __restrict__ qmask,
                float* __restrict__ C, int M, int N, int K)
{
    __shared__ float As[16][128];   // transposed A tile: As[k][m]
    __shared__ float Ws[16][128];   // W tile: Ws[k][n]

    const int tid = threadIdx.x;
    const int m0 = blockIdx.y * 128;
    const int n0 = blockIdx.x * 128;
    const int tx = tid & 15;
    const int ty = tid >> 4;

    float acc[8][8];
#pragma unroll
    for (int r = 0; r < 8; r++)
#pragma unroll
        for (int c = 0; c < 8; c++) acc[r][c] = 0.0f;

    for (int k0 = 0; k0 < K; k0 += 16) {
        // Load A tile (128x16) transposed and W tile (16x128)
#pragma unroll
        for (int i = 0; i < 2; i++) {
            int idx = tid + i * 256;           // 0..511
            int ar  = idx >> 2;                // 0..127
            int ac4 = idx & 3;                 // 0..3
            float4 av = *(const float4*)&A[(size_t)(m0 + ar) * K + k0 + ac4 * 4];
            As[ac4 * 4 + 0][ar] = av.x;
            As[ac4 * 4 + 1][ar] = av.y;
            As[ac4 * 4 + 2][ar] = av.z;
            As[ac4 * 4 + 3][ar] = av.w;
            int wr  = idx >> 5;                // 0..15
            int wc4 = idx & 31;                // 0..31
            *(float4*)&Ws[wr][wc4 * 4] =
                *(const float4*)&W[(size_t)(k0 + wr) * N + n0 + wc4 * 4];
        }
        __syncthreads();

#pragma unroll
        for (int kk = 0; kk < 16; kk++) {
            float a[8], b[8];
            *(float4*)&a[0] = *(float4*)&As[kk][ty * 8];
            *(float4*)&a[4] = *(float4*)&As[kk][ty * 8 + 4];
            *(float4*)&b[0] = *(float4*)&Ws[kk][tx * 8];
            *(float4*)&b[4] = *(float4*)&Ws[kk][tx * 8 + 4];
#pragma unroll
            for (int r = 0; r < 8; r++)
#pragma unroll
                for (int c = 0; c < 8; c++)
                    acc[r][c] = fmaf(a[r], b[c], acc[r][c]);
        }
        __syncthreads();
    }

    // Epilogue: bias (+ optional row mask), vectorized stores
#pragma unroll
    for (int r = 0; r < 8; r++) {
        int row = m0 + ty * 8 + r;
        float qm = 1.0f;
        if (QMASK) qm = (float)qmask[row];
#pragma unroll
        for (int c4 = 0; c4 < 2; c4++) {
            int col = n0 + tx * 8 + c4 * 4;
            float4 bv = *(const float4*)&bias[col];
            float4 val;
            val.x = (acc[r][c4 * 4 + 0] + bv.x) * qm;
            val.y = (acc[r][c4 * 4 + 1] + bv.y) * qm;
            val.z = (acc[r][c4 * 4 + 2] + bv.z) * qm;
            val.w = (acc[r][c4 * 4 + 3] + bv.w) * qm;
            *(float4*)&C[(size_t)row * N + col] = val;
        }
    }
}

// ---------------------------------------------------------------------------
// Causal flash attention, fp32.
// Block: one (batch,head, 128-row q tile). 256 threads (16x16).
// Loops over 128-key tiles with online softmax; P staged via padded SMEM.
// Q/K tiles stored transposed with row stride 132 floats (multiple of 4 for
// aligned float4 LDS; not a multiple of 8 to limit bank conflicts).
// ---------------------------------------------------------------------------
#define QK_STRIDE 132

__global__ __launch_bounds__(256, 1)
void attn_kernel(const int* __restrict__ v_mask)
{
    extern __shared__ float sm[];
    float* Qs = sm;                            // [64][132]  (transposed: Qs[d][i])
    float* Ks = Qs + 64 * QK_STRIDE;           // [64][132]  (transposed: Ks[d][j])
    float* Vs = Ks + 64 * QK_STRIDE;           // [128][64]  row-major
    float* Ps = Vs + 128 * 64;                 // [128][132] row-major, padded
    int*   vm = (int*)(Ps + 128 * 132);        // [128]

    const int tid = threadIdx.x;
    const int tx = tid & 15;
    const int ty = tid >> 4;
    const int bh = blockIdx.y;
    const int b  = bh >> 4;
    const int h  = bh & 15;
    const int qt = gridDim.x - 1 - blockIdx.x;   // heavy tiles scheduled first
    const int q0 = qt * 128;
    const float scale = 0.125f;           // 1/sqrt(64)

    // Load Q tile transposed: Qs[d][i]
#pragma unroll
    for (int t = 0; t < 8; t++) {
        int idx = tid + t * 256;           // 0..2047
        int i  = idx >> 4;                 // 0..127
        int d4 = idx & 15;                 // 0..15
        float4 v = *(const float4*)&g_Q[(size_t)(b * SS + q0 + i) * DD + h * 64 + d4 * 4];
        Qs[(d4 * 4 + 0) * QK_STRIDE + i] = v.x;
        Qs[(d4 * 4 + 1) * QK_STRIDE + i] = v.y;
        Qs[(d4 * 4 + 2) * QK_STRIDE + i] = v.z;
        Qs[(d4 * 4 + 3) * QK_STRIDE + i] = v.w;
    }

    float m[8], l[8], o[8][4];
#pragma unroll
    for (int r = 0; r < 8; r++) {
        m[r] = -1e30f; l[r] = 0.0f;
        o[r][0] = o[r][1] = o[r][2] = o[r][3] = 0.0f;
    }

    const int nkt = qt + 1;               // causal: only tiles kt <= qt
    for (int kt = 0; kt < nkt; kt++) {
        __syncthreads();   // previous AV done with Vs/Ps; previous S done with Ks

        // Load K tile transposed + V tile row-major + v_mask
#pragma unroll
        for (int t = 0; t < 8; t++) {
            int idx = tid + t * 256;
            int j  = idx >> 4;
            int d4 = idx & 15;
            size_t grow = (size_t)(b * SS + kt * 128 + j) * DD + h * 64 + d4 * 4;
            float4 kv = *(const float4*)&g_K[grow];
            Ks[(d4 * 4 + 0) * QK_STRIDE + j] = kv.x;
            Ks[(d4 * 4 + 1) * QK_STRIDE + j] = kv.y;
            Ks[(d4 * 4 + 2) * QK_STRIDE + j] = kv.z;
            Ks[(d4 * 4 + 3) * QK_STRIDE + j] = kv.w;
            float4 vv = *(const float4*)&g_V[grow];
            *(float4*)&Vs[j * 64 + d4 * 4] = vv;
        }
        if (tid < 128) vm[tid] = v_mask[b * SS + kt * 128 + tid];
        __syncthreads();

        // S = Q K^T  (128x128, 8x8 per thread)
        float s[8][8];
#pragma unroll
        for (int r = 0; r < 8; r++)
#pragma unroll
            for (int c = 0; c < 8; c++) s[r][c] = 0.0f;

#pragma unroll
        for (int d = 0; d < 64; d++) {
            float a[8], kb[8];
            *(float4*)&a[0]  = *(float4*)&Qs[d * QK_STRIDE + ty * 8];
            *(float4*)&a[4]  = *(float4*)&Qs[d * QK_STRIDE + ty * 8 + 4];
            *(float4*)&kb[0] = *(float4*)&Ks[d * QK_STRIDE + tx * 8];
            *(float4*)&kb[4] = *(float4*)&Ks[d * QK_STRIDE + tx * 8 + 4];
#pragma unroll
            for (int r = 0; r < 8; r++)
#pragma unroll
                for (int c = 0; c < 8; c++)
                    s[r][c] = fmaf(a[r], kb[c], s[r][c]);
        }

        // scale + v_mask + causal mask
        const bool diag = (kt == qt);
#pragma unroll
        for (int r = 0; r < 8; r++) {
            int qi = q0 + ty * 8 + r;
#pragma unroll
            for (int c = 0; c < 8; c++) {
                int jj = tx * 8 + c;
                float val = s[r][c] * scale;
                if (vm[jj] == 0) val = -1e12f;
                if (diag && (kt * 128 + jj > qi)) val = -1e12f;
                s[r][c] = val;
            }
        }

        // Online softmax per row (rows owned by ty-group; reduce across 16 tx lanes)
#pragma unroll
        for (int r = 0; r < 8; r++) {
            float mt = s[r][0];
#pragma unroll
            for (int c = 1; c < 8; c++) mt = fmaxf(mt, s[r][c]);
#pragma unroll
            for (int off = 8; off > 0; off >>= 1)
                mt = fmaxf(mt, __shfl_xor_sync(0xffffffffu, mt, off));
            float mn   = fmaxf(m[r], mt);
            float corr = __expf(m[r] - mn);
            m[r] = mn;
            float rs = 0.0f;
#pragma unroll
            for (int c = 0; c < 8; c++) {
                s[r][c] = __expf(s[r][c] - mn);
                rs += s[r][c];
            }
#pragma unroll
            for (int off = 8; off > 0; off >>= 1)
                rs += __shfl_xor_sync(0xffffffffu, rs, off);
            l[r] = l[r] * corr + rs;
            o[r][0] *= corr; o[r][1] *= corr; o[r][2] *= corr; o[r][3] *= corr;
        }

        // Stage P to SMEM (padded rows: stride 132)
#pragma unroll
        for (int r = 0; r < 8; r++) {
            float* prow = &Ps[(size_t)(ty * 8 + r) * 132 + tx * 8];
            *(float4*)&prow[0] = make_float4(s[r][0], s[r][1], s[r][2], s[r][3]);
            *(float4*)&prow[4] = make_float4(s[r][4], s[r][5], s[r][6], s[r][7]);
        }
        __syncthreads();

        // O += P * V   (128x64, 8 rows x 4 cols per thread)
#pragma unroll 8
        for (int j = 0; j < 128; j++) {
            float4 vj = *(float4*)&Vs[j * 64 + tx * 4];
#pragma unroll
            for (int r = 0; r < 8; r++) {
                float p = Ps[(size_t)(ty * 8 + r) * 132 + j];
                o[r][0] = fmaf(p, vj.x, o[r][0]);
                o[r][1] = fmaf(p, vj.y, o[r][1]);
                o[r][2] = fmaf(p, vj.z, o[r][2]);
                o[r][3] = fmaf(p, vj.w, o[r][3]);
            }
        }
    }

    // Normalize and store O tile
#pragma unroll
    for (int r = 0; r < 8; r++) {
        float inv = 1.0f / l[r];
        float4 ov = make_float4(o[r][0] * inv, o[r][1] * inv,
                                o[r][2] * inv, o[r][3] * inv);
        *(float4*)&g_O[(size_t)(b * SS + q0 + ty * 8 + r) * DD + h * 64 + tx * 4] = ov;
    }
}

// ---------------------------------------------------------------------------
// kernel_launch: QKV projections -> attention -> output projection
// ---------------------------------------------------------------------------
extern "C" void kernel_launch(void* const* d_in, const int* in_sizes, int n_in,
                              void* d_out, int out_size)
{
    const float* q      = (const float*)d_in[0];
    const float* k      = (const float*)d_in[1];
    const float* v      = (const float*)d_in[2];
    const int*   q_mask = (const int*)  d_in[3];
    const int*   v_mask = (const int*)  d_in[4];
    const float* Wq     = (const float*)d_in[5];
    const float* bq     = (const float*)d_in[6];
    const float* Wk     = (const float*)d_in[7];
    const float* bk     = (const float*)d_in[8];
    const float* Wv     = (const float*)d_in[9];
    const float* bv     = (const float*)d_in[10];
    const float* Wo     = (const float*)d_in[11];
    const float* bo     = (const float*)d_in[12];
    float* out = (float*)d_out;

    float *gq, *gk, *gv, *go;
    cudaGetSymbolAddress((void**)&gq, g_Q);
    cudaGetSymbolAddress((void**)&gk, g_K);
    cudaGetSymbolAddress((void**)&gv, g_V);
    cudaGetSymbolAddress((void**)&go, g_O);

    dim3 gemm_grid(DD / 128, MM / 128);   // (8, 64)
    dim3 gemm_blk(256);

    sgemm_bias<false><<<gemm_grid, gemm_blk>>>(q, Wq, bq, nullptr, gq, MM, DD, DD);
    sgemm_bias<false><<<gemm_grid, gemm_blk>>>(k, Wk, bk, nullptr, gk, MM, DD, DD);
    sgemm_bias<false><<<gemm_grid, gemm_blk>>>(v, Wv, bv, nullptr, gv, MM, DD, DD);

    const int SMEM_BYTES = (64 * QK_STRIDE * 2 + 128 * 64 + 128 * 132) * 4 + 128 * 4;
    cudaFuncSetAttribute(attn_kernel,
                         cudaFuncAttributeMaxDynamicSharedMemorySize, SMEM_BYTES);
    attn_kernel<<<dim3(SS / 128, BB * HH), 256, SMEM_BYTES>>>(v_mask);

    sgemm_bias<true><<<gemm_grid, gemm_blk>>>(go, Wo, bo, q_mask, out, MM, DD, DD);
}

// round 4
// speedup vs baseline: 1.6100x; 1.6100x over previous
#include <cuda_runtime.h>
#include <cuda_bf16.h>
#include <cstdint>

// Problem constants
#define BB 4
#define SS 2048
#define DD 1024
#define HH 16
#define MM (BB*SS)          // 8192 rows

// Scratch (device globals: allocation-free)
__device__ float g_Q[MM * DD];
__device__ float g_K[MM * DD];
__device__ float g_V[MM * DD];
__device__ float g_O[MM * DD];
__device__ __nv_bfloat16 g_Ahi[MM * DD];
__device__ __nv_bfloat16 g_Alo[MM * DD];
__device__ __nv_bfloat16 g_Whi[DD * DD];   // transposed: [N, K]
__device__ __nv_bfloat16 g_Wlo[DD * DD];   // transposed: [N, K]

// ---------------------------------------------------------------------------
// Portable (sm_80+) tensor-core helpers: mma.sync + ldmatrix + cp.async
// ---------------------------------------------------------------------------
__device__ __forceinline__ uint32_t smem_u32(const void* p) {
    uint32_t a;
    asm("{ .reg .u64 t; cvta.to.shared.u64 t, %1; cvt.u32.u64 %0, t; }"
        : "=r"(a) : "l"(p));
    return a;
}

__device__ __forceinline__ void ldsm4(uint32_t* r, uint32_t addr) {
    asm volatile("ldmatrix.sync.aligned.m8n8.x4.shared.b16 {%0,%1,%2,%3}, [%4];"
        : "=r"(r[0]), "=r"(r[1]), "=r"(r[2]), "=r"(r[3]) : "r"(addr));
}

__device__ __forceinline__ void mma16816(float* c, const uint32_t* a,
                                         const uint32_t* b) {
    asm volatile(
        "mma.sync.aligned.m16n8k16.row.col.f32.bf16.bf16.f32 "
        "{%0,%1,%2,%3}, {%4,%5,%6,%7}, {%8,%9}, {%0,%1,%2,%3};"
        : "+f"(c[0]), "+f"(c[1]), "+f"(c[2]), "+f"(c[3])
        : "r"(a[0]), "r"(a[1]), "r"(a[2]), "r"(a[3]), "r"(b[0]), "r"(b[1]));
}

__device__ __forceinline__ void cp16(uint32_t saddr, const void* g) {
    asm volatile("cp.async.cg.shared.global [%0], [%1], 16;"
                 :: "r"(saddr), "l"(g) : "memory");
}
#define CP_COMMIT() asm volatile("cp.async.commit_group;" ::: "memory")
#define CP_WAIT2()  asm volatile("cp.async.wait_group 2;" ::: "memory")

// SW128 swizzle on byte offsets within a tile (rows of 128B)
#define SWZ(o) ((o) ^ (((o) >> 3) & 0x70))

// ---------------------------------------------------------------------------
// Split-precision conversions
// ---------------------------------------------------------------------------
__global__ __launch_bounds__(256)
void split_kernel(const float* __restrict__ x,
                  __nv_bfloat16* __restrict__ hi,
                  __nv_bfloat16* __restrict__ lo, int n4)
{
    int i = blockIdx.x * blockDim.x + threadIdx.x;
    if (i >= n4) return;
    float4 v = ((const float4*)x)[i];
    __nv_bfloat16 h0 = __float2bfloat16(v.x);
    __nv_bfloat16 h1 = __float2bfloat16(v.y);
    __nv_bfloat16 h2 = __float2bfloat16(v.z);
    __nv_bfloat16 h3 = __float2bfloat16(v.w);
    __nv_bfloat16 l0 = __float2bfloat16(v.x - __bfloat162float(h0));
    __nv_bfloat16 l1 = __float2bfloat16(v.y - __bfloat162float(h1));
    __nv_bfloat16 l2 = __float2bfloat16(v.z - __bfloat162float(h2));
    __nv_bfloat16 l3 = __float2bfloat16(v.w - __bfloat162float(h3));
    __nv_bfloat162* hp = (__nv_bfloat162*)(hi + (size_t)i * 4);
    __nv_bfloat162* lp = (__nv_bfloat162*)(lo + (size_t)i * 4);
    hp[0] = __nv_bfloat162(h0, h1); hp[1] = __nv_bfloat162(h2, h3);
    lp[0] = __nv_bfloat162(l0, l1); lp[1] = __nv_bfloat162(l2, l3);
}

// W[K,N] fp32 -> Whi/Wlo [N,K] bf16 (transposed), 32x32 tiles
__global__ __launch_bounds__(256)
void wsplit_transpose_kernel(const float* __restrict__ W,
                             __nv_bfloat16* __restrict__ hi,
                             __nv_bfloat16* __restrict__ lo)
{
    __shared__ float t[32][33];
    int tx = threadIdx.x & 31;
    int ty = threadIdx.x >> 5;      // 0..7
    int n0 = blockIdx.x * 32;
    int k0 = blockIdx.y * 32;
#pragma unroll
    for (int i = 0; i < 4; i++)
        t[ty + 8 * i][tx] = W[(size_t)(k0 + ty + 8 * i) * DD + n0 + tx];
    __syncthreads();
#pragma unroll
    for (int i = 0; i < 4; i++) {
        int n = ty + 8 * i;
        float v = t[tx][n];
        __nv_bfloat16 h = __float2bfloat16(v);
        __nv_bfloat16 l = __float2bfloat16(v - __bfloat162float(h));
        hi[(size_t)(n0 + n) * DD + k0 + tx] = h;
        lo[(size_t)(n0 + n) * DD + k0 + tx] = l;
    }
}

// ---------------------------------------------------------------------------
// Split-bf16 tensor-core GEMM (mma.sync):
//   C[M,N] = Ahi/lo[M,K] x (Bhi/lo[N,K])^T + bias (optional * qmask[row])
// CTA tile 128x128, BK=64, 3-stage cp.async pipeline, SW128 swizzle.
// 8 warps, warp tile 64x32 (4 m-tiles of 16, 4 n-tiles of 8).
// 3 MMA terms: Ah*Bh + Ah*Bl + Al*Bh  (fp32 accumulate)
// ---------------------------------------------------------------------------
#define BK 64
#define TILE_B 16384            // 128 rows * 128 bytes
#define STAGE_B (4 * TILE_B)    // Ahi, Alo, Bhi, Blo
#define NSTAGE 3
#define NK (DD / BK)            // 16

template<bool QMASK>
__global__ __launch_bounds__(256)
void gemm_mma(const __nv_bfloat16* __restrict__ Ahi,
              const __nv_bfloat16* __restrict__ Alo,
              const __nv_bfloat16* __restrict__ Bhi,
              const __nv_bfloat16* __restrict__ Blo,
              const float* __restrict__ bias,
              const int* __restrict__ qmask,
              float* __restrict__ C)
{
    extern __shared__ char smc[];
    const uint32_t sbase = smem_u32(smc);

    const int tid  = threadIdx.x;
    const int lane = tid & 31;
    const int wid  = tid >> 5;
    const int wm   = wid & 1;          // 0..1 -> m offset wm*64
    const int wn   = wid >> 1;         // 0..3 -> n offset wn*32
    const int m0 = blockIdx.y * 128;
    const int n0 = blockIdx.x * 128;

    const char* srcs[4] = { (const char*)Ahi, (const char*)Alo,
                            (const char*)Bhi, (const char*)Blo };

    // stage loader: 4 tiles x 128 rows x 8 chunks(16B) = 16 cp.async/thread
    auto load_stage = [&](int it, int s) {
        const int kc = it * BK;
        const uint32_t stb = sbase + s * STAGE_B;
#pragma unroll
        for (int t = 0; t < 4; t++) {
            const int row0 = (t < 2) ? m0 : n0;
            const char* src = srcs[t];
#pragma unroll
            for (int i = 0; i < 4; i++) {
                int u = tid + i * 256;     // 0..1023
                int r = u >> 3;            // 0..127
                int c = u & 7;             // 0..7
                const void* g = src + ((size_t)(row0 + r) * DD + kc) * 2 + c * 16;
                uint32_t off = (uint32_t)(r * 128 + c * 16);
                cp16(stb + t * TILE_B + SWZ(off), g);
            }
        }
    };

    float acc[4][4][4];
#pragma unroll
    for (int mt = 0; mt < 4; mt++)
#pragma unroll
        for (int nt = 0; nt < 4; nt++)
#pragma unroll
            for (int e = 0; e < 4; e++) acc[mt][nt][e] = 0.0f;

    // prologue
    load_stage(0, 0); CP_COMMIT();
    load_stage(1, 1); CP_COMMIT();

    // fragment address components (constant per thread)
    const int a_row = wm * 64 + (lane & 15);
    const uint32_t a_bc = (uint32_t)((lane >> 4) << 4);
    const int b_row = wn * 32 + ((lane & 16) >> 1) + (lane & 7);
    const uint32_t b_bc = (uint32_t)((lane & 8) << 1);

    for (int it = 0; it < NK; it++) {
        if (it + 2 < NK) load_stage(it + 2, (it + 2) % NSTAGE);
        CP_COMMIT();
        CP_WAIT2();
        __syncthreads();

        const uint32_t stb = sbase + (it % NSTAGE) * STAGE_B;
        const uint32_t tAh = stb + 0 * TILE_B;
        const uint32_t tAl = stb + 1 * TILE_B;
        const uint32_t tBh = stb + 2 * TILE_B;
        const uint32_t tBl = stb + 3 * TILE_B;

        // 3 terms: (Ah,Bh), (Ah,Bl), (Al,Bh)
#pragma unroll
        for (int term = 0; term < 3; term++) {
            const uint32_t aT = (term == 2) ? tAl : tAh;
            const uint32_t bT = (term == 1) ? tBl : tBh;
#pragma unroll
            for (int ks = 0; ks < 4; ks++) {
                uint32_t af[4][4];
#pragma unroll
                for (int mt = 0; mt < 4; mt++) {
                    uint32_t off = (uint32_t)((a_row + mt * 16) * 128) +
                                   (uint32_t)(ks * 32) + a_bc;
                    ldsm4(af[mt], aT + SWZ(off));
                }
#pragma unroll
                for (int np = 0; np < 2; np++) {
                    uint32_t bf[4];
                    uint32_t off = (uint32_t)((b_row + np * 16) * 128) +
                                   (uint32_t)(ks * 32) + b_bc;
                    ldsm4(bf, bT + SWZ(off));
#pragma unroll
                    for (int mt = 0; mt < 4; mt++) {
                        mma16816(acc[mt][np * 2 + 0], af[mt], bf);
                        mma16816(acc[mt][np * 2 + 1], af[mt], bf + 2);
                    }
                }
            }
        }
        __syncthreads();
    }

    // Epilogue: bias (+ optional qmask), float2 stores
    const int col_base = n0 + wn * 32 + ((lane & 3) << 1);
    const int row_base = m0 + wm * 64 + (lane >> 2);
#pragma unroll
    for (int nt = 0; nt < 4; nt++) {
        const int col = col_base + nt * 8;
        const float b0 = bias[col];
        const float b1 = bias[col + 1];
#pragma unroll
        for (int mt = 0; mt < 4; mt++) {
            int r0 = row_base + mt * 16;
            float qm0 = 1.0f, qm1 = 1.0f;
            if (QMASK) { qm0 = (float)qmask[r0]; qm1 = (float)qmask[r0 + 8]; }
            float2 v0 = make_float2((acc[mt][nt][0] + b0) * qm0,
                                    (acc[mt][nt][1] + b1) * qm0);
            float2 v1 = make_float2((acc[mt][nt][2] + b0) * qm1,
                                    (acc[mt][nt][3] + b1) * qm1);
            *(float2*)&C[(size_t)r0 * DD + col] = v0;
            *(float2*)&C[(size_t)(r0 + 8) * DD + col] = v1;
        }
    }
}

// ---------------------------------------------------------------------------
// Causal flash attention, fp32 (unchanged from passing R2 kernel).
// ---------------------------------------------------------------------------
#define QK_STRIDE 132

__global__ __launch_bounds__(256, 1)
void attn_kernel(const int* __restrict__ v_mask)
{
    extern __shared__ float smf[];
    float* Qs = smf;                           // [64][132]
    float* Ks = Qs + 64 * QK_STRIDE;           // [64][132]
    float* Vs = Ks + 64 * QK_STRIDE;           // [128][64]
    float* Ps = Vs + 128 * 64;                 // [128][132]
    int*   vm = (int*)(Ps + 128 * 132);        // [128]

    const int tid = threadIdx.x;
    const int tx = tid & 15;
    const int ty = tid >> 4;
    const int bh = blockIdx.y;
    const int b  = bh >> 4;
    const int h  = bh & 15;
    const int qt = gridDim.x - 1 - blockIdx.x;
    const int q0 = qt * 128;
    const float scale = 0.125f;

#pragma unroll
    for (int t = 0; t < 8; t++) {
        int idx = tid + t * 256;
        int i  = idx >> 4;
        int d4 = idx & 15;
        float4 v = *(const float4*)&g_Q[(size_t)(b * SS + q0 + i) * DD + h * 64 + d4 * 4];
        Qs[(d4 * 4 + 0) * QK_STRIDE + i] = v.x;
        Qs[(d4 * 4 + 1) * QK_STRIDE + i] = v.y;
        Qs[(d4 * 4 + 2) * QK_STRIDE + i] = v.z;
        Qs[(d4 * 4 + 3) * QK_STRIDE + i] = v.w;
    }

    float m[8], l[8], o[8][4];
#pragma unroll
    for (int r = 0; r < 8; r++) {
        m[r] = -1e30f; l[r] = 0.0f;
        o[r][0] = o[r][1] = o[r][2] = o[r][3] = 0.0f;
    }

    const int nkt = qt + 1;
    for (int kt = 0; kt < nkt; kt++) {
        __syncthreads();
#pragma unroll
        for (int t = 0; t < 8; t++) {
            int idx = tid + t * 256;
            int j  = idx >> 4;
            int d4 = idx & 15;
            size_t grow = (size_t)(b * SS + kt * 128 + j) * DD + h * 64 + d4 * 4;
            float4 kv = *(const float4*)&g_K[grow];
            Ks[(d4 * 4 + 0) * QK_STRIDE + j] = kv.x;
            Ks[(d4 * 4 + 1) * QK_STRIDE + j] = kv.y;
            Ks[(d4 * 4 + 2) * QK_STRIDE + j] = kv.z;
            Ks[(d4 * 4 + 3) * QK_STRIDE + j] = kv.w;
            float4 vv = *(const float4*)&g_V[grow];
            *(float4*)&Vs[j * 64 + d4 * 4] = vv;
        }
        if (tid < 128) vm[tid] = v_mask[b * SS + kt * 128 + tid];
        __syncthreads();

        float s[8][8];
#pragma unroll
        for (int r = 0; r < 8; r++)
#pragma unroll
            for (int c = 0; c < 8; c++) s[r][c] = 0.0f;

#pragma unroll
        for (int d = 0; d < 64; d++) {
            float a[8], kb[8];
            *(float4*)&a[0]  = *(float4*)&Qs[d * QK_STRIDE + ty * 8];
            *(float4*)&a[4]  = *(float4*)&Qs[d * QK_STRIDE + ty * 8 + 4];
            *(float4*)&kb[0] = *(float4*)&Ks[d * QK_STRIDE + tx * 8];
            *(float4*)&kb[4] = *(float4*)&Ks[d * QK_STRIDE + tx * 8 + 4];
#pragma unroll
            for (int r = 0; r < 8; r++)
#pragma unroll
                for (int c = 0; c < 8; c++)
                    s[r][c] = fmaf(a[r], kb[c], s[r][c]);
        }

        const bool diag = (kt == qt);
#pragma unroll
        for (int r = 0; r < 8; r++) {
            int qi = q0 + ty * 8 + r;
#pragma unroll
            for (int c = 0; c < 8; c++) {
                int jj = tx * 8 + c;
                float val = s[r][c] * scale;
                if (vm[jj] == 0) val = -1e12f;
                if (diag && (kt * 128 + jj > qi)) val = -1e12f;
                s[r][c] = val;
            }
        }

#pragma unroll
        for (int r = 0; r < 8; r++) {
            float mt = s[r][0];
#pragma unroll
            for (int c = 1; c < 8; c++) mt = fmaxf(mt, s[r][c]);
#pragma unroll
            for (int off = 8; off > 0; off >>= 1)
                mt = fmaxf(mt, __shfl_xor_sync(0xffffffffu, mt, off));
            float mn   = fmaxf(m[r], mt);
            float corr = __expf(m[r] - mn);
            m[r] = mn;
            float rs = 0.0f;
#pragma unroll
            for (int c = 0; c < 8; c++) {
                s[r][c] = __expf(s[r][c] - mn);
                rs += s[r][c];
            }
#pragma unroll
            for (int off = 8; off > 0; off >>= 1)
                rs += __shfl_xor_sync(0xffffffffu, rs, off);
            l[r] = l[r] * corr + rs;
            o[r][0] *= corr; o[r][1] *= corr; o[r][2] *= corr; o[r][3] *= corr;
        }

#pragma unroll
        for (int r = 0; r < 8; r++) {
            float* prow = &Ps[(size_t)(ty * 8 + r) * 132 + tx * 8];
            *(float4*)&prow[0] = make_float4(s[r][0], s[r][1], s[r][2], s[r][3]);
            *(float4*)&prow[4] = make_float4(s[r][4], s[r][5], s[r][6], s[r][7]);
        }
        __syncthreads();

#pragma unroll 8
        for (int j = 0; j < 128; j++) {
            float4 vj = *(float4*)&Vs[j * 64 + tx * 4];
#pragma unroll
            for (int r = 0; r < 8; r++) {
                float p = Ps[(size_t)(ty * 8 + r) * 132 + j];
                o[r][0] = fmaf(p, vj.x, o[r][0]);
                o[r][1] = fmaf(p, vj.y, o[r][1]);
                o[r][2] = fmaf(p, vj.z, o[r][2]);
                o[r][3] = fmaf(p, vj.w, o[r][3]);
            }
        }
    }

#pragma unroll
    for (int r = 0; r < 8; r++) {
        float inv = 1.0f / l[r];
        float4 ov = make_float4(o[r][0] * inv, o[r][1] * inv,
                                o[r][2] * inv, o[r][3] * inv);
        *(float4*)&g_O[(size_t)(b * SS + q0 + ty * 8 + r) * DD + h * 64 + tx * 4] = ov;
    }
}

// ---------------------------------------------------------------------------
// kernel_launch
// ---------------------------------------------------------------------------
extern "C" void kernel_launch(void* const* d_in, const int* in_sizes, int n_in,
                              void* d_out, int out_size)
{
    const float* q      = (const float*)d_in[0];
    const float* k      = (const float*)d_in[1];
    const float* v      = (const float*)d_in[2];
    const int*   q_mask = (const int*)  d_in[3];
    const int*   v_mask = (const int*)  d_in[4];
    const float* Wq     = (const float*)d_in[5];
    const float* bq     = (const float*)d_in[6];
    const float* Wk     = (const float*)d_in[7];
    const float* bk     = (const float*)d_in[8];
    const float* Wv     = (const float*)d_in[9];
    const float* bv     = (const float*)d_in[10];
    const float* Wo     = (const float*)d_in[11];
    const float* bo     = (const float*)d_in[12];
    float* out = (float*)d_out;

    float *gq, *gk, *gv, *go;
    __nv_bfloat16 *ahi, *alo, *whi, *wlo;
    cudaGetSymbolAddress((void**)&gq, g_Q);
    cudaGetSymbolAddress((void**)&gk, g_K);
    cudaGetSymbolAddress((void**)&gv, g_V);
    cudaGetSymbolAddress((void**)&go, g_O);
    cudaGetSymbolAddress((void**)&ahi, g_Ahi);
    cudaGetSymbolAddress((void**)&alo, g_Alo);
    cudaGetSymbolAddress((void**)&whi, g_Whi);
    cudaGetSymbolAddress((void**)&wlo, g_Wlo);

    const int GEMM_SMEM = NSTAGE * STAGE_B;   // 196608
    cudaFuncSetAttribute(gemm_mma<false>,
                         cudaFuncAttributeMaxDynamicSharedMemorySize, GEMM_SMEM);
    cudaFuncSetAttribute(gemm_mma<true>,
                         cudaFuncAttributeMaxDynamicSharedMemorySize, GEMM_SMEM);

    dim3 gemm_grid(DD / 128, MM / 128);     // (8, 64)
    dim3 tr_grid(DD / 32, DD / 32);         // (32, 32)
    const int n4 = MM * DD / 4;
    const int split_blocks = (n4 + 255) / 256;

    // Q projection
    split_kernel<<<split_blocks, 256>>>(q, ahi, alo, n4);
    wsplit_transpose_kernel<<<tr_grid, 256>>>(Wq, whi, wlo);
    gemm_mma<false><<<gemm_grid, 256, GEMM_SMEM>>>(ahi, alo, whi, wlo, bq, nullptr, gq);
    // K projection
    split_kernel<<<split_blocks, 256>>>(k, ahi, alo, n4);
    wsplit_transpose_kernel<<<tr_grid, 256>>>(Wk, whi, wlo);
    gemm_mma<false><<<gemm_grid, 256, GEMM_SMEM>>>(ahi, alo, whi, wlo, bk, nullptr, gk);
    // V projection
    split_kernel<<<split_blocks, 256>>>(v, ahi, alo, n4);
    wsplit_transpose_kernel<<<tr_grid, 256>>>(Wv, whi, wlo);
    gemm_mma<false><<<gemm_grid, 256, GEMM_SMEM>>>(ahi, alo, whi, wlo, bv, nullptr, gv);

    // Attention
    const int ATTN_SMEM = (64 * QK_STRIDE * 2 + 128 * 64 + 128 * 132) * 4 + 128 * 4;
    cudaFuncSetAttribute(attn_kernel,
                         cudaFuncAttributeMaxDynamicSharedMemorySize, ATTN_SMEM);
    attn_kernel<<<dim3(SS / 128, BB * HH), 256, ATTN_SMEM>>>(v_mask);

    // Output projection (+ q_mask)
    split_kernel<<<split_blocks, 256>>>(go, ahi, alo, n4);
    wsplit_transpose_kernel<<<tr_grid, 256>>>(Wo, whi, wlo);
    gemm_mma<true><<<gemm_grid, 256, GEMM_SMEM>>>(ahi, alo, whi, wlo, bo, q_mask, out);
}

// round 5
// speedup vs baseline: 2.2964x; 1.4264x over previous
#include <cuda_runtime.h>
#include <cuda_bf16.h>
#include <cstdint>

// Problem constants
#define BB 4
#define SS 2048
#define DD 1024
#define HH 16
#define MM (BB*SS)          // 8192 rows

// Scratch (device globals: allocation-free)
__device__ float g_Q[MM * DD];
__device__ float g_K[MM * DD];
__device__ float g_V[MM * DD];
__device__ float g_O[MM * DD];
__device__ __nv_bfloat16 g_Ahi[MM * DD];
__device__ __nv_bfloat16 g_Alo[MM * DD];
__device__ __nv_bfloat16 g_Whi[DD * DD];   // transposed: [N, K]
__device__ __nv_bfloat16 g_Wlo[DD * DD];   // transposed: [N, K]

// ---------------------------------------------------------------------------
// Portable (sm_80+) tensor-core helpers: mma.sync + ldmatrix + cp.async
// ---------------------------------------------------------------------------
__device__ __forceinline__ uint32_t smem_u32(const void* p) {
    uint32_t a;
    asm("{ .reg .u64 t; cvta.to.shared.u64 t, %1; cvt.u32.u64 %0, t; }"
        : "=r"(a) : "l"(p));
    return a;
}

__device__ __forceinline__ void ldsm4(uint32_t* r, uint32_t addr) {
    asm volatile("ldmatrix.sync.aligned.m8n8.x4.shared.b16 {%0,%1,%2,%3}, [%4];"
        : "=r"(r[0]), "=r"(r[1]), "=r"(r[2]), "=r"(r[3]) : "r"(addr));
}

__device__ __forceinline__ void mma16816(float* c, const uint32_t* a,
                                         const uint32_t* b) {
    asm volatile(
        "mma.sync.aligned.m16n8k16.row.col.f32.bf16.bf16.f32 "
        "{%0,%1,%2,%3}, {%4,%5,%6,%7}, {%8,%9}, {%0,%1,%2,%3};"
        : "+f"(c[0]), "+f"(c[1]), "+f"(c[2]), "+f"(c[3])
        : "r"(a[0]), "r"(a[1]), "r"(a[2]), "r"(a[3]), "r"(b[0]), "r"(b[1]));
}

__device__ __forceinline__ void cp16(uint32_t saddr, const void* g) {
    asm volatile("cp.async.cg.shared.global [%0], [%1], 16;"
                 :: "r"(saddr), "l"(g) : "memory");
}
#define CP_COMMIT() asm volatile("cp.async.commit_group;" ::: "memory")
#define CP_WAIT2()  asm volatile("cp.async.wait_group 2;" ::: "memory")

// SW128 swizzle on byte offsets within a tile (rows of 128B)
#define SWZ(o) ((o) ^ (((o) >> 3) & 0x70))

__device__ __forceinline__ uint32_t pack_bf2(float a, float b) {
    __nv_bfloat162 t = __floats2bfloat162_rn(a, b);
    return *(uint32_t*)&t;
}
__device__ __forceinline__ void split_bf(float v, uint16_t& h, uint16_t& l) {
    __nv_bfloat16 hb = __float2bfloat16(v);
    __nv_bfloat16 lb = __float2bfloat16(v - __bfloat162float(hb));
    h = *(uint16_t*)&hb; l = *(uint16_t*)&lb;
}

// ---------------------------------------------------------------------------
// Split-precision conversions
// ---------------------------------------------------------------------------
__global__ __launch_bounds__(256)
void split_kernel(const float* __restrict__ x,
                  __nv_bfloat16* __restrict__ hi,
                  __nv_bfloat16* __restrict__ lo, int n4)
{
    int i = blockIdx.x * blockDim.x + threadIdx.x;
    if (i >= n4) return;
    float4 v = ((const float4*)x)[i];
    __nv_bfloat16 h0 = __float2bfloat16(v.x);
    __nv_bfloat16 h1 = __float2bfloat16(v.y);
    __nv_bfloat16 h2 = __float2bfloat16(v.z);
    __nv_bfloat16 h3 = __float2bfloat16(v.w);
    __nv_bfloat16 l0 = __float2bfloat16(v.x - __bfloat162float(h0));
    __nv_bfloat16 l1 = __float2bfloat16(v.y - __bfloat162float(h1));
    __nv_bfloat16 l2 = __float2bfloat16(v.z - __bfloat162float(h2));
    __nv_bfloat16 l3 = __float2bfloat16(v.w - __bfloat162float(h3));
    __nv_bfloat162* hp = (__nv_bfloat162*)(hi + (size_t)i * 4);
    __nv_bfloat162* lp = (__nv_bfloat162*)(lo + (size_t)i * 4);
    hp[0] = __nv_bfloat162(h0, h1); hp[1] = __nv_bfloat162(h2, h3);
    lp[0] = __nv_bfloat162(l0, l1); lp[1] = __nv_bfloat162(l2, l3);
}

// W[K,N] fp32 -> Whi/Wlo [N,K] bf16 (transposed), 32x32 tiles
__global__ __launch_bounds__(256)
void wsplit_transpose_kernel(const float* __restrict__ W,
                             __nv_bfloat16* __restrict__ hi,
                             __nv_bfloat16* __restrict__ lo)
{
    __shared__ float t[32][33];
    int tx = threadIdx.x & 31;
    int ty = threadIdx.x >> 5;      // 0..7
    int n0 = blockIdx.x * 32;
    int k0 = blockIdx.y * 32;
#pragma unroll
    for (int i = 0; i < 4; i++)
        t[ty + 8 * i][tx] = W[(size_t)(k0 + ty + 8 * i) * DD + n0 + tx];
    __syncthreads();
#pragma unroll
    for (int i = 0; i < 4; i++) {
        int n = ty + 8 * i;
        float v = t[tx][n];
        __nv_bfloat16 h = __float2bfloat16(v);
        __nv_bfloat16 l = __float2bfloat16(v - __bfloat162float(h));
        hi[(size_t)(n0 + n) * DD + k0 + tx] = h;
        lo[(size_t)(n0 + n) * DD + k0 + tx] = l;
    }
}

// ---------------------------------------------------------------------------
// Split-bf16 tensor-core GEMM (mma.sync) — unchanged from R4 (passing).
// ---------------------------------------------------------------------------
#define BK 64
#define TILE_B 16384            // 128 rows * 128 bytes
#define STAGE_B (4 * TILE_B)    // Ahi, Alo, Bhi, Blo
#define NSTAGE 3
#define NK (DD / BK)            // 16

template<bool QMASK>
__global__ __launch_bounds__(256)
void gemm_mma(const __nv_bfloat16* __restrict__ Ahi,
              const __nv_bfloat16* __restrict__ Alo,
              const __nv_bfloat16* __restrict__ Bhi,
              const __nv_bfloat16* __restrict__ Blo,
              const float* __restrict__ bias,
              const int* __restrict__ qmask,
              float* __restrict__ C)
{
    extern __shared__ char smc[];
    const uint32_t sbase = smem_u32(smc);

    const int tid  = threadIdx.x;
    const int lane = tid & 31;
    const int wid  = tid >> 5;
    const int wm   = wid & 1;
    const int wn   = wid >> 1;
    const int m0 = blockIdx.y * 128;
    const int n0 = blockIdx.x * 128;

    const char* srcs[4] = { (const char*)Ahi, (const char*)Alo,
                            (const char*)Bhi, (const char*)Blo };

    auto load_stage = [&](int it, int s) {
        const int kc = it * BK;
        const uint32_t stb = sbase + s * STAGE_B;
#pragma unroll
        for (int t = 0; t < 4; t++) {
            const int row0 = (t < 2) ? m0 : n0;
            const char* src = srcs[t];
#pragma unroll
            for (int i = 0; i < 4; i++) {
                int u = tid + i * 256;
                int r = u >> 3;
                int c = u & 7;
                const void* g = src + ((size_t)(row0 + r) * DD + kc) * 2 + c * 16;
                uint32_t off = (uint32_t)(r * 128 + c * 16);
                cp16(stb + t * TILE_B + SWZ(off), g);
            }
        }
    };

    float acc[4][4][4];
#pragma unroll
    for (int mt = 0; mt < 4; mt++)
#pragma unroll
        for (int nt = 0; nt < 4; nt++)
#pragma unroll
            for (int e = 0; e < 4; e++) acc[mt][nt][e] = 0.0f;

    load_stage(0, 0); CP_COMMIT();
    load_stage(1, 1); CP_COMMIT();

    const int a_row = wm * 64 + (lane & 15);
    const uint32_t a_bc = (uint32_t)((lane >> 4) << 4);
    const int b_row = wn * 32 + ((lane & 16) >> 1) + (lane & 7);
    const uint32_t b_bc = (uint32_t)((lane & 8) << 1);

    for (int it = 0; it < NK; it++) {
        if (it + 2 < NK) load_stage(it + 2, (it + 2) % NSTAGE);
        CP_COMMIT();
        CP_WAIT2();
        __syncthreads();

        const uint32_t stb = sbase + (it % NSTAGE) * STAGE_B;
        const uint32_t tAh = stb + 0 * TILE_B;
        const uint32_t tAl = stb + 1 * TILE_B;
        const uint32_t tBh = stb + 2 * TILE_B;
        const uint32_t tBl = stb + 3 * TILE_B;

#pragma unroll
        for (int term = 0; term < 3; term++) {
            const uint32_t aT = (term == 2) ? tAl : tAh;
            const uint32_t bT = (term == 1) ? tBl : tBh;
#pragma unroll
            for (int ks = 0; ks < 4; ks++) {
                uint32_t af[4][4];
#pragma unroll
                for (int mt = 0; mt < 4; mt++) {
                    uint32_t off = (uint32_t)((a_row + mt * 16) * 128) +
                                   (uint32_t)(ks * 32) + a_bc;
                    ldsm4(af[mt], aT + SWZ(off));
                }
#pragma unroll
                for (int np = 0; np < 2; np++) {
                    uint32_t bf[4];
                    uint32_t off = (uint32_t)((b_row + np * 16) * 128) +
                                   (uint32_t)(ks * 32) + b_bc;
                    ldsm4(bf, bT + SWZ(off));
#pragma unroll
                    for (int mt = 0; mt < 4; mt++) {
                        mma16816(acc[mt][np * 2 + 0], af[mt], bf);
                        mma16816(acc[mt][np * 2 + 1], af[mt], bf + 2);
                    }
                }
            }
        }
        __syncthreads();
    }

    const int col_base = n0 + wn * 32 + ((lane & 3) << 1);
    const int row_base = m0 + wm * 64 + (lane >> 2);
#pragma unroll
    for (int nt = 0; nt < 4; nt++) {
        const int col = col_base + nt * 8;
        const float b0 = bias[col];
        const float b1 = bias[col + 1];
#pragma unroll
        for (int mt = 0; mt < 4; mt++) {
            int r0 = row_base + mt * 16;
            float qm0 = 1.0f, qm1 = 1.0f;
            if (QMASK) { qm0 = (float)qmask[r0]; qm1 = (float)qmask[r0 + 8]; }
            float2 v0 = make_float2((acc[mt][nt][0] + b0) * qm0,
                                    (acc[mt][nt][1] + b1) * qm0);
            float2 v1 = make_float2((acc[mt][nt][2] + b0) * qm1,
                                    (acc[mt][nt][3] + b1) * qm1);
            *(float2*)&C[(size_t)r0 * DD + col] = v0;
            *(float2*)&C[(size_t)(r0 + 8) * DD + col] = v1;
        }
    }
}

// ---------------------------------------------------------------------------
// Tensor-core flash attention (mma.sync, split-bf16 QK^T and PV).
// 256 threads = 8 warps; warp w owns q rows w*16..w*16+15 of a 128-row tile.
// ---------------------------------------------------------------------------
// SMEM layout (byte offsets)
#define AT_QH 0
#define AT_QL 16384
#define AT_KH 32768
#define AT_KL 49152
#define AT_VH 65536          // Vt hi: [64 d][136 j] bf16, row stride 272B
#define AT_VL 82944          // Vt lo
#define AT_VM 100352         // float[128] additive mask
#define AT_SMEM 100864
#define VT_ROW 272

__global__ __launch_bounds__(256)
void attn_mma(const int* __restrict__ v_mask)
{
    extern __shared__ char smc[];
    const uint32_t sb = smem_u32(smc);

    const int tid  = threadIdx.x;
    const int lane = tid & 31;
    const int w    = tid >> 5;
    const int bh = blockIdx.y;
    const int b  = bh >> 4;
    const int h  = bh & 15;
    const int qt = gridDim.x - 1 - blockIdx.x;   // heavy tiles first
    const int q0 = qt * 128;
    const float scale = 0.125f;

    // ---- load Q tile (128 x 64 fp32) -> Qh/Ql bf16 SW128 ----
#pragma unroll
    for (int t = 0; t < 8; t++) {
        int idx = tid + t * 256;
        int i  = idx >> 4;
        int d4 = idx & 15;
        float4 v = *(const float4*)&g_Q[(size_t)(b * SS + q0 + i) * DD + h * 64 + d4 * 4];
        uint16_t h0, l0, h1, l1, h2, l2, h3, l3;
        split_bf(v.x, h0, l0); split_bf(v.y, h1, l1);
        split_bf(v.z, h2, l2); split_bf(v.w, h3, l3);
        uint32_t off = SWZ((uint32_t)(i * 128 + d4 * 8));
        *(uint32_t*)(smc + AT_QH + off)     = (uint32_t)h0 | ((uint32_t)h1 << 16);
        *(uint32_t*)(smc + AT_QH + off + 4) = (uint32_t)h2 | ((uint32_t)h3 << 16);
        *(uint32_t*)(smc + AT_QL + off)     = (uint32_t)l0 | ((uint32_t)l1 << 16);
        *(uint32_t*)(smc + AT_QL + off + 4) = (uint32_t)l2 | ((uint32_t)l3 << 16);
    }

    // fragment address components
    const int a_row = w * 16 + (lane & 15);
    const uint32_t a_bc = (uint32_t)((lane >> 4) << 4);
    const int b_rp  = ((lane & 16) >> 1) + (lane & 7);
    const uint32_t b_bc = (uint32_t)((lane & 8) << 1);

    float o[8][4];
#pragma unroll
    for (int nt = 0; nt < 8; nt++)
#pragma unroll
        for (int e = 0; e < 4; e++) o[nt][e] = 0.0f;
    float m_lo = -1e30f, m_hi = -1e30f, l_lo = 0.0f, l_hi = 0.0f;

    const int r = lane >> 2;
    const int qi_lo = q0 + w * 16 + r;
    const int qi_hi = qi_lo + 8;
    const int jc = (lane & 3) * 2;   // column offset within 8-col n-tile

    const int nkt = qt + 1;
    for (int kt = 0; kt < nkt; kt++) {
        __syncthreads();
        // ---- load K tile -> Kh/Kl ; V tile -> VtH/VtL (transposed) ----
#pragma unroll
        for (int t = 0; t < 8; t++) {
            int idx = tid + t * 256;
            int j  = idx >> 4;
            int d4 = idx & 15;
            size_t grow = (size_t)(b * SS + kt * 128 + j) * DD + h * 64 + d4 * 4;
            float4 kv = *(const float4*)&g_K[grow];
            uint16_t h0, l0, h1, l1, h2, l2, h3, l3;
            split_bf(kv.x, h0, l0); split_bf(kv.y, h1, l1);
            split_bf(kv.z, h2, l2); split_bf(kv.w, h3, l3);
            uint32_t off = SWZ((uint32_t)(j * 128 + d4 * 8));
            *(uint32_t*)(smc + AT_KH + off)     = (uint32_t)h0 | ((uint32_t)h1 << 16);
            *(uint32_t*)(smc + AT_KH + off + 4) = (uint32_t)h2 | ((uint32_t)h3 << 16);
            *(uint32_t*)(smc + AT_KL + off)     = (uint32_t)l0 | ((uint32_t)l1 << 16);
            *(uint32_t*)(smc + AT_KL + off + 4) = (uint32_t)l2 | ((uint32_t)l3 << 16);

            float4 vv = *(const float4*)&g_V[grow];
            float vals[4] = { vv.x, vv.y, vv.z, vv.w };
#pragma unroll
            for (int e = 0; e < 4; e++) {
                uint16_t vh, vl;
                split_bf(vals[e], vh, vl);
                int d = d4 * 4 + e;
                *(uint16_t*)(smc + AT_VH + d * VT_ROW + j * 2) = vh;
                *(uint16_t*)(smc + AT_VL + d * VT_ROW + j * 2) = vl;
            }
        }
        if (tid < 128) {
            ((float*)(smc + AT_VM))[tid] =
                v_mask[b * SS + kt * 128 + tid] ? 0.0f : -1e12f;
        }
        __syncthreads();

        // ---- S = Q K^T, 3-term split bf16 ----
        float s[16][4];
#pragma unroll
        for (int nt = 0; nt < 16; nt++)
#pragma unroll
            for (int e = 0; e < 4; e++) s[nt][e] = 0.0f;

#pragma unroll
        for (int term = 0; term < 3; term++) {
            const uint32_t aT = sb + ((term == 2) ? AT_QL : AT_QH);
            const uint32_t bT = sb + ((term == 1) ? AT_KL : AT_KH);
#pragma unroll
            for (int ks = 0; ks < 4; ks++) {
                uint32_t af[4];
                ldsm4(af, aT + SWZ((uint32_t)(a_row * 128 + ks * 32) + a_bc));
#pragma unroll
                for (int np = 0; np < 8; np++) {
                    uint32_t bf[4];
                    ldsm4(bf, bT + SWZ((uint32_t)((np * 16 + b_rp) * 128 + ks * 32) + b_bc));
                    mma16816(s[np * 2 + 0], af, bf);
                    mma16816(s[np * 2 + 1], af, bf + 2);
                }
            }
        }

        // ---- mask + online softmax ----
        const bool diag = (kt == qt);
        const float* mvm = (const float*)(smc + AT_VM);
        float mx_lo = -1e30f, mx_hi = -1e30f;
#pragma unroll
        for (int nt = 0; nt < 16; nt++) {
            int jl = nt * 8 + jc;
            int jg = kt * 128 + jl;
            float a0 = mvm[jl], a1 = mvm[jl + 1];
            float v0 = s[nt][0] * scale + a0;
            float v1 = s[nt][1] * scale + a1;
            float v2 = s[nt][2] * scale + a0;
            float v3 = s[nt][3] * scale + a1;
            if (diag) {
                if (jg     > qi_lo) v0 = -1e12f;
                if (jg + 1 > qi_lo) v1 = -1e12f;
                if (jg     > qi_hi) v2 = -1e12f;
                if (jg + 1 > qi_hi) v3 = -1e12f;
            }
            s[nt][0] = v0; s[nt][1] = v1; s[nt][2] = v2; s[nt][3] = v3;
            mx_lo = fmaxf(mx_lo, fmaxf(v0, v1));
            mx_hi = fmaxf(mx_hi, fmaxf(v2, v3));
        }
        mx_lo = fmaxf(mx_lo, __shfl_xor_sync(0xffffffffu, mx_lo, 1));
        mx_lo = fmaxf(mx_lo, __shfl_xor_sync(0xffffffffu, mx_lo, 2));
        mx_hi = fmaxf(mx_hi, __shfl_xor_sync(0xffffffffu, mx_hi, 1));
        mx_hi = fmaxf(mx_hi, __shfl_xor_sync(0xffffffffu, mx_hi, 2));

        float mn_lo = fmaxf(m_lo, mx_lo);
        float mn_hi = fmaxf(m_hi, mx_hi);
        float corr_lo = __expf(m_lo - mn_lo);
        float corr_hi = __expf(m_hi - mn_hi);
        m_lo = mn_lo; m_hi = mn_hi;

        float sum_lo = 0.0f, sum_hi = 0.0f;
#pragma unroll
        for (int nt = 0; nt < 16; nt++) {
            float p0 = __expf(s[nt][0] - mn_lo);
            float p1 = __expf(s[nt][1] - mn_lo);
            float p2 = __expf(s[nt][2] - mn_hi);
            float p3 = __expf(s[nt][3] - mn_hi);
            s[nt][0] = p0; s[nt][1] = p1; s[nt][2] = p2; s[nt][3] = p3;
            sum_lo += p0 + p1;
            sum_hi += p2 + p3;
        }
        sum_lo += __shfl_xor_sync(0xffffffffu, sum_lo, 1);
        sum_lo += __shfl_xor_sync(0xffffffffu, sum_lo, 2);
        sum_hi += __shfl_xor_sync(0xffffffffu, sum_hi, 1);
        sum_hi += __shfl_xor_sync(0xffffffffu, sum_hi, 2);
        l_lo = l_lo * corr_lo + sum_lo;
        l_hi = l_hi * corr_hi + sum_hi;

#pragma unroll
        for (int nt = 0; nt < 8; nt++) {
            o[nt][0] *= corr_lo; o[nt][1] *= corr_lo;
            o[nt][2] *= corr_hi; o[nt][3] *= corr_hi;
        }

        // ---- O += P V, 3-term split bf16 ----
#pragma unroll
        for (int ks = 0; ks < 8; ks++) {
            // pack P fragments (hi & lo) from s[2ks], s[2ks+1]
            uint32_t ah[4], al[4];
            {
                uint16_t h0, l0, h1, l1;
                split_bf(s[2*ks][0], h0, l0); split_bf(s[2*ks][1], h1, l1);
                ah[0] = (uint32_t)h0 | ((uint32_t)h1 << 16);
                al[0] = (uint32_t)l0 | ((uint32_t)l1 << 16);
                split_bf(s[2*ks][2], h0, l0); split_bf(s[2*ks][3], h1, l1);
                ah[1] = (uint32_t)h0 | ((uint32_t)h1 << 16);
                al[1] = (uint32_t)l0 | ((uint32_t)l1 << 16);
                split_bf(s[2*ks+1][0], h0, l0); split_bf(s[2*ks+1][1], h1, l1);
                ah[2] = (uint32_t)h0 | ((uint32_t)h1 << 16);
                al[2] = (uint32_t)l0 | ((uint32_t)l1 << 16);
                split_bf(s[2*ks+1][2], h0, l0); split_bf(s[2*ks+1][3], h1, l1);
                ah[3] = (uint32_t)h0 | ((uint32_t)h1 << 16);
                al[3] = (uint32_t)l0 | ((uint32_t)l1 << 16);
            }
#pragma unroll
            for (int np = 0; np < 4; np++) {
                uint32_t addr = (uint32_t)((np * 16 + b_rp) * VT_ROW + ks * 32) + b_bc;
                uint32_t bfh[4], bfl[4];
                ldsm4(bfh, sb + AT_VH + addr);
                ldsm4(bfl, sb + AT_VL + addr);
                mma16816(o[np * 2 + 0], ah, bfh);
                mma16816(o[np * 2 + 1], ah, bfh + 2);
                mma16816(o[np * 2 + 0], al, bfh);
                mma16816(o[np * 2 + 1], al, bfh + 2);
                mma16816(o[np * 2 + 0], ah, bfl);
                mma16816(o[np * 2 + 1], ah, bfl + 2);
            }
        }
    }

    // ---- normalize + store ----
    float inv_lo = 1.0f / l_lo;
    float inv_hi = 1.0f / l_hi;
    const size_t row_lo = (size_t)(b * SS + q0 + w * 16 + r) * DD + h * 64;
    const size_t row_hi = row_lo + 8 * DD;
#pragma unroll
    for (int nt = 0; nt < 8; nt++) {
        int d0 = nt * 8 + jc;
        *(float2*)&g_O[row_lo + d0] = make_float2(o[nt][0] * inv_lo, o[nt][1] * inv_lo);
        *(float2*)&g_O[row_hi + d0] = make_float2(o[nt][2] * inv_hi, o[nt][3] * inv_hi);
    }
}

// ---------------------------------------------------------------------------
// kernel_launch
// ---------------------------------------------------------------------------
extern "C" void kernel_launch(void* const* d_in, const int* in_sizes, int n_in,
                              void* d_out, int out_size)
{
    const float* q      = (const float*)d_in[0];
    const float* k      = (const float*)d_in[1];
    const float* v      = (const float*)d_in[2];
    const int*   q_mask = (const int*)  d_in[3];
    const int*   v_mask = (const int*)  d_in[4];
    const float* Wq     = (const float*)d_in[5];
    const float* bq     = (const float*)d_in[6];
    const float* Wk     = (const float*)d_in[7];
    const float* bk     = (const float*)d_in[8];
    const float* Wv     = (const float*)d_in[9];
    const float* bv     = (const float*)d_in[10];
    const float* Wo     = (const float*)d_in[11];
    const float* bo     = (const float*)d_in[12];
    float* out = (float*)d_out;

    float *gq, *gk, *gv, *go;
    __nv_bfloat16 *ahi, *alo, *whi, *wlo;
    cudaGetSymbolAddress((void**)&gq, g_Q);
    cudaGetSymbolAddress((void**)&gk, g_K);
    cudaGetSymbolAddress((void**)&gv, g_V);
    cudaGetSymbolAddress((void**)&go, g_O);
    cudaGetSymbolAddress((void**)&ahi, g_Ahi);
    cudaGetSymbolAddress((void**)&alo, g_Alo);
    cudaGetSymbolAddress((void**)&whi, g_Whi);
    cudaGetSymbolAddress((void**)&wlo, g_Wlo);

    const int GEMM_SMEM = NSTAGE * STAGE_B;   // 196608
    cudaFuncSetAttribute(gemm_mma<false>,
                         cudaFuncAttributeMaxDynamicSharedMemorySize, GEMM_SMEM);
    cudaFuncSetAttribute(gemm_mma<true>,
                         cudaFuncAttributeMaxDynamicSharedMemorySize, GEMM_SMEM);
    cudaFuncSetAttribute(attn_mma,
                         cudaFuncAttributeMaxDynamicSharedMemorySize, AT_SMEM);

    dim3 gemm_grid(DD / 128, MM / 128);     // (8, 64)
    dim3 tr_grid(DD / 32, DD / 32);         // (32, 32)
    const int n4 = MM * DD / 4;
    const int split_blocks = (n4 + 255) / 256;

    // Q projection
    split_kernel<<<split_blocks, 256>>>(q, ahi, alo, n4);
    wsplit_transpose_kernel<<<tr_grid, 256>>>(Wq, whi, wlo);
    gemm_mma<false><<<gemm_grid, 256, GEMM_SMEM>>>(ahi, alo, whi, wlo, bq, nullptr, gq);
    // K projection
    split_kernel<<<split_blocks, 256>>>(k, ahi, alo, n4);
    wsplit_transpose_kernel<<<tr_grid, 256>>>(Wk, whi, wlo);
    gemm_mma<false><<<gemm_grid, 256, GEMM_SMEM>>>(ahi, alo, whi, wlo, bk, nullptr, gk);
    // V projection
    split_kernel<<<split_blocks, 256>>>(v, ahi, alo, n4);
    wsplit_transpose_kernel<<<tr_grid, 256>>>(Wv, whi, wlo);
    gemm_mma<false><<<gemm_grid, 256, GEMM_SMEM>>>(ahi, alo, whi, wlo, bv, nullptr, gv);

    // Attention (tensor-core)
    attn_mma<<<dim3(SS / 128, BB * HH), 256, AT_SMEM>>>(v_mask);

    // Output projection (+ q_mask)
    split_kernel<<<split_blocks, 256>>>(go, ahi, alo, n4);
    wsplit_transpose_kernel<<<tr_grid, 256>>>(Wo, whi, wlo);
    gemm_mma<true><<<gemm_grid, 256, GEMM_SMEM>>>(ahi, alo, whi, wlo, bo, q_mask, out);
}

// round 6
// speedup vs baseline: 2.5887x; 1.1273x over previous
#include <cuda_runtime.h>
#include <cuda_bf16.h>
#include <cstdint>

// Problem constants
#define BB 4
#define SS 2048
#define DD 1024
#define HH 16
#define MM (BB*SS)          // 8192 rows

// Scratch (device globals: allocation-free). All interchange in split bf16.
__device__ __nv_bfloat16 g_Ahi[MM * DD];
__device__ __nv_bfloat16 g_Alo[MM * DD];
__device__ __nv_bfloat16 g_Whi[DD * DD];   // transposed weights: [N, K]
__device__ __nv_bfloat16 g_Wlo[DD * DD];
__device__ __nv_bfloat16 g_Qhi[MM * DD];   // [row][h*64+d]
__device__ __nv_bfloat16 g_Qlo[MM * DD];
__device__ __nv_bfloat16 g_Khi[MM * DD];
__device__ __nv_bfloat16 g_Klo[MM * DD];
__device__ __nv_bfloat16 g_Vthi[MM * DD];  // transposed: [(b*16+h)*64+d][S]
__device__ __nv_bfloat16 g_Vtlo[MM * DD];
__device__ __nv_bfloat16 g_Ohi[MM * DD];   // attention output, split
__device__ __nv_bfloat16 g_Olo[MM * DD];

// ---------------------------------------------------------------------------
// Helpers: mma.sync + ldmatrix + cp.async (portable sm_80+ path; tcgen05 is
// rejected by the harness's compute_103 virtual arch)
// ---------------------------------------------------------------------------
__device__ __forceinline__ uint32_t smem_u32(const void* p) {
    uint32_t a;
    asm("{ .reg .u64 t; cvta.to.shared.u64 t, %1; cvt.u32.u64 %0, t; }"
        : "=r"(a) : "l"(p));
    return a;
}

__device__ __forceinline__ void ldsm4(uint32_t* r, uint32_t addr) {
    asm volatile("ldmatrix.sync.aligned.m8n8.x4.shared.b16 {%0,%1,%2,%3}, [%4];"
        : "=r"(r[0]), "=r"(r[1]), "=r"(r[2]), "=r"(r[3]) : "r"(addr));
}

__device__ __forceinline__ void mma16816(float* c, const uint32_t* a,
                                         const uint32_t* b) {
    asm volatile(
        "mma.sync.aligned.m16n8k16.row.col.f32.bf16.bf16.f32 "
        "{%0,%1,%2,%3}, {%4,%5,%6,%7}, {%8,%9}, {%0,%1,%2,%3};"
        : "+f"(c[0]), "+f"(c[1]), "+f"(c[2]), "+f"(c[3])
        : "r"(a[0]), "r"(a[1]), "r"(a[2]), "r"(a[3]), "r"(b[0]), "r"(b[1]));
}

__device__ __forceinline__ void cp16(uint32_t saddr, const void* g) {
    asm volatile("cp.async.cg.shared.global [%0], [%1], 16;"
                 :: "r"(saddr), "l"(g) : "memory");
}
#define CP_COMMIT() asm volatile("cp.async.commit_group;" ::: "memory")
#define CP_WAIT2()  asm volatile("cp.async.wait_group 2;" ::: "memory")
#define CP_WAIT1()  asm volatile("cp.async.wait_group 1;" ::: "memory")

// SW128 swizzle on byte offsets within a tile (rows of 128B)
#define SWZ(o) ((o) ^ (((o) >> 3) & 0x70))

__device__ __forceinline__ void split_bf(float v, uint16_t& h, uint16_t& l) {
    __nv_bfloat16 hb = __float2bfloat16(v);
    __nv_bfloat16 lb = __float2bfloat16(v - __bfloat162float(hb));
    h = *(uint16_t*)&hb; l = *(uint16_t*)&lb;
}

// ---------------------------------------------------------------------------
// Split-precision conversions (inputs + weights)
// ---------------------------------------------------------------------------
__global__ __launch_bounds__(256)
void split_kernel(const float* __restrict__ x,
                  __nv_bfloat16* __restrict__ hi,
                  __nv_bfloat16* __restrict__ lo, int n4)
{
    int i = blockIdx.x * blockDim.x + threadIdx.x;
    if (i >= n4) return;
    float4 v = ((const float4*)x)[i];
    uint16_t h0,l0,h1,l1,h2,l2,h3,l3;
    split_bf(v.x,h0,l0); split_bf(v.y,h1,l1);
    split_bf(v.z,h2,l2); split_bf(v.w,h3,l3);
    uint2 hv = make_uint2((uint32_t)h0|((uint32_t)h1<<16),
                          (uint32_t)h2|((uint32_t)h3<<16));
    uint2 lv = make_uint2((uint32_t)l0|((uint32_t)l1<<16),
                          (uint32_t)l2|((uint32_t)l3<<16));
    *(uint2*)(hi + (size_t)i * 4) = hv;
    *(uint2*)(lo + (size_t)i * 4) = lv;
}

// W[K,N] fp32 -> Whi/Wlo [N,K] bf16 (transposed), 32x32 tiles
__global__ __launch_bounds__(256)
void wsplit_transpose_kernel(const float* __restrict__ W,
                             __nv_bfloat16* __restrict__ hi,
                             __nv_bfloat16* __restrict__ lo)
{
    __shared__ float t[32][33];
    int tx = threadIdx.x & 31;
    int ty = threadIdx.x >> 5;
    int n0 = blockIdx.x * 32;
    int k0 = blockIdx.y * 32;
#pragma unroll
    for (int i = 0; i < 4; i++)
        t[ty + 8 * i][tx] = W[(size_t)(k0 + ty + 8 * i) * DD + n0 + tx];
    __syncthreads();
#pragma unroll
    for (int i = 0; i < 4; i++) {
        int n = ty + 8 * i;
        float v = t[tx][n];
        uint16_t h, l;
        split_bf(v, h, l);
        *(uint16_t*)&hi[(size_t)(n0 + n) * DD + k0 + tx] = h;
        *(uint16_t*)&lo[(size_t)(n0 + n) * DD + k0 + tx] = l;
    }
}

// ---------------------------------------------------------------------------
// Split-bf16 tensor-core GEMM (mma.sync).
// Output modes: 0 = fp32 + qmask (final), 1 = split bf16 (Q/K), 2 = split
// bf16 transposed [(b*16+h)*64+d][S] (V).
// ---------------------------------------------------------------------------
#define BK 64
#define TILE_B 16384
#define STAGE_B (4 * TILE_B)
#define NSTAGE 3
#define NK (DD / BK)            // 16

template<int MODE>
__global__ __launch_bounds__(256)
void gemm_mma(const __nv_bfloat16* __restrict__ Ahi,
              const __nv_bfloat16* __restrict__ Alo,
              const __nv_bfloat16* __restrict__ Bhi,
              const __nv_bfloat16* __restrict__ Blo,
              const float* __restrict__ bias,
              const int* __restrict__ qmask,
              float* __restrict__ C,
              __nv_bfloat16* __restrict__ Chi,
              __nv_bfloat16* __restrict__ Clo)
{
    extern __shared__ char smc[];
    const uint32_t sbase = smem_u32(smc);

    const int tid  = threadIdx.x;
    const int lane = tid & 31;
    const int wid  = tid >> 5;
    const int wm   = wid & 1;
    const int wn   = wid >> 1;
    const int m0 = blockIdx.y * 128;
    const int n0 = blockIdx.x * 128;

    const char* srcs[4] = { (const char*)Ahi, (const char*)Alo,
                            (const char*)Bhi, (const char*)Blo };

    auto load_stage = [&](int it, int s) {
        const int kc = it * BK;
        const uint32_t stb = sbase + s * STAGE_B;
#pragma unroll
        for (int t = 0; t < 4; t++) {
            const int row0 = (t < 2) ? m0 : n0;
            const char* src = srcs[t];
#pragma unroll
            for (int i = 0; i < 4; i++) {
                int u = tid + i * 256;
                int r = u >> 3;
                int c = u & 7;
                const void* g = src + ((size_t)(row0 + r) * DD + kc) * 2 + c * 16;
                uint32_t off = (uint32_t)(r * 128 + c * 16);
                cp16(stb + t * TILE_B + SWZ(off), g);
            }
        }
    };

    float acc[4][4][4];
#pragma unroll
    for (int mt = 0; mt < 4; mt++)
#pragma unroll
        for (int nt = 0; nt < 4; nt++)
#pragma unroll
            for (int e = 0; e < 4; e++) acc[mt][nt][e] = 0.0f;

    load_stage(0, 0); CP_COMMIT();
    load_stage(1, 1); CP_COMMIT();

    const int a_row = wm * 64 + (lane & 15);
    const uint32_t a_bc = (uint32_t)((lane >> 4) << 4);
    const int b_row = wn * 32 + ((lane & 16) >> 1) + (lane & 7);
    const uint32_t b_bc = (uint32_t)((lane & 8) << 1);

    for (int it = 0; it < NK; it++) {
        if (it + 2 < NK) load_stage(it + 2, (it + 2) % NSTAGE);
        CP_COMMIT();
        CP_WAIT2();
        __syncthreads();

        const uint32_t stb = sbase + (it % NSTAGE) * STAGE_B;
        const uint32_t tAh = stb + 0 * TILE_B;
        const uint32_t tAl = stb + 1 * TILE_B;
        const uint32_t tBh = stb + 2 * TILE_B;
        const uint32_t tBl = stb + 3 * TILE_B;

#pragma unroll
        for (int term = 0; term < 3; term++) {
            const uint32_t aT = (term == 2) ? tAl : tAh;
            const uint32_t bT = (term == 1) ? tBl : tBh;
#pragma unroll
            for (int ks = 0; ks < 4; ks++) {
                uint32_t af[4][4];
#pragma unroll
                for (int mt = 0; mt < 4; mt++) {
                    uint32_t off = (uint32_t)((a_row + mt * 16) * 128) +
                                   (uint32_t)(ks * 32) + a_bc;
                    ldsm4(af[mt], aT + SWZ(off));
                }
#pragma unroll
                for (int np = 0; np < 2; np++) {
                    uint32_t bf[4];
                    uint32_t off = (uint32_t)((b_row + np * 16) * 128) +
                                   (uint32_t)(ks * 32) + b_bc;
                    ldsm4(bf, bT + SWZ(off));
#pragma unroll
                    for (int mt = 0; mt < 4; mt++) {
                        mma16816(acc[mt][np * 2 + 0], af[mt], bf);
                        mma16816(acc[mt][np * 2 + 1], af[mt], bf + 2);
                    }
                }
            }
        }
        __syncthreads();
    }

    // Epilogue
    const int col_base = n0 + wn * 32 + ((lane & 3) << 1);
    const int row_base = m0 + wm * 64 + (lane >> 2);
#pragma unroll
    for (int nt = 0; nt < 4; nt++) {
        const int col = col_base + nt * 8;
        const float b0 = bias[col];
        const float b1 = bias[col + 1];
#pragma unroll
        for (int mt = 0; mt < 4; mt++) {
            int r0 = row_base + mt * 16;
            float v0 = acc[mt][nt][0] + b0;
            float v1 = acc[mt][nt][1] + b1;
            float v2 = acc[mt][nt][2] + b0;
            float v3 = acc[mt][nt][3] + b1;
            if (MODE == 0) {
                float qm0 = (float)qmask[r0];
                float qm1 = (float)qmask[r0 + 8];
                *(float2*)&C[(size_t)r0 * DD + col] =
                    make_float2(v0 * qm0, v1 * qm0);
                *(float2*)&C[(size_t)(r0 + 8) * DD + col] =
                    make_float2(v2 * qm1, v3 * qm1);
            } else if (MODE == 1) {
                uint16_t h0,l0,h1,l1,h2,l2,h3,l3;
                split_bf(v0,h0,l0); split_bf(v1,h1,l1);
                split_bf(v2,h2,l2); split_bf(v3,h3,l3);
                *(uint32_t*)&Chi[(size_t)r0 * DD + col] =
                    (uint32_t)h0 | ((uint32_t)h1 << 16);
                *(uint32_t*)&Clo[(size_t)r0 * DD + col] =
                    (uint32_t)l0 | ((uint32_t)l1 << 16);
                *(uint32_t*)&Chi[(size_t)(r0 + 8) * DD + col] =
                    (uint32_t)h2 | ((uint32_t)h3 << 16);
                *(uint32_t*)&Clo[(size_t)(r0 + 8) * DD + col] =
                    (uint32_t)l2 | ((uint32_t)l3 << 16);
            } else {
                // transposed split: dst = (b*1024 + col)*SS + j
                uint16_t h, l;
                int rA = r0, rB = r0 + 8;
                size_t dA0 = ((size_t)(rA >> 11) * 1024 + col) * SS + (rA & 2047);
                size_t dA1 = ((size_t)(rA >> 11) * 1024 + col + 1) * SS + (rA & 2047);
                size_t dB0 = ((size_t)(rB >> 11) * 1024 + col) * SS + (rB & 2047);
                size_t dB1 = ((size_t)(rB >> 11) * 1024 + col + 1) * SS + (rB & 2047);
                split_bf(v0,h,l); *(uint16_t*)&Chi[dA0]=h; *(uint16_t*)&Clo[dA0]=l;
                split_bf(v1,h,l); *(uint16_t*)&Chi[dA1]=h; *(uint16_t*)&Clo[dA1]=l;
                split_bf(v2,h,l); *(uint16_t*)&Chi[dB0]=h; *(uint16_t*)&Clo[dB0]=l;
                split_bf(v3,h,l); *(uint16_t*)&Chi[dB1]=h; *(uint16_t*)&Clo[dB1]=l;
            }
        }
    }
}

// ---------------------------------------------------------------------------
// Tensor-core flash attention: presplit bf16 inputs, cp.async double-buffered.
// 256 threads = 8 warps; warp w owns q rows w*16..w*16+15 of a 128-row tile.
// ---------------------------------------------------------------------------
#define AQ_H 0
#define AQ_L 16384
#define ASTG 32768
#define SK_H 0
#define SK_L 16384
#define SV_H 32768
#define SV_L 50176
#define SVM  67584
#define STG_SZ 68608
#define AT_SMEM (ASTG + 2 * STG_SZ)   // 169984
#define VT_ROW 272

__global__ __launch_bounds__(256)
void attn_mma(const int* __restrict__ v_mask)
{
    extern __shared__ char smc[];
    const uint32_t sb = smem_u32(smc);

    const int tid  = threadIdx.x;
    const int lane = tid & 31;
    const int w    = tid >> 5;
    const int bh = blockIdx.y;
    const int b  = bh >> 4;
    const int h  = bh & 15;
    const int qt = gridDim.x - 1 - blockIdx.x;   // heavy tiles first
    const int q0 = qt * 128;
    const float scale = 0.125f;

    // ---- Q tile: cp.async from presplit g_Qhi/g_Qlo into SW128 SMEM ----
#pragma unroll
    for (int t = 0; t < 8; t++) {
        int idx = tid + t * 256;             // 0..2047
        const char* src = (idx < 1024) ? (const char*)g_Qhi : (const char*)g_Qlo;
        uint32_t dst = sb + ((idx < 1024) ? AQ_H : AQ_L);
        int r = (idx >> 3) & 127;
        int c = idx & 7;
        const void* g = src + ((size_t)(b * SS + q0 + r) * DD + h * 64) * 2 + c * 16;
        cp16(dst + SWZ((uint32_t)(r * 128 + c * 16)), g);
    }

    // stage loader for key tile kt into stage s
    auto load_stage = [&](int kt, int s) {
        const uint32_t stg = sb + ASTG + s * STG_SZ;
        // K hi/lo: 128 rows x 8 chunks x2
#pragma unroll
        for (int t = 0; t < 8; t++) {
            int idx = tid + t * 256;
            const char* src = (idx < 1024) ? (const char*)g_Khi : (const char*)g_Klo;
            uint32_t dst = stg + ((idx < 1024) ? SK_H : SK_L);
            int r = (idx >> 3) & 127;
            int c = idx & 7;
            const void* g = src + ((size_t)(b * SS + kt * 128 + r) * DD + h * 64) * 2 + c * 16;
            cp16(dst + SWZ((uint32_t)(r * 128 + c * 16)), g);
        }
        // V hi/lo transposed: 64 d-rows x 16 chunks x2
#pragma unroll
        for (int t = 0; t < 8; t++) {
            int idx = tid + t * 256;
            const char* src = (idx < 1024) ? (const char*)g_Vthi : (const char*)g_Vtlo;
            uint32_t dst = stg + ((idx < 1024) ? SV_H : SV_L);
            int rem = idx & 1023;
            int d = rem >> 4;
            int c = rem & 15;
            const void* g = src + (((size_t)(b * 16 + h) * 64 + d) * SS + kt * 128) * 2 + c * 16;
            cp16(dst + (uint32_t)(d * VT_ROW + c * 16), g);
        }
        if (tid < 128) {
            ((float*)(smc + ASTG + s * STG_SZ + SVM))[tid] =
                v_mask[b * SS + kt * 128 + tid] ? 0.0f : -1e12f;
        }
    };

    load_stage(0, 0);
    CP_COMMIT();    // group: Q + stage0

    // fragment address components
    const int a_row = w * 16 + (lane & 15);
    const uint32_t a_bc = (uint32_t)((lane >> 4) << 4);
    const int b_rp  = ((lane & 16) >> 1) + (lane & 7);
    const uint32_t b_bc = (uint32_t)((lane & 8) << 1);

    float o[8][4];
#pragma unroll
    for (int nt = 0; nt < 8; nt++)
#pragma unroll
        for (int e = 0; e < 4; e++) o[nt][e] = 0.0f;
    float m_lo = -1e30f, m_hi = -1e30f, l_lo = 0.0f, l_hi = 0.0f;

    const int r = lane >> 2;
    const int qi_lo = q0 + w * 16 + r;
    const int qi_hi = qi_lo + 8;
    const int jc = (lane & 3) * 2;

    const int nkt = qt + 1;
    for (int kt = 0; kt < nkt; kt++) {
        if (kt + 1 < nkt) load_stage(kt + 1, (kt + 1) & 1);
        CP_COMMIT();
        CP_WAIT1();
        __syncthreads();

        const uint32_t stg = sb + ASTG + (kt & 1) * STG_SZ;

        // ---- S = Q K^T, 3-term split bf16 ----
        float s[16][4];
#pragma unroll
        for (int nt = 0; nt < 16; nt++)
#pragma unroll
            for (int e = 0; e < 4; e++) s[nt][e] = 0.0f;

#pragma unroll
        for (int term = 0; term < 3; term++) {
            const uint32_t aT = sb + ((term == 2) ? AQ_L : AQ_H);
            const uint32_t bT = stg + ((term == 1) ? SK_L : SK_H);
#pragma unroll
            for (int ks = 0; ks < 4; ks++) {
                uint32_t af[4];
                ldsm4(af, aT + SWZ((uint32_t)(a_row * 128 + ks * 32) + a_bc));
#pragma unroll
                for (int np = 0; np < 8; np++) {
                    uint32_t bf[4];
                    ldsm4(bf, bT + SWZ((uint32_t)((np * 16 + b_rp) * 128 + ks * 32) + b_bc));
                    mma16816(s[np * 2 + 0], af, bf);
                    mma16816(s[np * 2 + 1], af, bf + 2);
                }
            }
        }

        // ---- mask + online softmax ----
        const bool diag = (kt == qt);
        const float* mvm = (const float*)(smc + ASTG + (kt & 1) * STG_SZ + SVM);
        float mx_lo = -1e30f, mx_hi = -1e30f;
#pragma unroll
        for (int nt = 0; nt < 16; nt++) {
            int jl = nt * 8 + jc;
            int jg = kt * 128 + jl;
            float a0 = mvm[jl], a1 = mvm[jl + 1];
            float v0 = s[nt][0] * scale + a0;
            float v1 = s[nt][1] * scale + a1;
            float v2 = s[nt][2] * scale + a0;
            float v3 = s[nt][3] * scale + a1;
            if (diag) {
                if (jg     > qi_lo) v0 = -1e12f;
                if (jg + 1 > qi_lo) v1 = -1e12f;
                if (jg     > qi_hi) v2 = -1e12f;
                if (jg + 1 > qi_hi) v3 = -1e12f;
            }
            s[nt][0] = v0; s[nt][1] = v1; s[nt][2] = v2; s[nt][3] = v3;
            mx_lo = fmaxf(mx_lo, fmaxf(v0, v1));
            mx_hi = fmaxf(mx_hi, fmaxf(v2, v3));
        }
        mx_lo = fmaxf(mx_lo, __shfl_xor_sync(0xffffffffu, mx_lo, 1));
        mx_lo = fmaxf(mx_lo, __shfl_xor_sync(0xffffffffu, mx_lo, 2));
        mx_hi = fmaxf(mx_hi, __shfl_xor_sync(0xffffffffu, mx_hi, 1));
        mx_hi = fmaxf(mx_hi, __shfl_xor_sync(0xffffffffu, mx_hi, 2));

        float mn_lo = fmaxf(m_lo, mx_lo);
        float mn_hi = fmaxf(m_hi, mx_hi);
        float corr_lo = __expf(m_lo - mn_lo);
        float corr_hi = __expf(m_hi - mn_hi);
        m_lo = mn_lo; m_hi = mn_hi;

        float sum_lo = 0.0f, sum_hi = 0.0f;
#pragma unroll
        for (int nt = 0; nt < 16; nt++) {
            float p0 = __expf(s[nt][0] - mn_lo);
            float p1 = __expf(s[nt][1] - mn_lo);
            float p2 = __expf(s[nt][2] - mn_hi);
            float p3 = __expf(s[nt][3] - mn_hi);
            s[nt][0] = p0; s[nt][1] = p1; s[nt][2] = p2; s[nt][3] = p3;
            sum_lo += p0 + p1;
            sum_hi += p2 + p3;
        }
        sum_lo += __shfl_xor_sync(0xffffffffu, sum_lo, 1);
        sum_lo += __shfl_xor_sync(0xffffffffu, sum_lo, 2);
        sum_hi += __shfl_xor_sync(0xffffffffu, sum_hi, 1);
        sum_hi += __shfl_xor_sync(0xffffffffu, sum_hi, 2);
        l_lo = l_lo * corr_lo + sum_lo;
        l_hi = l_hi * corr_hi + sum_hi;

#pragma unroll
        for (int nt = 0; nt < 8; nt++) {
            o[nt][0] *= corr_lo; o[nt][1] *= corr_lo;
            o[nt][2] *= corr_hi; o[nt][3] *= corr_hi;
        }

        // ---- O += P V, 3-term split bf16 ----
#pragma unroll
        for (int ks = 0; ks < 8; ks++) {
            uint32_t ah[4], al[4];
            {
                uint16_t h0, l0, h1, l1;
                split_bf(s[2*ks][0], h0, l0); split_bf(s[2*ks][1], h1, l1);
                ah[0] = (uint32_t)h0 | ((uint32_t)h1 << 16);
                al[0] = (uint32_t)l0 | ((uint32_t)l1 << 16);
                split_bf(s[2*ks][2], h0, l0); split_bf(s[2*ks][3], h1, l1);
                ah[1] = (uint32_t)h0 | ((uint32_t)h1 << 16);
                al[1] = (uint32_t)l0 | ((uint32_t)l1 << 16);
                split_bf(s[2*ks+1][0], h0, l0); split_bf(s[2*ks+1][1], h1, l1);
                ah[2] = (uint32_t)h0 | ((uint32_t)h1 << 16);
                al[2] = (uint32_t)l0 | ((uint32_t)l1 << 16);
                split_bf(s[2*ks+1][2], h0, l0); split_bf(s[2*ks+1][3], h1, l1);
                ah[3] = (uint32_t)h0 | ((uint32_t)h1 << 16);
                al[3] = (uint32_t)l0 | ((uint32_t)l1 << 16);
            }
#pragma unroll
            for (int np = 0; np < 4; np++) {
                uint32_t addr = (uint32_t)((np * 16 + b_rp) * VT_ROW + ks * 32) + b_bc;
                uint32_t bfh[4], bfl[4];
                ldsm4(bfh, stg + SV_H + addr);
                ldsm4(bfl, stg + SV_L + addr);
                mma16816(o[np * 2 + 0], ah, bfh);
                mma16816(o[np * 2 + 1], ah, bfh + 2);
                mma16816(o[np * 2 + 0], al, bfh);
                mma16816(o[np * 2 + 1], al, bfh + 2);
                mma16816(o[np * 2 + 0], ah, bfl);
                mma16816(o[np * 2 + 1], ah, bfl + 2);
            }
        }
        __syncthreads();   // all warps done with this stage before reuse
    }

    // ---- normalize + split + store to g_Ohi/g_Olo ----
    float inv_lo = 1.0f / l_lo;
    float inv_hi = 1.0f / l_hi;
    const size_t row_lo = (size_t)(b * SS + q0 + w * 16 + r) * DD + h * 64;
    const size_t row_hi = row_lo + 8 * DD;
#pragma unroll
    for (int nt = 0; nt < 8; nt++) {
        int d0 = nt * 8 + jc;
        uint16_t h0,l0,h1,l1;
        split_bf(o[nt][0] * inv_lo, h0, l0);
        split_bf(o[nt][1] * inv_lo, h1, l1);
        *(uint32_t*)&g_Ohi[row_lo + d0] = (uint32_t)h0 | ((uint32_t)h1 << 16);
        *(uint32_t*)&g_Olo[row_lo + d0] = (uint32_t)l0 | ((uint32_t)l1 << 16);
        split_bf(o[nt][2] * inv_hi, h0, l0);
        split_bf(o[nt][3] * inv_hi, h1, l1);
        *(uint32_t*)&g_Ohi[row_hi + d0] = (uint32_t)h0 | ((uint32_t)h1 << 16);
        *(uint32_t*)&g_Olo[row_hi + d0] = (uint32_t)l0 | ((uint32_t)l1 << 16);
    }
}

// ---------------------------------------------------------------------------
// kernel_launch
// ---------------------------------------------------------------------------
extern "C" void kernel_launch(void* const* d_in, const int* in_sizes, int n_in,
                              void* d_out, int out_size)
{
    const float* q      = (const float*)d_in[0];
    const float* k      = (const float*)d_in[1];
    const float* v      = (const float*)d_in[2];
    const int*   q_mask = (const int*)  d_in[3];
    const int*   v_mask = (const int*)  d_in[4];
    const float* Wq     = (const float*)d_in[5];
    const float* bq     = (const float*)d_in[6];
    const float* Wk     = (const float*)d_in[7];
    const float* bk     = (const float*)d_in[8];
    const float* Wv     = (const float*)d_in[9];
    const float* bv     = (const float*)d_in[10];
    const float* Wo     = (const float*)d_in[11];
    const float* bo     = (const float*)d_in[12];
    float* out = (float*)d_out;

    __nv_bfloat16 *ahi, *alo, *whi, *wlo;
    __nv_bfloat16 *qhi, *qlo, *khi, *klo, *vthi, *vtlo, *ohi, *olo;
    cudaGetSymbolAddress((void**)&ahi, g_Ahi);
    cudaGetSymbolAddress((void**)&alo, g_Alo);
    cudaGetSymbolAddress((void**)&whi, g_Whi);
    cudaGetSymbolAddress((void**)&wlo, g_Wlo);
    cudaGetSymbolAddress((void**)&qhi, g_Qhi);
    cudaGetSymbolAddress((void**)&qlo, g_Qlo);
    cudaGetSymbolAddress((void**)&khi, g_Khi);
    cudaGetSymbolAddress((void**)&klo, g_Klo);
    cudaGetSymbolAddress((void**)&vthi, g_Vthi);
    cudaGetSymbolAddress((void**)&vtlo, g_Vtlo);
    cudaGetSymbolAddress((void**)&ohi, g_Ohi);
    cudaGetSymbolAddress((void**)&olo, g_Olo);

    const int GEMM_SMEM = NSTAGE * STAGE_B;   // 196608
    cudaFuncSetAttribute(gemm_mma<0>,
                         cudaFuncAttributeMaxDynamicSharedMemorySize, GEMM_SMEM);
    cudaFuncSetAttribute(gemm_mma<1>,
                         cudaFuncAttributeMaxDynamicSharedMemorySize, GEMM_SMEM);
    cudaFuncSetAttribute(gemm_mma<2>,
                         cudaFuncAttributeMaxDynamicSharedMemorySize, GEMM_SMEM);
    cudaFuncSetAttribute(attn_mma,
                         cudaFuncAttributeMaxDynamicSharedMemorySize, AT_SMEM);

    dim3 gemm_grid(DD / 128, MM / 128);
    dim3 tr_grid(DD / 32, DD / 32);
    const int n4 = MM * DD / 4;
    const int split_blocks = (n4 + 255) / 256;

    // Q projection -> split bf16
    split_kernel<<<split_blocks, 256>>>(q, ahi, alo, n4);
    wsplit_transpose_kernel<<<tr_grid, 256>>>(Wq, whi, wlo);
    gemm_mma<1><<<gemm_grid, 256, GEMM_SMEM>>>(ahi, alo, whi, wlo, bq, nullptr,
                                               nullptr, qhi, qlo);
    // K projection -> split bf16
    split_kernel<<<split_blocks, 256>>>(k, ahi, alo, n4);
    wsplit_transpose_kernel<<<tr_grid, 256>>>(Wk, whi, wlo);
    gemm_mma<1><<<gemm_grid, 256, GEMM_SMEM>>>(ahi, alo, whi, wlo, bk, nullptr,
                                               nullptr, khi, klo);
    // V projection -> split bf16 transposed
    split_kernel<<<split_blocks, 256>>>(v, ahi, alo, n4);
    wsplit_transpose_kernel<<<tr_grid, 256>>>(Wv, whi, wlo);
    gemm_mma<2><<<gemm_grid, 256, GEMM_SMEM>>>(ahi, alo, whi, wlo, bv, nullptr,
                                               nullptr, vthi, vtlo);

    // Attention (tensor-core, double-buffered)
    attn_mma<<<dim3(SS / 128, BB * HH), 256, AT_SMEM>>>(v_mask);

    // Output projection (+ q_mask), reads presplit attention output
    wsplit_transpose_kernel<<<tr_grid, 256>>>(Wo, whi, wlo);
    gemm_mma<0><<<gemm_grid, 256, GEMM_SMEM>>>(ohi, olo, whi, wlo, bo, q_mask,
                                               out, nullptr, nullptr);
}

// round 7
// speedup vs baseline: 2.6005x; 1.0046x over previous
#include <cuda_runtime.h>
#include <cuda_bf16.h>
#include <cstdint>

// Problem constants
#define BB 4
#define SS 2048
#define DD 1024
#define HH 16
#define MM (BB*SS)          // 8192 rows

// Scratch (device globals: allocation-free). All interchange in split bf16.
__device__ __nv_bfloat16 g_Ahi[MM * DD];
__device__ __nv_bfloat16 g_Alo[MM * DD];
__device__ __nv_bfloat16 g_Whi[DD * DD];   // transposed weights: [N, K]
__device__ __nv_bfloat16 g_Wlo[DD * DD];
__device__ __nv_bfloat16 g_Qhi[MM * DD];   // [row][h*64+d]
__device__ __nv_bfloat16 g_Qlo[MM * DD];
__device__ __nv_bfloat16 g_Khi[MM * DD];
__device__ __nv_bfloat16 g_Klo[MM * DD];
__device__ __nv_bfloat16 g_Vthi[MM * DD];  // transposed: [(b*16+h)*64+d][S]
__device__ __nv_bfloat16 g_Vtlo[MM * DD];
__device__ __nv_bfloat16 g_Ohi[MM * DD];   // attention output, split
__device__ __nv_bfloat16 g_Olo[MM * DD];

// ---------------------------------------------------------------------------
// Helpers: mma.sync + ldmatrix + cp.async (portable sm_80+ path; tcgen05 is
// rejected by the harness's compute_103 virtual arch)
// ---------------------------------------------------------------------------
__device__ __forceinline__ uint32_t smem_u32(const void* p) {
    uint32_t a;
    asm("{ .reg .u64 t; cvta.to.shared.u64 t, %1; cvt.u32.u64 %0, t; }"
        : "=r"(a) : "l"(p));
    return a;
}

__device__ __forceinline__ void ldsm4(uint32_t* r, uint32_t addr) {
    asm volatile("ldmatrix.sync.aligned.m8n8.x4.shared.b16 {%0,%1,%2,%3}, [%4];"
        : "=r"(r[0]), "=r"(r[1]), "=r"(r[2]), "=r"(r[3]) : "r"(addr));
}

__device__ __forceinline__ void mma16816(float* c, const uint32_t* a,
                                         const uint32_t* b) {
    asm volatile(
        "mma.sync.aligned.m16n8k16.row.col.f32.bf16.bf16.f32 "
        "{%0,%1,%2,%3}, {%4,%5,%6,%7}, {%8,%9}, {%0,%1,%2,%3};"
        : "+f"(c[0]), "+f"(c[1]), "+f"(c[2]), "+f"(c[3])
        : "r"(a[0]), "r"(a[1]), "r"(a[2]), "r"(a[3]), "r"(b[0]), "r"(b[1]));
}

__device__ __forceinline__ void cp16(uint32_t saddr, const void* g) {
    asm volatile("cp.async.cg.shared.global [%0], [%1], 16;"
                 :: "r"(saddr), "l"(g) : "memory");
}
#define CP_COMMIT() asm volatile("cp.async.commit_group;" ::: "memory")
#define CP_WAIT0()  asm volatile("cp.async.wait_group 0;" ::: "memory")
#define CP_WAIT1()  asm volatile("cp.async.wait_group 1;" ::: "memory")

// SW128 swizzle on byte offsets within a tile (rows of 128B)
#define SWZ(o) ((o) ^ (((o) >> 3) & 0x70))

__device__ __forceinline__ void split_bf(float v, uint16_t& h, uint16_t& l) {
    __nv_bfloat16 hb = __float2bfloat16(v);
    __nv_bfloat16 lb = __float2bfloat16(v - __bfloat162float(hb));
    h = *(uint16_t*)&hb; l = *(uint16_t*)&lb;
}

// ---------------------------------------------------------------------------
// Split-precision conversions (inputs + weights)
// ---------------------------------------------------------------------------
__global__ __launch_bounds__(256)
void split_kernel(const float* __restrict__ x,
                  __nv_bfloat16* __restrict__ hi,
                  __nv_bfloat16* __restrict__ lo, int n4)
{
    int i = blockIdx.x * blockDim.x + threadIdx.x;
    if (i >= n4) return;
    float4 v = ((const float4*)x)[i];
    uint16_t h0,l0,h1,l1,h2,l2,h3,l3;
    split_bf(v.x,h0,l0); split_bf(v.y,h1,l1);
    split_bf(v.z,h2,l2); split_bf(v.w,h3,l3);
    uint2 hv = make_uint2((uint32_t)h0|((uint32_t)h1<<16),
                          (uint32_t)h2|((uint32_t)h3<<16));
    uint2 lv = make_uint2((uint32_t)l0|((uint32_t)l1<<16),
                          (uint32_t)l2|((uint32_t)l3<<16));
    *(uint2*)(hi + (size_t)i * 4) = hv;
    *(uint2*)(lo + (size_t)i * 4) = lv;
}

// W[K,N] fp32 -> Whi/Wlo [N,K] bf16 (transposed), 32x32 tiles
__global__ __launch_bounds__(256)
void wsplit_transpose_kernel(const float* __restrict__ W,
                             __nv_bfloat16* __restrict__ hi,
                             __nv_bfloat16* __restrict__ lo)
{
    __shared__ float t[32][33];
    int tx = threadIdx.x & 31;
    int ty = threadIdx.x >> 5;
    int n0 = blockIdx.x * 32;
    int k0 = blockIdx.y * 32;
#pragma unroll
    for (int i = 0; i < 4; i++)
        t[ty + 8 * i][tx] = W[(size_t)(k0 + ty + 8 * i) * DD + n0 + tx];
    __syncthreads();
#pragma unroll
    for (int i = 0; i < 4; i++) {
        int n = ty + 8 * i;
        float v = t[tx][n];
        uint16_t h, l;
        split_bf(v, h, l);
        *(uint16_t*)&hi[(size_t)(n0 + n) * DD + k0 + tx] = h;
        *(uint16_t*)&lo[(size_t)(n0 + n) * DD + k0 + tx] = l;
    }
}

// ---------------------------------------------------------------------------
// Split-bf16 tensor-core GEMM (mma.sync).
// Output modes: 0 = fp32 + qmask (final), 1 = split bf16 (Q/K), 2 = split
// bf16 transposed [(b*16+h)*64+d][S] (V) via SMEM-staged coalesced stores.
// ---------------------------------------------------------------------------
#define BK 64
#define TILE_B 16384
#define STAGE_B (4 * TILE_B)
#define NSTAGE 3
#define NK (DD / BK)            // 16

template<int MODE>
__global__ __launch_bounds__(256)
void gemm_mma(const __nv_bfloat16* __restrict__ Ahi,
              const __nv_bfloat16* __restrict__ Alo,
              const __nv_bfloat16* __restrict__ Bhi,
              const __nv_bfloat16* __restrict__ Blo,
              const float* __restrict__ bias,
              const int* __restrict__ qmask,
              float* __restrict__ C,
              __nv_bfloat16* __restrict__ Chi,
              __nv_bfloat16* __restrict__ Clo)
{
    extern __shared__ char smc[];
    const uint32_t sbase = smem_u32(smc);

    const int tid  = threadIdx.x;
    const int lane = tid & 31;
    const int wid  = tid >> 5;
    const int wm   = wid & 1;
    const int wn   = wid >> 1;
    const int m0 = blockIdx.y * 128;
    const int n0 = blockIdx.x * 128;

    const char* srcs[4] = { (const char*)Ahi, (const char*)Alo,
                            (const char*)Bhi, (const char*)Blo };

    auto load_stage = [&](int it, int s) {
        const int kc = it * BK;
        const uint32_t stb = sbase + s * STAGE_B;
#pragma unroll
        for (int t = 0; t < 4; t++) {
            const int row0 = (t < 2) ? m0 : n0;
            const char* src = srcs[t];
#pragma unroll
            for (int i = 0; i < 4; i++) {
                int u = tid + i * 256;
                int r = u >> 3;
                int c = u & 7;
                const void* g = src + ((size_t)(row0 + r) * DD + kc) * 2 + c * 16;
                uint32_t off = (uint32_t)(r * 128 + c * 16);
                cp16(stb + t * TILE_B + SWZ(off), g);
            }
        }
    };

    float acc[4][4][4];
#pragma unroll
    for (int mt = 0; mt < 4; mt++)
#pragma unroll
        for (int nt = 0; nt < 4; nt++)
#pragma unroll
            for (int e = 0; e < 4; e++) acc[mt][nt][e] = 0.0f;

    load_stage(0, 0); CP_COMMIT();
    load_stage(1, 1); CP_COMMIT();

    const int a_row = wm * 64 + (lane & 15);
    const uint32_t a_bc = (uint32_t)((lane >> 4) << 4);
    const int b_row = wn * 32 + ((lane & 16) >> 1) + (lane & 7);
    const uint32_t b_bc = (uint32_t)((lane & 8) << 1);

    for (int it = 0; it < NK; it++) {
        // 1-sync pipeline: wait for stage(it), publish it to all warps, then
        // issue stage(it+2) into the buffer consumed by compute(it-1) (safe:
        // every warp's compute(it-1) precedes this sync in program order).
        CP_WAIT1();
        __syncthreads();
        if (it + 2 < NK) load_stage(it + 2, (it + 2) % NSTAGE);
        CP_COMMIT();

        const uint32_t stb = sbase + (it % NSTAGE) * STAGE_B;
        const uint32_t tAh = stb + 0 * TILE_B;
        const uint32_t tAl = stb + 1 * TILE_B;
        const uint32_t tBh = stb + 2 * TILE_B;
        const uint32_t tBl = stb + 3 * TILE_B;

#pragma unroll
        for (int term = 0; term < 3; term++) {
            const uint32_t aT = (term == 2) ? tAl : tAh;
            const uint32_t bT = (term == 1) ? tBl : tBh;
#pragma unroll
            for (int ks = 0; ks < 4; ks++) {
                uint32_t af[4][4];
#pragma unroll
                for (int mt = 0; mt < 4; mt++) {
                    uint32_t off = (uint32_t)((a_row + mt * 16) * 128) +
                                   (uint32_t)(ks * 32) + a_bc;
                    ldsm4(af[mt], aT + SWZ(off));
                }
#pragma unroll
                for (int np = 0; np < 2; np++) {
                    uint32_t bf[4];
                    uint32_t off = (uint32_t)((b_row + np * 16) * 128) +
                                   (uint32_t)(ks * 32) + b_bc;
                    ldsm4(bf, bT + SWZ(off));
#pragma unroll
                    for (int mt = 0; mt < 4; mt++) {
                        mma16816(acc[mt][np * 2 + 0], af[mt], bf);
                        mma16816(acc[mt][np * 2 + 1], af[mt], bf + 2);
                    }
                }
            }
        }
    }

    // Epilogue
    const int col_base = n0 + wn * 32 + ((lane & 3) << 1);
    const int row_base = m0 + wm * 64 + (lane >> 2);

    if (MODE == 2) {
        // Stage transposed fp32 tile in SMEM: tb[col_local*132 + row_local]
        float* tb = (float*)smc;
        __syncthreads();   // all warps done reading stage buffers
#pragma unroll
        for (int nt = 0; nt < 4; nt++) {
            const int cl = wn * 32 + ((lane & 3) << 1) + nt * 8;
            const float b0 = bias[n0 + cl];
            const float b1 = bias[n0 + cl + 1];
#pragma unroll
            for (int mt = 0; mt < 4; mt++) {
                int rl = wm * 64 + (lane >> 2) + mt * 16;
                tb[cl * 132 + rl]           = acc[mt][nt][0] + b0;
                tb[(cl + 1) * 132 + rl]     = acc[mt][nt][1] + b1;
                tb[cl * 132 + rl + 8]       = acc[mt][nt][2] + b0;
                tb[(cl + 1) * 132 + rl + 8] = acc[mt][nt][3] + b1;
            }
        }
        __syncthreads();
        // Coalesced split stores: thread -> (col, half); 64 contiguous S elems
        const int c  = tid >> 1;
        const int hh = tid & 1;
        const float* src = tb + c * 132 + hh * 64;
        const int bidx = m0 >> 11;
        const size_t base = ((size_t)bidx * 1024 + n0 + c) * SS +
                            (m0 & 2047) + hh * 64;
        uint32_t hb[32], lb[32];
#pragma unroll
        for (int i = 0; i < 32; i++) {
            uint16_t ha, la, hbv, lbv;
            split_bf(src[2 * i],     ha,  la);
            split_bf(src[2 * i + 1], hbv, lbv);
            hb[i] = (uint32_t)ha | ((uint32_t)hbv << 16);
            lb[i] = (uint32_t)la | ((uint32_t)lbv << 16);
        }
#pragma unroll
        for (int u = 0; u < 8; u++) {
            *(uint4*)&Chi[base + u * 8] =
                make_uint4(hb[4*u], hb[4*u+1], hb[4*u+2], hb[4*u+3]);
            *(uint4*)&Clo[base + u * 8] =
                make_uint4(lb[4*u], lb[4*u+1], lb[4*u+2], lb[4*u+3]);
        }
        return;
    }

#pragma unroll
    for (int nt = 0; nt < 4; nt++) {
        const int col = col_base + nt * 8;
        const float b0 = bias[col];
        const float b1 = bias[col + 1];
#pragma unroll
        for (int mt = 0; mt < 4; mt++) {
            int r0 = row_base + mt * 16;
            float v0 = acc[mt][nt][0] + b0;
            float v1 = acc[mt][nt][1] + b1;
            float v2 = acc[mt][nt][2] + b0;
            float v3 = acc[mt][nt][3] + b1;
            if (MODE == 0) {
                float qm0 = (float)qmask[r0];
                float qm1 = (float)qmask[r0 + 8];
                *(float2*)&C[(size_t)r0 * DD + col] =
                    make_float2(v0 * qm0, v1 * qm0);
                *(float2*)&C[(size_t)(r0 + 8) * DD + col] =
                    make_float2(v2 * qm1, v3 * qm1);
            } else {
                uint16_t h0,l0,h1,l1,h2,l2,h3,l3;
                split_bf(v0,h0,l0); split_bf(v1,h1,l1);
                split_bf(v2,h2,l2); split_bf(v3,h3,l3);
                *(uint32_t*)&Chi[(size_t)r0 * DD + col] =
                    (uint32_t)h0 | ((uint32_t)h1 << 16);
                *(uint32_t*)&Clo[(size_t)r0 * DD + col] =
                    (uint32_t)l0 | ((uint32_t)l1 << 16);
                *(uint32_t*)&Chi[(size_t)(r0 + 8) * DD + col] =
                    (uint32_t)h2 | ((uint32_t)h3 << 16);
                *(uint32_t*)&Clo[(size_t)(r0 + 8) * DD + col] =
                    (uint32_t)l2 | ((uint32_t)l3 << 16);
            }
        }
    }
}

// ---------------------------------------------------------------------------
// Tensor-core flash attention: presplit bf16 inputs, cp.async double-buffered.
// 256 threads = 8 warps; warp w owns q rows w*16..w*16+15 of a 128-row tile.
// ---------------------------------------------------------------------------
#define AQ_H 0
#define AQ_L 16384
#define ASTG 32768
#define SK_H 0
#define SK_L 16384
#define SV_H 32768
#define SV_L 50176
#define SVM  67584
#define STG_SZ 68608
#define AT_SMEM (ASTG + 2 * STG_SZ)   // 169984
#define VT_ROW 272

__global__ __launch_bounds__(256)
void attn_mma(const int* __restrict__ v_mask)
{
    extern __shared__ char smc[];
    const uint32_t sb = smem_u32(smc);

    const int tid  = threadIdx.x;
    const int lane = tid & 31;
    const int w    = tid >> 5;
    const int bh = blockIdx.y;
    const int b  = bh >> 4;
    const int h  = bh & 15;
    const int qt = gridDim.x - 1 - blockIdx.x;   // heavy tiles first
    const int q0 = qt * 128;
    const float scale = 0.125f;

    // ---- Q tile: cp.async from presplit g_Qhi/g_Qlo into SW128 SMEM ----
#pragma unroll
    for (int t = 0; t < 8; t++) {
        int idx = tid + t * 256;             // 0..2047
        const char* src = (idx < 1024) ? (const char*)g_Qhi : (const char*)g_Qlo;
        uint32_t dst = sb + ((idx < 1024) ? AQ_H : AQ_L);
        int r = (idx >> 3) & 127;
        int c = idx & 7;
        const void* g = src + ((size_t)(b * SS + q0 + r) * DD + h * 64) * 2 + c * 16;
        cp16(dst + SWZ((uint32_t)(r * 128 + c * 16)), g);
    }

    // stage loader for key tile kt into stage s
    auto load_stage = [&](int kt, int s) {
        const uint32_t stg = sb + ASTG + s * STG_SZ;
#pragma unroll
        for (int t = 0; t < 8; t++) {
            int idx = tid + t * 256;
            const char* src = (idx < 1024) ? (const char*)g_Khi : (const char*)g_Klo;
            uint32_t dst = stg + ((idx < 1024) ? SK_H : SK_L);
            int r = (idx >> 3) & 127;
            int c = idx & 7;
            const void* g = src + ((size_t)(b * SS + kt * 128 + r) * DD + h * 64) * 2 + c * 16;
            cp16(dst + SWZ((uint32_t)(r * 128 + c * 16)), g);
        }
#pragma unroll
        for (int t = 0; t < 8; t++) {
            int idx = tid + t * 256;
            const char* src = (idx < 1024) ? (const char*)g_Vthi : (const char*)g_Vtlo;
            uint32_t dst = stg + ((idx < 1024) ? SV_H : SV_L);
            int rem = idx & 1023;
            int d = rem >> 4;
            int c = rem & 15;
            const void* g = src + (((size_t)(b * 16 + h) * 64 + d) * SS + kt * 128) * 2 + c * 16;
            cp16(dst + (uint32_t)(d * VT_ROW + c * 16), g);
        }
        if (tid < 128) {
            ((float*)(smc + ASTG + s * STG_SZ + SVM))[tid] =
                v_mask[b * SS + kt * 128 + tid] ? 0.0f : -1e12f;
        }
    };

    load_stage(0, 0);
    CP_COMMIT();    // group: Q + stage0

    // fragment address components
    const int a_row = w * 16 + (lane & 15);
    const uint32_t a_bc = (uint32_t)((lane >> 4) << 4);
    const int b_rp  = ((lane & 16) >> 1) + (lane & 7);
    const uint32_t b_bc = (uint32_t)((lane & 8) << 1);

    float o[8][4];
#pragma unroll
    for (int nt = 0; nt < 8; nt++)
#pragma unroll
        for (int e = 0; e < 4; e++) o[nt][e] = 0.0f;
    float m_lo = -1e30f, m_hi = -1e30f, l_lo = 0.0f, l_hi = 0.0f;

    const int r = lane >> 2;
    const int qi_lo = q0 + w * 16 + r;
    const int qi_hi = qi_lo + 8;
    const int jc = (lane & 3) * 2;

    const int nkt = qt + 1;
    for (int kt = 0; kt < nkt; kt++) {
        // 1-sync pipeline: wait for stage(kt), publish, then issue stage(kt+1)
        // (targets buffer consumed by compute(kt-1), guarded by this sync).
        CP_WAIT0();
        __syncthreads();
        if (kt + 1 < nkt) load_stage(kt + 1, (kt + 1) & 1);
        CP_COMMIT();

        const uint32_t stg = sb + ASTG + (kt & 1) * STG_SZ;

        // ---- S = Q K^T, 3-term split bf16 ----
        float s[16][4];
#pragma unroll
        for (int nt = 0; nt < 16; nt++)
#pragma unroll
            for (int e = 0; e < 4; e++) s[nt][e] = 0.0f;

#pragma unroll
        for (int term = 0; term < 3; term++) {
            const uint32_t aT = sb + ((term == 2) ? AQ_L : AQ_H);
            const uint32_t bT = stg + ((term == 1) ? SK_L : SK_H);
#pragma unroll
            for (int ks = 0; ks < 4; ks++) {
                uint32_t af[4];
                ldsm4(af, aT + SWZ((uint32_t)(a_row * 128 + ks * 32) + a_bc));
#pragma unroll
                for (int np = 0; np < 8; np++) {
                    uint32_t bf[4];
                    ldsm4(bf, bT + SWZ((uint32_t)((np * 16 + b_rp) * 128 + ks * 32) + b_bc));
                    mma16816(s[np * 2 + 0], af, bf);
                    mma16816(s[np * 2 + 1], af, bf + 2);
                }
            }
        }

        // ---- mask + online softmax ----
        const bool diag = (kt == qt);
        const float* mvm = (const float*)(smc + ASTG + (kt & 1) * STG_SZ + SVM);
        float mx_lo = -1e30f, mx_hi = -1e30f;
#pragma unroll
        for (int nt = 0; nt < 16; nt++) {
            int jl = nt * 8 + jc;
            int jg = kt * 128 + jl;
            float a0 = mvm[jl], a1 = mvm[jl + 1];
            float v0 = s[nt][0] * scale + a0;
            float v1 = s[nt][1] * scale + a1;
            float v2 = s[nt][2] * scale + a0;
            float v3 = s[nt][3] * scale + a1;
            if (diag) {
                if (jg     > qi_lo) v0 = -1e12f;
                if (jg + 1 > qi_lo) v1 = -1e12f;
                if (jg     > qi_hi) v2 = -1e12f;
                if (jg + 1 > qi_hi) v3 = -1e12f;
            }
            s[nt][0] = v0; s[nt][1] = v1; s[nt][2] = v2; s[nt][3] = v3;
            mx_lo = fmaxf(mx_lo, fmaxf(v0, v1));
            mx_hi = fmaxf(mx_hi, fmaxf(v2, v3));
        }
        mx_lo = fmaxf(mx_lo, __shfl_xor_sync(0xffffffffu, mx_lo, 1));
        mx_lo = fmaxf(mx_lo, __shfl_xor_sync(0xffffffffu, mx_lo, 2));
        mx_hi = fmaxf(mx_hi, __shfl_xor_sync(0xffffffffu, mx_hi, 1));
        mx_hi = fmaxf(mx_hi, __shfl_xor_sync(0xffffffffu, mx_hi, 2));

        float mn_lo = fmaxf(m_lo, mx_lo);
        float mn_hi = fmaxf(m_hi, mx_hi);
        float corr_lo = __expf(m_lo - mn_lo);
        float corr_hi = __expf(m_hi - mn_hi);
        m_lo = mn_lo; m_hi = mn_hi;

        float sum_lo = 0.0f, sum_hi = 0.0f;
#pragma unroll
        for (int nt = 0; nt < 16; nt++) {
            float p0 = __expf(s[nt][0] - mn_lo);
            float p1 = __expf(s[nt][1] - mn_lo);
            float p2 = __expf(s[nt][2] - mn_hi);
            float p3 = __expf(s[nt][3] - mn_hi);
            s[nt][0] = p0; s[nt][1] = p1; s[nt][2] = p2; s[nt][3] = p3;
            sum_lo += p0 + p1;
            sum_hi += p2 + p3;
        }
        sum_lo += __shfl_xor_sync(0xffffffffu, sum_lo, 1);
        sum_lo += __shfl_xor_sync(0xffffffffu, sum_lo, 2);
        sum_hi += __shfl_xor_sync(0xffffffffu, sum_hi, 1);
        sum_hi += __shfl_xor_sync(0xffffffffu, sum_hi, 2);
        l_lo = l_lo * corr_lo + sum_lo;
        l_hi = l_hi * corr_hi + sum_hi;

#pragma unroll
        for (int nt = 0; nt < 8; nt++) {
            o[nt][0] *= corr_lo; o[nt][1] *= corr_lo;
            o[nt][2] *= corr_hi; o[nt][3] *= corr_hi;
        }

        // ---- O += P V, 3-term split bf16 ----
#pragma unroll
        for (int ks = 0; ks < 8; ks++) {
            uint32_t ah[4], al[4];
            {
                uint16_t h0, l0, h1, l1;
                split_bf(s[2*ks][0], h0, l0); split_bf(s[2*ks][1], h1, l1);
                ah[0] = (uint32_t)h0 | ((uint32_t)h1 << 16);
                al[0] = (uint32_t)l0 | ((uint32_t)l1 << 16);
                split_bf(s[2*ks][2], h0, l0); split_bf(s[2*ks][3], h1, l1);
                ah[1] = (uint32_t)h0 | ((uint32_t)h1 << 16);
                al[1] = (uint32_t)l0 | ((uint32_t)l1 << 16);
                split_bf(s[2*ks+1][0], h0, l0); split_bf(s[2*ks+1][1], h1, l1);
                ah[2] = (uint32_t)h0 | ((uint32_t)h1 << 16);
                al[2] = (uint32_t)l0 | ((uint32_t)l1 << 16);
                split_bf(s[2*ks+1][2], h0, l0); split_bf(s[2*ks+1][3], h1, l1);
                ah[3] = (uint32_t)h0 | ((uint32_t)h1 << 16);
                al[3] = (uint32_t)l0 | ((uint32_t)l1 << 16);
            }
#pragma unroll
            for (int np = 0; np < 4; np++) {
                uint32_t addr = (uint32_t)((np * 16 + b_rp) * VT_ROW + ks * 32) + b_bc;
                uint32_t bfh[4], bfl[4];
                ldsm4(bfh, stg + SV_H + addr);
                ldsm4(bfl, stg + SV_L + addr);
                mma16816(o[np * 2 + 0], ah, bfh);
                mma16816(o[np * 2 + 1], ah, bfh + 2);
                mma16816(o[np * 2 + 0], al, bfh);
                mma16816(o[np * 2 + 1], al, bfh + 2);
                mma16816(o[np * 2 + 0], ah, bfl);
                mma16816(o[np * 2 + 1], ah, bfl + 2);
            }
        }
    }

    // ---- normalize + split + store to g_Ohi/g_Olo ----
    float inv_lo = 1.0f / l_lo;
    float inv_hi = 1.0f / l_hi;
    const size_t row_lo = (size_t)(b * SS + q0 + w * 16 + r) * DD + h * 64;
    const size_t row_hi = row_lo + 8 * DD;
#pragma unroll
    for (int nt = 0; nt < 8; nt++) {
        int d0 = nt * 8 + jc;
        uint16_t h0,l0,h1,l1;
        split_bf(o[nt][0] * inv_lo, h0, l0);
        split_bf(o[nt][1] * inv_lo, h1, l1);
        *(uint32_t*)&g_Ohi[row_lo + d0] = (uint32_t)h0 | ((uint32_t)h1 << 16);
        *(uint32_t*)&g_Olo[row_lo + d0] = (uint32_t)l0 | ((uint32_t)l1 << 16);
        split_bf(o[nt][2] * inv_hi, h0, l0);
        split_bf(o[nt][3] * inv_hi, h1, l1);
        *(uint32_t*)&g_Ohi[row_hi + d0] = (uint32_t)h0 | ((uint32_t)h1 << 16);
        *(uint32_t*)&g_Olo[row_hi + d0] = (uint32_t)l0 | ((uint32_t)l1 << 16);
    }
}

// ---------------------------------------------------------------------------
// kernel_launch
// ---------------------------------------------------------------------------
extern "C" void kernel_launch(void* const* d_in, const int* in_sizes, int n_in,
                              void* d_out, int out_size)
{
    const float* q      = (const float*)d_in[0];
    const float* k      = (const float*)d_in[1];
    const float* v      = (const float*)d_in[2];
    const int*   q_mask = (const int*)  d_in[3];
    const int*   v_mask = (const int*)  d_in[4];
    const float* Wq     = (const float*)d_in[5];
    const float* bq     = (const float*)d_in[6];
    const float* Wk     = (const float*)d_in[7];
    const float* bk     = (const float*)d_in[8];
    const float* Wv     = (const float*)d_in[9];
    const float* bv     = (const float*)d_in[10];
    const float* Wo     = (const float*)d_in[11];
    const float* bo     = (const float*)d_in[12];
    float* out = (float*)d_out;

    __nv_bfloat16 *ahi, *alo, *whi, *wlo;
    __nv_bfloat16 *qhi, *qlo, *khi, *klo, *vthi, *vtlo, *ohi, *olo;
    cudaGetSymbolAddress((void**)&ahi, g_Ahi);
    cudaGetSymbolAddress((void**)&alo, g_Alo);
    cudaGetSymbolAddress((void**)&whi, g_Whi);
    cudaGetSymbolAddress((void**)&wlo, g_Wlo);
    cudaGetSymbolAddress((void**)&qhi, g_Qhi);
    cudaGetSymbolAddress((void**)&qlo, g_Qlo);
    cudaGetSymbolAddress((void**)&khi, g_Khi);
    cudaGetSymbolAddress((void**)&klo, g_Klo);
    cudaGetSymbolAddress((void**)&vthi, g_Vthi);
    cudaGetSymbolAddress((void**)&vtlo, g_Vtlo);
    cudaGetSymbolAddress((void**)&ohi, g_Ohi);
    cudaGetSymbolAddress((void**)&olo, g_Olo);

    const int GEMM_SMEM = NSTAGE * STAGE_B;   // 196608
    cudaFuncSetAttribute(gemm_mma<0>,
                         cudaFuncAttributeMaxDynamicSharedMemorySize, GEMM_SMEM);
    cudaFuncSetAttribute(gemm_mma<1>,
                         cudaFuncAttributeMaxDynamicSharedMemorySize, GEMM_SMEM);
    cudaFuncSetAttribute(gemm_mma<2>,
                         cudaFuncAttributeMaxDynamicSharedMemorySize, GEMM_SMEM);
    cudaFuncSetAttribute(attn_mma,
                         cudaFuncAttributeMaxDynamicSharedMemorySize, AT_SMEM);

    dim3 gemm_grid(DD / 128, MM / 128);
    dim3 tr_grid(DD / 32, DD / 32);
    const int n4 = MM * DD / 4;
    const int split_blocks = (n4 + 255) / 256;

    // Q projection -> split bf16
    split_kernel<<<split_blocks, 256>>>(q, ahi, alo, n4);
    wsplit_transpose_kernel<<<tr_grid, 256>>>(Wq, whi, wlo);
    gemm_mma<1><<<gemm_grid, 256, GEMM_SMEM>>>(ahi, alo, whi, wlo, bq, nullptr,
                                               nullptr, qhi, qlo);
    // K projection -> split bf16
    split_kernel<<<split_blocks, 256>>>(k, ahi, alo, n4);
    wsplit_transpose_kernel<<<tr_grid, 256>>>(Wk, whi, wlo);
    gemm_mma<1><<<gemm_grid, 256, GEMM_SMEM>>>(ahi, alo, whi, wlo, bk, nullptr,
                                               nullptr, khi, klo);
    // V projection -> split bf16 transposed
    split_kernel<<<split_blocks, 256>>>(v, ahi, alo, n4);
    wsplit_transpose_kernel<<<tr_grid, 256>>>(Wv, whi, wlo);
    gemm_mma<2><<<gemm_grid, 256, GEMM_SMEM>>>(ahi, alo, whi, wlo, bv, nullptr,
                                               nullptr, vthi, vtlo);

    // Attention (tensor-core, double-buffered)
    attn_mma<<<dim3(SS / 128, BB * HH), 256, AT_SMEM>>>(v_mask);

    // Output projection (+ q_mask), reads presplit attention output
    wsplit_transpose_kernel<<<tr_grid, 256>>>(Wo, whi, wlo);
    gemm_mma<0><<<gemm_grid, 256, GEMM_SMEM>>>(ohi, olo, whi, wlo, bo, q_mask,
                                               out, nullptr, nullptr);
}

// round 8
// speedup vs baseline: 2.7690x; 1.0648x over previous
#include <cuda_runtime.h>
#include <cuda_bf16.h>
#include <cstdint>

// Problem constants
#define BB 4
#define SS 2048
#define DD 1024
#define HH 16
#define MM (BB*SS)          // 8192 rows

// Scratch (device globals: allocation-free). All interchange in split bf16.
__device__ __nv_bfloat16 g_Ahi[MM * DD];
__device__ __nv_bfloat16 g_Alo[MM * DD];
__device__ __nv_bfloat16 g_Whi[DD * DD];   // transposed weights: [N, K]
__device__ __nv_bfloat16 g_Wlo[DD * DD];
__device__ __nv_bfloat16 g_Qhi[MM * DD];   // [row][h*64+d]
__device__ __nv_bfloat16 g_Qlo[MM * DD];
__device__ __nv_bfloat16 g_Khi[MM * DD];
__device__ __nv_bfloat16 g_Klo[MM * DD];
__device__ __nv_bfloat16 g_Vthi[MM * DD];  // transposed: [(b*16+h)*64+d][S]
__device__ __nv_bfloat16 g_Vtlo[MM * DD];
__device__ __nv_bfloat16 g_Ohi[MM * DD];   // attention output, split
__device__ __nv_bfloat16 g_Olo[MM * DD];

// ---------------------------------------------------------------------------
// Helpers: mma.sync + ldmatrix + cp.async (portable sm_80+ path; tcgen05 is
// rejected by the harness's compute_103 virtual arch)
// ---------------------------------------------------------------------------
__device__ __forceinline__ uint32_t smem_u32(const void* p) {
    uint32_t a;
    asm("{ .reg .u64 t; cvta.to.shared.u64 t, %1; cvt.u32.u64 %0, t; }"
        : "=r"(a) : "l"(p));
    return a;
}

__device__ __forceinline__ void ldsm4(uint32_t* r, uint32_t addr) {
    asm volatile("ldmatrix.sync.aligned.m8n8.x4.shared.b16 {%0,%1,%2,%3}, [%4];"
        : "=r"(r[0]), "=r"(r[1]), "=r"(r[2]), "=r"(r[3]) : "r"(addr));
}

__device__ __forceinline__ void mma16816(float* c, const uint32_t* a,
                                         const uint32_t* b) {
    asm volatile(
        "mma.sync.aligned.m16n8k16.row.col.f32.bf16.bf16.f32 "
        "{%0,%1,%2,%3}, {%4,%5,%6,%7}, {%8,%9}, {%0,%1,%2,%3};"
        : "+f"(c[0]), "+f"(c[1]), "+f"(c[2]), "+f"(c[3])
        : "r"(a[0]), "r"(a[1]), "r"(a[2]), "r"(a[3]), "r"(b[0]), "r"(b[1]));
}

__device__ __forceinline__ void cp16(uint32_t saddr, const void* g) {
    asm volatile("cp.async.cg.shared.global [%0], [%1], 16;"
                 :: "r"(saddr), "l"(g) : "memory");
}
#define CP_COMMIT() asm volatile("cp.async.commit_group;" ::: "memory")
#define CP_WAIT0()  asm volatile("cp.async.wait_group 0;" ::: "memory")
#define CP_WAIT1()  asm volatile("cp.async.wait_group 1;" ::: "memory")

// SW128 swizzle on byte offsets within a tile (rows of 128B)
#define SWZ(o) ((o) ^ (((o) >> 3) & 0x70))

__device__ __forceinline__ void split_bf(float v, uint16_t& h, uint16_t& l) {
    __nv_bfloat16 hb = __float2bfloat16(v);
    __nv_bfloat16 lb = __float2bfloat16(v - __bfloat162float(hb));
    h = *(uint16_t*)&hb; l = *(uint16_t*)&lb;
}

// ---------------------------------------------------------------------------
// Split-precision conversions (inputs + weights)
// ---------------------------------------------------------------------------
__global__ __launch_bounds__(256)
void split_kernel(const float* __restrict__ x,
                  __nv_bfloat16* __restrict__ hi,
                  __nv_bfloat16* __restrict__ lo, int n4)
{
    int i = blockIdx.x * blockDim.x + threadIdx.x;
    if (i >= n4) return;
    float4 v = ((const float4*)x)[i];
    uint16_t h0,l0,h1,l1,h2,l2,h3,l3;
    split_bf(v.x,h0,l0); split_bf(v.y,h1,l1);
    split_bf(v.z,h2,l2); split_bf(v.w,h3,l3);
    uint2 hv = make_uint2((uint32_t)h0|((uint32_t)h1<<16),
                          (uint32_t)h2|((uint32_t)h3<<16));
    uint2 lv = make_uint2((uint32_t)l0|((uint32_t)l1<<16),
                          (uint32_t)l2|((uint32_t)l3<<16));
    *(uint2*)(hi + (size_t)i * 4) = hv;
    *(uint2*)(lo + (size_t)i * 4) = lv;
}

// W[K,N] fp32 -> Whi/Wlo [N,K] bf16 (transposed), 32x32 tiles
__global__ __launch_bounds__(256)
void wsplit_transpose_kernel(const float* __restrict__ W,
                             __nv_bfloat16* __restrict__ hi,
                             __nv_bfloat16* __restrict__ lo)
{
    __shared__ float t[32][33];
    int tx = threadIdx.x & 31;
    int ty = threadIdx.x >> 5;
    int n0 = blockIdx.x * 32;
    int k0 = blockIdx.y * 32;
#pragma unroll
    for (int i = 0; i < 4; i++)
        t[ty + 8 * i][tx] = W[(size_t)(k0 + ty + 8 * i) * DD + n0 + tx];
    __syncthreads();
#pragma unroll
    for (int i = 0; i < 4; i++) {
        int n = ty + 8 * i;
        float v = t[tx][n];
        uint16_t h, l;
        split_bf(v, h, l);
        *(uint16_t*)&hi[(size_t)(n0 + n) * DD + k0 + tx] = h;
        *(uint16_t*)&lo[(size_t)(n0 + n) * DD + k0 + tx] = l;
    }
}

// ---------------------------------------------------------------------------
// Split-bf16 tensor-core GEMM (mma.sync), ks-outer fragment sharing.
// Output modes: 0 = fp32 + qmask (final), 1 = split bf16 (Q/K), 2 = split
// bf16 transposed [(b*16+h)*64+d][S] (V) via SMEM-staged coalesced stores.
// ---------------------------------------------------------------------------
#define BK 64
#define TILE_B 16384
#define STAGE_B (4 * TILE_B)
#define NSTAGE 3
#define NK (DD / BK)            // 16

template<int MODE>
__global__ __launch_bounds__(256)
void gemm_mma(const __nv_bfloat16* __restrict__ Ahi,
              const __nv_bfloat16* __restrict__ Alo,
              const __nv_bfloat16* __restrict__ Bhi,
              const __nv_bfloat16* __restrict__ Blo,
              const float* __restrict__ bias,
              const int* __restrict__ qmask,
              float* __restrict__ C,
              __nv_bfloat16* __restrict__ Chi,
              __nv_bfloat16* __restrict__ Clo)
{
    extern __shared__ char smc[];
    const uint32_t sbase = smem_u32(smc);

    const int tid  = threadIdx.x;
    const int lane = tid & 31;
    const int wid  = tid >> 5;
    const int wm   = wid & 1;
    const int wn   = wid >> 1;
    const int m0 = blockIdx.y * 128;
    const int n0 = blockIdx.x * 128;

    const char* srcs[4] = { (const char*)Ahi, (const char*)Alo,
                            (const char*)Bhi, (const char*)Blo };

    auto load_stage = [&](int it, int s) {
        const int kc = it * BK;
        const uint32_t stb = sbase + s * STAGE_B;
#pragma unroll
        for (int t = 0; t < 4; t++) {
            const int row0 = (t < 2) ? m0 : n0;
            const char* src = srcs[t];
#pragma unroll
            for (int i = 0; i < 4; i++) {
                int u = tid + i * 256;
                int r = u >> 3;
                int c = u & 7;
                const void* g = src + ((size_t)(row0 + r) * DD + kc) * 2 + c * 16;
                uint32_t off = (uint32_t)(r * 128 + c * 16);
                cp16(stb + t * TILE_B + SWZ(off), g);
            }
        }
    };

    float acc[4][4][4];
#pragma unroll
    for (int mt = 0; mt < 4; mt++)
#pragma unroll
        for (int nt = 0; nt < 4; nt++)
#pragma unroll
            for (int e = 0; e < 4; e++) acc[mt][nt][e] = 0.0f;

    load_stage(0, 0); CP_COMMIT();
    load_stage(1, 1); CP_COMMIT();

    const int a_row = wm * 64 + (lane & 15);
    const uint32_t a_bc = (uint32_t)((lane >> 4) << 4);
    const int b_row = wn * 32 + ((lane & 16) >> 1) + (lane & 7);
    const uint32_t b_bc = (uint32_t)((lane & 8) << 1);

    for (int it = 0; it < NK; it++) {
        CP_WAIT1();
        __syncthreads();
        if (it + 2 < NK) load_stage(it + 2, (it + 2) % NSTAGE);
        CP_COMMIT();

        const uint32_t stb = sbase + (it % NSTAGE) * STAGE_B;
        const uint32_t tAh = stb + 0 * TILE_B;
        const uint32_t tAl = stb + 1 * TILE_B;
        const uint32_t tBh = stb + 2 * TILE_B;
        const uint32_t tBl = stb + 3 * TILE_B;

        // ks-outer: load A hi+lo fragments once, run all 3 terms from regs
#pragma unroll
        for (int ks = 0; ks < 4; ks++) {
            uint32_t ah[4][4], al[4][4];
#pragma unroll
            for (int mt = 0; mt < 4; mt++) {
                uint32_t off = (uint32_t)((a_row + mt * 16) * 128) +
                               (uint32_t)(ks * 32) + a_bc;
                ldsm4(ah[mt], tAh + SWZ(off));
                ldsm4(al[mt], tAl + SWZ(off));
            }
#pragma unroll
            for (int np = 0; np < 2; np++) {
                uint32_t bh[4], bl[4];
                uint32_t off = (uint32_t)((b_row + np * 16) * 128) +
                               (uint32_t)(ks * 32) + b_bc;
                ldsm4(bh, tBh + SWZ(off));
                ldsm4(bl, tBl + SWZ(off));
#pragma unroll
                for (int mt = 0; mt < 4; mt++) {
                    mma16816(acc[mt][np * 2 + 0], ah[mt], bh);
                    mma16816(acc[mt][np * 2 + 1], ah[mt], bh + 2);
                    mma16816(acc[mt][np * 2 + 0], ah[mt], bl);
                    mma16816(acc[mt][np * 2 + 1], ah[mt], bl + 2);
                    mma16816(acc[mt][np * 2 + 0], al[mt], bh);
                    mma16816(acc[mt][np * 2 + 1], al[mt], bh + 2);
                }
            }
        }
    }

    // Epilogue
    const int col_base = n0 + wn * 32 + ((lane & 3) << 1);
    const int row_base = m0 + wm * 64 + (lane >> 2);

    if (MODE == 2) {
        // Stage transposed fp32 tile in SMEM: tb[col_local*132 + row_local]
        float* tb = (float*)smc;
        __syncthreads();   // all warps done reading stage buffers
#pragma unroll
        for (int nt = 0; nt < 4; nt++) {
            const int cl = wn * 32 + ((lane & 3) << 1) + nt * 8;
            const float b0 = bias[n0 + cl];
            const float b1 = bias[n0 + cl + 1];
#pragma unroll
            for (int mt = 0; mt < 4; mt++) {
                int rl = wm * 64 + (lane >> 2) + mt * 16;
                tb[cl * 132 + rl]           = acc[mt][nt][0] + b0;
                tb[(cl + 1) * 132 + rl]     = acc[mt][nt][1] + b1;
                tb[cl * 132 + rl + 8]       = acc[mt][nt][2] + b0;
                tb[(cl + 1) * 132 + rl + 8] = acc[mt][nt][3] + b1;
            }
        }
        __syncthreads();
        // Coalesced split stores: thread -> (col, half); 64 contiguous S elems
        const int c  = tid >> 1;
        const int hh = tid & 1;
        const float* src = tb + c * 132 + hh * 64;
        const int bidx = m0 >> 11;
        const size_t base = ((size_t)bidx * 1024 + n0 + c) * SS +
                            (m0 & 2047) + hh * 64;
        uint32_t hb[32], lb[32];
#pragma unroll
        for (int i = 0; i < 32; i++) {
            uint16_t ha, la, hbv, lbv;
            split_bf(src[2 * i],     ha,  la);
            split_bf(src[2 * i + 1], hbv, lbv);
            hb[i] = (uint32_t)ha | ((uint32_t)hbv << 16);
            lb[i] = (uint32_t)la | ((uint32_t)lbv << 16);
        }
#pragma unroll
        for (int u = 0; u < 8; u++) {
            *(uint4*)&Chi[base + u * 8] =
                make_uint4(hb[4*u], hb[4*u+1], hb[4*u+2], hb[4*u+3]);
            *(uint4*)&Clo[base + u * 8] =
                make_uint4(lb[4*u], lb[4*u+1], lb[4*u+2], lb[4*u+3]);
        }
        return;
    }

#pragma unroll
    for (int nt = 0; nt < 4; nt++) {
        const int col = col_base + nt * 8;
        const float b0 = bias[col];
        const float b1 = bias[col + 1];
#pragma unroll
        for (int mt = 0; mt < 4; mt++) {
            int r0 = row_base + mt * 16;
            float v0 = acc[mt][nt][0] + b0;
            float v1 = acc[mt][nt][1] + b1;
            float v2 = acc[mt][nt][2] + b0;
            float v3 = acc[mt][nt][3] + b1;
            if (MODE == 0) {
                float qm0 = (float)qmask[r0];
                float qm1 = (float)qmask[r0 + 8];
                *(float2*)&C[(size_t)r0 * DD + col] =
                    make_float2(v0 * qm0, v1 * qm0);
                *(float2*)&C[(size_t)(r0 + 8) * DD + col] =
                    make_float2(v2 * qm1, v3 * qm1);
            } else {
                uint16_t h0,l0,h1,l1,h2,l2,h3,l3;
                split_bf(v0,h0,l0); split_bf(v1,h1,l1);
                split_bf(v2,h2,l2); split_bf(v3,h3,l3);
                *(uint32_t*)&Chi[(size_t)r0 * DD + col] =
                    (uint32_t)h0 | ((uint32_t)h1 << 16);
                *(uint32_t*)&Clo[(size_t)r0 * DD + col] =
                    (uint32_t)l0 | ((uint32_t)l1 << 16);
                *(uint32_t*)&Chi[(size_t)(r0 + 8) * DD + col] =
                    (uint32_t)h2 | ((uint32_t)h3 << 16);
                *(uint32_t*)&Clo[(size_t)(r0 + 8) * DD + col] =
                    (uint32_t)l2 | ((uint32_t)l3 << 16);
            }
        }
    }
}

// ---------------------------------------------------------------------------
// Tensor-core flash attention: presplit bf16 inputs, cp.async double-buffered,
// Q fragments cached in registers across the whole kt loop.
// ---------------------------------------------------------------------------
#define AQ_H 0
#define AQ_L 16384
#define ASTG 32768
#define SK_H 0
#define SK_L 16384
#define SV_H 32768
#define SV_L 50176
#define SVM  67584
#define STG_SZ 68608
#define AT_SMEM (ASTG + 2 * STG_SZ)   // 169984
#define VT_ROW 272

__global__ __launch_bounds__(256, 1)
void attn_mma(const int* __restrict__ v_mask)
{
    extern __shared__ char smc[];
    const uint32_t sb = smem_u32(smc);

    const int tid  = threadIdx.x;
    const int lane = tid & 31;
    const int w    = tid >> 5;
    const int bh = blockIdx.y;
    const int b  = bh >> 4;
    const int h  = bh & 15;
    const int qt = gridDim.x - 1 - blockIdx.x;   // heavy tiles first
    const int q0 = qt * 128;
    const float scale = 0.125f;

    // ---- Q tile: cp.async from presplit g_Qhi/g_Qlo into SW128 SMEM ----
#pragma unroll
    for (int t = 0; t < 8; t++) {
        int idx = tid + t * 256;             // 0..2047
        const char* src = (idx < 1024) ? (const char*)g_Qhi : (const char*)g_Qlo;
        uint32_t dst = sb + ((idx < 1024) ? AQ_H : AQ_L);
        int r = (idx >> 3) & 127;
        int c = idx & 7;
        const void* g = src + ((size_t)(b * SS + q0 + r) * DD + h * 64) * 2 + c * 16;
        cp16(dst + SWZ((uint32_t)(r * 128 + c * 16)), g);
    }

    // stage loader for key tile kt into stage s
    auto load_stage = [&](int kt, int s) {
        const uint32_t stg = sb + ASTG + s * STG_SZ;
#pragma unroll
        for (int t = 0; t < 8; t++) {
            int idx = tid + t * 256;
            const char* src = (idx < 1024) ? (const char*)g_Khi : (const char*)g_Klo;
            uint32_t dst = stg + ((idx < 1024) ? SK_H : SK_L);
            int r = (idx >> 3) & 127;
            int c = idx & 7;
            const void* g = src + ((size_t)(b * SS + kt * 128 + r) * DD + h * 64) * 2 + c * 16;
            cp16(dst + SWZ((uint32_t)(r * 128 + c * 16)), g);
        }
#pragma unroll
        for (int t = 0; t < 8; t++) {
            int idx = tid + t * 256;
            const char* src = (idx < 1024) ? (const char*)g_Vthi : (const char*)g_Vtlo;
            uint32_t dst = stg + ((idx < 1024) ? SV_H : SV_L);
            int rem = idx & 1023;
            int d = rem >> 4;
            int c = rem & 15;
            const void* g = src + (((size_t)(b * 16 + h) * 64 + d) * SS + kt * 128) * 2 + c * 16;
            cp16(dst + (uint32_t)(d * VT_ROW + c * 16), g);
        }
        if (tid < 128) {
            ((float*)(smc + ASTG + s * STG_SZ + SVM))[tid] =
                v_mask[b * SS + kt * 128 + tid] ? 0.0f : -1e12f;
        }
    };

    load_stage(0, 0);
    CP_COMMIT();    // group: Q + stage0
    CP_WAIT0();
    __syncthreads();

    // fragment address components
    const int a_row = w * 16 + (lane & 15);
    const uint32_t a_bc = (uint32_t)((lane >> 4) << 4);
    const int b_rp  = ((lane & 16) >> 1) + (lane & 7);
    const uint32_t b_bc = (uint32_t)((lane & 8) << 1);

    // ---- preload Q fragments (loop-invariant): 32 registers ----
    uint32_t qh[4][4], ql[4][4];
#pragma unroll
    for (int ks = 0; ks < 4; ks++) {
        uint32_t off = SWZ((uint32_t)(a_row * 128 + ks * 32) + a_bc);
        ldsm4(qh[ks], sb + AQ_H + off);
        ldsm4(ql[ks], sb + AQ_L + off);
    }

    float o[8][4];
#pragma unroll
    for (int nt = 0; nt < 8; nt++)
#pragma unroll
        for (int e = 0; e < 4; e++) o[nt][e] = 0.0f;
    float m_lo = -1e30f, m_hi = -1e30f, l_lo = 0.0f, l_hi = 0.0f;

    const int r = lane >> 2;
    const int qi_lo = q0 + w * 16 + r;
    const int qi_hi = qi_lo + 8;
    const int jc = (lane & 3) * 2;

    const int nkt = qt + 1;
    for (int kt = 0; kt < nkt; kt++) {
        // stage(kt) is resident & published; prefetch stage(kt+1) now.
        if (kt + 1 < nkt) { load_stage(kt + 1, (kt + 1) & 1); CP_COMMIT(); }

        const uint32_t stg = sb + ASTG + (kt & 1) * STG_SZ;

        // ---- S = Q K^T, 3-term split bf16, K fragments shared ----
        float s[16][4];
#pragma unroll
        for (int nt = 0; nt < 16; nt++)
#pragma unroll
            for (int e = 0; e < 4; e++) s[nt][e] = 0.0f;

#pragma unroll
        for (int ks = 0; ks < 4; ks++) {
#pragma unroll
            for (int np = 0; np < 8; np++) {
                uint32_t off = SWZ((uint32_t)((np * 16 + b_rp) * 128 + ks * 32) + b_bc);
                uint32_t kh[4], kl[4];
                ldsm4(kh, stg + SK_H + off);
                ldsm4(kl, stg + SK_L + off);
                mma16816(s[np * 2 + 0], qh[ks], kh);
                mma16816(s[np * 2 + 1], qh[ks], kh + 2);
                mma16816(s[np * 2 + 0], ql[ks], kh);
                mma16816(s[np * 2 + 1], ql[ks], kh + 2);
                mma16816(s[np * 2 + 0], qh[ks], kl);
                mma16816(s[np * 2 + 1], qh[ks], kl + 2);
            }
        }

        // ---- mask + online softmax ----
        const bool diag = (kt == qt);
        const float* mvm = (const float*)(smc + ASTG + (kt & 1) * STG_SZ + SVM);
        float mx_lo = -1e30f, mx_hi = -1e30f;
#pragma unroll
        for (int nt = 0; nt < 16; nt++) {
            int jl = nt * 8 + jc;
            int jg = kt * 128 + jl;
            float a0 = mvm[jl], a1 = mvm[jl + 1];
            float v0 = s[nt][0] * scale + a0;
            float v1 = s[nt][1] * scale + a1;
            float v2 = s[nt][2] * scale + a0;
            float v3 = s[nt][3] * scale + a1;
            if (diag) {
                if (jg     > qi_lo) v0 = -1e12f;
                if (jg + 1 > qi_lo) v1 = -1e12f;
                if (jg     > qi_hi) v2 = -1e12f;
                if (jg + 1 > qi_hi) v3 = -1e12f;
            }
            s[nt][0] = v0; s[nt][1] = v1; s[nt][2] = v2; s[nt][3] = v3;
            mx_lo = fmaxf(mx_lo, fmaxf(v0, v1));
            mx_hi = fmaxf(mx_hi, fmaxf(v2, v3));
        }
        mx_lo = fmaxf(mx_lo, __shfl_xor_sync(0xffffffffu, mx_lo, 1));
        mx_lo = fmaxf(mx_lo, __shfl_xor_sync(0xffffffffu, mx_lo, 2));
        mx_hi = fmaxf(mx_hi, __shfl_xor_sync(0xffffffffu, mx_hi, 1));
        mx_hi = fmaxf(mx_hi, __shfl_xor_sync(0xffffffffu, mx_hi, 2));

        float mn_lo = fmaxf(m_lo, mx_lo);
        float mn_hi = fmaxf(m_hi, mx_hi);
        float corr_lo = __expf(m_lo - mn_lo);
        float corr_hi = __expf(m_hi - mn_hi);
        m_lo = mn_lo; m_hi = mn_hi;

        float sum_lo = 0.0f, sum_hi = 0.0f;
#pragma unroll
        for (int nt = 0; nt < 16; nt++) {
            float p0 = __expf(s[nt][0] - mn_lo);
            float p1 = __expf(s[nt][1] - mn_lo);
            float p2 = __expf(s[nt][2] - mn_hi);
            float p3 = __expf(s[nt][3] - mn_hi);
            s[nt][0] = p0; s[nt][1] = p1; s[nt][2] = p2; s[nt][3] = p3;
            sum_lo += p0 + p1;
            sum_hi += p2 + p3;
        }
        sum_lo += __shfl_xor_sync(0xffffffffu, sum_lo, 1);
        sum_lo += __shfl_xor_sync(0xffffffffu, sum_lo, 2);
        sum_hi += __shfl_xor_sync(0xffffffffu, sum_hi, 1);
        sum_hi += __shfl_xor_sync(0xffffffffu, sum_hi, 2);
        l_lo = l_lo * corr_lo + sum_lo;
        l_hi = l_hi * corr_hi + sum_hi;

#pragma unroll
        for (int nt = 0; nt < 8; nt++) {
            o[nt][0] *= corr_lo; o[nt][1] *= corr_lo;
            o[nt][2] *= corr_hi; o[nt][3] *= corr_hi;
        }

        // ---- O += P V, 3-term split bf16 ----
#pragma unroll
        for (int ks = 0; ks < 8; ks++) {
            uint32_t ah[4], al[4];
            {
                uint16_t h0, l0, h1, l1;
                split_bf(s[2*ks][0], h0, l0); split_bf(s[2*ks][1], h1, l1);
                ah[0] = (uint32_t)h0 | ((uint32_t)h1 << 16);
                al[0] = (uint32_t)l0 | ((uint32_t)l1 << 16);
                split_bf(s[2*ks][2], h0, l0); split_bf(s[2*ks][3], h1, l1);
                ah[1] = (uint32_t)h0 | ((uint32_t)h1 << 16);
                al[1] = (uint32_t)l0 | ((uint32_t)l1 << 16);
                split_bf(s[2*ks+1][0], h0, l0); split_bf(s[2*ks+1][1], h1, l1);
                ah[2] = (uint32_t)h0 | ((uint32_t)h1 << 16);
                al[2] = (uint32_t)l0 | ((uint32_t)l1 << 16);
                split_bf(s[2*ks+1][2], h0, l0); split_bf(s[2*ks+1][3], h1, l1);
                ah[3] = (uint32_t)h0 | ((uint32_t)h1 << 16);
                al[3] = (uint32_t)l0 | ((uint32_t)l1 << 16);
            }
#pragma unroll
            for (int np = 0; np < 4; np++) {
                uint32_t addr = (uint32_t)((np * 16 + b_rp) * VT_ROW + ks * 32) + b_bc;
                uint32_t bfh[4], bfl[4];
                ldsm4(bfh, stg + SV_H + addr);
                ldsm4(bfl, stg + SV_L + addr);
                mma16816(o[np * 2 + 0], ah, bfh);
                mma16816(o[np * 2 + 1], ah, bfh + 2);
                mma16816(o[np * 2 + 0], al, bfh);
                mma16816(o[np * 2 + 1], al, bfh + 2);
                mma16816(o[np * 2 + 0], ah, bfl);
                mma16816(o[np * 2 + 1], ah, bfl + 2);
            }
        }

        // publish stage(kt+1) + guard buffer reuse for stage(kt+2)
        CP_WAIT0();
        __syncthreads();
    }

    // ---- normalize + split + store to g_Ohi/g_Olo ----
    float inv_lo = 1.0f / l_lo;
    float inv_hi = 1.0f / l_hi;
    const size_t row_lo = (size_t)(b * SS + q0 + w * 16 + r) * DD + h * 64;
    const size_t row_hi = row_lo + 8 * DD;
#pragma unroll
    for (int nt = 0; nt < 8; nt++) {
        int d0 = nt * 8 + jc;
        uint16_t h0,l0,h1,l1;
        split_bf(o[nt][0] * inv_lo, h0, l0);
        split_bf(o[nt][1] * inv_lo, h1, l1);
        *(uint32_t*)&g_Ohi[row_lo + d0] = (uint32_t)h0 | ((uint32_t)h1 << 16);
        *(uint32_t*)&g_Olo[row_lo + d0] = (uint32_t)l0 | ((uint32_t)l1 << 16);
        split_bf(o[nt][2] * inv_hi, h0, l0);
        split_bf(o[nt][3] * inv_hi, h1, l1);
        *(uint32_t*)&g_Ohi[row_hi + d0] = (uint32_t)h0 | ((uint32_t)h1 << 16);
        *(uint32_t*)&g_Olo[row_hi + d0] = (uint32_t)l0 | ((uint32_t)l1 << 16);
    }
}

// ---------------------------------------------------------------------------
// kernel_launch
// ---------------------------------------------------------------------------
extern "C" void kernel_launch(void* const* d_in, const int* in_sizes, int n_in,
                              void* d_out, int out_size)
{
    const float* q      = (const float*)d_in[0];
    const float* k      = (const float*)d_in[1];
    const float* v      = (const float*)d_in[2];
    const int*   q_mask = (const int*)  d_in[3];
    const int*   v_mask = (const int*)  d_in[4];
    const float* Wq     = (const float*)d_in[5];
    const float* bq     = (const float*)d_in[6];
    const float* Wk     = (const float*)d_in[7];
    const float* bk     = (const float*)d_in[8];
    const float* Wv     = (const float*)d_in[9];
    const float* bv     = (const float*)d_in[10];
    const float* Wo     = (const float*)d_in[11];
    const float* bo     = (const float*)d_in[12];
    float* out = (float*)d_out;

    __nv_bfloat16 *ahi, *alo, *whi, *wlo;
    __nv_bfloat16 *qhi, *qlo, *khi, *klo, *vthi, *vtlo, *ohi, *olo;
    cudaGetSymbolAddress((void**)&ahi, g_Ahi);
    cudaGetSymbolAddress((void**)&alo, g_Alo);
    cudaGetSymbolAddress((void**)&whi, g_Whi);
    cudaGetSymbolAddress((void**)&wlo, g_Wlo);
    cudaGetSymbolAddress((void**)&qhi, g_Qhi);
    cudaGetSymbolAddress((void**)&qlo, g_Qlo);
    cudaGetSymbolAddress((void**)&khi, g_Khi);
    cudaGetSymbolAddress((void**)&klo, g_Klo);
    cudaGetSymbolAddress((void**)&vthi, g_Vthi);
    cudaGetSymbolAddress((void**)&vtlo, g_Vtlo);
    cudaGetSymbolAddress((void**)&ohi, g_Ohi);
    cudaGetSymbolAddress((void**)&olo, g_Olo);

    const int GEMM_SMEM = NSTAGE * STAGE_B;   // 196608
    cudaFuncSetAttribute(gemm_mma<0>,
                         cudaFuncAttributeMaxDynamicSharedMemorySize, GEMM_SMEM);
    cudaFuncSetAttribute(gemm_mma<1>,
                         cudaFuncAttributeMaxDynamicSharedMemorySize, GEMM_SMEM);
    cudaFuncSetAttribute(gemm_mma<2>,
                         cudaFuncAttributeMaxDynamicSharedMemorySize, GEMM_SMEM);
    cudaFuncSetAttribute(attn_mma,
                         cudaFuncAttributeMaxDynamicSharedMemorySize, AT_SMEM);

    dim3 gemm_grid(DD / 128, MM / 128);
    dim3 tr_grid(DD / 32, DD / 32);
    const int n4 = MM * DD / 4;
    const int split_blocks = (n4 + 255) / 256;

    // Q projection -> split bf16
    split_kernel<<<split_blocks, 256>>>(q, ahi, alo, n4);
    wsplit_transpose_kernel<<<tr_grid, 256>>>(Wq, whi, wlo);
    gemm_mma<1><<<gemm_grid, 256, GEMM_SMEM>>>(ahi, alo, whi, wlo, bq, nullptr,
                                               nullptr, qhi, qlo);
    // K projection -> split bf16
    split_kernel<<<split_blocks, 256>>>(k, ahi, alo, n4);
    wsplit_transpose_kernel<<<tr_grid, 256>>>(Wk, whi, wlo);
    gemm_mma<1><<<gemm_grid, 256, GEMM_SMEM>>>(ahi, alo, whi, wlo, bk, nullptr,
                                               nullptr, khi, klo);
    // V projection -> split bf16 transposed
    split_kernel<<<split_blocks, 256>>>(v, ahi, alo, n4);
    wsplit_transpose_kernel<<<tr_grid, 256>>>(Wv, whi, wlo);
    gemm_mma<2><<<gemm_grid, 256, GEMM_SMEM>>>(ahi, alo, whi, wlo, bv, nullptr,
                                               nullptr, vthi, vtlo);

    // Attention (tensor-core, double-buffered, Q cached in registers)
    attn_mma<<<dim3(SS / 128, BB * HH), 256, AT_SMEM>>>(v_mask);

    // Output projection (+ q_mask), reads presplit attention output
    wsplit_transpose_kernel<<<tr_grid, 256>>>(Wo, whi, wlo);
    gemm_mma<0><<<gemm_grid, 256, GEMM_SMEM>>>(ohi, olo, whi, wlo, bo, q_mask,
                                               out, nullptr, nullptr);
}

// round 9
// speedup vs baseline: 2.9525x; 1.0663x over previous
#include <cuda_runtime.h>
#include <cuda_bf16.h>
#include <cstdint>

// Problem constants
#define BB 4
#define SS 2048
#define DD 1024
#define HH 16
#define MM (BB*SS)          // 8192 rows

// Scratch (device globals: allocation-free). All interchange in split bf16.
__device__ __nv_bfloat16 g_Aqhi[MM * DD];
__device__ __nv_bfloat16 g_Aqlo[MM * DD];
__device__ __nv_bfloat16 g_Akhi[MM * DD];
__device__ __nv_bfloat16 g_Aklo[MM * DD];
__device__ __nv_bfloat16 g_Avhi[MM * DD];
__device__ __nv_bfloat16 g_Avlo[MM * DD];
__device__ __nv_bfloat16 g_Wqhi[DD * DD];  // transposed weights: [N, K]
__device__ __nv_bfloat16 g_Wqlo[DD * DD];
__device__ __nv_bfloat16 g_Wkhi[DD * DD];
__device__ __nv_bfloat16 g_Wklo[DD * DD];
__device__ __nv_bfloat16 g_Wvhi[DD * DD];
__device__ __nv_bfloat16 g_Wvlo[DD * DD];
__device__ __nv_bfloat16 g_Wohi[DD * DD];
__device__ __nv_bfloat16 g_Wolo[DD * DD];
__device__ __nv_bfloat16 g_Qhi[MM * DD];   // [row][h*64+d]
__device__ __nv_bfloat16 g_Qlo[MM * DD];
__device__ __nv_bfloat16 g_Khi[MM * DD];
__device__ __nv_bfloat16 g_Klo[MM * DD];
__device__ __nv_bfloat16 g_Vthi[MM * DD];  // transposed: [(b*16+h)*64+d][S]
__device__ __nv_bfloat16 g_Vtlo[MM * DD];
__device__ __nv_bfloat16 g_Ohi[MM * DD];   // attention output, split
__device__ __nv_bfloat16 g_Olo[MM * DD];

// ---------------------------------------------------------------------------
// Helpers: mma.sync + ldmatrix + cp.async (portable sm_80+ path; tcgen05 is
// rejected by the harness's compute_103 virtual arch)
// ---------------------------------------------------------------------------
__device__ __forceinline__ uint32_t smem_u32(const void* p) {
    uint32_t a;
    asm("{ .reg .u64 t; cvta.to.shared.u64 t, %1; cvt.u32.u64 %0, t; }"
        : "=r"(a) : "l"(p));
    return a;
}

__device__ __forceinline__ void ldsm4(uint32_t* r, uint32_t addr) {
    asm volatile("ldmatrix.sync.aligned.m8n8.x4.shared.b16 {%0,%1,%2,%3}, [%4];"
        : "=r"(r[0]), "=r"(r[1]), "=r"(r[2]), "=r"(r[3]) : "r"(addr));
}

__device__ __forceinline__ void mma16816(float* c, const uint32_t* a,
                                         const uint32_t* b) {
    asm volatile(
        "mma.sync.aligned.m16n8k16.row.col.f32.bf16.bf16.f32 "
        "{%0,%1,%2,%3}, {%4,%5,%6,%7}, {%8,%9}, {%0,%1,%2,%3};"
        : "+f"(c[0]), "+f"(c[1]), "+f"(c[2]), "+f"(c[3])
        : "r"(a[0]), "r"(a[1]), "r"(a[2]), "r"(a[3]), "r"(b[0]), "r"(b[1]));
}

__device__ __forceinline__ void cp16(uint32_t saddr, const void* g) {
    asm volatile("cp.async.cg.shared.global [%0], [%1], 16;"
                 :: "r"(saddr), "l"(g) : "memory");
}
#define CP_COMMIT() asm volatile("cp.async.commit_group;" ::: "memory")
#define CP_WAIT0()  asm volatile("cp.async.wait_group 0;" ::: "memory")

// SW128 swizzle on byte offsets within a tile (rows of 128B)
#define SWZ(o) ((o) ^ (((o) >> 3) & 0x70))

__device__ __forceinline__ void split_bf(float v, uint16_t& h, uint16_t& l) {
    __nv_bfloat16 hb = __float2bfloat16(v);
    __nv_bfloat16 lb = __float2bfloat16(v - __bfloat162float(hb));
    h = *(uint16_t*)&hb; l = *(uint16_t*)&lb;
}

// ---------------------------------------------------------------------------
// Fused split of q,k,v inputs (blockIdx.y selects tensor)
// ---------------------------------------------------------------------------
__global__ __launch_bounds__(256)
void split3_kernel(const float* __restrict__ x0, const float* __restrict__ x1,
                   const float* __restrict__ x2, int n4)
{
    int i = blockIdx.x * blockDim.x + threadIdx.x;
    if (i >= n4) return;
    const float* x;
    __nv_bfloat16 *hi, *lo;
    if (blockIdx.y == 0)      { x = x0; hi = g_Aqhi; lo = g_Aqlo; }
    else if (blockIdx.y == 1) { x = x1; hi = g_Akhi; lo = g_Aklo; }
    else                      { x = x2; hi = g_Avhi; lo = g_Avlo; }
    float4 v = ((const float4*)x)[i];
    uint16_t h0,l0,h1,l1,h2,l2,h3,l3;
    split_bf(v.x,h0,l0); split_bf(v.y,h1,l1);
    split_bf(v.z,h2,l2); split_bf(v.w,h3,l3);
    uint2 hv = make_uint2((uint32_t)h0|((uint32_t)h1<<16),
                          (uint32_t)h2|((uint32_t)h3<<16));
    uint2 lv = make_uint2((uint32_t)l0|((uint32_t)l1<<16),
                          (uint32_t)l2|((uint32_t)l3<<16));
    *(uint2*)(hi + (size_t)i * 4) = hv;
    *(uint2*)(lo + (size_t)i * 4) = lv;
}

// Fused W[K,N] fp32 -> Whi/Wlo [N,K] bf16 (transposed), all 4 weights
__global__ __launch_bounds__(256)
void wsplit4_kernel(const float* __restrict__ W0, const float* __restrict__ W1,
                    const float* __restrict__ W2, const float* __restrict__ W3)
{
    __shared__ float t[32][33];
    const float* W;
    __nv_bfloat16 *hi, *lo;
    if (blockIdx.z == 0)      { W = W0; hi = g_Wqhi; lo = g_Wqlo; }
    else if (blockIdx.z == 1) { W = W1; hi = g_Wkhi; lo = g_Wklo; }
    else if (blockIdx.z == 2) { W = W2; hi = g_Wvhi; lo = g_Wvlo; }
    else                      { W = W3; hi = g_Wohi; lo = g_Wolo; }
    int tx = threadIdx.x & 31;
    int ty = threadIdx.x >> 5;
    int n0 = blockIdx.x * 32;
    int k0 = blockIdx.y * 32;
#pragma unroll
    for (int i = 0; i < 4; i++)
        t[ty + 8 * i][tx] = W[(size_t)(k0 + ty + 8 * i) * DD + n0 + tx];
    __syncthreads();
#pragma unroll
    for (int i = 0; i < 4; i++) {
        int n = ty + 8 * i;
        float v = t[tx][n];
        uint16_t h, l;
        split_bf(v, h, l);
        *(uint16_t*)&hi[(size_t)(n0 + n) * DD + k0 + tx] = h;
        *(uint16_t*)&lo[(size_t)(n0 + n) * DD + k0 + tx] = l;
    }
}

// ---------------------------------------------------------------------------
// Split-bf16 tensor-core GEMM (mma.sync), CTA tile 128x256, warp tile 64x64.
// 2-stage cp.async pipeline (96KB/stage). Output modes:
//   0 = fp32 + qmask (final), 1 = split bf16 (Q/K),
//   2 = split bf16 transposed [(b*16+h)*64+d][S] (V), SMEM-staged stores.
// ---------------------------------------------------------------------------
#define BK 64
#define GA_H 0
#define GA_L 16384
#define GB_H 32768
#define GB_L 65536
#define G_STAGE 98304
#define GEMM_SMEM (2 * G_STAGE)   // 196608
#define NK (DD / BK)              // 16

template<int MODE>
__global__ __launch_bounds__(256)
void gemm_mma(const __nv_bfloat16* __restrict__ Ahi,
              const __nv_bfloat16* __restrict__ Alo,
              const __nv_bfloat16* __restrict__ Bhi,
              const __nv_bfloat16* __restrict__ Blo,
              const float* __restrict__ bias,
              const int* __restrict__ qmask,
              float* __restrict__ C,
              __nv_bfloat16* __restrict__ Chi,
              __nv_bfloat16* __restrict__ Clo)
{
    extern __shared__ char smc[];
    const uint32_t sbase = smem_u32(smc);

    const int tid  = threadIdx.x;
    const int lane = tid & 31;
    const int wid  = tid >> 5;
    const int wm   = wid & 1;          // 2 x 64 rows
    const int wn   = wid >> 1;         // 4 x 64 cols
    const int m0 = blockIdx.y * 128;
    const int n0 = blockIdx.x * 256;

    auto load_stage = [&](int it, int s) {
        const int kc = it * BK;
        const uint32_t stb = sbase + s * G_STAGE;
        // A hi/lo: 2 x 128 rows x 8 chunks
#pragma unroll
        for (int i = 0; i < 8; i++) {
            int u = tid + i * 256;          // 0..2047
            int half = u >> 10;
            int rem = u & 1023;
            int r = rem >> 3, c = rem & 7;
            const char* src = half ? (const char*)Alo : (const char*)Ahi;
            cp16(stb + (half ? GA_L : GA_H) + SWZ((uint32_t)(r * 128 + c * 16)),
                 src + ((size_t)(m0 + r) * DD + kc) * 2 + c * 16);
        }
        // B hi/lo: 2 x 256 rows x 8 chunks
#pragma unroll
        for (int i = 0; i < 16; i++) {
            int u = tid + i * 256;          // 0..4095
            int half = u >> 11;
            int rem = u & 2047;
            int r = rem >> 3, c = rem & 7;
            const char* src = half ? (const char*)Blo : (const char*)Bhi;
            cp16(stb + (half ? GB_L : GB_H) + SWZ((uint32_t)(r * 128 + c * 16)),
                 src + ((size_t)(n0 + r) * DD + kc) * 2 + c * 16);
        }
    };

    float acc[4][8][4];
#pragma unroll
    for (int mt = 0; mt < 4; mt++)
#pragma unroll
        for (int nt = 0; nt < 8; nt++)
#pragma unroll
            for (int e = 0; e < 4; e++) acc[mt][nt][e] = 0.0f;

    load_stage(0, 0);
    CP_COMMIT();
    CP_WAIT0();
    __syncthreads();

    const int a_row = wm * 64 + (lane & 15);
    const uint32_t a_bc = (uint32_t)((lane >> 4) << 4);
    const int b_row = wn * 64 + ((lane & 16) >> 1) + (lane & 7);
    const uint32_t b_bc = (uint32_t)((lane & 8) << 1);

    for (int it = 0; it < NK; it++) {
        if (it + 1 < NK) { load_stage(it + 1, (it + 1) & 1); CP_COMMIT(); }

        const uint32_t stb = sbase + (it & 1) * G_STAGE;
        const uint32_t tAh = stb + GA_H;
        const uint32_t tAl = stb + GA_L;
        const uint32_t tBh = stb + GB_H;
        const uint32_t tBl = stb + GB_L;

#pragma unroll
        for (int ks = 0; ks < 4; ks++) {
            uint32_t ah[4][4], al[4][4];
#pragma unroll
            for (int mt = 0; mt < 4; mt++) {
                uint32_t off = (uint32_t)((a_row + mt * 16) * 128) +
                               (uint32_t)(ks * 32) + a_bc;
                ldsm4(ah[mt], tAh + SWZ(off));
                ldsm4(al[mt], tAl + SWZ(off));
            }
#pragma unroll
            for (int np = 0; np < 4; np++) {
                uint32_t bh[4], bl[4];
                uint32_t off = (uint32_t)((b_row + np * 16) * 128) +
                               (uint32_t)(ks * 32) + b_bc;
                ldsm4(bh, tBh + SWZ(off));
                ldsm4(bl, tBl + SWZ(off));
#pragma unroll
                for (int mt = 0; mt < 4; mt++) {
                    mma16816(acc[mt][np * 2 + 0], ah[mt], bh);
                    mma16816(acc[mt][np * 2 + 1], ah[mt], bh + 2);
                    mma16816(acc[mt][np * 2 + 0], ah[mt], bl);
                    mma16816(acc[mt][np * 2 + 1], ah[mt], bl + 2);
                    mma16816(acc[mt][np * 2 + 0], al[mt], bh);
                    mma16816(acc[mt][np * 2 + 1], al[mt], bh + 2);
                }
            }
        }

        CP_WAIT0();
        __syncthreads();
    }

    // Epilogue
    if (MODE == 2) {
        // Stage transposed fp32 tile in SMEM: tb[col_local*132 + row_local]
        float* tb = (float*)smc;
#pragma unroll
        for (int nt = 0; nt < 8; nt++) {
            const int cl = wn * 64 + ((lane & 3) << 1) + nt * 8;
            const float b0 = bias[n0 + cl];
            const float b1 = bias[n0 + cl + 1];
#pragma unroll
            for (int mt = 0; mt < 4; mt++) {
                int rl = wm * 64 + (lane >> 2) + mt * 16;
                tb[cl * 132 + rl]           = acc[mt][nt][0] + b0;
                tb[(cl + 1) * 132 + rl]     = acc[mt][nt][1] + b1;
                tb[cl * 132 + rl + 8]       = acc[mt][nt][2] + b0;
                tb[(cl + 1) * 132 + rl + 8] = acc[mt][nt][3] + b1;
            }
        }
        __syncthreads();
        // Coalesced-in-S split stores: thread = one column, 128 S-elems
        const int c = tid;                 // 0..255
        const float* src = tb + c * 132;
        const size_t base = ((size_t)(m0 >> 11) * 1024 + n0 + c) * SS +
                            (m0 & 2047);
#pragma unroll
        for (int u = 0; u < 8; u++) {
            uint32_t hb[8], lb[8];
#pragma unroll
            for (int i = 0; i < 8; i++) {
                uint16_t ha, la, hbv, lbv;
                split_bf(src[u * 16 + 2 * i],     ha,  la);
                split_bf(src[u * 16 + 2 * i + 1], hbv, lbv);
                hb[i] = (uint32_t)ha | ((uint32_t)hbv << 16);
                lb[i] = (uint32_t)la | ((uint32_t)lbv << 16);
            }
            *(uint4*)&Chi[base + u * 16]     = make_uint4(hb[0], hb[1], hb[2], hb[3]);
            *(uint4*)&Chi[base + u * 16 + 8] = make_uint4(hb[4], hb[5], hb[6], hb[7]);
            *(uint4*)&Clo[base + u * 16]     = make_uint4(lb[0], lb[1], lb[2], lb[3]);
            *(uint4*)&Clo[base + u * 16 + 8] = make_uint4(lb[4], lb[5], lb[6], lb[7]);
        }
        return;
    }

    const int col_base = n0 + wn * 64 + ((lane & 3) << 1);
    const int row_base = m0 + wm * 64 + (lane >> 2);
#pragma unroll
    for (int nt = 0; nt < 8; nt++) {
        const int col = col_base + nt * 8;
        const float b0 = bias[col];
        const float b1 = bias[col + 1];
#pragma unroll
        for (int mt = 0; mt < 4; mt++) {
            int r0 = row_base + mt * 16;
            float v0 = acc[mt][nt][0] + b0;
            float v1 = acc[mt][nt][1] + b1;
            float v2 = acc[mt][nt][2] + b0;
            float v3 = acc[mt][nt][3] + b1;
            if (MODE == 0) {
                float qm0 = (float)qmask[r0];
                float qm1 = (float)qmask[r0 + 8];
                *(float2*)&C[(size_t)r0 * DD + col] =
                    make_float2(v0 * qm0, v1 * qm0);
                *(float2*)&C[(size_t)(r0 + 8) * DD + col] =
                    make_float2(v2 * qm1, v3 * qm1);
            } else {
                uint16_t h0,l0,h1,l1,h2,l2,h3,l3;
                split_bf(v0,h0,l0); split_bf(v1,h1,l1);
                split_bf(v2,h2,l2); split_bf(v3,h3,l3);
                *(uint32_t*)&Chi[(size_t)r0 * DD + col] =
                    (uint32_t)h0 | ((uint32_t)h1 << 16);
                *(uint32_t*)&Clo[(size_t)r0 * DD + col] =
                    (uint32_t)l0 | ((uint32_t)l1 << 16);
                *(uint32_t*)&Chi[(size_t)(r0 + 8) * DD + col] =
                    (uint32_t)h2 | ((uint32_t)h3 << 16);
                *(uint32_t*)&Clo[(size_t)(r0 + 8) * DD + col] =
                    (uint32_t)l2 | ((uint32_t)l3 << 16);
            }
        }
    }
}

// ---------------------------------------------------------------------------
// Tensor-core flash attention: presplit bf16 inputs, cp.async double-buffered,
// Q fragments cached in registers across the whole kt loop. (Unchanged R8.)
// ---------------------------------------------------------------------------
#define AQ_H 0
#define AQ_L 16384
#define ASTG 32768
#define SK_H 0
#define SK_L 16384
#define SV_H 32768
#define SV_L 50176
#define SVM  67584
#define STG_SZ 68608
#define AT_SMEM (ASTG + 2 * STG_SZ)   // 169984
#define VT_ROW 272

__global__ __launch_bounds__(256, 1)
void attn_mma(const int* __restrict__ v_mask)
{
    extern __shared__ char smc[];
    const uint32_t sb = smem_u32(smc);

    const int tid  = threadIdx.x;
    const int lane = tid & 31;
    const int w    = tid >> 5;
    const int bh = blockIdx.y;
    const int b  = bh >> 4;
    const int h  = bh & 15;
    const int qt = gridDim.x - 1 - blockIdx.x;   // heavy tiles first
    const int q0 = qt * 128;
    const float scale = 0.125f;

    // ---- Q tile: cp.async from presplit g_Qhi/g_Qlo into SW128 SMEM ----
#pragma unroll
    for (int t = 0; t < 8; t++) {
        int idx = tid + t * 256;             // 0..2047
        const char* src = (idx < 1024) ? (const char*)g_Qhi : (const char*)g_Qlo;
        uint32_t dst = sb + ((idx < 1024) ? AQ_H : AQ_L);
        int r = (idx >> 3) & 127;
        int c = idx & 7;
        const void* g = src + ((size_t)(b * SS + q0 + r) * DD + h * 64) * 2 + c * 16;
        cp16(dst + SWZ((uint32_t)(r * 128 + c * 16)), g);
    }

    // stage loader for key tile kt into stage s
    auto load_stage = [&](int kt, int s) {
        const uint32_t stg = sb + ASTG + s * STG_SZ;
#pragma unroll
        for (int t = 0; t < 8; t++) {
            int idx = tid + t * 256;
            const char* src = (idx < 1024) ? (const char*)g_Khi : (const char*)g_Klo;
            uint32_t dst = stg + ((idx < 1024) ? SK_H : SK_L);
            int r = (idx >> 3) & 127;
            int c = idx & 7;
            const void* g = src + ((size_t)(b * SS + kt * 128 + r) * DD + h * 64) * 2 + c * 16;
            cp16(dst + SWZ((uint32_t)(r * 128 + c * 16)), g);
        }
#pragma unroll
        for (int t = 0; t < 8; t++) {
            int idx = tid + t * 256;
            const char* src = (idx < 1024) ? (const char*)g_Vthi : (const char*)g_Vtlo;
            uint32_t dst = stg + ((idx < 1024) ? SV_H : SV_L);
            int rem = idx & 1023;
            int d = rem >> 4;
            int c = rem & 15;
            const void* g = src + (((size_t)(b * 16 + h) * 64 + d) * SS + kt * 128) * 2 + c * 16;
            cp16(dst + (uint32_t)(d * VT_ROW + c * 16), g);
        }
        if (tid < 128) {
            ((float*)(smc + ASTG + s * STG_SZ + SVM))[tid] =
                v_mask[b * SS + kt * 128 + tid] ? 0.0f : -1e12f;
        }
    };

    load_stage(0, 0);
    CP_COMMIT();    // group: Q + stage0
    CP_WAIT0();
    __syncthreads();

    // fragment address components
    const int a_row = w * 16 + (lane & 15);
    const uint32_t a_bc = (uint32_t)((lane >> 4) << 4);
    const int b_rp  = ((lane & 16) >> 1) + (lane & 7);
    const uint32_t b_bc = (uint32_t)((lane & 8) << 1);

    // ---- preload Q fragments (loop-invariant): 32 registers ----
    uint32_t qh[4][4], ql[4][4];
#pragma unroll
    for (int ks = 0; ks < 4; ks++) {
        uint32_t off = SWZ((uint32_t)(a_row * 128 + ks * 32) + a_bc);
        ldsm4(qh[ks], sb + AQ_H + off);
        ldsm4(ql[ks], sb + AQ_L + off);
    }

    float o[8][4];
#pragma unroll
    for (int nt = 0; nt < 8; nt++)
#pragma unroll
        for (int e = 0; e < 4; e++) o[nt][e] = 0.0f;
    float m_lo = -1e30f, m_hi = -1e30f, l_lo = 0.0f, l_hi = 0.0f;

    const int r = lane >> 2;
    const int qi_lo = q0 + w * 16 + r;
    const int qi_hi = qi_lo + 8;
    const int jc = (lane & 3) * 2;

    const int nkt = qt + 1;
    for (int kt = 0; kt < nkt; kt++) {
        if (kt + 1 < nkt) { load_stage(kt + 1, (kt + 1) & 1); CP_COMMIT(); }

        const uint32_t stg = sb + ASTG + (kt & 1) * STG_SZ;

        // ---- S = Q K^T, 3-term split bf16, K fragments shared ----
        float s[16][4];
#pragma unroll
        for (int nt = 0; nt < 16; nt++)
#pragma unroll
            for (int e = 0; e < 4; e++) s[nt][e] = 0.0f;

#pragma unroll
        for (int ks = 0; ks < 4; ks++) {
#pragma unroll
            for (int np = 0; np < 8; np++) {
                uint32_t off = SWZ((uint32_t)((np * 16 + b_rp) * 128 + ks * 32) + b_bc);
                uint32_t kh[4], kl[4];
                ldsm4(kh, stg + SK_H + off);
                ldsm4(kl, stg + SK_L + off);
                mma16816(s[np * 2 + 0], qh[ks], kh);
                mma16816(s[np * 2 + 1], qh[ks], kh + 2);
                mma16816(s[np * 2 + 0], ql[ks], kh);
                mma16816(s[np * 2 + 1], ql[ks], kh + 2);
                mma16816(s[np * 2 + 0], qh[ks], kl);
                mma16816(s[np * 2 + 1], qh[ks], kl + 2);
            }
        }

        // ---- mask + online softmax ----
        const bool diag = (kt == qt);
        const float* mvm = (const float*)(smc + ASTG + (kt & 1) * STG_SZ + SVM);
        float mx_lo = -1e30f, mx_hi = -1e30f;
#pragma unroll
        for (int nt = 0; nt < 16; nt++) {
            int jl = nt * 8 + jc;
            int jg = kt * 128 + jl;
            float a0 = mvm[jl], a1 = mvm[jl + 1];
            float v0 = s[nt][0] * scale + a0;
            float v1 = s[nt][1] * scale + a1;
            float v2 = s[nt][2] * scale + a0;
            float v3 = s[nt][3] * scale + a1;
            if (diag) {
                if (jg     > qi_lo) v0 = -1e12f;
                if (jg + 1 > qi_lo) v1 = -1e12f;
                if (jg     > qi_hi) v2 = -1e12f;
                if (jg + 1 > qi_hi) v3 = -1e12f;
            }
            s[nt][0] = v0; s[nt][1] = v1; s[nt][2] = v2; s[nt][3] = v3;
            mx_lo = fmaxf(mx_lo, fmaxf(v0, v1));
            mx_hi = fmaxf(mx_hi, fmaxf(v2, v3));
        }
        mx_lo = fmaxf(mx_lo, __shfl_xor_sync(0xffffffffu, mx_lo, 1));
        mx_lo = fmaxf(mx_lo, __shfl_xor_sync(0xffffffffu, mx_lo, 2));
        mx_hi = fmaxf(mx_hi, __shfl_xor_sync(0xffffffffu, mx_hi, 1));
        mx_hi = fmaxf(mx_hi, __shfl_xor_sync(0xffffffffu, mx_hi, 2));

        float mn_lo = fmaxf(m_lo, mx_lo);
        float mn_hi = fmaxf(m_hi, mx_hi);
        float corr_lo = __expf(m_lo - mn_lo);
        float corr_hi = __expf(m_hi - mn_hi);
        m_lo = mn_lo; m_hi = mn_hi;

        float sum_lo = 0.0f, sum_hi = 0.0f;
#pragma unroll
        for (int nt = 0; nt < 16; nt++) {
            float p0 = __expf(s[nt][0] - mn_lo);
            float p1 = __expf(s[nt][1] - mn_lo);
            float p2 = __expf(s[nt][2] - mn_hi);
            float p3 = __expf(s[nt][3] - mn_hi);
            s[nt][0] = p0; s[nt][1] = p1; s[nt][2] = p2; s[nt][3] = p3;
            sum_lo += p0 + p1;
            sum_hi += p2 + p3;
        }
        sum_lo += __shfl_xor_sync(0xffffffffu, sum_lo, 1);
        sum_lo += __shfl_xor_sync(0xffffffffu, sum_lo, 2);
        sum_hi += __shfl_xor_sync(0xffffffffu, sum_hi, 1);
        sum_hi += __shfl_xor_sync(0xffffffffu, sum_hi, 2);
        l_lo = l_lo * corr_lo + sum_lo;
        l_hi = l_hi * corr_hi + sum_hi;

#pragma unroll
        for (int nt = 0; nt < 8; nt++) {
            o[nt][0] *= corr_lo; o[nt][1] *= corr_lo;
            o[nt][2] *= corr_hi; o[nt][3] *= corr_hi;
        }

        // ---- O += P V, 3-term split bf16 ----
#pragma unroll
        for (int ks = 0; ks < 8; ks++) {
            uint32_t ah[4], al[4];
            {
                uint16_t h0, l0, h1, l1;
                split_bf(s[2*ks][0], h0, l0); split_bf(s[2*ks][1], h1, l1);
                ah[0] = (uint32_t)h0 | ((uint32_t)h1 << 16);
                al[0] = (uint32_t)l0 | ((uint32_t)l1 << 16);
                split_bf(s[2*ks][2], h0, l0); split_bf(s[2*ks][3], h1, l1);
                ah[1] = (uint32_t)h0 | ((uint32_t)h1 << 16);
                al[1] = (uint32_t)l0 | ((uint32_t)l1 << 16);
                split_bf(s[2*ks+1][0], h0, l0); split_bf(s[2*ks+1][1], h1, l1);
                ah[2] = (uint32_t)h0 | ((uint32_t)h1 << 16);
                al[2] = (uint32_t)l0 | ((uint32_t)l1 << 16);
                split_bf(s[2*ks+1][2], h0, l0); split_bf(s[2*ks+1][3], h1, l1);
                ah[3] = (uint32_t)h0 | ((uint32_t)h1 << 16);
                al[3] = (uint32_t)l0 | ((uint32_t)l1 << 16);
            }
#pragma unroll
            for (int np = 0; np < 4; np++) {
                uint32_t addr = (uint32_t)((np * 16 + b_rp) * VT_ROW + ks * 32) + b_bc;
                uint32_t bfh[4], bfl[4];
                ldsm4(bfh, stg + SV_H + addr);
                ldsm4(bfl, stg + SV_L + addr);
                mma16816(o[np * 2 + 0], ah, bfh);
                mma16816(o[np * 2 + 1], ah, bfh + 2);
                mma16816(o[np * 2 + 0], al, bfh);
                mma16816(o[np * 2 + 1], al, bfh + 2);
                mma16816(o[np * 2 + 0], ah, bfl);
                mma16816(o[np * 2 + 1], ah, bfl + 2);
            }
        }

        CP_WAIT0();
        __syncthreads();
    }

    // ---- normalize + split + store to g_Ohi/g_Olo ----
    float inv_lo = 1.0f / l_lo;
    float inv_hi = 1.0f / l_hi;
    const size_t row_lo = (size_t)(b * SS + q0 + w * 16 + r) * DD + h * 64;
    const size_t row_hi = row_lo + 8 * DD;
#pragma unroll
    for (int nt = 0; nt < 8; nt++) {
        int d0 = nt * 8 + jc;
        uint16_t h0,l0,h1,l1;
        split_bf(o[nt][0] * inv_lo, h0, l0);
        split_bf(o[nt][1] * inv_lo, h1, l1);
        *(uint32_t*)&g_Ohi[row_lo + d0] = (uint32_t)h0 | ((uint32_t)h1 << 16);
        *(uint32_t*)&g_Olo[row_lo + d0] = (uint32_t)l0 | ((uint32_t)l1 << 16);
        split_bf(o[nt][2] * inv_hi, h0, l0);
        split_bf(o[nt][3] * inv_hi, h1, l1);
        *(uint32_t*)&g_Ohi[row_hi + d0] = (uint32_t)h0 | ((uint32_t)h1 << 16);
        *(uint32_t*)&g_Olo[row_hi + d0] = (uint32_t)l0 | ((uint32_t)l1 << 16);
    }
}

// ---------------------------------------------------------------------------
// kernel_launch
// ---------------------------------------------------------------------------
extern "C" void kernel_launch(void* const* d_in, const int* in_sizes, int n_in,
                              void* d_out, int out_size)
{
    const float* q      = (const float*)d_in[0];
    const float* k      = (const float*)d_in[1];
    const float* v      = (const float*)d_in[2];
    const int*   q_mask = (const int*)  d_in[3];
    const int*   v_mask = (const int*)  d_in[4];
    const float* Wq     = (const float*)d_in[5];
    const float* bq     = (const float*)d_in[6];
    const float* Wk     = (const float*)d_in[7];
    const float* bk     = (const float*)d_in[8];
    const float* Wv     = (const float*)d_in[9];
    const float* bv     = (const float*)d_in[10];
    const float* Wo     = (const float*)d_in[11];
    const float* bo     = (const float*)d_in[12];
    float* out = (float*)d_out;

    __nv_bfloat16 *aqh, *aql, *akh, *akl, *avh, *avl;
    __nv_bfloat16 *wqh, *wql, *wkh, *wkl, *wvh, *wvl, *woh, *wol;
    __nv_bfloat16 *qhi, *qlo, *khi, *klo, *vthi, *vtlo, *ohi, *olo;
    cudaGetSymbolAddress((void**)&aqh, g_Aqhi);
    cudaGetSymbolAddress((void**)&aql, g_Aqlo);
    cudaGetSymbolAddress((void**)&akh, g_Akhi);
    cudaGetSymbolAddress((void**)&akl, g_Aklo);
    cudaGetSymbolAddress((void**)&avh, g_Avhi);
    cudaGetSymbolAddress((void**)&avl, g_Avlo);
    cudaGetSymbolAddress((void**)&wqh, g_Wqhi);
    cudaGetSymbolAddress((void**)&wql, g_Wqlo);
    cudaGetSymbolAddress((void**)&wkh, g_Wkhi);
    cudaGetSymbolAddress((void**)&wkl, g_Wklo);
    cudaGetSymbolAddress((void**)&wvh, g_Wvhi);
    cudaGetSymbolAddress((void**)&wvl, g_Wvlo);
    cudaGetSymbolAddress((void**)&woh, g_Wohi);
    cudaGetSymbolAddress((void**)&wol, g_Wolo);
    cudaGetSymbolAddress((void**)&qhi, g_Qhi);
    cudaGetSymbolAddress((void**)&qlo, g_Qlo);
    cudaGetSymbolAddress((void**)&khi, g_Khi);
    cudaGetSymbolAddress((void**)&klo, g_Klo);
    cudaGetSymbolAddress((void**)&vthi, g_Vthi);
    cudaGetSymbolAddress((void**)&vtlo, g_Vtlo);
    cudaGetSymbolAddress((void**)&ohi, g_Ohi);
    cudaGetSymbolAddress((void**)&olo, g_Olo);

    cudaFuncSetAttribute(gemm_mma<0>,
                         cudaFuncAttributeMaxDynamicSharedMemorySize, GEMM_SMEM);
    cudaFuncSetAttribute(gemm_mma<1>,
                         cudaFuncAttributeMaxDynamicSharedMemorySize, GEMM_SMEM);
    cudaFuncSetAttribute(gemm_mma<2>,
                         cudaFuncAttributeMaxDynamicSharedMemorySize, GEMM_SMEM);
    cudaFuncSetAttribute(attn_mma,
                         cudaFuncAttributeMaxDynamicSharedMemorySize, AT_SMEM);

    dim3 gemm_grid(DD / 256, MM / 128);     // (4, 64)
    const int n4 = MM * DD / 4;

    // Prep: fused input splits + fused weight splits
    split3_kernel<<<dim3((n4 + 255) / 256, 3), 256>>>(q, k, v, n4);
    wsplit4_kernel<<<dim3(DD / 32, DD / 32, 4), 256>>>(Wq, Wk, Wv, Wo);

    // Projections
    gemm_mma<1><<<gemm_grid, 256, GEMM_SMEM>>>(aqh, aql, wqh, wql, bq, nullptr,
                                               nullptr, qhi, qlo);
    gemm_mma<1><<<gemm_grid, 256, GEMM_SMEM>>>(akh, akl, wkh, wkl, bk, nullptr,
                                               nullptr, khi, klo);
    gemm_mma<2><<<gemm_grid, 256, GEMM_SMEM>>>(avh, avl, wvh, wvl, bv, nullptr,
                                               nullptr, vthi, vtlo);

    // Attention (tensor-core, double-buffered, Q cached in registers)
    attn_mma<<<dim3(SS / 128, BB * HH), 256, AT_SMEM>>>(v_mask);

    // Output projection (+ q_mask), reads presplit attention output
    gemm_mma<0><<<gemm_grid, 256, GEMM_SMEM>>>(ohi, olo, woh, wol, bo, q_mask,
                                               out, nullptr, nullptr);
}

// round 10
// speedup vs baseline: 2.9757x; 1.0078x over previous
#include <cuda_runtime.h>
#include <cuda_bf16.h>
#include <cstdint>

// Problem constants
#define BB 4
#define SS 2048
#define DD 1024
#define HH 16
#define MM (BB*SS)          // 8192 rows

// Scratch (device globals: allocation-free). All interchange in split bf16.
__device__ __nv_bfloat16 g_Aqhi[MM * DD];
__device__ __nv_bfloat16 g_Aqlo[MM * DD];
__device__ __nv_bfloat16 g_Akhi[MM * DD];
__device__ __nv_bfloat16 g_Aklo[MM * DD];
__device__ __nv_bfloat16 g_Avhi[MM * DD];
__device__ __nv_bfloat16 g_Avlo[MM * DD];
__device__ __nv_bfloat16 g_Wqhi[DD * DD];  // transposed weights: [N, K]
__device__ __nv_bfloat16 g_Wqlo[DD * DD];
__device__ __nv_bfloat16 g_Wkhi[DD * DD];
__device__ __nv_bfloat16 g_Wklo[DD * DD];
__device__ __nv_bfloat16 g_Wvhi[DD * DD];
__device__ __nv_bfloat16 g_Wvlo[DD * DD];
__device__ __nv_bfloat16 g_Wohi[DD * DD];
__device__ __nv_bfloat16 g_Wolo[DD * DD];
__device__ __nv_bfloat16 g_Qhi[MM * DD];   // [row][h*64+d]
__device__ __nv_bfloat16 g_Qlo[MM * DD];
__device__ __nv_bfloat16 g_Khi[MM * DD];
__device__ __nv_bfloat16 g_Klo[MM * DD];
__device__ __nv_bfloat16 g_Vthi[MM * DD];  // transposed: [(b*16+h)*64+d][S]
__device__ __nv_bfloat16 g_Vtlo[MM * DD];
__device__ __nv_bfloat16 g_Ohi[MM * DD];   // attention output, split
__device__ __nv_bfloat16 g_Olo[MM * DD];

// ---------------------------------------------------------------------------
// Helpers: mma.sync + ldmatrix + cp.async
// ---------------------------------------------------------------------------
__device__ __forceinline__ uint32_t smem_u32(const void* p) {
    uint32_t a;
    asm("{ .reg .u64 t; cvta.to.shared.u64 t, %1; cvt.u32.u64 %0, t; }"
        : "=r"(a) : "l"(p));
    return a;
}

__device__ __forceinline__ void ldsm4(uint32_t* r, uint32_t addr) {
    asm volatile("ldmatrix.sync.aligned.m8n8.x4.shared.b16 {%0,%1,%2,%3}, [%4];"
        : "=r"(r[0]), "=r"(r[1]), "=r"(r[2]), "=r"(r[3]) : "r"(addr));
}

__device__ __forceinline__ void mma16816(float* c, const uint32_t* a,
                                         const uint32_t* b) {
    asm volatile(
        "mma.sync.aligned.m16n8k16.row.col.f32.bf16.bf16.f32 "
        "{%0,%1,%2,%3}, {%4,%5,%6,%7}, {%8,%9}, {%0,%1,%2,%3};"
        : "+f"(c[0]), "+f"(c[1]), "+f"(c[2]), "+f"(c[3])
        : "r"(a[0]), "r"(a[1]), "r"(a[2]), "r"(a[3]), "r"(b[0]), "r"(b[1]));
}

__device__ __forceinline__ void cp16(uint32_t saddr, const void* g) {
    asm volatile("cp.async.cg.shared.global [%0], [%1], 16;"
                 :: "r"(saddr), "l"(g) : "memory");
}
#define CP_COMMIT() asm volatile("cp.async.commit_group;" ::: "memory")
#define CP_WAIT0()  asm volatile("cp.async.wait_group 0;" ::: "memory")

// SW128 swizzle on byte offsets within a tile (rows of 128B)
#define SWZ(o) ((o) ^ (((o) >> 3) & 0x70))

__device__ __forceinline__ void split_bf(float v, uint16_t& h, uint16_t& l) {
    __nv_bfloat16 hb = __float2bfloat16(v);
    __nv_bfloat16 lb = __float2bfloat16(v - __bfloat162float(hb));
    h = *(uint16_t*)&hb; l = *(uint16_t*)&lb;
}

// ---------------------------------------------------------------------------
// Fused split of q,k,v inputs (blockIdx.y selects tensor)
// ---------------------------------------------------------------------------
__global__ __launch_bounds__(256)
void split3_kernel(const float* __restrict__ x0, const float* __restrict__ x1,
                   const float* __restrict__ x2, int n4)
{
    int i = blockIdx.x * blockDim.x + threadIdx.x;
    if (i >= n4) return;
    const float* x;
    __nv_bfloat16 *hi, *lo;
    if (blockIdx.y == 0)      { x = x0; hi = g_Aqhi; lo = g_Aqlo; }
    else if (blockIdx.y == 1) { x = x1; hi = g_Akhi; lo = g_Aklo; }
    else                      { x = x2; hi = g_Avhi; lo = g_Avlo; }
    float4 v = ((const float4*)x)[i];
    uint16_t h0,l0,h1,l1,h2,l2,h3,l3;
    split_bf(v.x,h0,l0); split_bf(v.y,h1,l1);
    split_bf(v.z,h2,l2); split_bf(v.w,h3,l3);
    uint2 hv = make_uint2((uint32_t)h0|((uint32_t)h1<<16),
                          (uint32_t)h2|((uint32_t)h3<<16));
    uint2 lv = make_uint2((uint32_t)l0|((uint32_t)l1<<16),
                          (uint32_t)l2|((uint32_t)l3<<16));
    *(uint2*)(hi + (size_t)i * 4) = hv;
    *(uint2*)(lo + (size_t)i * 4) = lv;
}

// Fused W[K,N] fp32 -> Whi/Wlo [N,K] bf16 (transposed), all 4 weights
__global__ __launch_bounds__(256)
void wsplit4_kernel(const float* __restrict__ W0, const float* __restrict__ W1,
                    const float* __restrict__ W2, const float* __restrict__ W3)
{
    __shared__ float t[32][33];
    const float* W;
    __nv_bfloat16 *hi, *lo;
    if (blockIdx.z == 0)      { W = W0; hi = g_Wqhi; lo = g_Wqlo; }
    else if (blockIdx.z == 1) { W = W1; hi = g_Wkhi; lo = g_Wklo; }
    else if (blockIdx.z == 2) { W = W2; hi = g_Wvhi; lo = g_Wvlo; }
    else                      { W = W3; hi = g_Wohi; lo = g_Wolo; }
    int tx = threadIdx.x & 31;
    int ty = threadIdx.x >> 5;
    int n0 = blockIdx.x * 32;
    int k0 = blockIdx.y * 32;
#pragma unroll
    for (int i = 0; i < 4; i++)
        t[ty + 8 * i][tx] = W[(size_t)(k0 + ty + 8 * i) * DD + n0 + tx];
    __syncthreads();
#pragma unroll
    for (int i = 0; i < 4; i++) {
        int n = ty + 8 * i;
        float v = t[tx][n];
        uint16_t h, l;
        split_bf(v, h, l);
        *(uint16_t*)&hi[(size_t)(n0 + n) * DD + k0 + tx] = h;
        *(uint16_t*)&lo[(size_t)(n0 + n) * DD + k0 + tx] = l;
    }
}

// ---------------------------------------------------------------------------
// GEMM mainloop shared pieces (CTA tile 128x256, warp tile 64x64, BK=64,
// 2-stage cp.async pipeline). MMA ordering: per (ks,np), three term-passes
// of 8 independent MMAs (acc reuse distance 8) to cover HMMA latency.
// ---------------------------------------------------------------------------
#define BK 64
#define GA_H 0
#define GA_L 16384
#define GB_H 32768
#define GB_L 65536
#define G_STAGE 98304
#define GEMM_SMEM (2 * G_STAGE)   // 196608
#define NK (DD / BK)              // 16

#define GEMM_LOAD_STAGE(Ahi_, Alo_, Bhi_, Blo_, it, s)                         \
    do {                                                                       \
        const int kc_ = (it) * BK;                                             \
        const uint32_t stb_ = sbase + (s) * G_STAGE;                           \
        _Pragma("unroll")                                                      \
        for (int i_ = 0; i_ < 8; i_++) {                                       \
            int u_ = tid + i_ * 256;                                           \
            int half_ = u_ >> 10;                                              \
            int rem_ = u_ & 1023;                                              \
            int r_ = rem_ >> 3, c_ = rem_ & 7;                                 \
            const char* src_ = half_ ? (const char*)(Alo_) : (const char*)(Ahi_);\
            cp16(stb_ + (half_ ? GA_L : GA_H) + SWZ((uint32_t)(r_ * 128 + c_ * 16)),\
                 src_ + ((size_t)(m0 + r_) * DD + kc_) * 2 + c_ * 16);         \
        }                                                                      \
        _Pragma("unroll")                                                      \
        for (int i_ = 0; i_ < 16; i_++) {                                      \
            int u_ = tid + i_ * 256;                                           \
            int half_ = u_ >> 11;                                              \
            int rem_ = u_ & 2047;                                              \
            int r_ = rem_ >> 3, c_ = rem_ & 7;                                 \
            const char* src_ = half_ ? (const char*)(Blo_) : (const char*)(Bhi_);\
            cp16(stb_ + (half_ ? GB_L : GB_H) + SWZ((uint32_t)(r_ * 128 + c_ * 16)),\
                 src_ + ((size_t)(n0 + r_) * DD + kc_) * 2 + c_ * 16);         \
        }                                                                      \
    } while (0)

// Mainloop body: accumulates into acc[4][8][4].
#define GEMM_MAINLOOP(Ahi_, Alo_, Bhi_, Blo_)                                  \
    GEMM_LOAD_STAGE(Ahi_, Alo_, Bhi_, Blo_, 0, 0);                             \
    CP_COMMIT(); CP_WAIT0(); __syncthreads();                                  \
    for (int it = 0; it < NK; it++) {                                          \
        if (it + 1 < NK) {                                                     \
            GEMM_LOAD_STAGE(Ahi_, Alo_, Bhi_, Blo_, it + 1, (it + 1) & 1);     \
            CP_COMMIT();                                                       \
        }                                                                      \
        const uint32_t stb = sbase + (it & 1) * G_STAGE;                       \
        _Pragma("unroll")                                                      \
        for (int ks = 0; ks < 4; ks++) {                                       \
            uint32_t ah[4][4], al[4][4];                                       \
            _Pragma("unroll")                                                  \
            for (int mt = 0; mt < 4; mt++) {                                   \
                uint32_t off = (uint32_t)((a_row + mt * 16) * 128) +           \
                               (uint32_t)(ks * 32) + a_bc;                     \
                ldsm4(ah[mt], stb + GA_H + SWZ(off));                          \
                ldsm4(al[mt], stb + GA_L + SWZ(off));                          \
            }                                                                  \
            _Pragma("unroll")                                                  \
            for (int np = 0; np < 4; np++) {                                   \
                uint32_t bh[4], bl[4];                                         \
                uint32_t off = (uint32_t)((b_row + np * 16) * 128) +           \
                               (uint32_t)(ks * 32) + b_bc;                     \
                ldsm4(bh, stb + GB_H + SWZ(off));                              \
                ldsm4(bl, stb + GB_L + SWZ(off));                              \
                /* term-pass 1: ah*bh (8 independent MMAs) */                  \
                _Pragma("unroll")                                              \
                for (int mt = 0; mt < 4; mt++) {                               \
                    mma16816(acc[mt][np * 2 + 0], ah[mt], bh);                 \
                    mma16816(acc[mt][np * 2 + 1], ah[mt], bh + 2);             \
                }                                                              \
                /* term-pass 2: ah*bl */                                       \
                _Pragma("unroll")                                              \
                for (int mt = 0; mt < 4; mt++) {                               \
                    mma16816(acc[mt][np * 2 + 0], ah[mt], bl);                 \
                    mma16816(acc[mt][np * 2 + 1], ah[mt], bl + 2);             \
                }                                                              \
                /* term-pass 3: al*bh */                                       \
                _Pragma("unroll")                                              \
                for (int mt = 0; mt < 4; mt++) {                               \
                    mma16816(acc[mt][np * 2 + 0], al[mt], bh);                 \
                    mma16816(acc[mt][np * 2 + 1], al[mt], bh + 2);             \
                }                                                              \
            }                                                                  \
        }                                                                      \
        CP_WAIT0();                                                            \
        __syncthreads();                                                       \
    }

// ---------------------------------------------------------------------------
// Merged Q/K/V projection GEMM (blockIdx.z selects input/weight/output).
// z=0: Q (row split out), z=1: K (row split out), z=2: V (transposed out).
// ---------------------------------------------------------------------------
__global__ __launch_bounds__(256)
void gemm_qkv(const float* __restrict__ bq, const float* __restrict__ bk,
              const float* __restrict__ bv)
{
    extern __shared__ char smc[];
    const uint32_t sbase = smem_u32(smc);

    const int tid  = threadIdx.x;
    const int lane = tid & 31;
    const int wid  = tid >> 5;
    const int wm   = wid & 1;
    const int wn   = wid >> 1;
    const int m0 = blockIdx.y * 128;
    const int n0 = blockIdx.x * 256;
    const int z  = blockIdx.z;

    const __nv_bfloat16* Ahi = (z == 0) ? g_Aqhi : (z == 1) ? g_Akhi : g_Avhi;
    const __nv_bfloat16* Alo = (z == 0) ? g_Aqlo : (z == 1) ? g_Aklo : g_Avlo;
    const __nv_bfloat16* Bhi = (z == 0) ? g_Wqhi : (z == 1) ? g_Wkhi : g_Wvhi;
    const __nv_bfloat16* Blo = (z == 0) ? g_Wqlo : (z == 1) ? g_Wklo : g_Wvlo;
    const float* bias = (z == 0) ? bq : (z == 1) ? bk : bv;

    float acc[4][8][4];
#pragma unroll
    for (int mt = 0; mt < 4; mt++)
#pragma unroll
        for (int nt = 0; nt < 8; nt++)
#pragma unroll
            for (int e = 0; e < 4; e++) acc[mt][nt][e] = 0.0f;

    const int a_row = wm * 64 + (lane & 15);
    const uint32_t a_bc = (uint32_t)((lane >> 4) << 4);
    const int b_row = wn * 64 + ((lane & 16) >> 1) + (lane & 7);
    const uint32_t b_bc = (uint32_t)((lane & 8) << 1);

    GEMM_MAINLOOP(Ahi, Alo, Bhi, Blo);

    if (z == 2) {
        // V: transposed epilogue via SMEM staging, coalesced-in-S stores
        float* tb = (float*)smc;
#pragma unroll
        for (int nt = 0; nt < 8; nt++) {
            const int cl = wn * 64 + ((lane & 3) << 1) + nt * 8;
            const float b0 = bias[n0 + cl];
            const float b1 = bias[n0 + cl + 1];
#pragma unroll
            for (int mt = 0; mt < 4; mt++) {
                int rl = wm * 64 + (lane >> 2) + mt * 16;
                tb[cl * 132 + rl]           = acc[mt][nt][0] + b0;
                tb[(cl + 1) * 132 + rl]     = acc[mt][nt][1] + b1;
                tb[cl * 132 + rl + 8]       = acc[mt][nt][2] + b0;
                tb[(cl + 1) * 132 + rl + 8] = acc[mt][nt][3] + b1;
            }
        }
        __syncthreads();
        const int c = tid;
        const float* src = tb + c * 132;
        const size_t base = ((size_t)(m0 >> 11) * 1024 + n0 + c) * SS +
                            (m0 & 2047);
#pragma unroll
        for (int u = 0; u < 8; u++) {
            uint32_t hb[8], lb[8];
#pragma unroll
            for (int i = 0; i < 8; i++) {
                uint16_t ha, la, hbv, lbv;
                split_bf(src[u * 16 + 2 * i],     ha,  la);
                split_bf(src[u * 16 + 2 * i + 1], hbv, lbv);
                hb[i] = (uint32_t)ha | ((uint32_t)hbv << 16);
                lb[i] = (uint32_t)la | ((uint32_t)lbv << 16);
            }
            *(uint4*)&g_Vthi[base + u * 16]     = make_uint4(hb[0], hb[1], hb[2], hb[3]);
            *(uint4*)&g_Vthi[base + u * 16 + 8] = make_uint4(hb[4], hb[5], hb[6], hb[7]);
            *(uint4*)&g_Vtlo[base + u * 16]     = make_uint4(lb[0], lb[1], lb[2], lb[3]);
            *(uint4*)&g_Vtlo[base + u * 16 + 8] = make_uint4(lb[4], lb[5], lb[6], lb[7]);
        }
        return;
    }

    __nv_bfloat16* Chi = (z == 0) ? g_Qhi : g_Khi;
    __nv_bfloat16* Clo = (z == 0) ? g_Qlo : g_Klo;
    const int col_base = n0 + wn * 64 + ((lane & 3) << 1);
    const int row_base = m0 + wm * 64 + (lane >> 2);
#pragma unroll
    for (int nt = 0; nt < 8; nt++) {
        const int col = col_base + nt * 8;
        const float b0 = bias[col];
        const float b1 = bias[col + 1];
#pragma unroll
        for (int mt = 0; mt < 4; mt++) {
            int r0 = row_base + mt * 16;
            float v0 = acc[mt][nt][0] + b0;
            float v1 = acc[mt][nt][1] + b1;
            float v2 = acc[mt][nt][2] + b0;
            float v3 = acc[mt][nt][3] + b1;
            uint16_t h0,l0,h1,l1,h2,l2,h3,l3;
            split_bf(v0,h0,l0); split_bf(v1,h1,l1);
            split_bf(v2,h2,l2); split_bf(v3,h3,l3);
            *(uint32_t*)&Chi[(size_t)r0 * DD + col] =
                (uint32_t)h0 | ((uint32_t)h1 << 16);
            *(uint32_t*)&Clo[(size_t)r0 * DD + col] =
                (uint32_t)l0 | ((uint32_t)l1 << 16);
            *(uint32_t*)&Chi[(size_t)(r0 + 8) * DD + col] =
                (uint32_t)h2 | ((uint32_t)h3 << 16);
            *(uint32_t*)&Clo[(size_t)(r0 + 8) * DD + col] =
                (uint32_t)l2 | ((uint32_t)l3 << 16);
        }
    }
}

// ---------------------------------------------------------------------------
// Output projection GEMM: reads presplit O, writes fp32 + qmask.
// ---------------------------------------------------------------------------
__global__ __launch_bounds__(256)
void gemm_out(const float* __restrict__ bias, const int* __restrict__ qmask,
              float* __restrict__ C)
{
    extern __shared__ char smc[];
    const uint32_t sbase = smem_u32(smc);

    const int tid  = threadIdx.x;
    const int lane = tid & 31;
    const int wid  = tid >> 5;
    const int wm   = wid & 1;
    const int wn   = wid >> 1;
    const int m0 = blockIdx.y * 128;
    const int n0 = blockIdx.x * 256;

    float acc[4][8][4];
#pragma unroll
    for (int mt = 0; mt < 4; mt++)
#pragma unroll
        for (int nt = 0; nt < 8; nt++)
#pragma unroll
            for (int e = 0; e < 4; e++) acc[mt][nt][e] = 0.0f;

    const int a_row = wm * 64 + (lane & 15);
    const uint32_t a_bc = (uint32_t)((lane >> 4) << 4);
    const int b_row = wn * 64 + ((lane & 16) >> 1) + (lane & 7);
    const uint32_t b_bc = (uint32_t)((lane & 8) << 1);

    GEMM_MAINLOOP(g_Ohi, g_Olo, g_Wohi, g_Wolo);

    const int col_base = n0 + wn * 64 + ((lane & 3) << 1);
    const int row_base = m0 + wm * 64 + (lane >> 2);
#pragma unroll
    for (int nt = 0; nt < 8; nt++) {
        const int col = col_base + nt * 8;
        const float b0 = bias[col];
        const float b1 = bias[col + 1];
#pragma unroll
        for (int mt = 0; mt < 4; mt++) {
            int r0 = row_base + mt * 16;
            float qm0 = (float)qmask[r0];
            float qm1 = (float)qmask[r0 + 8];
            *(float2*)&C[(size_t)r0 * DD + col] =
                make_float2((acc[mt][nt][0] + b0) * qm0,
                            (acc[mt][nt][1] + b1) * qm0);
            *(float2*)&C[(size_t)(r0 + 8) * DD + col] =
                make_float2((acc[mt][nt][2] + b0) * qm1,
                            (acc[mt][nt][3] + b1) * qm1);
        }
    }
}

// ---------------------------------------------------------------------------
// Tensor-core flash attention: presplit bf16 inputs, cp.async double-buffered,
// Q fragments cached in registers across the whole kt loop. (Unchanged R8/R9.)
// ---------------------------------------------------------------------------
#define AQ_H 0
#define AQ_L 16384
#define ASTG 32768
#define SK_H 0
#define SK_L 16384
#define SV_H 32768
#define SV_L 50176
#define SVM  67584
#define STG_SZ 68608
#define AT_SMEM (ASTG + 2 * STG_SZ)   // 169984
#define VT_ROW 272

__global__ __launch_bounds__(256, 1)
void attn_mma(const int* __restrict__ v_mask)
{
    extern __shared__ char smc[];
    const uint32_t sb = smem_u32(smc);

    const int tid  = threadIdx.x;
    const int lane = tid & 31;
    const int w    = tid >> 5;
    const int bh = blockIdx.y;
    const int b  = bh >> 4;
    const int h  = bh & 15;
    const int qt = gridDim.x - 1 - blockIdx.x;   // heavy tiles first
    const int q0 = qt * 128;
    const float scale = 0.125f;

    // ---- Q tile: cp.async from presplit g_Qhi/g_Qlo into SW128 SMEM ----
#pragma unroll
    for (int t = 0; t < 8; t++) {
        int idx = tid + t * 256;             // 0..2047
        const char* src = (idx < 1024) ? (const char*)g_Qhi : (const char*)g_Qlo;
        uint32_t dst = sb + ((idx < 1024) ? AQ_H : AQ_L);
        int r = (idx >> 3) & 127;
        int c = idx & 7;
        const void* g = src + ((size_t)(b * SS + q0 + r) * DD + h * 64) * 2 + c * 16;
        cp16(dst + SWZ((uint32_t)(r * 128 + c * 16)), g);
    }

    // stage loader for key tile kt into stage s
    auto load_stage = [&](int kt, int s) {
        const uint32_t stg = sb + ASTG + s * STG_SZ;
#pragma unroll
        for (int t = 0; t < 8; t++) {
            int idx = tid + t * 256;
            const char* src = (idx < 1024) ? (const char*)g_Khi : (const char*)g_Klo;
            uint32_t dst = stg + ((idx < 1024) ? SK_H : SK_L);
            int r = (idx >> 3) & 127;
            int c = idx & 7;
            const void* g = src + ((size_t)(b * SS + kt * 128 + r) * DD + h * 64) * 2 + c * 16;
            cp16(dst + SWZ((uint32_t)(r * 128 + c * 16)), g);
        }
#pragma unroll
        for (int t = 0; t < 8; t++) {
            int idx = tid + t * 256;
            const char* src = (idx < 1024) ? (const char*)g_Vthi : (const char*)g_Vtlo;
            uint32_t dst = stg + ((idx < 1024) ? SV_H : SV_L);
            int rem = idx & 1023;
            int d = rem >> 4;
            int c = rem & 15;
            const void* g = src + (((size_t)(b * 16 + h) * 64 + d) * SS + kt * 128) * 2 + c * 16;
            cp16(dst + (uint32_t)(d * VT_ROW + c * 16), g);
        }
        if (tid < 128) {
            ((float*)(smc + ASTG + s * STG_SZ + SVM))[tid] =
                v_mask[b * SS + kt * 128 + tid] ? 0.0f : -1e12f;
        }
    };

    load_stage(0, 0);
    CP_COMMIT();    // group: Q + stage0
    CP_WAIT0();
    __syncthreads();

    // fragment address components
    const int a_row = w * 16 + (lane & 15);
    const uint32_t a_bc = (uint32_t)((lane >> 4) << 4);
    const int b_rp  = ((lane & 16) >> 1) + (lane & 7);
    const uint32_t b_bc = (uint32_t)((lane & 8) << 1);

    // ---- preload Q fragments (loop-invariant): 32 registers ----
    uint32_t qh[4][4], ql[4][4];
#pragma unroll
    for (int ks = 0; ks < 4; ks++) {
        uint32_t off = SWZ((uint32_t)(a_row * 128 + ks * 32) + a_bc);
        ldsm4(qh[ks], sb + AQ_H + off);
        ldsm4(ql[ks], sb + AQ_L + off);
    }

    float o[8][4];
#pragma unroll
    for (int nt = 0; nt < 8; nt++)
#pragma unroll
        for (int e = 0; e < 4; e++) o[nt][e] = 0.0f;
    float m_lo = -1e30f, m_hi = -1e30f, l_lo = 0.0f, l_hi = 0.0f;

    const int r = lane >> 2;
    const int qi_lo = q0 + w * 16 + r;
    const int qi_hi = qi_lo + 8;
    const int jc = (lane & 3) * 2;

    const int nkt = qt + 1;
    for (int kt = 0; kt < nkt; kt++) {
        if (kt + 1 < nkt) { load_stage(kt + 1, (kt + 1) & 1); CP_COMMIT(); }

        const uint32_t stg = sb + ASTG + (kt & 1) * STG_SZ;

        // ---- S = Q K^T, 3-term split bf16, K fragments shared ----
        float s[16][4];
#pragma unroll
        for (int nt = 0; nt < 16; nt++)
#pragma unroll
            for (int e = 0; e < 4; e++) s[nt][e] = 0.0f;

#pragma unroll
        for (int ks = 0; ks < 4; ks++) {
#pragma unroll
            for (int np = 0; np < 8; np++) {
                uint32_t off = SWZ((uint32_t)((np * 16 + b_rp) * 128 + ks * 32) + b_bc);
                uint32_t kh[4], kl[4];
                ldsm4(kh, stg + SK_H + off);
                ldsm4(kl, stg + SK_L + off);
                mma16816(s[np * 2 + 0], qh[ks], kh);
                mma16816(s[np * 2 + 1], qh[ks], kh + 2);
                mma16816(s[np * 2 + 0], ql[ks], kh);
                mma16816(s[np * 2 + 1], ql[ks], kh + 2);
                mma16816(s[np * 2 + 0], qh[ks], kl);
                mma16816(s[np * 2 + 1], qh[ks], kl + 2);
            }
        }

        // ---- mask + online softmax ----
        const bool diag = (kt == qt);
        const float* mvm = (const float*)(smc + ASTG + (kt & 1) * STG_SZ + SVM);
        float mx_lo = -1e30f, mx_hi = -1e30f;
#pragma unroll
        for (int nt = 0; nt < 16; nt++) {
            int jl = nt * 8 + jc;
            int jg = kt * 128 + jl;
            float a0 = mvm[jl], a1 = mvm[jl + 1];
            float v0 = s[nt][0] * scale + a0;
            float v1 = s[nt][1] * scale + a1;
            float v2 = s[nt][2] * scale + a0;
            float v3 = s[nt][3] * scale + a1;
            if (diag) {
                if (jg     > qi_lo) v0 = -1e12f;
                if (jg + 1 > qi_lo) v1 = -1e12f;
                if (jg     > qi_hi) v2 = -1e12f;
                if (jg + 1 > qi_hi) v3 = -1e12f;
            }
            s[nt][0] = v0; s[nt][1] = v1; s[nt][2] = v2; s[nt][3] = v3;
            mx_lo = fmaxf(mx_lo, fmaxf(v0, v1));
            mx_hi = fmaxf(mx_hi, fmaxf(v2, v3));
        }
        mx_lo = fmaxf(mx_lo, __shfl_xor_sync(0xffffffffu, mx_lo, 1));
        mx_lo = fmaxf(mx_lo, __shfl_xor_sync(0xffffffffu, mx_lo, 2));
        mx_hi = fmaxf(mx_hi, __shfl_xor_sync(0xffffffffu, mx_hi, 1));
        mx_hi = fmaxf(mx_hi, __shfl_xor_sync(0xffffffffu, mx_hi, 2));

        float mn_lo = fmaxf(m_lo, mx_lo);
        float mn_hi = fmaxf(m_hi, mx_hi);
        float corr_lo = __expf(m_lo - mn_lo);
        float corr_hi = __expf(m_hi - mn_hi);
        m_lo = mn_lo; m_hi = mn_hi;

        float sum_lo = 0.0f, sum_hi = 0.0f;
#pragma unroll
        for (int nt = 0; nt < 16; nt++) {
            float p0 = __expf(s[nt][0] - mn_lo);
            float p1 = __expf(s[nt][1] - mn_lo);
            float p2 = __expf(s[nt][2] - mn_hi);
            float p3 = __expf(s[nt][3] - mn_hi);
            s[nt][0] = p0; s[nt][1] = p1; s[nt][2] = p2; s[nt][3] = p3;
            sum_lo += p0 + p1;
            sum_hi += p2 + p3;
        }
        sum_lo += __shfl_xor_sync(0xffffffffu, sum_lo, 1);
        sum_lo += __shfl_xor_sync(0xffffffffu, sum_lo, 2);
        sum_hi += __shfl_xor_sync(0xffffffffu, sum_hi, 1);
        sum_hi += __shfl_xor_sync(0xffffffffu, sum_hi, 2);
        l_lo = l_lo * corr_lo + sum_lo;
        l_hi = l_hi * corr_hi + sum_hi;

#pragma unroll
        for (int nt = 0; nt < 8; nt++) {
            o[nt][0] *= corr_lo; o[nt][1] *= corr_lo;
            o[nt][2] *= corr_hi; o[nt][3] *= corr_hi;
        }

        // ---- O += P V, 3-term split bf16 ----
#pragma unroll
        for (int ks = 0; ks < 8; ks++) {
            uint32_t ah[4], al[4];
            {
                uint16_t h0, l0, h1, l1;
                split_bf(s[2*ks][0], h0, l0); split_bf(s[2*ks][1], h1, l1);
                ah[0] = (uint32_t)h0 | ((uint32_t)h1 << 16);
                al[0] = (uint32_t)l0 | ((uint32_t)l1 << 16);
                split_bf(s[2*ks][2], h0, l0); split_bf(s[2*ks][3], h1, l1);
                ah[1] = (uint32_t)h0 | ((uint32_t)h1 << 16);
                al[1] = (uint32_t)l0 | ((uint32_t)l1 << 16);
                split_bf(s[2*ks+1][0], h0, l0); split_bf(s[2*ks+1][1], h1, l1);
                ah[2] = (uint32_t)h0 | ((uint32_t)h1 << 16);
                al[2] = (uint32_t)l0 | ((uint32_t)l1 << 16);
                split_bf(s[2*ks+1][2], h0, l0); split_bf(s[2*ks+1][3], h1, l1);
                ah[3] = (uint32_t)h0 | ((uint32_t)h1 << 16);
                al[3] = (uint32_t)l0 | ((uint32_t)l1 << 16);
            }
#pragma unroll
            for (int np = 0; np < 4; np++) {
                uint32_t addr = (uint32_t)((np * 16 + b_rp) * VT_ROW + ks * 32) + b_bc;
                uint32_t bfh[4], bfl[4];
                ldsm4(bfh, stg + SV_H + addr);
                ldsm4(bfl, stg + SV_L + addr);
                mma16816(o[np * 2 + 0], ah, bfh);
                mma16816(o[np * 2 + 1], ah, bfh + 2);
                mma16816(o[np * 2 + 0], al, bfh);
                mma16816(o[np * 2 + 1], al, bfh + 2);
                mma16816(o[np * 2 + 0], ah, bfl);
                mma16816(o[np * 2 + 1], ah, bfl + 2);
            }
        }

        CP_WAIT0();
        __syncthreads();
    }

    // ---- normalize + split + store to g_Ohi/g_Olo ----
    float inv_lo = 1.0f / l_lo;
    float inv_hi = 1.0f / l_hi;
    const size_t row_lo = (size_t)(b * SS + q0 + w * 16 + r) * DD + h * 64;
    const size_t row_hi = row_lo + 8 * DD;
#pragma unroll
    for (int nt = 0; nt < 8; nt++) {
        int d0 = nt * 8 + jc;
        uint16_t h0,l0,h1,l1;
        split_bf(o[nt][0] * inv_lo, h0, l0);
        split_bf(o[nt][1] * inv_lo, h1, l1);
        *(uint32_t*)&g_Ohi[row_lo + d0] = (uint32_t)h0 | ((uint32_t)h1 << 16);
        *(uint32_t*)&g_Olo[row_lo + d0] = (uint32_t)l0 | ((uint32_t)l1 << 16);
        split_bf(o[nt][2] * inv_hi, h0, l0);
        split_bf(o[nt][3] * inv_hi, h1, l1);
        *(uint32_t*)&g_Ohi[row_hi + d0] = (uint32_t)h0 | ((uint32_t)h1 << 16);
        *(uint32_t*)&g_Olo[row_hi + d0] = (uint32_t)l0 | ((uint32_t)l1 << 16);
    }
}

// ---------------------------------------------------------------------------
// kernel_launch
// ---------------------------------------------------------------------------
extern "C" void kernel_launch(void* const* d_in, const int* in_sizes, int n_in,
                              void* d_out, int out_size)
{
    const float* q      = (const float*)d_in[0];
    const float* k      = (const float*)d_in[1];
    const float* v      = (const float*)d_in[2];
    const int*   q_mask = (const int*)  d_in[3];
    const int*   v_mask = (const int*)  d_in[4];
    const float* Wq     = (const float*)d_in[5];
    const float* bq     = (const float*)d_in[6];
    const float* Wk     = (const float*)d_in[7];
    const float* bk     = (const float*)d_in[8];
    const float* Wv     = (const float*)d_in[9];
    const float* bv     = (const float*)d_in[10];
    const float* Wo     = (const float*)d_in[11];
    const float* bo     = (const float*)d_in[12];
    float* out = (float*)d_out;

    cudaFuncSetAttribute(gemm_qkv,
                         cudaFuncAttributeMaxDynamicSharedMemorySize, GEMM_SMEM);
    cudaFuncSetAttribute(gemm_out,
                         cudaFuncAttributeMaxDynamicSharedMemorySize, GEMM_SMEM);
    cudaFuncSetAttribute(attn_mma,
                         cudaFuncAttributeMaxDynamicSharedMemorySize, AT_SMEM);

    const int n4 = MM * DD / 4;

    // Prep: fused input splits + fused weight splits
    split3_kernel<<<dim3((n4 + 255) / 256, 3), 256>>>(q, k, v, n4);
    wsplit4_kernel<<<dim3(DD / 32, DD / 32, 4), 256>>>(Wq, Wk, Wv, Wo);

    // Merged Q/K/V projections: one launch, 768 CTAs
    gemm_qkv<<<dim3(DD / 256, MM / 128, 3), 256, GEMM_SMEM>>>(bq, bk, bv);

    // Attention (tensor-core, double-buffered, Q cached in registers)
    attn_mma<<<dim3(SS / 128, BB * HH), 256, AT_SMEM>>>(v_mask);

    // Output projection (+ q_mask), reads presplit attention output
    gemm_out<<<dim3(DD / 256, MM / 128), 256, GEMM_SMEM>>>(bo, q_mask, out);
}

// round 11
// speedup vs baseline: 3.0021x; 1.0089x over previous
#include <cuda_runtime.h>
#include <cuda_bf16.h>
#include <cstdint>

// Problem constants
#define BB 4
#define SS 2048
#define DD 1024
#define HH 16
#define MM (BB*SS)          // 8192 rows

// Q pre-scale: 1/sqrt(64) * log2(e)  (softmax done in base-2)
#define QSCALE 0.18033688011112042f

// Scratch (device globals: allocation-free). All interchange in split bf16.
__device__ __nv_bfloat16 g_Aqhi[MM * DD];
__device__ __nv_bfloat16 g_Aqlo[MM * DD];
__device__ __nv_bfloat16 g_Akhi[MM * DD];
__device__ __nv_bfloat16 g_Aklo[MM * DD];
__device__ __nv_bfloat16 g_Avhi[MM * DD];
__device__ __nv_bfloat16 g_Avlo[MM * DD];
__device__ __nv_bfloat16 g_Wqhi[DD * DD];  // transposed weights: [N, K]
__device__ __nv_bfloat16 g_Wqlo[DD * DD];
__device__ __nv_bfloat16 g_Wkhi[DD * DD];
__device__ __nv_bfloat16 g_Wklo[DD * DD];
__device__ __nv_bfloat16 g_Wvhi[DD * DD];
__device__ __nv_bfloat16 g_Wvlo[DD * DD];
__device__ __nv_bfloat16 g_Wohi[DD * DD];
__device__ __nv_bfloat16 g_Wolo[DD * DD];
__device__ __nv_bfloat16 g_Qhi[MM * DD];   // [row][h*64+d], pre-scaled
__device__ __nv_bfloat16 g_Qlo[MM * DD];
__device__ __nv_bfloat16 g_Khi[MM * DD];
__device__ __nv_bfloat16 g_Klo[MM * DD];
__device__ __nv_bfloat16 g_Vthi[MM * DD];  // transposed: [(b*16+h)*64+d][S]
__device__ __nv_bfloat16 g_Vtlo[MM * DD];
__device__ __nv_bfloat16 g_Ohi[MM * DD];   // attention output, split
__device__ __nv_bfloat16 g_Olo[MM * DD];

// ---------------------------------------------------------------------------
// Helpers
// ---------------------------------------------------------------------------
__device__ __forceinline__ uint32_t smem_u32(const void* p) {
    uint32_t a;
    asm("{ .reg .u64 t; cvta.to.shared.u64 t, %1; cvt.u32.u64 %0, t; }"
        : "=r"(a) : "l"(p));
    return a;
}

__device__ __forceinline__ void ldsm4(uint32_t* r, uint32_t addr) {
    asm volatile("ldmatrix.sync.aligned.m8n8.x4.shared.b16 {%0,%1,%2,%3}, [%4];"
        : "=r"(r[0]), "=r"(r[1]), "=r"(r[2]), "=r"(r[3]) : "r"(addr));
}

__device__ __forceinline__ void mma16816(float* c, const uint32_t* a,
                                         const uint32_t* b) {
    asm volatile(
        "mma.sync.aligned.m16n8k16.row.col.f32.bf16.bf16.f32 "
        "{%0,%1,%2,%3}, {%4,%5,%6,%7}, {%8,%9}, {%0,%1,%2,%3};"
        : "+f"(c[0]), "+f"(c[1]), "+f"(c[2]), "+f"(c[3])
        : "r"(a[0]), "r"(a[1]), "r"(a[2]), "r"(a[3]), "r"(b[0]), "r"(b[1]));
}

__device__ __forceinline__ void cp16(uint32_t saddr, const void* g) {
    asm volatile("cp.async.cg.shared.global [%0], [%1], 16;"
                 :: "r"(saddr), "l"(g) : "memory");
}
#define CP_COMMIT() asm volatile("cp.async.commit_group;" ::: "memory")
#define CP_WAIT0()  asm volatile("cp.async.wait_group 0;" ::: "memory")

// SW128 swizzle on byte offsets within a tile (rows of 128B)
#define SWZ(o) ((o) ^ (((o) >> 3) & 0x70))

__device__ __forceinline__ void split_bf(float v, uint16_t& h, uint16_t& l) {
    __nv_bfloat16 hb = __float2bfloat16(v);
    __nv_bfloat16 lb = __float2bfloat16(v - __bfloat162float(hb));
    h = *(uint16_t*)&hb; l = *(uint16_t*)&lb;
}

// Fast truncation split of 2 floats -> packed hi bf16x2 + lo bf16x2.
__device__ __forceinline__ void split_pack2(float a, float b,
                                            uint32_t& hi2, uint32_t& lo2) {
    uint32_t ba = __float_as_uint(a), bb = __float_as_uint(b);
    asm("prmt.b32 %0, %1, %2, 0x7632;" : "=r"(hi2) : "r"(ba), "r"(bb));
    float la = a - __uint_as_float(ba & 0xFFFF0000u);
    float lb = b - __uint_as_float(bb & 0xFFFF0000u);
    asm("cvt.rn.bf16x2.f32 %0, %1, %2;" : "=r"(lo2) : "f"(lb), "f"(la));
}

__device__ __forceinline__ float ex2f(float x) {
    float y;
    asm("ex2.approx.f32 %0, %1;" : "=f"(y) : "f"(x));
    return y;
}

// ---------------------------------------------------------------------------
// Fused split of q,k,v inputs (blockIdx.y selects tensor)
// ---------------------------------------------------------------------------
__global__ __launch_bounds__(256)
void split3_kernel(const float* __restrict__ x0, const float* __restrict__ x1,
                   const float* __restrict__ x2, int n4)
{
    int i = blockIdx.x * blockDim.x + threadIdx.x;
    if (i >= n4) return;
    const float* x;
    __nv_bfloat16 *hi, *lo;
    if (blockIdx.y == 0)      { x = x0; hi = g_Aqhi; lo = g_Aqlo; }
    else if (blockIdx.y == 1) { x = x1; hi = g_Akhi; lo = g_Aklo; }
    else                      { x = x2; hi = g_Avhi; lo = g_Avlo; }
    float4 v = ((const float4*)x)[i];
    uint16_t h0,l0,h1,l1,h2,l2,h3,l3;
    split_bf(v.x,h0,l0); split_bf(v.y,h1,l1);
    split_bf(v.z,h2,l2); split_bf(v.w,h3,l3);
    uint2 hv = make_uint2((uint32_t)h0|((uint32_t)h1<<16),
                          (uint32_t)h2|((uint32_t)h3<<16));
    uint2 lv = make_uint2((uint32_t)l0|((uint32_t)l1<<16),
                          (uint32_t)l2|((uint32_t)l3<<16));
    *(uint2*)(hi + (size_t)i * 4) = hv;
    *(uint2*)(lo + (size_t)i * 4) = lv;
}

// Fused W[K,N] fp32 -> Whi/Wlo [N,K] bf16 (transposed), all 4 weights
__global__ __launch_bounds__(256)
void wsplit4_kernel(const float* __restrict__ W0, const float* __restrict__ W1,
                    const float* __restrict__ W2, const float* __restrict__ W3)
{
    __shared__ float t[32][33];
    const float* W;
    __nv_bfloat16 *hi, *lo;
    if (blockIdx.z == 0)      { W = W0; hi = g_Wqhi; lo = g_Wqlo; }
    else if (blockIdx.z == 1) { W = W1; hi = g_Wkhi; lo = g_Wklo; }
    else if (blockIdx.z == 2) { W = W2; hi = g_Wvhi; lo = g_Wvlo; }
    else                      { W = W3; hi = g_Wohi; lo = g_Wolo; }
    int tx = threadIdx.x & 31;
    int ty = threadIdx.x >> 5;
    int n0 = blockIdx.x * 32;
    int k0 = blockIdx.y * 32;
#pragma unroll
    for (int i = 0; i < 4; i++)
        t[ty + 8 * i][tx] = W[(size_t)(k0 + ty + 8 * i) * DD + n0 + tx];
    __syncthreads();
#pragma unroll
    for (int i = 0; i < 4; i++) {
        int n = ty + 8 * i;
        float v = t[tx][n];
        uint16_t h, l;
        split_bf(v, h, l);
        *(uint16_t*)&hi[(size_t)(n0 + n) * DD + k0 + tx] = h;
        *(uint16_t*)&lo[(size_t)(n0 + n) * DD + k0 + tx] = l;
    }
}

// ---------------------------------------------------------------------------
// GEMM mainloop (CTA tile 128x256, warp tile 64x64, BK=64, 2-stage pipeline).
// ---------------------------------------------------------------------------
#define BK 64
#define GA_H 0
#define GA_L 16384
#define GB_H 32768
#define GB_L 65536
#define G_STAGE 98304
#define GEMM_SMEM (2 * G_STAGE)   // 196608
#define NK (DD / BK)              // 16

#define GEMM_LOAD_STAGE(Ahi_, Alo_, Bhi_, Blo_, it, s)                         \
    do {                                                                       \
        const int kc_ = (it) * BK;                                             \
        const uint32_t stb_ = sbase + (s) * G_STAGE;                           \
        _Pragma("unroll")                                                      \
        for (int i_ = 0; i_ < 8; i_++) {                                       \
            int u_ = tid + i_ * 256;                                           \
            int half_ = u_ >> 10;                                              \
            int rem_ = u_ & 1023;                                              \
            int r_ = rem_ >> 3, c_ = rem_ & 7;                                 \
            const char* src_ = half_ ? (const char*)(Alo_) : (const char*)(Ahi_);\
            cp16(stb_ + (half_ ? GA_L : GA_H) + SWZ((uint32_t)(r_ * 128 + c_ * 16)),\
                 src_ + ((size_t)(m0 + r_) * DD + kc_) * 2 + c_ * 16);         \
        }                                                                      \
        _Pragma("unroll")                                                      \
        for (int i_ = 0; i_ < 16; i_++) {                                      \
            int u_ = tid + i_ * 256;                                           \
            int half_ = u_ >> 11;                                              \
            int rem_ = u_ & 2047;                                              \
            int r_ = rem_ >> 3, c_ = rem_ & 7;                                 \
            const char* src_ = half_ ? (const char*)(Blo_) : (const char*)(Bhi_);\
            cp16(stb_ + (half_ ? GB_L : GB_H) + SWZ((uint32_t)(r_ * 128 + c_ * 16)),\
                 src_ + ((size_t)(n0 + r_) * DD + kc_) * 2 + c_ * 16);         \
        }                                                                      \
    } while (0)

#define GEMM_MAINLOOP(Ahi_, Alo_, Bhi_, Blo_)                                  \
    GEMM_LOAD_STAGE(Ahi_, Alo_, Bhi_, Blo_, 0, 0);                             \
    CP_COMMIT(); CP_WAIT0(); __syncthreads();                                  \
    for (int it = 0; it < NK; it++) {                                          \
        if (it + 1 < NK) {                                                     \
            GEMM_LOAD_STAGE(Ahi_, Alo_, Bhi_, Blo_, it + 1, (it + 1) & 1);     \
            CP_COMMIT();                                                       \
        }                                                                      \
        const uint32_t stb = sbase + (it & 1) * G_STAGE;                       \
        _Pragma("unroll")                                                      \
        for (int ks = 0; ks < 4; ks++) {                                       \
            uint32_t ah[4][4], al[4][4];                                       \
            _Pragma("unroll")                                                  \
            for (int mt = 0; mt < 4; mt++) {                                   \
                uint32_t off = (uint32_t)((a_row + mt * 16) * 128) +           \
                               (uint32_t)(ks * 32) + a_bc;                     \
                ldsm4(ah[mt], stb + GA_H + SWZ(off));                          \
                ldsm4(al[mt], stb + GA_L + SWZ(off));                          \
            }                                                                  \
            _Pragma("unroll")                                                  \
            for (int np = 0; np < 4; np++) {                                   \
                uint32_t bh[4], bl[4];                                         \
                uint32_t off = (uint32_t)((b_row + np * 16) * 128) +           \
                               (uint32_t)(ks * 32) + b_bc;                     \
                ldsm4(bh, stb + GB_H + SWZ(off));                              \
                ldsm4(bl, stb + GB_L + SWZ(off));                              \
                _Pragma("unroll")                                              \
                for (int mt = 0; mt < 4; mt++) {                               \
                    mma16816(acc[mt][np * 2 + 0], ah[mt], bh);                 \
                    mma16816(acc[mt][np * 2 + 1], ah[mt], bh + 2);             \
                }                                                              \
                _Pragma("unroll")                                              \
                for (int mt = 0; mt < 4; mt++) {                               \
                    mma16816(acc[mt][np * 2 + 0], ah[mt], bl);                 \
                    mma16816(acc[mt][np * 2 + 1], ah[mt], bl + 2);             \
                }                                                              \
                _Pragma("unroll")                                              \
                for (int mt = 0; mt < 4; mt++) {                               \
                    mma16816(acc[mt][np * 2 + 0], al[mt], bh);                 \
                    mma16816(acc[mt][np * 2 + 1], al[mt], bh + 2);             \
                }                                                              \
            }                                                                  \
        }                                                                      \
        CP_WAIT0();                                                            \
        __syncthreads();                                                       \
    }

// ---------------------------------------------------------------------------
// Merged Q/K/V projection GEMM (blockIdx.z: 0=Q (prescaled), 1=K, 2=V trans).
// ---------------------------------------------------------------------------
__global__ __launch_bounds__(256)
void gemm_qkv(const float* __restrict__ bq, const float* __restrict__ bk,
              const float* __restrict__ bv)
{
    extern __shared__ char smc[];
    const uint32_t sbase = smem_u32(smc);

    const int tid  = threadIdx.x;
    const int lane = tid & 31;
    const int wid  = tid >> 5;
    const int wm   = wid & 1;
    const int wn   = wid >> 1;
    const int m0 = blockIdx.y * 128;
    const int n0 = blockIdx.x * 256;
    const int z  = blockIdx.z;

    const __nv_bfloat16* Ahi = (z == 0) ? g_Aqhi : (z == 1) ? g_Akhi : g_Avhi;
    const __nv_bfloat16* Alo = (z == 0) ? g_Aqlo : (z == 1) ? g_Aklo : g_Avlo;
    const __nv_bfloat16* Bhi = (z == 0) ? g_Wqhi : (z == 1) ? g_Wkhi : g_Wvhi;
    const __nv_bfloat16* Blo = (z == 0) ? g_Wqlo : (z == 1) ? g_Wklo : g_Wvlo;
    const float* bias = (z == 0) ? bq : (z == 1) ? bk : bv;

    float acc[4][8][4];
#pragma unroll
    for (int mt = 0; mt < 4; mt++)
#pragma unroll
        for (int nt = 0; nt < 8; nt++)
#pragma unroll
            for (int e = 0; e < 4; e++) acc[mt][nt][e] = 0.0f;

    const int a_row = wm * 64 + (lane & 15);
    const uint32_t a_bc = (uint32_t)((lane >> 4) << 4);
    const int b_row = wn * 64 + ((lane & 16) >> 1) + (lane & 7);
    const uint32_t b_bc = (uint32_t)((lane & 8) << 1);

    GEMM_MAINLOOP(Ahi, Alo, Bhi, Blo);

    if (z == 2) {
        // V: transposed epilogue via SMEM staging, coalesced-in-S stores
        float* tb = (float*)smc;
#pragma unroll
        for (int nt = 0; nt < 8; nt++) {
            const int cl = wn * 64 + ((lane & 3) << 1) + nt * 8;
            const float b0 = bias[n0 + cl];
            const float b1 = bias[n0 + cl + 1];
#pragma unroll
            for (int mt = 0; mt < 4; mt++) {
                int rl = wm * 64 + (lane >> 2) + mt * 16;
                tb[cl * 132 + rl]           = acc[mt][nt][0] + b0;
                tb[(cl + 1) * 132 + rl]     = acc[mt][nt][1] + b1;
                tb[cl * 132 + rl + 8]       = acc[mt][nt][2] + b0;
                tb[(cl + 1) * 132 + rl + 8] = acc[mt][nt][3] + b1;
            }
        }
        __syncthreads();
        const int c = tid;
        const float* src = tb + c * 132;
        const size_t base = ((size_t)(m0 >> 11) * 1024 + n0 + c) * SS +
                            (m0 & 2047);
#pragma unroll
        for (int u = 0; u < 8; u++) {
            uint32_t hb[8], lb[8];
#pragma unroll
            for (int i = 0; i < 8; i++) {
                uint16_t ha, la, hbv, lbv;
                split_bf(src[u * 16 + 2 * i],     ha,  la);
                split_bf(src[u * 16 + 2 * i + 1], hbv, lbv);
                hb[i] = (uint32_t)ha | ((uint32_t)hbv << 16);
                lb[i] = (uint32_t)la | ((uint32_t)lbv << 16);
            }
            *(uint4*)&g_Vthi[base + u * 16]     = make_uint4(hb[0], hb[1], hb[2], hb[3]);
            *(uint4*)&g_Vthi[base + u * 16 + 8] = make_uint4(hb[4], hb[5], hb[6], hb[7]);
            *(uint4*)&g_Vtlo[base + u * 16]     = make_uint4(lb[0], lb[1], lb[2], lb[3]);
            *(uint4*)&g_Vtlo[base + u * 16 + 8] = make_uint4(lb[4], lb[5], lb[6], lb[7]);
        }
        return;
    }

    __nv_bfloat16* Chi = (z == 0) ? g_Qhi : g_Khi;
    __nv_bfloat16* Clo = (z == 0) ? g_Qlo : g_Klo;
    const float sc = (z == 0) ? QSCALE : 1.0f;
    const int col_base = n0 + wn * 64 + ((lane & 3) << 1);
    const int row_base = m0 + wm * 64 + (lane >> 2);
#pragma unroll
    for (int nt = 0; nt < 8; nt++) {
        const int col = col_base + nt * 8;
        const float b0 = bias[col];
        const float b1 = bias[col + 1];
#pragma unroll
        for (int mt = 0; mt < 4; mt++) {
            int r0 = row_base + mt * 16;
            float v0 = (acc[mt][nt][0] + b0) * sc;
            float v1 = (acc[mt][nt][1] + b1) * sc;
            float v2 = (acc[mt][nt][2] + b0) * sc;
            float v3 = (acc[mt][nt][3] + b1) * sc;
            uint16_t h0,l0,h1,l1,h2,l2,h3,l3;
            split_bf(v0,h0,l0); split_bf(v1,h1,l1);
            split_bf(v2,h2,l2); split_bf(v3,h3,l3);
            *(uint32_t*)&Chi[(size_t)r0 * DD + col] =
                (uint32_t)h0 | ((uint32_t)h1 << 16);
            *(uint32_t*)&Clo[(size_t)r0 * DD + col] =
                (uint32_t)l0 | ((uint32_t)l1 << 16);
            *(uint32_t*)&Chi[(size_t)(r0 + 8) * DD + col] =
                (uint32_t)h2 | ((uint32_t)h3 << 16);
            *(uint32_t*)&Clo[(size_t)(r0 + 8) * DD + col] =
                (uint32_t)l2 | ((uint32_t)l3 << 16);
        }
    }
}

// ---------------------------------------------------------------------------
// Output projection GEMM: reads presplit O, writes fp32 + qmask.
// ---------------------------------------------------------------------------
__global__ __launch_bounds__(256)
void gemm_out(const float* __restrict__ bias, const int* __restrict__ qmask,
              float* __restrict__ C)
{
    extern __shared__ char smc[];
    const uint32_t sbase = smem_u32(smc);

    const int tid  = threadIdx.x;
    const int lane = tid & 31;
    const int wid  = tid >> 5;
    const int wm   = wid & 1;
    const int wn   = wid >> 1;
    const int m0 = blockIdx.y * 128;
    const int n0 = blockIdx.x * 256;

    float acc[4][8][4];
#pragma unroll
    for (int mt = 0; mt < 4; mt++)
#pragma unroll
        for (int nt = 0; nt < 8; nt++)
#pragma unroll
            for (int e = 0; e < 4; e++) acc[mt][nt][e] = 0.0f;

    const int a_row = wm * 64 + (lane & 15);
    const uint32_t a_bc = (uint32_t)((lane >> 4) << 4);
    const int b_row = wn * 64 + ((lane & 16) >> 1) + (lane & 7);
    const uint32_t b_bc = (uint32_t)((lane & 8) << 1);

    GEMM_MAINLOOP(g_Ohi, g_Olo, g_Wohi, g_Wolo);

    const int col_base = n0 + wn * 64 + ((lane & 3) << 1);
    const int row_base = m0 + wm * 64 + (lane >> 2);
#pragma unroll
    for (int nt = 0; nt < 8; nt++) {
        const int col = col_base + nt * 8;
        const float b0 = bias[col];
        const float b1 = bias[col + 1];
#pragma unroll
        for (int mt = 0; mt < 4; mt++) {
            int r0 = row_base + mt * 16;
            float qm0 = (float)qmask[r0];
            float qm1 = (float)qmask[r0 + 8];
            *(float2*)&C[(size_t)r0 * DD + col] =
                make_float2((acc[mt][nt][0] + b0) * qm0,
                            (acc[mt][nt][1] + b1) * qm0);
            *(float2*)&C[(size_t)(r0 + 8) * DD + col] =
                make_float2((acc[mt][nt][2] + b0) * qm1,
                            (acc[mt][nt][3] + b1) * qm1);
        }
    }
}

// ---------------------------------------------------------------------------
// Tensor-core flash attention: presplit inputs (Q pre-scaled), base-2 softmax,
// np-paired MMAs for ILP, truncation split packs, double-buffered cp.async.
// ---------------------------------------------------------------------------
#define AQ_H 0
#define AQ_L 16384
#define ASTG 32768
#define SK_H 0
#define SK_L 16384
#define SV_H 32768
#define SV_L 50176
#define SVM  67584
#define STG_SZ 68608
#define AT_SMEM (ASTG + 2 * STG_SZ)   // 169984
#define VT_ROW 272

__global__ __launch_bounds__(256, 1)
void attn_mma(const int* __restrict__ v_mask)
{
    extern __shared__ char smc[];
    const uint32_t sb = smem_u32(smc);

    const int tid  = threadIdx.x;
    const int lane = tid & 31;
    const int w    = tid >> 5;
    const int bh = blockIdx.y;
    const int b  = bh >> 4;
    const int h  = bh & 15;
    const int qt = gridDim.x - 1 - blockIdx.x;   // heavy tiles first
    const int q0 = qt * 128;

    // ---- Q tile: cp.async from presplit g_Qhi/g_Qlo into SW128 SMEM ----
#pragma unroll
    for (int t = 0; t < 8; t++) {
        int idx = tid + t * 256;
        const char* src = (idx < 1024) ? (const char*)g_Qhi : (const char*)g_Qlo;
        uint32_t dst = sb + ((idx < 1024) ? AQ_H : AQ_L);
        int r = (idx >> 3) & 127;
        int c = idx & 7;
        const void* g = src + ((size_t)(b * SS + q0 + r) * DD + h * 64) * 2 + c * 16;
        cp16(dst + SWZ((uint32_t)(r * 128 + c * 16)), g);
    }

    auto load_stage = [&](int kt, int s) {
        const uint32_t stg = sb + ASTG + s * STG_SZ;
#pragma unroll
        for (int t = 0; t < 8; t++) {
            int idx = tid + t * 256;
            const char* src = (idx < 1024) ? (const char*)g_Khi : (const char*)g_Klo;
            uint32_t dst = stg + ((idx < 1024) ? SK_H : SK_L);
            int r = (idx >> 3) & 127;
            int c = idx & 7;
            const void* g = src + ((size_t)(b * SS + kt * 128 + r) * DD + h * 64) * 2 + c * 16;
            cp16(dst + SWZ((uint32_t)(r * 128 + c * 16)), g);
        }
#pragma unroll
        for (int t = 0; t < 8; t++) {
            int idx = tid + t * 256;
            const char* src = (idx < 1024) ? (const char*)g_Vthi : (const char*)g_Vtlo;
            uint32_t dst = stg + ((idx < 1024) ? SV_H : SV_L);
            int rem = idx & 1023;
            int d = rem >> 4;
            int c = rem & 15;
            const void* g = src + (((size_t)(b * 16 + h) * 64 + d) * SS + kt * 128) * 2 + c * 16;
            cp16(dst + (uint32_t)(d * VT_ROW + c * 16), g);
        }
        if (tid < 128) {
            ((float*)(smc + ASTG + s * STG_SZ + SVM))[tid] =
                v_mask[b * SS + kt * 128 + tid] ? 0.0f : -1e12f;
        }
    };

    load_stage(0, 0);
    CP_COMMIT();
    CP_WAIT0();
    __syncthreads();

    const int a_row = w * 16 + (lane & 15);
    const uint32_t a_bc = (uint32_t)((lane >> 4) << 4);
    const int b_rp  = ((lane & 16) >> 1) + (lane & 7);
    const uint32_t b_bc = (uint32_t)((lane & 8) << 1);

    // preload Q-hi fragments (loop-invariant); Q-lo reloaded per ks
    uint32_t qh[4][4];
    uint32_t qoff[4];
#pragma unroll
    for (int ks = 0; ks < 4; ks++) {
        qoff[ks] = SWZ((uint32_t)(a_row * 128 + ks * 32) + a_bc);
        ldsm4(qh[ks], sb + AQ_H + qoff[ks]);
    }

    float o[8][4];
#pragma unroll
    for (int nt = 0; nt < 8; nt++)
#pragma unroll
        for (int e = 0; e < 4; e++) o[nt][e] = 0.0f;
    float m_lo = -1e30f, m_hi = -1e30f, l_lo = 0.0f, l_hi = 0.0f;

    const int r = lane >> 2;
    const int qi_lo = q0 + w * 16 + r;
    const int qi_hi = qi_lo + 8;
    const int jc = (lane & 3) * 2;

    const int nkt = qt + 1;
    for (int kt = 0; kt < nkt; kt++) {
        if (kt + 1 < nkt) { load_stage(kt + 1, (kt + 1) & 1); CP_COMMIT(); }

        const uint32_t stg = sb + ASTG + (kt & 1) * STG_SZ;

        // ---- S = Q K^T, np-paired for ILP (acc reuse distance 4) ----
        float s[16][4];
#pragma unroll
        for (int nt = 0; nt < 16; nt++)
#pragma unroll
            for (int e = 0; e < 4; e++) s[nt][e] = 0.0f;

#pragma unroll
        for (int ks = 0; ks < 4; ks++) {
            uint32_t ql[4];
            ldsm4(ql, sb + AQ_L + qoff[ks]);
#pragma unroll
            for (int npp = 0; npp < 4; npp++) {
                const int np0 = npp * 2, np1 = npp * 2 + 1;
                uint32_t kh0[4], kh1[4], kl0[4], kl1[4];
                uint32_t off0 = SWZ((uint32_t)((np0 * 16 + b_rp) * 128 + ks * 32) + b_bc);
                uint32_t off1 = SWZ((uint32_t)((np1 * 16 + b_rp) * 128 + ks * 32) + b_bc);
                ldsm4(kh0, stg + SK_H + off0);
                ldsm4(kh1, stg + SK_H + off1);
                ldsm4(kl0, stg + SK_L + off0);
                ldsm4(kl1, stg + SK_L + off1);
                float* s0 = s[npp * 4 + 0];
                float* s1 = s[npp * 4 + 1];
                float* s2 = s[npp * 4 + 2];
                float* s3 = s[npp * 4 + 3];
                mma16816(s0, qh[ks], kh0); mma16816(s1, qh[ks], kh0 + 2);
                mma16816(s2, qh[ks], kh1); mma16816(s3, qh[ks], kh1 + 2);
                mma16816(s0, ql,     kh0); mma16816(s1, ql,     kh0 + 2);
                mma16816(s2, ql,     kh1); mma16816(s3, ql,     kh1 + 2);
                mma16816(s0, qh[ks], kl0); mma16816(s1, qh[ks], kl0 + 2);
                mma16816(s2, qh[ks], kl1); mma16816(s3, qh[ks], kl1 + 2);
            }
        }

        // ---- mask + online softmax (base-2; Q pre-scaled by 0.125*log2e) ----
        const bool diag = (kt == qt);
        const float* mvm = (const float*)(smc + ASTG + (kt & 1) * STG_SZ + SVM);
        float mx_lo = -1e30f, mx_hi = -1e30f;
#pragma unroll
        for (int nt = 0; nt < 16; nt++) {
            int jl = nt * 8 + jc;
            int jg = kt * 128 + jl;
            float2 av = *(const float2*)&mvm[jl];
            float v0 = s[nt][0] + av.x;
            float v1 = s[nt][1] + av.y;
            float v2 = s[nt][2] + av.x;
            float v3 = s[nt][3] + av.y;
            if (diag) {
                if (jg     > qi_lo) v0 = -1e12f;
                if (jg + 1 > qi_lo) v1 = -1e12f;
                if (jg     > qi_hi) v2 = -1e12f;
                if (jg + 1 > qi_hi) v3 = -1e12f;
            }
            s[nt][0] = v0; s[nt][1] = v1; s[nt][2] = v2; s[nt][3] = v3;
            mx_lo = fmaxf(mx_lo, fmaxf(v0, v1));
            mx_hi = fmaxf(mx_hi, fmaxf(v2, v3));
        }
        mx_lo = fmaxf(mx_lo, __shfl_xor_sync(0xffffffffu, mx_lo, 1));
        mx_lo = fmaxf(mx_lo, __shfl_xor_sync(0xffffffffu, mx_lo, 2));
        mx_hi = fmaxf(mx_hi, __shfl_xor_sync(0xffffffffu, mx_hi, 1));
        mx_hi = fmaxf(mx_hi, __shfl_xor_sync(0xffffffffu, mx_hi, 2));

        float mn_lo = fmaxf(m_lo, mx_lo);
        float mn_hi = fmaxf(m_hi, mx_hi);
        float corr_lo = ex2f(m_lo - mn_lo);
        float corr_hi = ex2f(m_hi - mn_hi);
        m_lo = mn_lo; m_hi = mn_hi;

        float sum_lo = 0.0f, sum_hi = 0.0f;
#pragma unroll
        for (int nt = 0; nt < 16; nt++) {
            float p0 = ex2f(s[nt][0] - mn_lo);
            float p1 = ex2f(s[nt][1] - mn_lo);
            float p2 = ex2f(s[nt][2] - mn_hi);
            float p3 = ex2f(s[nt][3] - mn_hi);
            s[nt][0] = p0; s[nt][1] = p1; s[nt][2] = p2; s[nt][3] = p3;
            sum_lo += p0 + p1;
            sum_hi += p2 + p3;
        }
        sum_lo += __shfl_xor_sync(0xffffffffu, sum_lo, 1);
        sum_lo += __shfl_xor_sync(0xffffffffu, sum_lo, 2);
        sum_hi += __shfl_xor_sync(0xffffffffu, sum_hi, 1);
        sum_hi += __shfl_xor_sync(0xffffffffu, sum_hi, 2);
        l_lo = l_lo * corr_lo + sum_lo;
        l_hi = l_hi * corr_hi + sum_hi;

#pragma unroll
        for (int nt = 0; nt < 8; nt++) {
            o[nt][0] *= corr_lo; o[nt][1] *= corr_lo;
            o[nt][2] *= corr_hi; o[nt][3] *= corr_hi;
        }

        // ---- O += P V, np-paired, truncation-split packs ----
#pragma unroll
        for (int ks = 0; ks < 8; ks++) {
            uint32_t ah[4], al[4];
            split_pack2(s[2*ks][0],   s[2*ks][1],   ah[0], al[0]);
            split_pack2(s[2*ks][2],   s[2*ks][3],   ah[1], al[1]);
            split_pack2(s[2*ks+1][0], s[2*ks+1][1], ah[2], al[2]);
            split_pack2(s[2*ks+1][2], s[2*ks+1][3], ah[3], al[3]);
#pragma unroll
            for (int npp = 0; npp < 2; npp++) {
                const int np0 = npp * 2, np1 = npp * 2 + 1;
                uint32_t a0 = (uint32_t)((np0 * 16 + b_rp) * VT_ROW + ks * 32) + b_bc;
                uint32_t a1 = (uint32_t)((np1 * 16 + b_rp) * VT_ROW + ks * 32) + b_bc;
                uint32_t bh0[4], bh1[4], bl0[4], bl1[4];
                ldsm4(bh0, stg + SV_H + a0);
                ldsm4(bh1, stg + SV_H + a1);
                ldsm4(bl0, stg + SV_L + a0);
                ldsm4(bl1, stg + SV_L + a1);
                float* o0 = o[np0 * 2 + 0];
                float* o1 = o[np0 * 2 + 1];
                float* o2 = o[np1 * 2 + 0];
                float* o3 = o[np1 * 2 + 1];
                mma16816(o0, ah, bh0); mma16816(o1, ah, bh0 + 2);
                mma16816(o2, ah, bh1); mma16816(o3, ah, bh1 + 2);
                mma16816(o0, al, bh0); mma16816(o1, al, bh0 + 2);
                mma16816(o2, al, bh1); mma16816(o3, al, bh1 + 2);
                mma16816(o0, ah, bl0); mma16816(o1, ah, bl0 + 2);
                mma16816(o2, ah, bl1); mma16816(o3, ah, bl1 + 2);
            }
        }

        CP_WAIT0();
        __syncthreads();
    }

    // ---- normalize + split + store to g_Ohi/g_Olo ----
    float inv_lo = 1.0f / l_lo;
    float inv_hi = 1.0f / l_hi;
    const size_t row_lo = (size_t)(b * SS + q0 + w * 16 + r) * DD + h * 64;
    const size_t row_hi = row_lo + 8 * DD;
#pragma unroll
    for (int nt = 0; nt < 8; nt++) {
        int d0 = nt * 8 + jc;
        uint16_t h0,l0,h1,l1;
        split_bf(o[nt][0] * inv_lo, h0, l0);
        split_bf(o[nt][1] * inv_lo, h1, l1);
        *(uint32_t*)&g_Ohi[row_lo + d0] = (uint32_t)h0 | ((uint32_t)h1 << 16);
        *(uint32_t*)&g_Olo[row_lo + d0] = (uint32_t)l0 | ((uint32_t)l1 << 16);
        split_bf(o[nt][2] * inv_hi, h0, l0);
        split_bf(o[nt][3] * inv_hi, h1, l1);
        *(uint32_t*)&g_Ohi[row_hi + d0] = (uint32_t)h0 | ((uint32_t)h1 << 16);
        *(uint32_t*)&g_Olo[row_hi + d0] = (uint32_t)l0 | ((uint32_t)l1 << 16);
    }
}

// ---------------------------------------------------------------------------
// kernel_launch
// ---------------------------------------------------------------------------
extern "C" void kernel_launch(void* const* d_in, const int* in_sizes, int n_in,
                              void* d_out, int out_size)
{
    const float* q      = (const float*)d_in[0];
    const float* k      = (const float*)d_in[1];
    const float* v      = (const float*)d_in[2];
    const int*   q_mask = (const int*)  d_in[3];
    const int*   v_mask = (const int*)  d_in[4];
    const float* Wq     = (const float*)d_in[5];
    const float* bq     = (const float*)d_in[6];
    const float* Wk     = (const float*)d_in[7];
    const float* bk     = (const float*)d_in[8];
    const float* Wv     = (const float*)d_in[9];
    const float* bv     = (const float*)d_in[10];
    const float* Wo     = (const float*)d_in[11];
    const float* bo     = (const float*)d_in[12];
    float* out = (float*)d_out;

    cudaFuncSetAttribute(gemm_qkv,
                         cudaFuncAttributeMaxDynamicSharedMemorySize, GEMM_SMEM);
    cudaFuncSetAttribute(gemm_out,
                         cudaFuncAttributeMaxDynamicSharedMemorySize, GEMM_SMEM);
    cudaFuncSetAttribute(attn_mma,
                         cudaFuncAttributeMaxDynamicSharedMemorySize, AT_SMEM);

    const int n4 = MM * DD / 4;

    split3_kernel<<<dim3((n4 + 255) / 256, 3), 256>>>(q, k, v, n4);
    wsplit4_kernel<<<dim3(DD / 32, DD / 32, 4), 256>>>(Wq, Wk, Wv, Wo);

    gemm_qkv<<<dim3(DD / 256, MM / 128, 3), 256, GEMM_SMEM>>>(bq, bk, bv);

    attn_mma<<<dim3(SS / 128, BB * HH), 256, AT_SMEM>>>(v_mask);

    gemm_out<<<dim3(DD / 256, MM / 128), 256, GEMM_SMEM>>>(bo, q_mask, out);
}

// round 12
// speedup vs baseline: 3.0746x; 1.0242x over previous
#include <cuda_runtime.h>
#include <cuda_bf16.h>
#include <cstdint>

// Problem constants
#define BB 4
#define SS 2048
#define DD 1024
#define HH 16
#define MM (BB*SS)          // 8192 rows

// Q pre-scale: 1/sqrt(64) * log2(e)  (softmax done in base-2)
#define QSCALE 0.18033688011112042f

// Scratch (device globals: allocation-free). All interchange in split bf16.
__device__ __nv_bfloat16 g_Aqhi[MM * DD];
__device__ __nv_bfloat16 g_Aqlo[MM * DD];
__device__ __nv_bfloat16 g_Akhi[MM * DD];
__device__ __nv_bfloat16 g_Aklo[MM * DD];
__device__ __nv_bfloat16 g_Avhi[MM * DD];
__device__ __nv_bfloat16 g_Avlo[MM * DD];
__device__ __nv_bfloat16 g_Wqhi[DD * DD];  // transposed weights: [N, K]
__device__ __nv_bfloat16 g_Wqlo[DD * DD];
__device__ __nv_bfloat16 g_Wkhi[DD * DD];
__device__ __nv_bfloat16 g_Wklo[DD * DD];
__device__ __nv_bfloat16 g_Wvhi[DD * DD];
__device__ __nv_bfloat16 g_Wvlo[DD * DD];
__device__ __nv_bfloat16 g_Wohi[DD * DD];
__device__ __nv_bfloat16 g_Wolo[DD * DD];
__device__ __nv_bfloat16 g_Qhi[MM * DD];   // [row][h*64+d], pre-scaled
__device__ __nv_bfloat16 g_Qlo[MM * DD];
__device__ __nv_bfloat16 g_Khi[MM * DD];
__device__ __nv_bfloat16 g_Klo[MM * DD];
__device__ __nv_bfloat16 g_Vthi[MM * DD];  // transposed: [(b*16+h)*64+d][S]
__device__ __nv_bfloat16 g_Vtlo[MM * DD];
__device__ __nv_bfloat16 g_Ohi[MM * DD];   // attention output, split
__device__ __nv_bfloat16 g_Olo[MM * DD];

// ---------------------------------------------------------------------------
// Helpers
// ---------------------------------------------------------------------------
__device__ __forceinline__ uint32_t smem_u32(const void* p) {
    uint32_t a;
    asm("{ .reg .u64 t; cvta.to.shared.u64 t, %1; cvt.u32.u64 %0, t; }"
        : "=r"(a) : "l"(p));
    return a;
}

__device__ __forceinline__ void ldsm4(uint32_t* r, uint32_t addr) {
    asm volatile("ldmatrix.sync.aligned.m8n8.x4.shared.b16 {%0,%1,%2,%3}, [%4];"
        : "=r"(r[0]), "=r"(r[1]), "=r"(r[2]), "=r"(r[3]) : "r"(addr));
}

__device__ __forceinline__ void mma16816(float* c, const uint32_t* a,
                                         const uint32_t* b) {
    asm volatile(
        "mma.sync.aligned.m16n8k16.row.col.f32.bf16.bf16.f32 "
        "{%0,%1,%2,%3}, {%4,%5,%6,%7}, {%8,%9}, {%0,%1,%2,%3};"
        : "+f"(c[0]), "+f"(c[1]), "+f"(c[2]), "+f"(c[3])
        : "r"(a[0]), "r"(a[1]), "r"(a[2]), "r"(a[3]), "r"(b[0]), "r"(b[1]));
}

__device__ __forceinline__ void cp16(uint32_t saddr, const void* g) {
    asm volatile("cp.async.cg.shared.global [%0], [%1], 16;"
                 :: "r"(saddr), "l"(g) : "memory");
}
#define CP_COMMIT() asm volatile("cp.async.commit_group;" ::: "memory")
#define CP_WAIT0()  asm volatile("cp.async.wait_group 0;" ::: "memory")

// SW128 swizzle on byte offsets within a tile (rows of 128B)
#define SWZ(o) ((o) ^ (((o) >> 3) & 0x70))

__device__ __forceinline__ void split_bf(float v, uint16_t& h, uint16_t& l) {
    __nv_bfloat16 hb = __float2bfloat16(v);
    __nv_bfloat16 lb = __float2bfloat16(v - __bfloat162float(hb));
    h = *(uint16_t*)&hb; l = *(uint16_t*)&lb;
}

// Fast truncation split of 2 floats -> packed hi bf16x2 + lo bf16x2.
__device__ __forceinline__ void split_pack2(float a, float b,
                                            uint32_t& hi2, uint32_t& lo2) {
    uint32_t ba = __float_as_uint(a), bb = __float_as_uint(b);
    asm("prmt.b32 %0, %1, %2, 0x7632;" : "=r"(hi2) : "r"(ba), "r"(bb));
    float la = a - __uint_as_float(ba & 0xFFFF0000u);
    float lb = b - __uint_as_float(bb & 0xFFFF0000u);
    asm("cvt.rn.bf16x2.f32 %0, %1, %2;" : "=r"(lo2) : "f"(lb), "f"(la));
}

__device__ __forceinline__ float ex2f(float x) {
    float y;
    asm("ex2.approx.f32 %0, %1;" : "=f"(y) : "f"(x));
    return y;
}

// ---------------------------------------------------------------------------
// Fused split of q,k,v inputs (blockIdx.y selects tensor)
// ---------------------------------------------------------------------------
__global__ __launch_bounds__(256)
void split3_kernel(const float* __restrict__ x0, const float* __restrict__ x1,
                   const float* __restrict__ x2, int n4)
{
    int i = blockIdx.x * blockDim.x + threadIdx.x;
    if (i >= n4) return;
    const float* x;
    __nv_bfloat16 *hi, *lo;
    if (blockIdx.y == 0)      { x = x0; hi = g_Aqhi; lo = g_Aqlo; }
    else if (blockIdx.y == 1) { x = x1; hi = g_Akhi; lo = g_Aklo; }
    else                      { x = x2; hi = g_Avhi; lo = g_Avlo; }
    float4 v = ((const float4*)x)[i];
    uint16_t h0,l0,h1,l1,h2,l2,h3,l3;
    split_bf(v.x,h0,l0); split_bf(v.y,h1,l1);
    split_bf(v.z,h2,l2); split_bf(v.w,h3,l3);
    uint2 hv = make_uint2((uint32_t)h0|((uint32_t)h1<<16),
                          (uint32_t)h2|((uint32_t)h3<<16));
    uint2 lv = make_uint2((uint32_t)l0|((uint32_t)l1<<16),
                          (uint32_t)l2|((uint32_t)l3<<16));
    *(uint2*)(hi + (size_t)i * 4) = hv;
    *(uint2*)(lo + (size_t)i * 4) = lv;
}

// Fused W[K,N] fp32 -> Whi/Wlo [N,K] bf16 (transposed), all 4 weights
__global__ __launch_bounds__(256)
void wsplit4_kernel(const float* __restrict__ W0, const float* __restrict__ W1,
                    const float* __restrict__ W2, const float* __restrict__ W3)
{
    __shared__ float t[32][33];
    const float* W;
    __nv_bfloat16 *hi, *lo;
    if (blockIdx.z == 0)      { W = W0; hi = g_Wqhi; lo = g_Wqlo; }
    else if (blockIdx.z == 1) { W = W1; hi = g_Wkhi; lo = g_Wklo; }
    else if (blockIdx.z == 2) { W = W2; hi = g_Wvhi; lo = g_Wvlo; }
    else                      { W = W3; hi = g_Wohi; lo = g_Wolo; }
    int tx = threadIdx.x & 31;
    int ty = threadIdx.x >> 5;
    int n0 = blockIdx.x * 32;
    int k0 = blockIdx.y * 32;
#pragma unroll
    for (int i = 0; i < 4; i++)
        t[ty + 8 * i][tx] = W[(size_t)(k0 + ty + 8 * i) * DD + n0 + tx];
    __syncthreads();
#pragma unroll
    for (int i = 0; i < 4; i++) {
        int n = ty + 8 * i;
        float v = t[tx][n];
        uint16_t h, l;
        split_bf(v, h, l);
        *(uint16_t*)&hi[(size_t)(n0 + n) * DD + k0 + tx] = h;
        *(uint16_t*)&lo[(size_t)(n0 + n) * DD + k0 + tx] = l;
    }
}

// ---------------------------------------------------------------------------
// GEMM mainloop (CTA tile 128x256, warp tile 64x64, BK=64, 2-stage pipeline).
// ---------------------------------------------------------------------------
#define BK 64
#define GA_H 0
#define GA_L 16384
#define GB_H 32768
#define GB_L 65536
#define G_STAGE 98304
#define GEMM_SMEM (2 * G_STAGE)   // 196608
#define NK (DD / BK)              // 16

#define GEMM_LOAD_STAGE(Ahi_, Alo_, Bhi_, Blo_, it, s)                         \
    do {                                                                       \
        const int kc_ = (it) * BK;                                             \
        const uint32_t stb_ = sbase + (s) * G_STAGE;                           \
        _Pragma("unroll")                                                      \
        for (int i_ = 0; i_ < 8; i_++) {                                       \
            int u_ = tid + i_ * 256;                                           \
            int half_ = u_ >> 10;                                              \
            int rem_ = u_ & 1023;                                              \
            int r_ = rem_ >> 3, c_ = rem_ & 7;                                 \
            const char* src_ = half_ ? (const char*)(Alo_) : (const char*)(Ahi_);\
            cp16(stb_ + (half_ ? GA_L : GA_H) + SWZ((uint32_t)(r_ * 128 + c_ * 16)),\
                 src_ + ((size_t)(m0 + r_) * DD + kc_) * 2 + c_ * 16);         \
        }                                                                      \
        _Pragma("unroll")                                                      \
        for (int i_ = 0; i_ < 16; i_++) {                                      \
            int u_ = tid + i_ * 256;                                           \
            int half_ = u_ >> 11;                                              \
            int rem_ = u_ & 2047;                                              \
            int r_ = rem_ >> 3, c_ = rem_ & 7;                                 \
            const char* src_ = half_ ? (const char*)(Blo_) : (const char*)(Bhi_);\
            cp16(stb_ + (half_ ? GB_L : GB_H) + SWZ((uint32_t)(r_ * 128 + c_ * 16)),\
                 src_ + ((size_t)(n0 + r_) * DD + kc_) * 2 + c_ * 16);         \
        }                                                                      \
    } while (0)

#define GEMM_MAINLOOP(Ahi_, Alo_, Bhi_, Blo_)                                  \
    GEMM_LOAD_STAGE(Ahi_, Alo_, Bhi_, Blo_, 0, 0);                             \
    CP_COMMIT(); CP_WAIT0(); __syncthreads();                                  \
    for (int it = 0; it < NK; it++) {                                          \
        if (it + 1 < NK) {                                                     \
            GEMM_LOAD_STAGE(Ahi_, Alo_, Bhi_, Blo_, it + 1, (it + 1) & 1);     \
            CP_COMMIT();                                                       \
        }                                                                      \
        const uint32_t stb = sbase + (it & 1) * G_STAGE;                       \
        _Pragma("unroll")                                                      \
        for (int ks = 0; ks < 4; ks++) {                                       \
            uint32_t ah[4][4], al[4][4];                                       \
            _Pragma("unroll")                                                  \
            for (int mt = 0; mt < 4; mt++) {                                   \
                uint32_t off = (uint32_t)((a_row + mt * 16) * 128) +           \
                               (uint32_t)(ks * 32) + a_bc;                     \
                ldsm4(ah[mt], stb + GA_H + SWZ(off));                          \
                ldsm4(al[mt], stb + GA_L + SWZ(off));                          \
            }                                                                  \
            _Pragma("unroll")                                                  \
            for (int np = 0; np < 4; np++) {                                   \
                uint32_t bh[4], bl[4];                                         \
                uint32_t off = (uint32_t)((b_row + np * 16) * 128) +           \
                               (uint32_t)(ks * 32) + b_bc;                     \
                ldsm4(bh, stb + GB_H + SWZ(off));                              \
                ldsm4(bl, stb + GB_L + SWZ(off));                              \
                _Pragma("unroll")                                              \
                for (int mt = 0; mt < 4; mt++) {                               \
                    mma16816(acc[mt][np * 2 + 0], ah[mt], bh);                 \
                    mma16816(acc[mt][np * 2 + 1], ah[mt], bh + 2);             \
                }                                                              \
                _Pragma("unroll")                                              \
                for (int mt = 0; mt < 4; mt++) {                               \
                    mma16816(acc[mt][np * 2 + 0], ah[mt], bl);                 \
                    mma16816(acc[mt][np * 2 + 1], ah[mt], bl + 2);             \
                }                                                              \
                _Pragma("unroll")                                              \
                for (int mt = 0; mt < 4; mt++) {                               \
                    mma16816(acc[mt][np * 2 + 0], al[mt], bh);                 \
                    mma16816(acc[mt][np * 2 + 1], al[mt], bh + 2);             \
                }                                                              \
            }                                                                  \
        }                                                                      \
        CP_WAIT0();                                                            \
        __syncthreads();                                                       \
    }

// ---------------------------------------------------------------------------
// Merged Q/K/V projection GEMM (blockIdx.z: 0=Q (prescaled), 1=K, 2=V trans).
// ---------------------------------------------------------------------------
__global__ __launch_bounds__(256)
void gemm_qkv(const float* __restrict__ bq, const float* __restrict__ bk,
              const float* __restrict__ bv)
{
    extern __shared__ char smc[];
    const uint32_t sbase = smem_u32(smc);

    const int tid  = threadIdx.x;
    const int lane = tid & 31;
    const int wid  = tid >> 5;
    const int wm   = wid & 1;
    const int wn   = wid >> 1;
    const int m0 = blockIdx.y * 128;
    const int n0 = blockIdx.x * 256;
    const int z  = blockIdx.z;

    const __nv_bfloat16* Ahi = (z == 0) ? g_Aqhi : (z == 1) ? g_Akhi : g_Avhi;
    const __nv_bfloat16* Alo = (z == 0) ? g_Aqlo : (z == 1) ? g_Aklo : g_Avlo;
    const __nv_bfloat16* Bhi = (z == 0) ? g_Wqhi : (z == 1) ? g_Wkhi : g_Wvhi;
    const __nv_bfloat16* Blo = (z == 0) ? g_Wqlo : (z == 1) ? g_Wklo : g_Wvlo;
    const float* bias = (z == 0) ? bq : (z == 1) ? bk : bv;

    float acc[4][8][4];
#pragma unroll
    for (int mt = 0; mt < 4; mt++)
#pragma unroll
        for (int nt = 0; nt < 8; nt++)
#pragma unroll
            for (int e = 0; e < 4; e++) acc[mt][nt][e] = 0.0f;

    const int a_row = wm * 64 + (lane & 15);
    const uint32_t a_bc = (uint32_t)((lane >> 4) << 4);
    const int b_row = wn * 64 + ((lane & 16) >> 1) + (lane & 7);
    const uint32_t b_bc = (uint32_t)((lane & 8) << 1);

    GEMM_MAINLOOP(Ahi, Alo, Bhi, Blo);

    if (z == 2) {
        // V: transposed epilogue via SMEM staging, coalesced-in-S stores
        float* tb = (float*)smc;
#pragma unroll
        for (int nt = 0; nt < 8; nt++) {
            const int cl = wn * 64 + ((lane & 3) << 1) + nt * 8;
            const float b0 = bias[n0 + cl];
            const float b1 = bias[n0 + cl + 1];
#pragma unroll
            for (int mt = 0; mt < 4; mt++) {
                int rl = wm * 64 + (lane >> 2) + mt * 16;
                tb[cl * 132 + rl]           = acc[mt][nt][0] + b0;
                tb[(cl + 1) * 132 + rl]     = acc[mt][nt][1] + b1;
                tb[cl * 132 + rl + 8]       = acc[mt][nt][2] + b0;
                tb[(cl + 1) * 132 + rl + 8] = acc[mt][nt][3] + b1;
            }
        }
        __syncthreads();
        const int c = tid;
        const float* src = tb + c * 132;
        const size_t base = ((size_t)(m0 >> 11) * 1024 + n0 + c) * SS +
                            (m0 & 2047);
#pragma unroll
        for (int u = 0; u < 8; u++) {
            uint32_t hb[8], lb[8];
#pragma unroll
            for (int i = 0; i < 8; i++) {
                uint16_t ha, la, hbv, lbv;
                split_bf(src[u * 16 + 2 * i],     ha,  la);
                split_bf(src[u * 16 + 2 * i + 1], hbv, lbv);
                hb[i] = (uint32_t)ha | ((uint32_t)hbv << 16);
                lb[i] = (uint32_t)la | ((uint32_t)lbv << 16);
            }
            *(uint4*)&g_Vthi[base + u * 16]     = make_uint4(hb[0], hb[1], hb[2], hb[3]);
            *(uint4*)&g_Vthi[base + u * 16 + 8] = make_uint4(hb[4], hb[5], hb[6], hb[7]);
            *(uint4*)&g_Vtlo[base + u * 16]     = make_uint4(lb[0], lb[1], lb[2], lb[3]);
            *(uint4*)&g_Vtlo[base + u * 16 + 8] = make_uint4(lb[4], lb[5], lb[6], lb[7]);
        }
        return;
    }

    __nv_bfloat16* Chi = (z == 0) ? g_Qhi : g_Khi;
    __nv_bfloat16* Clo = (z == 0) ? g_Qlo : g_Klo;
    const float sc = (z == 0) ? QSCALE : 1.0f;
    const int col_base = n0 + wn * 64 + ((lane & 3) << 1);
    const int row_base = m0 + wm * 64 + (lane >> 2);
#pragma unroll
    for (int nt = 0; nt < 8; nt++) {
        const int col = col_base + nt * 8;
        const float b0 = bias[col];
        const float b1 = bias[col + 1];
#pragma unroll
        for (int mt = 0; mt < 4; mt++) {
            int r0 = row_base + mt * 16;
            float v0 = (acc[mt][nt][0] + b0) * sc;
            float v1 = (acc[mt][nt][1] + b1) * sc;
            float v2 = (acc[mt][nt][2] + b0) * sc;
            float v3 = (acc[mt][nt][3] + b1) * sc;
            uint16_t h0,l0,h1,l1,h2,l2,h3,l3;
            split_bf(v0,h0,l0); split_bf(v1,h1,l1);
            split_bf(v2,h2,l2); split_bf(v3,h3,l3);
            *(uint32_t*)&Chi[(size_t)r0 * DD + col] =
                (uint32_t)h0 | ((uint32_t)h1 << 16);
            *(uint32_t*)&Clo[(size_t)r0 * DD + col] =
                (uint32_t)l0 | ((uint32_t)l1 << 16);
            *(uint32_t*)&Chi[(size_t)(r0 + 8) * DD + col] =
                (uint32_t)h2 | ((uint32_t)h3 << 16);
            *(uint32_t*)&Clo[(size_t)(r0 + 8) * DD + col] =
                (uint32_t)l2 | ((uint32_t)l3 << 16);
        }
    }
}

// ---------------------------------------------------------------------------
// Output projection GEMM: reads presplit O, writes fp32 + qmask.
// ---------------------------------------------------------------------------
__global__ __launch_bounds__(256)
void gemm_out(const float* __restrict__ bias, const int* __restrict__ qmask,
              float* __restrict__ C)
{
    extern __shared__ char smc[];
    const uint32_t sbase = smem_u32(smc);

    const int tid  = threadIdx.x;
    const int lane = tid & 31;
    const int wid  = tid >> 5;
    const int wm   = wid & 1;
    const int wn   = wid >> 1;
    const int m0 = blockIdx.y * 128;
    const int n0 = blockIdx.x * 256;

    float acc[4][8][4];
#pragma unroll
    for (int mt = 0; mt < 4; mt++)
#pragma unroll
        for (int nt = 0; nt < 8; nt++)
#pragma unroll
            for (int e = 0; e < 4; e++) acc[mt][nt][e] = 0.0f;

    const int a_row = wm * 64 + (lane & 15);
    const uint32_t a_bc = (uint32_t)((lane >> 4) << 4);
    const int b_row = wn * 64 + ((lane & 16) >> 1) + (lane & 7);
    const uint32_t b_bc = (uint32_t)((lane & 8) << 1);

    GEMM_MAINLOOP(g_Ohi, g_Olo, g_Wohi, g_Wolo);

    const int col_base = n0 + wn * 64 + ((lane & 3) << 1);
    const int row_base = m0 + wm * 64 + (lane >> 2);
#pragma unroll
    for (int nt = 0; nt < 8; nt++) {
        const int col = col_base + nt * 8;
        const float b0 = bias[col];
        const float b1 = bias[col + 1];
#pragma unroll
        for (int mt = 0; mt < 4; mt++) {
            int r0 = row_base + mt * 16;
            float qm0 = (float)qmask[r0];
            float qm1 = (float)qmask[r0 + 8];
            *(float2*)&C[(size_t)r0 * DD + col] =
                make_float2((acc[mt][nt][0] + b0) * qm0,
                            (acc[mt][nt][1] + b1) * qm0);
            *(float2*)&C[(size_t)(r0 + 8) * DD + col] =
                make_float2((acc[mt][nt][2] + b0) * qm1,
                            (acc[mt][nt][3] + b1) * qm1);
        }
    }
}

// ---------------------------------------------------------------------------
// Tensor-core flash attention, 2-CTA/SM shape:
// 128 threads (4 warps), q-tile 64 rows, key-block 64, double-buffered.
// Q pre-scaled, base-2 softmax, truncation-split P packs.
// ---------------------------------------------------------------------------
#define AQ_H 0
#define AQ_L 8192
#define ASTG 16384
#define SK_H 0
#define SK_L 8192
#define SV_H 16384
#define SV_L 25600
#define SVM  34816
#define STG_SZ 35072
#define AT_SMEM (ASTG + 2 * STG_SZ)   // 86528
#define VT_ROW 144

__global__ __launch_bounds__(128, 2)
void attn_mma(const int* __restrict__ v_mask)
{
    extern __shared__ char smc[];
    const uint32_t sb = smem_u32(smc);

    const int tid  = threadIdx.x;
    const int lane = tid & 31;
    const int w    = tid >> 5;              // 0..3
    const int bh = blockIdx.y;
    const int b  = bh >> 4;
    const int h  = bh & 15;
    const int qt = gridDim.x - 1 - blockIdx.x;   // heavy tiles first
    const int q0 = qt * 64;

    // ---- Q tile (64 x 64): cp.async from presplit g_Qhi/g_Qlo ----
#pragma unroll
    for (int t = 0; t < 8; t++) {
        int idx = tid + t * 128;             // 0..1023
        const char* src = (idx < 512) ? (const char*)g_Qhi : (const char*)g_Qlo;
        uint32_t dst = sb + ((idx < 512) ? AQ_H : AQ_L);
        int r = (idx >> 3) & 63;
        int c = idx & 7;
        const void* g = src + ((size_t)(b * SS + q0 + r) * DD + h * 64) * 2 + c * 16;
        cp16(dst + SWZ((uint32_t)(r * 128 + c * 16)), g);
    }

    auto load_stage = [&](int kt, int s) {
        const uint32_t stg = sb + ASTG + s * STG_SZ;
        // K tile (64 rows x 64 d), hi+lo
#pragma unroll
        for (int t = 0; t < 8; t++) {
            int idx = tid + t * 128;         // 0..1023
            const char* src = (idx < 512) ? (const char*)g_Khi : (const char*)g_Klo;
            uint32_t dst = stg + ((idx < 512) ? SK_H : SK_L);
            int r = (idx >> 3) & 63;
            int c = idx & 7;
            const void* g = src + ((size_t)(b * SS + kt * 64 + r) * DD + h * 64) * 2 + c * 16;
            cp16(dst + SWZ((uint32_t)(r * 128 + c * 16)), g);
        }
        // V tile transposed (64 d x 64 j), hi+lo; row stride 144B
#pragma unroll
        for (int t = 0; t < 8; t++) {
            int idx = tid + t * 128;
            const char* src = (idx < 512) ? (const char*)g_Vthi : (const char*)g_Vtlo;
            uint32_t dst = stg + ((idx < 512) ? SV_H : SV_L);
            int rem = idx & 511;
            int d = rem >> 3;
            int c = rem & 7;
            const void* g = src + (((size_t)(b * 16 + h) * 64 + d) * SS + kt * 64) * 2 + c * 16;
            cp16(dst + (uint32_t)(d * VT_ROW + c * 16), g);
        }
        if (tid < 64) {
            ((float*)(smc + ASTG + s * STG_SZ + SVM))[tid] =
                v_mask[b * SS + kt * 64 + tid] ? 0.0f : -1e12f;
        }
    };

    load_stage(0, 0);
    CP_COMMIT();
    CP_WAIT0();
    __syncthreads();

    const int a_row = w * 16 + (lane & 15);
    const uint32_t a_bc = (uint32_t)((lane >> 4) << 4);
    const int b_rp  = ((lane & 16) >> 1) + (lane & 7);
    const uint32_t b_bc = (uint32_t)((lane & 8) << 1);

    // preload Q hi+lo fragments (loop-invariant)
    uint32_t qh[4][4], ql[4][4];
#pragma unroll
    for (int ks = 0; ks < 4; ks++) {
        uint32_t off = SWZ((uint32_t)(a_row * 128 + ks * 32) + a_bc);
        ldsm4(qh[ks], sb + AQ_H + off);
        ldsm4(ql[ks], sb + AQ_L + off);
    }

    float o[8][4];
#pragma unroll
    for (int nt = 0; nt < 8; nt++)
#pragma unroll
        for (int e = 0; e < 4; e++) o[nt][e] = 0.0f;
    float m_lo = -1e30f, m_hi = -1e30f, l_lo = 0.0f, l_hi = 0.0f;

    const int r = lane >> 2;
    const int qi_lo = q0 + w * 16 + r;
    const int qi_hi = qi_lo + 8;
    const int jc = (lane & 3) * 2;

    const int nkt = qt + 1;
    for (int kt = 0; kt < nkt; kt++) {
        if (kt + 1 < nkt) { load_stage(kt + 1, (kt + 1) & 1); CP_COMMIT(); }

        const uint32_t stg = sb + ASTG + (kt & 1) * STG_SZ;

        // ---- S = Q K^T over 64 keys: s[8][4], np-paired ----
        float s[8][4];
#pragma unroll
        for (int nt = 0; nt < 8; nt++)
#pragma unroll
            for (int e = 0; e < 4; e++) s[nt][e] = 0.0f;

#pragma unroll
        for (int ks = 0; ks < 4; ks++) {
#pragma unroll
            for (int npp = 0; npp < 2; npp++) {
                const int np0 = npp * 2, np1 = npp * 2 + 1;
                uint32_t kh0[4], kh1[4], kl0[4], kl1[4];
                uint32_t off0 = SWZ((uint32_t)((np0 * 16 + b_rp) * 128 + ks * 32) + b_bc);
                uint32_t off1 = SWZ((uint32_t)((np1 * 16 + b_rp) * 128 + ks * 32) + b_bc);
                ldsm4(kh0, stg + SK_H + off0);
                ldsm4(kh1, stg + SK_H + off1);
                ldsm4(kl0, stg + SK_L + off0);
                ldsm4(kl1, stg + SK_L + off1);
                float* s0 = s[npp * 4 + 0];
                float* s1 = s[npp * 4 + 1];
                float* s2 = s[npp * 4 + 2];
                float* s3 = s[npp * 4 + 3];
                mma16816(s0, qh[ks], kh0); mma16816(s1, qh[ks], kh0 + 2);
                mma16816(s2, qh[ks], kh1); mma16816(s3, qh[ks], kh1 + 2);
                mma16816(s0, ql[ks], kh0); mma16816(s1, ql[ks], kh0 + 2);
                mma16816(s2, ql[ks], kh1); mma16816(s3, ql[ks], kh1 + 2);
                mma16816(s0, qh[ks], kl0); mma16816(s1, qh[ks], kl0 + 2);
                mma16816(s2, qh[ks], kl1); mma16816(s3, qh[ks], kl1 + 2);
            }
        }

        // ---- mask + online softmax (base-2) ----
        const bool diag = (kt == qt);
        const float* mvm = (const float*)(smc + ASTG + (kt & 1) * STG_SZ + SVM);
        float mx_lo = -1e30f, mx_hi = -1e30f;
#pragma unroll
        for (int nt = 0; nt < 8; nt++) {
            int jl = nt * 8 + jc;
            int jg = kt * 64 + jl;
            float2 av = *(const float2*)&mvm[jl];
            float v0 = s[nt][0] + av.x;
            float v1 = s[nt][1] + av.y;
            float v2 = s[nt][2] + av.x;
            float v3 = s[nt][3] + av.y;
            if (diag) {
                if (jg     > qi_lo) v0 = -1e12f;
                if (jg + 1 > qi_lo) v1 = -1e12f;
                if (jg     > qi_hi) v2 = -1e12f;
                if (jg + 1 > qi_hi) v3 = -1e12f;
            }
            s[nt][0] = v0; s[nt][1] = v1; s[nt][2] = v2; s[nt][3] = v3;
            mx_lo = fmaxf(mx_lo, fmaxf(v0, v1));
            mx_hi = fmaxf(mx_hi, fmaxf(v2, v3));
        }
        mx_lo = fmaxf(mx_lo, __shfl_xor_sync(0xffffffffu, mx_lo, 1));
        mx_lo = fmaxf(mx_lo, __shfl_xor_sync(0xffffffffu, mx_lo, 2));
        mx_hi = fmaxf(mx_hi, __shfl_xor_sync(0xffffffffu, mx_hi, 1));
        mx_hi = fmaxf(mx_hi, __shfl_xor_sync(0xffffffffu, mx_hi, 2));

        float mn_lo = fmaxf(m_lo, mx_lo);
        float mn_hi = fmaxf(m_hi, mx_hi);
        float corr_lo = ex2f(m_lo - mn_lo);
        float corr_hi = ex2f(m_hi - mn_hi);
        m_lo = mn_lo; m_hi = mn_hi;

        float sum_lo = 0.0f, sum_hi = 0.0f;
#pragma unroll
        for (int nt = 0; nt < 8; nt++) {
            float p0 = ex2f(s[nt][0] - mn_lo);
            float p1 = ex2f(s[nt][1] - mn_lo);
            float p2 = ex2f(s[nt][2] - mn_hi);
            float p3 = ex2f(s[nt][3] - mn_hi);
            s[nt][0] = p0; s[nt][1] = p1; s[nt][2] = p2; s[nt][3] = p3;
            sum_lo += p0 + p1;
            sum_hi += p2 + p3;
        }
        sum_lo += __shfl_xor_sync(0xffffffffu, sum_lo, 1);
        sum_lo += __shfl_xor_sync(0xffffffffu, sum_lo, 2);
        sum_hi += __shfl_xor_sync(0xffffffffu, sum_hi, 1);
        sum_hi += __shfl_xor_sync(0xffffffffu, sum_hi, 2);
        l_lo = l_lo * corr_lo + sum_lo;
        l_hi = l_hi * corr_hi + sum_hi;

#pragma unroll
        for (int nt = 0; nt < 8; nt++) {
            o[nt][0] *= corr_lo; o[nt][1] *= corr_lo;
            o[nt][2] *= corr_hi; o[nt][3] *= corr_hi;
        }

        // ---- O += P V over 64 keys (ks 0..3), np-paired over d ----
#pragma unroll
        for (int ks = 0; ks < 4; ks++) {
            uint32_t ah[4], al[4];
            split_pack2(s[2*ks][0],   s[2*ks][1],   ah[0], al[0]);
            split_pack2(s[2*ks][2],   s[2*ks][3],   ah[1], al[1]);
            split_pack2(s[2*ks+1][0], s[2*ks+1][1], ah[2], al[2]);
            split_pack2(s[2*ks+1][2], s[2*ks+1][3], ah[3], al[3]);
#pragma unroll
            for (int npp = 0; npp < 2; npp++) {
                const int np0 = npp * 2, np1 = npp * 2 + 1;
                uint32_t a0 = (uint32_t)((np0 * 16 + b_rp) * VT_ROW + ks * 32) + b_bc;
                uint32_t a1 = (uint32_t)((np1 * 16 + b_rp) * VT_ROW + ks * 32) + b_bc;
                uint32_t bh0[4], bh1[4], bl0[4], bl1[4];
                ldsm4(bh0, stg + SV_H + a0);
                ldsm4(bh1, stg + SV_H + a1);
                ldsm4(bl0, stg + SV_L + a0);
                ldsm4(bl1, stg + SV_L + a1);
                float* o0 = o[np0 * 2 + 0];
                float* o1 = o[np0 * 2 + 1];
                float* o2 = o[np1 * 2 + 0];
                float* o3 = o[np1 * 2 + 1];
                mma16816(o0, ah, bh0); mma16816(o1, ah, bh0 + 2);
                mma16816(o2, ah, bh1); mma16816(o3, ah, bh1 + 2);
                mma16816(o0, al, bh0); mma16816(o1, al, bh0 + 2);
                mma16816(o2, al, bh1); mma16816(o3, al, bh1 + 2);
                mma16816(o0, ah, bl0); mma16816(o1, ah, bl0 + 2);
                mma16816(o2, ah, bl1); mma16816(o3, ah, bl1 + 2);
            }
        }

        CP_WAIT0();
        __syncthreads();
    }

    // ---- normalize + split + store to g_Ohi/g_Olo ----
    float inv_lo = 1.0f / l_lo;
    float inv_hi = 1.0f / l_hi;
    const size_t row_lo = (size_t)(b * SS + q0 + w * 16 + r) * DD + h * 64;
    const size_t row_hi = row_lo + 8 * DD;
#pragma unroll
    for (int nt = 0; nt < 8; nt++) {
        int d0 = nt * 8 + jc;
        uint16_t h0,l0,h1,l1;
        split_bf(o[nt][0] * inv_lo, h0, l0);
        split_bf(o[nt][1] * inv_lo, h1, l1);
        *(uint32_t*)&g_Ohi[row_lo + d0] = (uint32_t)h0 | ((uint32_t)h1 << 16);
        *(uint32_t*)&g_Olo[row_lo + d0] = (uint32_t)l0 | ((uint32_t)l1 << 16);
        split_bf(o[nt][2] * inv_hi, h0, l0);
        split_bf(o[nt][3] * inv_hi, h1, l1);
        *(uint32_t*)&g_Ohi[row_hi + d0] = (uint32_t)h0 | ((uint32_t)h1 << 16);
        *(uint32_t*)&g_Olo[row_hi + d0] = (uint32_t)l0 | ((uint32_t)l1 << 16);
    }
}

// ---------------------------------------------------------------------------
// kernel_launch
// ---------------------------------------------------------------------------
extern "C" void kernel_launch(void* const* d_in, const int* in_sizes, int n_in,
                              void* d_out, int out_size)
{
    const float* q      = (const float*)d_in[0];
    const float* k      = (const float*)d_in[1];
    const float* v      = (const float*)d_in[2];
    const int*   q_mask = (const int*)  d_in[3];
    const int*   v_mask = (const int*)  d_in[4];
    const float* Wq     = (const float*)d_in[5];
    const float* bq     = (const float*)d_in[6];
    const float* Wk     = (const float*)d_in[7];
    const float* bk     = (const float*)d_in[8];
    const float* Wv     = (const float*)d_in[9];
    const float* bv     = (const float*)d_in[10];
    const float* Wo     = (const float*)d_in[11];
    const float* bo     = (const float*)d_in[12];
    float* out = (float*)d_out;

    cudaFuncSetAttribute(gemm_qkv,
                         cudaFuncAttributeMaxDynamicSharedMemorySize, GEMM_SMEM);
    cudaFuncSetAttribute(gemm_out,
                         cudaFuncAttributeMaxDynamicSharedMemorySize, GEMM_SMEM);
    cudaFuncSetAttribute(attn_mma,
                         cudaFuncAttributeMaxDynamicSharedMemorySize, AT_SMEM);

    const int n4 = MM * DD / 4;

    split3_kernel<<<dim3((n4 + 255) / 256, 3), 256>>>(q, k, v, n4);
    wsplit4_kernel<<<dim3(DD / 32, DD / 32, 4), 256>>>(Wq, Wk, Wv, Wo);

    gemm_qkv<<<dim3(DD / 256, MM / 128, 3), 256, GEMM_SMEM>>>(bq, bk, bv);

    // Attention: 128-thread CTAs, 64-row q tiles, 2 CTAs/SM
    attn_mma<<<dim3(SS / 64, BB * HH), 128, AT_SMEM>>>(v_mask);

    gemm_out<<<dim3(DD / 256, MM / 128), 256, GEMM_SMEM>>>(bo, q_mask, out);
}

// round 14
// speedup vs baseline: 3.0850x; 1.0034x over previous
#include <cuda_runtime.h>
#include <cuda_bf16.h>
#include <cstdint>

// Problem constants
#define BB 4
#define SS 2048
#define DD 1024
#define HH 16
#define MM (BB*SS)          // 8192 rows

// Q pre-scale: 1/sqrt(64) * log2(e)  (softmax done in base-2)
#define QSCALE 0.18033688011112042f

// Scratch (device globals: allocation-free). All interchange in split bf16.
__device__ __nv_bfloat16 g_Aqhi[MM * DD];
__device__ __nv_bfloat16 g_Aqlo[MM * DD];
__device__ __nv_bfloat16 g_Akhi[MM * DD];
__device__ __nv_bfloat16 g_Aklo[MM * DD];
__device__ __nv_bfloat16 g_Avhi[MM * DD];
__device__ __nv_bfloat16 g_Avlo[MM * DD];
__device__ __nv_bfloat16 g_Wqhi[DD * DD];  // transposed weights: [N, K]
__device__ __nv_bfloat16 g_Wqlo[DD * DD];
__device__ __nv_bfloat16 g_Wkhi[DD * DD];
__device__ __nv_bfloat16 g_Wklo[DD * DD];
__device__ __nv_bfloat16 g_Wvhi[DD * DD];
__device__ __nv_bfloat16 g_Wvlo[DD * DD];
__device__ __nv_bfloat16 g_Wohi[DD * DD];
__device__ __nv_bfloat16 g_Wolo[DD * DD];
__device__ __nv_bfloat16 g_Qhi[MM * DD];   // [row][h*64+d], pre-scaled
__device__ __nv_bfloat16 g_Qlo[MM * DD];
__device__ __nv_bfloat16 g_Khi[MM * DD];
__device__ __nv_bfloat16 g_Klo[MM * DD];
__device__ __nv_bfloat16 g_Vthi[MM * DD];  // transposed: [(b*16+h)*64+d][S]
__device__ __nv_bfloat16 g_Vtlo[MM * DD];
__device__ __nv_bfloat16 g_Ohi[MM * DD];   // attention output, split
__device__ __nv_bfloat16 g_Olo[MM * DD];

// ---------------------------------------------------------------------------
// Helpers
// ---------------------------------------------------------------------------
__device__ __forceinline__ uint32_t smem_u32(const void* p) {
    uint32_t a;
    asm("{ .reg .u64 t; cvta.to.shared.u64 t, %1; cvt.u32.u64 %0, t; }"
        : "=r"(a) : "l"(p));
    return a;
}

__device__ __forceinline__ void ldsm4(uint32_t* r, uint32_t addr) {
    asm volatile("ldmatrix.sync.aligned.m8n8.x4.shared.b16 {%0,%1,%2,%3}, [%4];"
        : "=r"(r[0]), "=r"(r[1]), "=r"(r[2]), "=r"(r[3]) : "r"(addr));
}

__device__ __forceinline__ void mma16816(float* c, const uint32_t* a,
                                         const uint32_t* b) {
    asm volatile(
        "mma.sync.aligned.m16n8k16.row.col.f32.bf16.bf16.f32 "
        "{%0,%1,%2,%3}, {%4,%5,%6,%7}, {%8,%9}, {%0,%1,%2,%3};"
        : "+f"(c[0]), "+f"(c[1]), "+f"(c[2]), "+f"(c[3])
        : "r"(a[0]), "r"(a[1]), "r"(a[2]), "r"(a[3]), "r"(b[0]), "r"(b[1]));
}

__device__ __forceinline__ void cp16(uint32_t saddr, const void* g) {
    asm volatile("cp.async.cg.shared.global [%0], [%1], 16;"
                 :: "r"(saddr), "l"(g) : "memory");
}
#define CP_COMMIT() asm volatile("cp.async.commit_group;" ::: "memory")
#define CP_WAIT0()  asm volatile("cp.async.wait_group 0;" ::: "memory")

// SW128 swizzle on byte offsets within a tile (rows of 128B)
#define SWZ(o) ((o) ^ (((o) >> 3) & 0x70))

__device__ __forceinline__ void split_bf(float v, uint16_t& h, uint16_t& l) {
    __nv_bfloat16 hb = __float2bfloat16(v);
    __nv_bfloat16 lb = __float2bfloat16(v - __bfloat162float(hb));
    h = *(uint16_t*)&hb; l = *(uint16_t*)&lb;
}

// Fast truncation split of 2 floats -> packed hi bf16x2 + lo bf16x2.
__device__ __forceinline__ void split_pack2(float a, float b,
                                            uint32_t& hi2, uint32_t& lo2) {
    uint32_t ba = __float_as_uint(a), bb = __float_as_uint(b);
    asm("prmt.b32 %0, %1, %2, 0x7632;" : "=r"(hi2) : "r"(ba), "r"(bb));
    float la = a - __uint_as_float(ba & 0xFFFF0000u);
    float lb = b - __uint_as_float(bb & 0xFFFF0000u);
    asm("cvt.rn.bf16x2.f32 %0, %1, %2;" : "=r"(lo2) : "f"(lb), "f"(la));
}

__device__ __forceinline__ float ex2f(float x) {
    float y;
    asm("ex2.approx.f32 %0, %1;" : "=f"(y) : "f"(x));
    return y;
}

// ---------------------------------------------------------------------------
// Fused split of q,k,v inputs (blockIdx.y selects tensor)
// ---------------------------------------------------------------------------
__global__ __launch_bounds__(256)
void split3_kernel(const float* __restrict__ x0, const float* __restrict__ x1,
                   const float* __restrict__ x2, int n4)
{
    int i = blockIdx.x * blockDim.x + threadIdx.x;
    if (i >= n4) return;
    const float* x;
    __nv_bfloat16 *hi, *lo;
    if (blockIdx.y == 0)      { x = x0; hi = g_Aqhi; lo = g_Aqlo; }
    else if (blockIdx.y == 1) { x = x1; hi = g_Akhi; lo = g_Aklo; }
    else                      { x = x2; hi = g_Avhi; lo = g_Avlo; }
    float4 v = ((const float4*)x)[i];
    uint16_t h0,l0,h1,l1,h2,l2,h3,l3;
    split_bf(v.x,h0,l0); split_bf(v.y,h1,l1);
    split_bf(v.z,h2,l2); split_bf(v.w,h3,l3);
    uint2 hv = make_uint2((uint32_t)h0|((uint32_t)h1<<16),
                          (uint32_t)h2|((uint32_t)h3<<16));
    uint2 lv = make_uint2((uint32_t)l0|((uint32_t)l1<<16),
                          (uint32_t)l2|((uint32_t)l3<<16));
    *(uint2*)(hi + (size_t)i * 4) = hv;
    *(uint2*)(lo + (size_t)i * 4) = lv;
}

// Fused W[K,N] fp32 -> Whi/Wlo [N,K] bf16 (transposed), all 4 weights
__global__ __launch_bounds__(256)
void wsplit4_kernel(const float* __restrict__ W0, const float* __restrict__ W1,
                    const float* __restrict__ W2, const float* __restrict__ W3)
{
    __shared__ float t[32][33];
    const float* W;
    __nv_bfloat16 *hi, *lo;
    if (blockIdx.z == 0)      { W = W0; hi = g_Wqhi; lo = g_Wqlo; }
    else if (blockIdx.z == 1) { W = W1; hi = g_Wkhi; lo = g_Wklo; }
    else if (blockIdx.z == 2) { W = W2; hi = g_Wvhi; lo = g_Wvlo; }
    else                      { W = W3; hi = g_Wohi; lo = g_Wolo; }
    int tx = threadIdx.x & 31;
    int ty = threadIdx.x >> 5;
    int n0 = blockIdx.x * 32;
    int k0 = blockIdx.y * 32;
#pragma unroll
    for (int i = 0; i < 4; i++)
        t[ty + 8 * i][tx] = W[(size_t)(k0 + ty + 8 * i) * DD + n0 + tx];
    __syncthreads();
#pragma unroll
    for (int i = 0; i < 4; i++) {
        int n = ty + 8 * i;
        float v = t[tx][n];
        uint16_t h, l;
        split_bf(v, h, l);
        *(uint16_t*)&hi[(size_t)(n0 + n) * DD + k0 + tx] = h;
        *(uint16_t*)&lo[(size_t)(n0 + n) * DD + k0 + tx] = l;
    }
}

// ---------------------------------------------------------------------------
// GEMM mainloop (CTA tile 128x256, warp tile 64x64, BK=64, 2-stage pipeline).
// ---------------------------------------------------------------------------
#define BK 64
#define GA_H 0
#define GA_L 16384
#define GB_H 32768
#define GB_L 65536
#define G_STAGE 98304
#define GEMM_SMEM (2 * G_STAGE)   // 196608
#define NK (DD / BK)              // 16

#define GEMM_LOAD_STAGE(Ahi_, Alo_, Bhi_, Blo_, it, s)                         \
    do {                                                                       \
        const int kc_ = (it) * BK;                                             \
        const uint32_t stb_ = sbase + (s) * G_STAGE;                           \
        _Pragma("unroll")                                                      \
        for (int i_ = 0; i_ < 8; i_++) {                                       \
            int u_ = tid + i_ * 256;                                           \
            int half_ = u_ >> 10;                                              \
            int rem_ = u_ & 1023;                                              \
            int r_ = rem_ >> 3, c_ = rem_ & 7;                                 \
            const char* src_ = half_ ? (const char*)(Alo_) : (const char*)(Ahi_);\
            cp16(stb_ + (half_ ? GA_L : GA_H) + SWZ((uint32_t)(r_ * 128 + c_ * 16)),\
                 src_ + ((size_t)(m0 + r_) * DD + kc_) * 2 + c_ * 16);         \
        }                                                                      \
        _Pragma("unroll")                                                      \
        for (int i_ = 0; i_ < 16; i_++) {                                      \
            int u_ = tid + i_ * 256;                                           \
            int half_ = u_ >> 11;                                              \
            int rem_ = u_ & 2047;                                              \
            int r_ = rem_ >> 3, c_ = rem_ & 7;                                 \
            const char* src_ = half_ ? (const char*)(Blo_) : (const char*)(Bhi_);\
            cp16(stb_ + (half_ ? GB_L : GB_H) + SWZ((uint32_t)(r_ * 128 + c_ * 16)),\
                 src_ + ((size_t)(n0 + r_) * DD + kc_) * 2 + c_ * 16);         \
        }                                                                      \
    } while (0)

#define GEMM_MAINLOOP(Ahi_, Alo_, Bhi_, Blo_)                                  \
    GEMM_LOAD_STAGE(Ahi_, Alo_, Bhi_, Blo_, 0, 0);                             \
    CP_COMMIT(); CP_WAIT0(); __syncthreads();                                  \
    for (int it = 0; it < NK; it++) {                                          \
        if (it + 1 < NK) {                                                     \
            GEMM_LOAD_STAGE(Ahi_, Alo_, Bhi_, Blo_, it + 1, (it + 1) & 1);     \
            CP_COMMIT();                                                       \
        }                                                                      \
        const uint32_t stb = sbase + (it & 1) * G_STAGE;                       \
        _Pragma("unroll")                                                      \
        for (int ks = 0; ks < 4; ks++) {                                       \
            uint32_t ah[4][4], al[4][4];                                       \
            _Pragma("unroll")                                                  \
            for (int mt = 0; mt < 4; mt++) {                                   \
                uint32_t off = (uint32_t)((a_row + mt * 16) * 128) +           \
                               (uint32_t)(ks * 32) + a_bc;                     \
                ldsm4(ah[mt], stb + GA_H + SWZ(off));                          \
                ldsm4(al[mt], stb + GA_L + SWZ(off));                          \
            }                                                                  \
            _Pragma("unroll")                                                  \
            for (int np = 0; np < 4; np++) {                                   \
                uint32_t bh[4], bl[4];                                         \
                uint32_t off = (uint32_t)((b_row + np * 16) * 128) +           \
                               (uint32_t)(ks * 32) + b_bc;                     \
                ldsm4(bh, stb + GB_H + SWZ(off));                              \
                ldsm4(bl, stb + GB_L + SWZ(off));                              \
                _Pragma("unroll")                                              \
                for (int mt = 0; mt < 4; mt++) {                               \
                    mma16816(acc[mt][np * 2 + 0], ah[mt], bh);                 \
                    mma16816(acc[mt][np * 2 + 1], ah[mt], bh + 2);             \
                }                                                              \
                _Pragma("unroll")                                              \
                for (int mt = 0; mt < 4; mt++) {                               \
                    mma16816(acc[mt][np * 2 + 0], ah[mt], bl);                 \
                    mma16816(acc[mt][np * 2 + 1], ah[mt], bl + 2);             \
                }                                                              \
                _Pragma("unroll")                                              \
                for (int mt = 0; mt < 4; mt++) {                               \
                    mma16816(acc[mt][np * 2 + 0], al[mt], bh);                 \
                    mma16816(acc[mt][np * 2 + 1], al[mt], bh + 2);             \
                }                                                              \
            }                                                                  \
        }                                                                      \
        CP_WAIT0();                                                            \
        __syncthreads();                                                       \
    }

// ---------------------------------------------------------------------------
// Merged Q/K/V projection GEMM (blockIdx.z: 0=Q (prescaled), 1=K, 2=V trans).
// ---------------------------------------------------------------------------
__global__ __launch_bounds__(256)
void gemm_qkv(const float* __restrict__ bq, const float* __restrict__ bk,
              const float* __restrict__ bv)
{
    extern __shared__ char smc[];
    const uint32_t sbase = smem_u32(smc);

    const int tid  = threadIdx.x;
    const int lane = tid & 31;
    const int wid  = tid >> 5;
    const int wm   = wid & 1;
    const int wn   = wid >> 1;
    const int m0 = blockIdx.y * 128;
    const int n0 = blockIdx.x * 256;
    const int z  = blockIdx.z;

    const __nv_bfloat16* Ahi = (z == 0) ? g_Aqhi : (z == 1) ? g_Akhi : g_Avhi;
    const __nv_bfloat16* Alo = (z == 0) ? g_Aqlo : (z == 1) ? g_Aklo : g_Avlo;
    const __nv_bfloat16* Bhi = (z == 0) ? g_Wqhi : (z == 1) ? g_Wkhi : g_Wvhi;
    const __nv_bfloat16* Blo = (z == 0) ? g_Wqlo : (z == 1) ? g_Wklo : g_Wvlo;
    const float* bias = (z == 0) ? bq : (z == 1) ? bk : bv;

    float acc[4][8][4];
#pragma unroll
    for (int mt = 0; mt < 4; mt++)
#pragma unroll
        for (int nt = 0; nt < 8; nt++)
#pragma unroll
            for (int e = 0; e < 4; e++) acc[mt][nt][e] = 0.0f;

    const int a_row = wm * 64 + (lane & 15);
    const uint32_t a_bc = (uint32_t)((lane >> 4) << 4);
    const int b_row = wn * 64 + ((lane & 16) >> 1) + (lane & 7);
    const uint32_t b_bc = (uint32_t)((lane & 8) << 1);

    GEMM_MAINLOOP(Ahi, Alo, Bhi, Blo);

    if (z == 2) {
        // V: transposed epilogue via SMEM staging, coalesced-in-S stores
        float* tb = (float*)smc;
#pragma unroll
        for (int nt = 0; nt < 8; nt++) {
            const int cl = wn * 64 + ((lane & 3) << 1) + nt * 8;
            const float b0 = bias[n0 + cl];
            const float b1 = bias[n0 + cl + 1];
#pragma unroll
            for (int mt = 0; mt < 4; mt++) {
                int rl = wm * 64 + (lane >> 2) + mt * 16;
                tb[cl * 132 + rl]           = acc[mt][nt][0] + b0;
                tb[(cl + 1) * 132 + rl]     = acc[mt][nt][1] + b1;
                tb[cl * 132 + rl + 8]       = acc[mt][nt][2] + b0;
                tb[(cl + 1) * 132 + rl + 8] = acc[mt][nt][3] + b1;
            }
        }
        __syncthreads();
        const int c = tid;
        const float* src = tb + c * 132;
        const size_t base = ((size_t)(m0 >> 11) * 1024 + n0 + c) * SS +
                            (m0 & 2047);
#pragma unroll
        for (int u = 0; u < 8; u++) {
            uint32_t hb[8], lb[8];
#pragma unroll
            for (int i = 0; i < 8; i++) {
                uint16_t ha, la, hbv, lbv;
                split_bf(src[u * 16 + 2 * i],     ha,  la);
                split_bf(src[u * 16 + 2 * i + 1], hbv, lbv);
                hb[i] = (uint32_t)ha | ((uint32_t)hbv << 16);
                lb[i] = (uint32_t)la | ((uint32_t)lbv << 16);
            }
            *(uint4*)&g_Vthi[base + u * 16]     = make_uint4(hb[0], hb[1], hb[2], hb[3]);
            *(uint4*)&g_Vthi[base + u * 16 + 8] = make_uint4(hb[4], hb[5], hb[6], hb[7]);
            *(uint4*)&g_Vtlo[base + u * 16]     = make_uint4(lb[0], lb[1], lb[2], lb[3]);
            *(uint4*)&g_Vtlo[base + u * 16 + 8] = make_uint4(lb[4], lb[5], lb[6], lb[7]);
        }
        return;
    }

    __nv_bfloat16* Chi = (z == 0) ? g_Qhi : g_Khi;
    __nv_bfloat16* Clo = (z == 0) ? g_Qlo : g_Klo;
    const float sc = (z == 0) ? QSCALE : 1.0f;
    const int col_base = n0 + wn * 64 + ((lane & 3) << 1);
    const int row_base = m0 + wm * 64 + (lane >> 2);
#pragma unroll
    for (int nt = 0; nt < 8; nt++) {
        const int col = col_base + nt * 8;
        const float b0 = bias[col];
        const float b1 = bias[col + 1];
#pragma unroll
        for (int mt = 0; mt < 4; mt++) {
            int r0 = row_base + mt * 16;
            float v0 = (acc[mt][nt][0] + b0) * sc;
            float v1 = (acc[mt][nt][1] + b1) * sc;
            float v2 = (acc[mt][nt][2] + b0) * sc;
            float v3 = (acc[mt][nt][3] + b1) * sc;
            uint16_t h0,l0,h1,l1,h2,l2,h3,l3;
            split_bf(v0,h0,l0); split_bf(v1,h1,l1);
            split_bf(v2,h2,l2); split_bf(v3,h3,l3);
            *(uint32_t*)&Chi[(size_t)r0 * DD + col] =
                (uint32_t)h0 | ((uint32_t)h1 << 16);
            *(uint32_t*)&Clo[(size_t)r0 * DD + col] =
                (uint32_t)l0 | ((uint32_t)l1 << 16);
            *(uint32_t*)&Chi[(size_t)(r0 + 8) * DD + col] =
                (uint32_t)h2 | ((uint32_t)h3 << 16);
            *(uint32_t*)&Clo[(size_t)(r0 + 8) * DD + col] =
                (uint32_t)l2 | ((uint32_t)l3 << 16);
        }
    }
}

// ---------------------------------------------------------------------------
// Output projection GEMM: reads presplit O, writes fp32 + qmask.
// ---------------------------------------------------------------------------
__global__ __launch_bounds__(256)
void gemm_out(const float* __restrict__ bias, const int* __restrict__ qmask,
              float* __restrict__ C)
{
    extern __shared__ char smc[];
    const uint32_t sbase = smem_u32(smc);

    const int tid  = threadIdx.x;
    const int lane = tid & 31;
    const int wid  = tid >> 5;
    const int wm   = wid & 1;
    const int wn   = wid >> 1;
    const int m0 = blockIdx.y * 128;
    const int n0 = blockIdx.x * 256;

    float acc[4][8][4];
#pragma unroll
    for (int mt = 0; mt < 4; mt++)
#pragma unroll
        for (int nt = 0; nt < 8; nt++)
#pragma unroll
            for (int e = 0; e < 4; e++) acc[mt][nt][e] = 0.0f;

    const int a_row = wm * 64 + (lane & 15);
    const uint32_t a_bc = (uint32_t)((lane >> 4) << 4);
    const int b_row = wn * 64 + ((lane & 16) >> 1) + (lane & 7);
    const uint32_t b_bc = (uint32_t)((lane & 8) << 1);

    GEMM_MAINLOOP(g_Ohi, g_Olo, g_Wohi, g_Wolo);

    const int col_base = n0 + wn * 64 + ((lane & 3) << 1);
    const int row_base = m0 + wm * 64 + (lane >> 2);
#pragma unroll
    for (int nt = 0; nt < 8; nt++) {
        const int col = col_base + nt * 8;
        const float b0 = bias[col];
        const float b1 = bias[col + 1];
#pragma unroll
        for (int mt = 0; mt < 4; mt++) {
            int r0 = row_base + mt * 16;
            float qm0 = (float)qmask[r0];
            float qm1 = (float)qmask[r0 + 8];
            *(float2*)&C[(size_t)r0 * DD + col] =
                make_float2((acc[mt][nt][0] + b0) * qm0,
                            (acc[mt][nt][1] + b1) * qm0);
            *(float2*)&C[(size_t)(r0 + 8) * DD + col] =
                make_float2((acc[mt][nt][2] + b0) * qm1,
                            (acc[mt][nt][3] + b1) * qm1);
        }
    }
}

// ---------------------------------------------------------------------------
// Tensor-core flash attention, 3-CTA/SM shape via SMEM overlay:
// stage1 = [0, 35072), stage0 = [35072, 70144)  -- disjoint.
// Q (16 KB) is overlaid on stage1's first 16 KB; it is consumed into
// registers before the first stage-1 load (guarded by __syncthreads).
// 128 threads (4 warps), q-tile 64 rows, key-block 64.
// ---------------------------------------------------------------------------
#define AQ_H 0
#define AQ_L 8192
#define SK_H 0
#define SK_L 8192
#define SV_H 16384
#define SV_L 25600
#define SVM  34816
#define STG_SZ 35072
#define STG1_BASE 0
#define STG0_BASE STG_SZ
#define AT_SMEM (2 * STG_SZ)   // 70144
#define VT_ROW 144

__global__ __launch_bounds__(128, 3)
void attn_mma(const int* __restrict__ v_mask)
{
    extern __shared__ char smc[];
    const uint32_t sb = smem_u32(smc);

    const int tid  = threadIdx.x;
    const int lane = tid & 31;
    const int w    = tid >> 5;              // 0..3
    const int bh = blockIdx.y;
    const int b  = bh >> 4;
    const int h  = bh & 15;
    const int qt = gridDim.x - 1 - blockIdx.x;   // heavy tiles first
    const int q0 = qt * 64;

    // ---- Q tile (64 x 64): cp.async into the (future stage-1) region ----
#pragma unroll
    for (int t = 0; t < 8; t++) {
        int idx = tid + t * 128;             // 0..1023
        const char* src = (idx < 512) ? (const char*)g_Qhi : (const char*)g_Qlo;
        uint32_t dst = sb + ((idx < 512) ? AQ_H : AQ_L);
        int r = (idx >> 3) & 63;
        int c = idx & 7;
        const void* g = src + ((size_t)(b * SS + q0 + r) * DD + h * 64) * 2 + c * 16;
        cp16(dst + SWZ((uint32_t)(r * 128 + c * 16)), g);
    }

    auto load_stage = [&](int kt, int s) {
        const uint32_t stg = sb + (s ? STG1_BASE : STG0_BASE);
        // K tile (64 rows x 64 d), hi+lo
#pragma unroll
        for (int t = 0; t < 8; t++) {
            int idx = tid + t * 128;         // 0..1023
            const char* src = (idx < 512) ? (const char*)g_Khi : (const char*)g_Klo;
            uint32_t dst = stg + ((idx < 512) ? SK_H : SK_L);
            int r = (idx >> 3) & 63;
            int c = idx & 7;
            const void* g = src + ((size_t)(b * SS + kt * 64 + r) * DD + h * 64) * 2 + c * 16;
            cp16(dst + SWZ((uint32_t)(r * 128 + c * 16)), g);
        }
        // V tile transposed (64 d x 64 j), hi+lo; row stride 144B
#pragma unroll
        for (int t = 0; t < 8; t++) {
            int idx = tid + t * 128;
            const char* src = (idx < 512) ? (const char*)g_Vthi : (const char*)g_Vtlo;
            uint32_t dst = stg + ((idx < 512) ? SV_H : SV_L);
            int rem = idx & 511;
            int d = rem >> 3;
            int c = rem & 7;
            const void* g = src + (((size_t)(b * 16 + h) * 64 + d) * SS + kt * 64) * 2 + c * 16;
            cp16(dst + (uint32_t)(d * VT_ROW + c * 16), g);
        }
        if (tid < 64) {
            ((float*)(smc + (s ? STG1_BASE : STG0_BASE) + SVM))[tid] =
                v_mask[b * SS + kt * 64 + tid] ? 0.0f : -1e12f;
        }
    };

    load_stage(0, 0);   // stage0 region does not overlap Q
    CP_COMMIT();
    CP_WAIT0();
    __syncthreads();

    const int a_row = w * 16 + (lane & 15);
    const uint32_t a_bc = (uint32_t)((lane >> 4) << 4);
    const int b_rp  = ((lane & 16) >> 1) + (lane & 7);
    const uint32_t b_bc = (uint32_t)((lane & 8) << 1);

    // preload Q hi+lo fragments into registers (Q SMEM is dead afterwards)
    uint32_t qh[4][4], ql[4][4];
#pragma unroll
    for (int ks = 0; ks < 4; ks++) {
        uint32_t off = SWZ((uint32_t)(a_row * 128 + ks * 32) + a_bc);
        ldsm4(qh[ks], sb + AQ_H + off);
        ldsm4(ql[ks], sb + AQ_L + off);
    }
    __syncthreads();   // all warps done reading Q before stage1 overwrites it

    float o[8][4];
#pragma unroll
    for (int nt = 0; nt < 8; nt++)
#pragma unroll
        for (int e = 0; e < 4; e++) o[nt][e] = 0.0f;
    float m_lo = -1e30f, m_hi = -1e30f, l_lo = 0.0f, l_hi = 0.0f;

    const int r = lane >> 2;
    const int qi_lo = q0 + w * 16 + r;
    const int qi_hi = qi_lo + 8;
    const int jc = (lane & 3) * 2;

    const int nkt = qt + 1;
    for (int kt = 0; kt < nkt; kt++) {
        if (kt + 1 < nkt) { load_stage(kt + 1, (kt + 1) & 1); CP_COMMIT(); }

        const uint32_t stg = sb + ((kt & 1) ? STG1_BASE : STG0_BASE);

        // ---- S = Q K^T over 64 keys: s[8][4], np-paired ----
        float s[8][4];
#pragma unroll
        for (int nt = 0; nt < 8; nt++)
#pragma unroll
            for (int e = 0; e < 4; e++) s[nt][e] = 0.0f;

#pragma unroll
        for (int ks = 0; ks < 4; ks++) {
#pragma unroll
            for (int npp = 0; npp < 2; npp++) {
                const int np0 = npp * 2, np1 = npp * 2 + 1;
                uint32_t kh0[4], kh1[4], kl0[4], kl1[4];
                uint32_t off0 = SWZ((uint32_t)((np0 * 16 + b_rp) * 128 + ks * 32) + b_bc);
                uint32_t off1 = SWZ((uint32_t)((np1 * 16 + b_rp) * 128 + ks * 32) + b_bc);
                ldsm4(kh0, stg + SK_H + off0);
                ldsm4(kh1, stg + SK_H + off1);
                ldsm4(kl0, stg + SK_L + off0);
                ldsm4(kl1, stg + SK_L + off1);
                float* s0 = s[npp * 4 + 0];
                float* s1 = s[npp * 4 + 1];
                float* s2 = s[npp * 4 + 2];
                float* s3 = s[npp * 4 + 3];
                mma16816(s0, qh[ks], kh0); mma16816(s1, qh[ks], kh0 + 2);
                mma16816(s2, qh[ks], kh1); mma16816(s3, qh[ks], kh1 + 2);
                mma16816(s0, ql[ks], kh0); mma16816(s1, ql[ks], kh0 + 2);
                mma16816(s2, ql[ks], kh1); mma16816(s3, ql[ks], kh1 + 2);
                mma16816(s0, qh[ks], kl0); mma16816(s1, qh[ks], kl0 + 2);
                mma16816(s2, qh[ks], kl1); mma16816(s3, qh[ks], kl1 + 2);
            }
        }

        // ---- mask + online softmax (base-2) ----
        const bool diag = (kt == qt);
        const float* mvm = (const float*)(smc + ((kt & 1) ? STG1_BASE : STG0_BASE) + SVM);
        float mx_lo = -1e30f, mx_hi = -1e30f;
#pragma unroll
        for (int nt = 0; nt < 8; nt++) {
            int jl = nt * 8 + jc;
            int jg = kt * 64 + jl;
            float2 av = *(const float2*)&mvm[jl];
            float v0 = s[nt][0] + av.x;
            float v1 = s[nt][1] + av.y;
            float v2 = s[nt][2] + av.x;
            float v3 = s[nt][3] + av.y;
            if (diag) {
                if (jg     > qi_lo) v0 = -1e12f;
                if (jg + 1 > qi_lo) v1 = -1e12f;
                if (jg     > qi_hi) v2 = -1e12f;
                if (jg + 1 > qi_hi) v3 = -1e12f;
            }
            s[nt][0] = v0; s[nt][1] = v1; s[nt][2] = v2; s[nt][3] = v3;
            mx_lo = fmaxf(mx_lo, fmaxf(v0, v1));
            mx_hi = fmaxf(mx_hi, fmaxf(v2, v3));
        }
        mx_lo = fmaxf(mx_lo, __shfl_xor_sync(0xffffffffu, mx_lo, 1));
        mx_lo = fmaxf(mx_lo, __shfl_xor_sync(0xffffffffu, mx_lo, 2));
        mx_hi = fmaxf(mx_hi, __shfl_xor_sync(0xffffffffu, mx_hi, 1));
        mx_hi = fmaxf(mx_hi, __shfl_xor_sync(0xffffffffu, mx_hi, 2));

        float mn_lo = fmaxf(m_lo, mx_lo);
        float mn_hi = fmaxf(m_hi, mx_hi);
        float corr_lo = ex2f(m_lo - mn_lo);
        float corr_hi = ex2f(m_hi - mn_hi);
        m_lo = mn_lo; m_hi = mn_hi;

        float sum_lo = 0.0f, sum_hi = 0.0f;
#pragma unroll
        for (int nt = 0; nt < 8; nt++) {
            float p0 = ex2f(s[nt][0] - mn_lo);
            float p1 = ex2f(s[nt][1] - mn_lo);
            float p2 = ex2f(s[nt][2] - mn_hi);
            float p3 = ex2f(s[nt][3] - mn_hi);
            s[nt][0] = p0; s[nt][1] = p1; s[nt][2] = p2; s[nt][3] = p3;
            sum_lo += p0 + p1;
            sum_hi += p2 + p3;
        }
        sum_lo += __shfl_xor_sync(0xffffffffu, sum_lo, 1);
        sum_lo += __shfl_xor_sync(0xffffffffu, sum_lo, 2);
        sum_hi += __shfl_xor_sync(0xffffffffu, sum_hi, 1);
        sum_hi += __shfl_xor_sync(0xffffffffu, sum_hi, 2);
        l_lo = l_lo * corr_lo + sum_lo;
        l_hi = l_hi * corr_hi + sum_hi;

#pragma unroll
        for (int nt = 0; nt < 8; nt++) {
            o[nt][0] *= corr_lo; o[nt][1] *= corr_lo;
            o[nt][2] *= corr_hi; o[nt][3] *= corr_hi;
        }

        // ---- O += P V over 64 keys (ks 0..3), np-paired over d ----
#pragma unroll
        for (int ks = 0; ks < 4; ks++) {
            uint32_t ah[4], al[4];
            split_pack2(s[2*ks][0],   s[2*ks][1],   ah[0], al[0]);
            split_pack2(s[2*ks][2],   s[2*ks][3],   ah[1], al[1]);
            split_pack2(s[2*ks+1][0], s[2*ks+1][1], ah[2], al[2]);
            split_pack2(s[2*ks+1][2], s[2*ks+1][3], ah[3], al[3]);
#pragma unroll
            for (int npp = 0; npp < 2; npp++) {
                const int np0 = npp * 2, np1 = npp * 2 + 1;
                uint32_t a0 = (uint32_t)((np0 * 16 + b_rp) * VT_ROW + ks * 32) + b_bc;
                uint32_t a1 = (uint32_t)((np1 * 16 + b_rp) * VT_ROW + ks * 32) + b_bc;
                uint32_t bh0[4], bh1[4], bl0[4], bl1[4];
                ldsm4(bh0, stg + SV_H + a0);
                ldsm4(bh1, stg + SV_H + a1);
                ldsm4(bl0, stg + SV_L + a0);
                ldsm4(bl1, stg + SV_L + a1);
                float* o0 = o[np0 * 2 + 0];
                float* o1 = o[np0 * 2 + 1];
                float* o2 = o[np1 * 2 + 0];
                float* o3 = o[np1 * 2 + 1];
                mma16816(o0, ah, bh0); mma16816(o1, ah, bh0 + 2);
                mma16816(o2, ah, bh1); mma16816(o3, ah, bh1 + 2);
                mma16816(o0, al, bh0); mma16816(o1, al, bh0 + 2);
                mma16816(o2, al, bh1); mma16816(o3, al, bh1 + 2);
                mma16816(o0, ah, bl0); mma16816(o1, ah, bl0 + 2);
                mma16816(o2, ah, bl1); mma16816(o3, ah, bl1 + 2);
            }
        }

        CP_WAIT0();
        __syncthreads();
    }

    // ---- normalize + split + store to g_Ohi/g_Olo ----
    float inv_lo = 1.0f / l_lo;
    float inv_hi = 1.0f / l_hi;
    const size_t row_lo = (size_t)(b * SS + q0 + w * 16 + r) * DD + h * 64;
    const size_t row_hi = row_lo + 8 * DD;
#pragma unroll
    for (int nt = 0; nt < 8; nt++) {
        int d0 = nt * 8 + jc;
        uint16_t h0,l0,h1,l1;
        split_bf(o[nt][0] * inv_lo, h0, l0);
        split_bf(o[nt][1] * inv_lo, h1, l1);
        *(uint32_t*)&g_Ohi[row_lo + d0] = (uint32_t)h0 | ((uint32_t)h1 << 16);
        *(uint32_t*)&g_Olo[row_lo + d0] = (uint32_t)l0 | ((uint32_t)l1 << 16);
        split_bf(o[nt][2] * inv_hi, h0, l0);
        split_bf(o[nt][3] * inv_hi, h1, l1);
        *(uint32_t*)&g_Ohi[row_hi + d0] = (uint32_t)h0 | ((uint32_t)h1 << 16);
        *(uint32_t*)&g_Olo[row_hi + d0] = (uint32_t)l0 | ((uint32_t)l1 << 16);
    }
}

// ---------------------------------------------------------------------------
// kernel_launch
// ---------------------------------------------------------------------------
extern "C" void kernel_launch(void* const* d_in, const int* in_sizes, int n_in,
                              void* d_out, int out_size)
{
    const float* q      = (const float*)d_in[0];
    const float* k      = (const float*)d_in[1];
    const float* v      = (const float*)d_in[2];
    const int*   q_mask = (const int*)  d_in[3];
    const int*   v_mask = (const int*)  d_in[4];
    const float* Wq     = (const float*)d_in[5];
    const float* bq     = (const float*)d_in[6];
    const float* Wk     = (const float*)d_in[7];
    const float* bk     = (const float*)d_in[8];
    const float* Wv     = (const float*)d_in[9];
    const float* bv     = (const float*)d_in[10];
    const float* Wo     = (const float*)d_in[11];
    const float* bo     = (const float*)d_in[12];
    float* out = (float*)d_out;

    cudaFuncSetAttribute(gemm_qkv,
                         cudaFuncAttributeMaxDynamicSharedMemorySize, GEMM_SMEM);
    cudaFuncSetAttribute(gemm_out,
                         cudaFuncAttributeMaxDynamicSharedMemorySize, GEMM_SMEM);
    cudaFuncSetAttribute(attn_mma,
                         cudaFuncAttributeMaxDynamicSharedMemorySize, AT_SMEM);

    const int n4 = MM * DD / 4;

    split3_kernel<<<dim3((n4 + 255) / 256, 3), 256>>>(q, k, v, n4);
    wsplit4_kernel<<<dim3(DD / 32, DD / 32, 4), 256>>>(Wq, Wk, Wv, Wo);

    gemm_qkv<<<dim3(DD / 256, MM / 128, 3), 256, GEMM_SMEM>>>(bq, bk, bv);

    // Attention: 128-thread CTAs, 64-row q tiles, 3 CTAs/SM (disjoint stages,
    // Q overlaid on stage1)
    attn_mma<<<dim3(SS / 64, BB * HH), 128, AT_SMEM>>>(v_mask);

    gemm_out<<<dim3(DD / 256, MM / 128), 256, GEMM_SMEM>>>(bo, q_mask, out);
}

// round 15
// speedup vs baseline: 3.2173x; 1.0429x over previous
#include <cuda_runtime.h>
#include <cuda_bf16.h>
#include <cstdint>

// Problem constants
#define BB 4
#define SS 2048
#define DD 1024
#define HH 16
#define MM (BB*SS)          // 8192 rows

// Q pre-scale: 1/sqrt(64) * log2(e)  (softmax done in base-2)
#define QSCALE 0.18033688011112042f

// Scratch (device globals: allocation-free). All interchange in split bf16.
__device__ __nv_bfloat16 g_Aqhi[MM * DD];
__device__ __nv_bfloat16 g_Aqlo[MM * DD];
__device__ __nv_bfloat16 g_Akhi[MM * DD];
__device__ __nv_bfloat16 g_Aklo[MM * DD];
__device__ __nv_bfloat16 g_Avhi[MM * DD];
__device__ __nv_bfloat16 g_Avlo[MM * DD];
__device__ __nv_bfloat16 g_Wqhi[DD * DD];  // transposed weights: [N, K]
__device__ __nv_bfloat16 g_Wqlo[DD * DD];
__device__ __nv_bfloat16 g_Wkhi[DD * DD];
__device__ __nv_bfloat16 g_Wklo[DD * DD];
__device__ __nv_bfloat16 g_Wvhi[DD * DD];
__device__ __nv_bfloat16 g_Wvlo[DD * DD];
__device__ __nv_bfloat16 g_Wohi[DD * DD];
__device__ __nv_bfloat16 g_Wolo[DD * DD];
__device__ __nv_bfloat16 g_Qhi[MM * DD];   // [row][h*64+d], pre-scaled
__device__ __nv_bfloat16 g_Qlo[MM * DD];
__device__ __nv_bfloat16 g_Khi[MM * DD];
__device__ __nv_bfloat16 g_Klo[MM * DD];
__device__ __nv_bfloat16 g_Vthi[MM * DD];  // transposed: [(b*16+h)*64+d][S]
__device__ __nv_bfloat16 g_Vtlo[MM * DD];
__device__ __nv_bfloat16 g_Ohi[MM * DD];   // attention output, split
__device__ __nv_bfloat16 g_Olo[MM * DD];

// ---------------------------------------------------------------------------
// Helpers
// ---------------------------------------------------------------------------
__device__ __forceinline__ uint32_t smem_u32(const void* p) {
    uint32_t a;
    asm("{ .reg .u64 t; cvta.to.shared.u64 t, %1; cvt.u32.u64 %0, t; }"
        : "=r"(a) : "l"(p));
    return a;
}

__device__ __forceinline__ void ldsm4(uint32_t* r, uint32_t addr) {
    asm volatile("ldmatrix.sync.aligned.m8n8.x4.shared.b16 {%0,%1,%2,%3}, [%4];"
        : "=r"(r[0]), "=r"(r[1]), "=r"(r[2]), "=r"(r[3]) : "r"(addr));
}

__device__ __forceinline__ void mma16816(float* c, const uint32_t* a,
                                         const uint32_t* b) {
    asm volatile(
        "mma.sync.aligned.m16n8k16.row.col.f32.bf16.bf16.f32 "
        "{%0,%1,%2,%3}, {%4,%5,%6,%7}, {%8,%9}, {%0,%1,%2,%3};"
        : "+f"(c[0]), "+f"(c[1]), "+f"(c[2]), "+f"(c[3])
        : "r"(a[0]), "r"(a[1]), "r"(a[2]), "r"(a[3]), "r"(b[0]), "r"(b[1]));
}

__device__ __forceinline__ void cp16(uint32_t saddr, const void* g) {
    asm volatile("cp.async.cg.shared.global [%0], [%1], 16;"
                 :: "r"(saddr), "l"(g) : "memory");
}
#define CP_COMMIT() asm volatile("cp.async.commit_group;" ::: "memory")
#define CP_WAIT0()  asm volatile("cp.async.wait_group 0;" ::: "memory")

// Swizzles: SW128 for 128B rows (attention), SW64 for 64B rows (GEMM)
#define SWZ(o)   ((o) ^ (((o) >> 3) & 0x70))
#define SWZ64(o) ((o) ^ (((o) >> 3) & 0x30))

__device__ __forceinline__ void split_bf(float v, uint16_t& h, uint16_t& l) {
    __nv_bfloat16 hb = __float2bfloat16(v);
    __nv_bfloat16 lb = __float2bfloat16(v - __bfloat162float(hb));
    h = *(uint16_t*)&hb; l = *(uint16_t*)&lb;
}

// Fast truncation split of 2 floats -> packed hi bf16x2 + lo bf16x2.
__device__ __forceinline__ void split_pack2(float a, float b,
                                            uint32_t& hi2, uint32_t& lo2) {
    uint32_t ba = __float_as_uint(a), bb = __float_as_uint(b);
    asm("prmt.b32 %0, %1, %2, 0x7632;" : "=r"(hi2) : "r"(ba), "r"(bb));
    float la = a - __uint_as_float(ba & 0xFFFF0000u);
    float lb = b - __uint_as_float(bb & 0xFFFF0000u);
    asm("cvt.rn.bf16x2.f32 %0, %1, %2;" : "=r"(lo2) : "f"(lb), "f"(la));
}

__device__ __forceinline__ float ex2f(float x) {
    float y;
    asm("ex2.approx.f32 %0, %1;" : "=f"(y) : "f"(x));
    return y;
}

// ---------------------------------------------------------------------------
// Fused split of q,k,v inputs (blockIdx.y selects tensor)
// ---------------------------------------------------------------------------
__global__ __launch_bounds__(256)
void split3_kernel(const float* __restrict__ x0, const float* __restrict__ x1,
                   const float* __restrict__ x2, int n4)
{
    int i = blockIdx.x * blockDim.x + threadIdx.x;
    if (i >= n4) return;
    const float* x;
    __nv_bfloat16 *hi, *lo;
    if (blockIdx.y == 0)      { x = x0; hi = g_Aqhi; lo = g_Aqlo; }
    else if (blockIdx.y == 1) { x = x1; hi = g_Akhi; lo = g_Aklo; }
    else                      { x = x2; hi = g_Avhi; lo = g_Avlo; }
    float4 v = ((const float4*)x)[i];
    uint16_t h0,l0,h1,l1,h2,l2,h3,l3;
    split_bf(v.x,h0,l0); split_bf(v.y,h1,l1);
    split_bf(v.z,h2,l2); split_bf(v.w,h3,l3);
    uint2 hv = make_uint2((uint32_t)h0|((uint32_t)h1<<16),
                          (uint32_t)h2|((uint32_t)h3<<16));
    uint2 lv = make_uint2((uint32_t)l0|((uint32_t)l1<<16),
                          (uint32_t)l2|((uint32_t)l3<<16));
    *(uint2*)(hi + (size_t)i * 4) = hv;
    *(uint2*)(lo + (size_t)i * 4) = lv;
}

// Fused W[K,N] fp32 -> Whi/Wlo [N,K] bf16 (transposed), all 4 weights
__global__ __launch_bounds__(256)
void wsplit4_kernel(const float* __restrict__ W0, const float* __restrict__ W1,
                    const float* __restrict__ W2, const float* __restrict__ W3)
{
    __shared__ float t[32][33];
    const float* W;
    __nv_bfloat16 *hi, *lo;
    if (blockIdx.z == 0)      { W = W0; hi = g_Wqhi; lo = g_Wqlo; }
    else if (blockIdx.z == 1) { W = W1; hi = g_Wkhi; lo = g_Wklo; }
    else if (blockIdx.z == 2) { W = W2; hi = g_Wvhi; lo = g_Wvlo; }
    else                      { W = W3; hi = g_Wohi; lo = g_Wolo; }
    int tx = threadIdx.x & 31;
    int ty = threadIdx.x >> 5;
    int n0 = blockIdx.x * 32;
    int k0 = blockIdx.y * 32;
#pragma unroll
    for (int i = 0; i < 4; i++)
        t[ty + 8 * i][tx] = W[(size_t)(k0 + ty + 8 * i) * DD + n0 + tx];
    __syncthreads();
#pragma unroll
    for (int i = 0; i < 4; i++) {
        int n = ty + 8 * i;
        float v = t[tx][n];
        uint16_t h, l;
        split_bf(v, h, l);
        *(uint16_t*)&hi[(size_t)(n0 + n) * DD + k0 + tx] = h;
        *(uint16_t*)&lo[(size_t)(n0 + n) * DD + k0 + tx] = l;
    }
}

// ---------------------------------------------------------------------------
// GEMM: CTA tile 128x128, warp tile 32x64, BK=32, 2-stage, 2 CTAs/SM.
// SMEM rows are 64B -> SW64 swizzle. Stage = 32KB; GEMM_SMEM = 64KB.
// ---------------------------------------------------------------------------
#define BK 32
#define GA_H 0
#define GA_L 8192
#define GB_H 16384
#define GB_L 24576
#define G_STAGE 32768
#define GEMM_SMEM (2 * G_STAGE)   // 65536
#define NK (DD / BK)              // 32

#define GEMM_LOAD_STAGE(Ahi_, Alo_, Bhi_, Blo_, it, s)                         \
    do {                                                                       \
        const int kc_ = (it) * BK;                                             \
        const uint32_t stb_ = sbase + (s) * G_STAGE;                           \
        _Pragma("unroll")                                                      \
        for (int i_ = 0; i_ < 4; i_++) {                                       \
            int u_ = tid + i_ * 256;          /* 0..1023 */                    \
            int half_ = u_ >> 9;                                               \
            int rem_ = u_ & 511;                                               \
            int r_ = rem_ >> 2, c_ = rem_ & 3;                                 \
            const char* src_ = half_ ? (const char*)(Alo_) : (const char*)(Ahi_);\
            cp16(stb_ + (half_ ? GA_L : GA_H) + SWZ64((uint32_t)(r_ * 64 + c_ * 16)),\
                 src_ + ((size_t)(m0 + r_) * DD + kc_) * 2 + c_ * 16);         \
        }                                                                      \
        _Pragma("unroll")                                                      \
        for (int i_ = 0; i_ < 4; i_++) {                                       \
            int u_ = tid + i_ * 256;                                           \
            int half_ = u_ >> 9;                                               \
            int rem_ = u_ & 511;                                               \
            int r_ = rem_ >> 2, c_ = rem_ & 3;                                 \
            const char* src_ = half_ ? (const char*)(Blo_) : (const char*)(Bhi_);\
            cp16(stb_ + (half_ ? GB_L : GB_H) + SWZ64((uint32_t)(r_ * 64 + c_ * 16)),\
                 src_ + ((size_t)(n0 + r_) * DD + kc_) * 2 + c_ * 16);         \
        }                                                                      \
    } while (0)

#define GEMM_MAINLOOP(Ahi_, Alo_, Bhi_, Blo_)                                  \
    GEMM_LOAD_STAGE(Ahi_, Alo_, Bhi_, Blo_, 0, 0);                             \
    CP_COMMIT(); CP_WAIT0(); __syncthreads();                                  \
    for (int it = 0; it < NK; it++) {                                          \
        if (it + 1 < NK) {                                                     \
            GEMM_LOAD_STAGE(Ahi_, Alo_, Bhi_, Blo_, it + 1, (it + 1) & 1);     \
            CP_COMMIT();                                                       \
        }                                                                      \
        const uint32_t stb = sbase + (it & 1) * G_STAGE;                       \
        _Pragma("unroll")                                                      \
        for (int ks = 0; ks < 2; ks++) {                                       \
            uint32_t ah[2][4], al[2][4];                                       \
            _Pragma("unroll")                                                  \
            for (int mt = 0; mt < 2; mt++) {                                   \
                uint32_t off = (uint32_t)((a_row + mt * 16) * 64) +            \
                               (uint32_t)(ks * 32) + a_bc;                     \
                ldsm4(ah[mt], stb + GA_H + SWZ64(off));                        \
                ldsm4(al[mt], stb + GA_L + SWZ64(off));                        \
            }                                                                  \
            _Pragma("unroll")                                                  \
            for (int np = 0; np < 4; np++) {                                   \
                uint32_t bh[4], bl[4];                                         \
                uint32_t off = (uint32_t)((b_row + np * 16) * 64) +            \
                               (uint32_t)(ks * 32) + b_bc;                     \
                ldsm4(bh, stb + GB_H + SWZ64(off));                            \
                ldsm4(bl, stb + GB_L + SWZ64(off));                            \
                _Pragma("unroll")                                              \
                for (int mt = 0; mt < 2; mt++) {                               \
                    mma16816(acc[mt][np * 2 + 0], ah[mt], bh);                 \
                    mma16816(acc[mt][np * 2 + 1], ah[mt], bh + 2);             \
                }                                                              \
                _Pragma("unroll")                                              \
                for (int mt = 0; mt < 2; mt++) {                               \
                    mma16816(acc[mt][np * 2 + 0], ah[mt], bl);                 \
                    mma16816(acc[mt][np * 2 + 1], ah[mt], bl + 2);             \
                }                                                              \
                _Pragma("unroll")                                              \
                for (int mt = 0; mt < 2; mt++) {                               \
                    mma16816(acc[mt][np * 2 + 0], al[mt], bh);                 \
                    mma16816(acc[mt][np * 2 + 1], al[mt], bh + 2);             \
                }                                                              \
            }                                                                  \
        }                                                                      \
        CP_WAIT0();                                                            \
        __syncthreads();                                                       \
    }

// ---------------------------------------------------------------------------
// Merged Q/K/V projection GEMM (blockIdx.z: 0=Q (prescaled), 1=K, 2=V trans).
// ---------------------------------------------------------------------------
__global__ __launch_bounds__(256, 2)
void gemm_qkv(const float* __restrict__ bq, const float* __restrict__ bk,
              const float* __restrict__ bv)
{
    extern __shared__ char smc[];
    const uint32_t sbase = smem_u32(smc);

    const int tid  = threadIdx.x;
    const int lane = tid & 31;
    const int wid  = tid >> 5;
    const int wm   = wid & 3;          // 4 x 32 rows
    const int wn   = wid >> 2;         // 2 x 64 cols
    const int m0 = blockIdx.y * 128;
    const int n0 = blockIdx.x * 128;
    const int z  = blockIdx.z;

    const __nv_bfloat16* Ahi = (z == 0) ? g_Aqhi : (z == 1) ? g_Akhi : g_Avhi;
    const __nv_bfloat16* Alo = (z == 0) ? g_Aqlo : (z == 1) ? g_Aklo : g_Avlo;
    const __nv_bfloat16* Bhi = (z == 0) ? g_Wqhi : (z == 1) ? g_Wkhi : g_Wvhi;
    const __nv_bfloat16* Blo = (z == 0) ? g_Wqlo : (z == 1) ? g_Wklo : g_Wvlo;
    const float* bias = (z == 0) ? bq : (z == 1) ? bk : bv;

    float acc[2][8][4];
#pragma unroll
    for (int mt = 0; mt < 2; mt++)
#pragma unroll
        for (int nt = 0; nt < 8; nt++)
#pragma unroll
            for (int e = 0; e < 4; e++) acc[mt][nt][e] = 0.0f;

    const int a_row = wm * 32 + (lane & 15);
    const uint32_t a_bc = (uint32_t)((lane >> 4) << 4);
    const int b_row = wn * 64 + ((lane & 16) >> 1) + (lane & 7);
    const uint32_t b_bc = (uint32_t)((lane & 8) << 1);

    GEMM_MAINLOOP(Ahi, Alo, Bhi, Blo);

    if (z == 2) {
        // V: transposed epilogue via two 64-column SMEM staging passes.
        float* tb = (float*)smc;   // 64 cols x 132 floats = 33792 B
#pragma unroll
        for (int pass = 0; pass < 2; pass++) {
            if (wn == pass) {
#pragma unroll
                for (int nt = 0; nt < 8; nt++) {
                    const int cl = ((lane & 3) << 1) + nt * 8;   // 0..63 local
                    const float b0 = bias[n0 + pass * 64 + cl];
                    const float b1 = bias[n0 + pass * 64 + cl + 1];
#pragma unroll
                    for (int mt = 0; mt < 2; mt++) {
                        int rl = wm * 32 + (lane >> 2) + mt * 16;
                        tb[cl * 132 + rl]           = acc[mt][nt][0] + b0;
                        tb[(cl + 1) * 132 + rl]     = acc[mt][nt][1] + b1;
                        tb[cl * 132 + rl + 8]       = acc[mt][nt][2] + b0;
                        tb[(cl + 1) * 132 + rl + 8] = acc[mt][nt][3] + b1;
                    }
                }
            }
            __syncthreads();
            // copy out: 64 cols x 128 rows; 4 threads per col, 32 floats each
            const int cl = tid >> 2;
            const int qh4 = tid & 3;
            const float* src = tb + cl * 132 + qh4 * 32;
            const int col = n0 + pass * 64 + cl;
            const size_t base = ((size_t)(m0 >> 11) * 1024 + col) * SS +
                                (m0 & 2047) + qh4 * 32;
            uint32_t hb[16], lb[16];
#pragma unroll
            for (int i = 0; i < 16; i++) {
                uint16_t ha, la, hbv, lbv;
                split_bf(src[2 * i],     ha,  la);
                split_bf(src[2 * i + 1], hbv, lbv);
                hb[i] = (uint32_t)ha | ((uint32_t)hbv << 16);
                lb[i] = (uint32_t)la | ((uint32_t)lbv << 16);
            }
#pragma unroll
            for (int u = 0; u < 4; u++) {
                *(uint4*)&g_Vthi[base + u * 8] =
                    make_uint4(hb[4*u], hb[4*u+1], hb[4*u+2], hb[4*u+3]);
                *(uint4*)&g_Vtlo[base + u * 8] =
                    make_uint4(lb[4*u], lb[4*u+1], lb[4*u+2], lb[4*u+3]);
            }
            __syncthreads();
        }
        return;
    }

    __nv_bfloat16* Chi = (z == 0) ? g_Qhi : g_Khi;
    __nv_bfloat16* Clo = (z == 0) ? g_Qlo : g_Klo;
    const float sc = (z == 0) ? QSCALE : 1.0f;
    const int col_base = n0 + wn * 64 + ((lane & 3) << 1);
    const int row_base = m0 + wm * 32 + (lane >> 2);
#pragma unroll
    for (int nt = 0; nt < 8; nt++) {
        const int col = col_base + nt * 8;
        const float b0 = bias[col];
        const float b1 = bias[col + 1];
#pragma unroll
        for (int mt = 0; mt < 2; mt++) {
            int r0 = row_base + mt * 16;
            float v0 = (acc[mt][nt][0] + b0) * sc;
            float v1 = (acc[mt][nt][1] + b1) * sc;
            float v2 = (acc[mt][nt][2] + b0) * sc;
            float v3 = (acc[mt][nt][3] + b1) * sc;
            uint16_t h0,l0,h1,l1,h2,l2,h3,l3;
            split_bf(v0,h0,l0); split_bf(v1,h1,l1);
            split_bf(v2,h2,l2); split_bf(v3,h3,l3);
            *(uint32_t*)&Chi[(size_t)r0 * DD + col] =
                (uint32_t)h0 | ((uint32_t)h1 << 16);
            *(uint32_t*)&Clo[(size_t)r0 * DD + col] =
                (uint32_t)l0 | ((uint32_t)l1 << 16);
            *(uint32_t*)&Chi[(size_t)(r0 + 8) * DD + col] =
                (uint32_t)h2 | ((uint32_t)h3 << 16);
            *(uint32_t*)&Clo[(size_t)(r0 + 8) * DD + col] =
                (uint32_t)l2 | ((uint32_t)l3 << 16);
        }
    }
}

// ---------------------------------------------------------------------------
// Output projection GEMM: reads presplit O, writes fp32 + qmask.
// ---------------------------------------------------------------------------
__global__ __launch_bounds__(256, 2)
void gemm_out(const float* __restrict__ bias, const int* __restrict__ qmask,
              float* __restrict__ C)
{
    extern __shared__ char smc[];
    const uint32_t sbase = smem_u32(smc);

    const int tid  = threadIdx.x;
    const int lane = tid & 31;
    const int wid  = tid >> 5;
    const int wm   = wid & 3;
    const int wn   = wid >> 2;
    const int m0 = blockIdx.y * 128;
    const int n0 = blockIdx.x * 128;

    float acc[2][8][4];
#pragma unroll
    for (int mt = 0; mt < 2; mt++)
#pragma unroll
        for (int nt = 0; nt < 8; nt++)
#pragma unroll
            for (int e = 0; e < 4; e++) acc[mt][nt][e] = 0.0f;

    const int a_row = wm * 32 + (lane & 15);
    const uint32_t a_bc = (uint32_t)((lane >> 4) << 4);
    const int b_row = wn * 64 + ((lane & 16) >> 1) + (lane & 7);
    const uint32_t b_bc = (uint32_t)((lane & 8) << 1);

    GEMM_MAINLOOP(g_Ohi, g_Olo, g_Wohi, g_Wolo);

    const int col_base = n0 + wn * 64 + ((lane & 3) << 1);
    const int row_base = m0 + wm * 32 + (lane >> 2);
#pragma unroll
    for (int nt = 0; nt < 8; nt++) {
        const int col = col_base + nt * 8;
        const float b0 = bias[col];
        const float b1 = bias[col + 1];
#pragma unroll
        for (int mt = 0; mt < 2; mt++) {
            int r0 = row_base + mt * 16;
            float qm0 = (float)qmask[r0];
            float qm1 = (float)qmask[r0 + 8];
            *(float2*)&C[(size_t)r0 * DD + col] =
                make_float2((acc[mt][nt][0] + b0) * qm0,
                            (acc[mt][nt][1] + b1) * qm0);
            *(float2*)&C[(size_t)(r0 + 8) * DD + col] =
                make_float2((acc[mt][nt][2] + b0) * qm1,
                            (acc[mt][nt][3] + b1) * qm1);
        }
    }
}

// ---------------------------------------------------------------------------
// Tensor-core flash attention (unchanged from R14): 3 CTAs/SM via overlay,
// stage1 = [0, 35072), stage0 = [35072, 70144); Q overlaid on stage1.
// ---------------------------------------------------------------------------
#define AQ_H 0
#define AQ_L 8192
#define SK_H 0
#define SK_L 8192
#define SV_H 16384
#define SV_L 25600
#define SVM  34816
#define STG_SZ 35072
#define STG1_BASE 0
#define STG0_BASE STG_SZ
#define AT_SMEM (2 * STG_SZ)   // 70144
#define VT_ROW 144

__global__ __launch_bounds__(128, 3)
void attn_mma(const int* __restrict__ v_mask)
{
    extern __shared__ char smc[];
    const uint32_t sb = smem_u32(smc);

    const int tid  = threadIdx.x;
    const int lane = tid & 31;
    const int w    = tid >> 5;
    const int bh = blockIdx.y;
    const int b  = bh >> 4;
    const int h  = bh & 15;
    const int qt = gridDim.x - 1 - blockIdx.x;
    const int q0 = qt * 64;

#pragma unroll
    for (int t = 0; t < 8; t++) {
        int idx = tid + t * 128;
        const char* src = (idx < 512) ? (const char*)g_Qhi : (const char*)g_Qlo;
        uint32_t dst = sb + ((idx < 512) ? AQ_H : AQ_L);
        int r = (idx >> 3) & 63;
        int c = idx & 7;
        const void* g = src + ((size_t)(b * SS + q0 + r) * DD + h * 64) * 2 + c * 16;
        cp16(dst + SWZ((uint32_t)(r * 128 + c * 16)), g);
    }

    auto load_stage = [&](int kt, int s) {
        const uint32_t stg = sb + (s ? STG1_BASE : STG0_BASE);
#pragma unroll
        for (int t = 0; t < 8; t++) {
            int idx = tid + t * 128;
            const char* src = (idx < 512) ? (const char*)g_Khi : (const char*)g_Klo;
            uint32_t dst = stg + ((idx < 512) ? SK_H : SK_L);
            int r = (idx >> 3) & 63;
            int c = idx & 7;
            const void* g = src + ((size_t)(b * SS + kt * 64 + r) * DD + h * 64) * 2 + c * 16;
            cp16(dst + SWZ((uint32_t)(r * 128 + c * 16)), g);
        }
#pragma unroll
        for (int t = 0; t < 8; t++) {
            int idx = tid + t * 128;
            const char* src = (idx < 512) ? (const char*)g_Vthi : (const char*)g_Vtlo;
            uint32_t dst = stg + ((idx < 512) ? SV_H : SV_L);
            int rem = idx & 511;
            int d = rem >> 3;
            int c = rem & 7;
            const void* g = src + (((size_t)(b * 16 + h) * 64 + d) * SS + kt * 64) * 2 + c * 16;
            cp16(dst + (uint32_t)(d * VT_ROW + c * 16), g);
        }
        if (tid < 64) {
            ((float*)(smc + (s ? STG1_BASE : STG0_BASE) + SVM))[tid] =
                v_mask[b * SS + kt * 64 + tid] ? 0.0f : -1e12f;
        }
    };

    load_stage(0, 0);
    CP_COMMIT();
    CP_WAIT0();
    __syncthreads();

    const int a_row = w * 16 + (lane & 15);
    const uint32_t a_bc = (uint32_t)((lane >> 4) << 4);
    const int b_rp  = ((lane & 16) >> 1) + (lane & 7);
    const uint32_t b_bc = (uint32_t)((lane & 8) << 1);

    uint32_t qh[4][4], ql[4][4];
#pragma unroll
    for (int ks = 0; ks < 4; ks++) {
        uint32_t off = SWZ((uint32_t)(a_row * 128 + ks * 32) + a_bc);
        ldsm4(qh[ks], sb + AQ_H + off);
        ldsm4(ql[ks], sb + AQ_L + off);
    }
    __syncthreads();   // Q consumed before stage1 overwrites it

    float o[8][4];
#pragma unroll
    for (int nt = 0; nt < 8; nt++)
#pragma unroll
        for (int e = 0; e < 4; e++) o[nt][e] = 0.0f;
    float m_lo = -1e30f, m_hi = -1e30f, l_lo = 0.0f, l_hi = 0.0f;

    const int r = lane >> 2;
    const int qi_lo = q0 + w * 16 + r;
    const int qi_hi = qi_lo + 8;
    const int jc = (lane & 3) * 2;

    const int nkt = qt + 1;
    for (int kt = 0; kt < nkt; kt++) {
        if (kt + 1 < nkt) { load_stage(kt + 1, (kt + 1) & 1); CP_COMMIT(); }

        const uint32_t stg = sb + ((kt & 1) ? STG1_BASE : STG0_BASE);

        float s[8][4];
#pragma unroll
        for (int nt = 0; nt < 8; nt++)
#pragma unroll
            for (int e = 0; e < 4; e++) s[nt][e] = 0.0f;

#pragma unroll
        for (int ks = 0; ks < 4; ks++) {
#pragma unroll
            for (int npp = 0; npp < 2; npp++) {
                const int np0 = npp * 2, np1 = npp * 2 + 1;
                uint32_t kh0[4], kh1[4], kl0[4], kl1[4];
                uint32_t off0 = SWZ((uint32_t)((np0 * 16 + b_rp) * 128 + ks * 32) + b_bc);
                uint32_t off1 = SWZ((uint32_t)((np1 * 16 + b_rp) * 128 + ks * 32) + b_bc);
                ldsm4(kh0, stg + SK_H + off0);
                ldsm4(kh1, stg + SK_H + off1);
                ldsm4(kl0, stg + SK_L + off0);
                ldsm4(kl1, stg + SK_L + off1);
                float* s0 = s[npp * 4 + 0];
                float* s1 = s[npp * 4 + 1];
                float* s2 = s[npp * 4 + 2];
                float* s3 = s[npp * 4 + 3];
                mma16816(s0, qh[ks], kh0); mma16816(s1, qh[ks], kh0 + 2);
                mma16816(s2, qh[ks], kh1); mma16816(s3, qh[ks], kh1 + 2);
                mma16816(s0, ql[ks], kh0); mma16816(s1, ql[ks], kh0 + 2);
                mma16816(s2, ql[ks], kh1); mma16816(s3, ql[ks], kh1 + 2);
                mma16816(s0, qh[ks], kl0); mma16816(s1, qh[ks], kl0 + 2);
                mma16816(s2, qh[ks], kl1); mma16816(s3, qh[ks], kl1 + 2);
            }
        }

        const bool diag = (kt == qt);
        const float* mvm = (const float*)(smc + ((kt & 1) ? STG1_BASE : STG0_BASE) + SVM);
        float mx_lo = -1e30f, mx_hi = -1e30f;
#pragma unroll
        for (int nt = 0; nt < 8; nt++) {
            int jl = nt * 8 + jc;
            int jg = kt * 64 + jl;
            float2 av = *(const float2*)&mvm[jl];
            float v0 = s[nt][0] + av.x;
            float v1 = s[nt][1] + av.y;
            float v2 = s[nt][2] + av.x;
            float v3 = s[nt][3] + av.y;
            if (diag) {
                if (jg     > qi_lo) v0 = -1e12f;
                if (jg + 1 > qi_lo) v1 = -1e12f;
                if (jg     > qi_hi) v2 = -1e12f;
                if (jg + 1 > qi_hi) v3 = -1e12f;
            }
            s[nt][0] = v0; s[nt][1] = v1; s[nt][2] = v2; s[nt][3] = v3;
            mx_lo = fmaxf(mx_lo, fmaxf(v0, v1));
            mx_hi = fmaxf(mx_hi, fmaxf(v2, v3));
        }
        mx_lo = fmaxf(mx_lo, __shfl_xor_sync(0xffffffffu, mx_lo, 1));
        mx_lo = fmaxf(mx_lo, __shfl_xor_sync(0xffffffffu, mx_lo, 2));
        mx_hi = fmaxf(mx_hi, __shfl_xor_sync(0xffffffffu, mx_hi, 1));
        mx_hi = fmaxf(mx_hi, __shfl_xor_sync(0xffffffffu, mx_hi, 2));

        float mn_lo = fmaxf(m_lo, mx_lo);
        float mn_hi = fmaxf(m_hi, mx_hi);
        float corr_lo = ex2f(m_lo - mn_lo);
        float corr_hi = ex2f(m_hi - mn_hi);
        m_lo = mn_lo; m_hi = mn_hi;

        float sum_lo = 0.0f, sum_hi = 0.0f;
#pragma unroll
        for (int nt = 0; nt < 8; nt++) {
            float p0 = ex2f(s[nt][0] - mn_lo);
            float p1 = ex2f(s[nt][1] - mn_lo);
            float p2 = ex2f(s[nt][2] - mn_hi);
            float p3 = ex2f(s[nt][3] - mn_hi);
            s[nt][0] = p0; s[nt][1] = p1; s[nt][2] = p2; s[nt][3] = p3;
            sum_lo += p0 + p1;
            sum_hi += p2 + p3;
        }
        sum_lo += __shfl_xor_sync(0xffffffffu, sum_lo, 1);
        sum_lo += __shfl_xor_sync(0xffffffffu, sum_lo, 2);
        sum_hi += __shfl_xor_sync(0xffffffffu, sum_hi, 1);
        sum_hi += __shfl_xor_sync(0xffffffffu, sum_hi, 2);
        l_lo = l_lo * corr_lo + sum_lo;
        l_hi = l_hi * corr_hi + sum_hi;

#pragma unroll
        for (int nt = 0; nt < 8; nt++) {
            o[nt][0] *= corr_lo; o[nt][1] *= corr_lo;
            o[nt][2] *= corr_hi; o[nt][3] *= corr_hi;
        }

#pragma unroll
        for (int ks = 0; ks < 4; ks++) {
            uint32_t ah[4], al[4];
            split_pack2(s[2*ks][0],   s[2*ks][1],   ah[0], al[0]);
            split_pack2(s[2*ks][2],   s[2*ks][3],   ah[1], al[1]);
            split_pack2(s[2*ks+1][0], s[2*ks+1][1], ah[2], al[2]);
            split_pack2(s[2*ks+1][2], s[2*ks+1][3], ah[3], al[3]);
#pragma unroll
            for (int npp = 0; npp < 2; npp++) {
                const int np0 = npp * 2, np1 = npp * 2 + 1;
                uint32_t a0 = (uint32_t)((np0 * 16 + b_rp) * VT_ROW + ks * 32) + b_bc;
                uint32_t a1 = (uint32_t)((np1 * 16 + b_rp) * VT_ROW + ks * 32) + b_bc;
                uint32_t bh0[4], bh1[4], bl0[4], bl1[4];
                ldsm4(bh0, stg + SV_H + a0);
                ldsm4(bh1, stg + SV_H + a1);
                ldsm4(bl0, stg + SV_L + a0);
                ldsm4(bl1, stg + SV_L + a1);
                float* o0 = o[np0 * 2 + 0];
                float* o1 = o[np0 * 2 + 1];
                float* o2 = o[np1 * 2 + 0];
                float* o3 = o[np1 * 2 + 1];
                mma16816(o0, ah, bh0); mma16816(o1, ah, bh0 + 2);
                mma16816(o2, ah, bh1); mma16816(o3, ah, bh1 + 2);
                mma16816(o0, al, bh0); mma16816(o1, al, bh0 + 2);
                mma16816(o2, al, bh1); mma16816(o3, al, bh1 + 2);
                mma16816(o0, ah, bl0); mma16816(o1, ah, bl0 + 2);
                mma16816(o2, ah, bl1); mma16816(o3, ah, bl1 + 2);
            }
        }

        CP_WAIT0();
        __syncthreads();
    }

    float inv_lo = 1.0f / l_lo;
    float inv_hi = 1.0f / l_hi;
    const size_t row_lo = (size_t)(b * SS + q0 + w * 16 + r) * DD + h * 64;
    const size_t row_hi = row_lo + 8 * DD;
#pragma unroll
    for (int nt = 0; nt < 8; nt++) {
        int d0 = nt * 8 + jc;
        uint16_t h0,l0,h1,l1;
        split_bf(o[nt][0] * inv_lo, h0, l0);
        split_bf(o[nt][1] * inv_lo, h1, l1);
        *(uint32_t*)&g_Ohi[row_lo + d0] = (uint32_t)h0 | ((uint32_t)h1 << 16);
        *(uint32_t*)&g_Olo[row_lo + d0] = (uint32_t)l0 | ((uint32_t)l1 << 16);
        split_bf(o[nt][2] * inv_hi, h0, l0);
        split_bf(o[nt][3] * inv_hi, h1, l1);
        *(uint32_t*)&g_Ohi[row_hi + d0] = (uint32_t)h0 | ((uint32_t)h1 << 16);
        *(uint32_t*)&g_Olo[row_hi + d0] = (uint32_t)l0 | ((uint32_t)l1 << 16);
    }
}

// ---------------------------------------------------------------------------
// kernel_launch
// ---------------------------------------------------------------------------
extern "C" void kernel_launch(void* const* d_in, const int* in_sizes, int n_in,
                              void* d_out, int out_size)
{
    const float* q      = (const float*)d_in[0];
    const float* k      = (const float*)d_in[1];
    const float* v      = (const float*)d_in[2];
    const int*   q_mask = (const int*)  d_in[3];
    const int*   v_mask = (const int*)  d_in[4];
    const float* Wq     = (const float*)d_in[5];
    const float* bq     = (const float*)d_in[6];
    const float* Wk     = (const float*)d_in[7];
    const float* bk     = (const float*)d_in[8];
    const float* Wv     = (const float*)d_in[9];
    const float* bv     = (const float*)d_in[10];
    const float* Wo     = (const float*)d_in[11];
    const float* bo     = (const float*)d_in[12];
    float* out = (float*)d_out;

    cudaFuncSetAttribute(gemm_qkv,
                         cudaFuncAttributeMaxDynamicSharedMemorySize, GEMM_SMEM);
    cudaFuncSetAttribute(gemm_out,
                         cudaFuncAttributeMaxDynamicSharedMemorySize, GEMM_SMEM);
    cudaFuncSetAttribute(attn_mma,
                         cudaFuncAttributeMaxDynamicSharedMemorySize, AT_SMEM);

    const int n4 = MM * DD / 4;

    split3_kernel<<<dim3((n4 + 255) / 256, 3), 256>>>(q, k, v, n4);
    wsplit4_kernel<<<dim3(DD / 32, DD / 32, 4), 256>>>(Wq, Wk, Wv, Wo);

    // Merged Q/K/V projections: 128x128 tiles, 2 CTAs/SM
    gemm_qkv<<<dim3(DD / 128, MM / 128, 3), 256, GEMM_SMEM>>>(bq, bk, bv);

    // Attention: 128-thread CTAs, 64-row q tiles, 3 CTAs/SM
    attn_mma<<<dim3(SS / 64, BB * HH), 128, AT_SMEM>>>(v_mask);

    gemm_out<<<dim3(DD / 128, MM / 128), 256, GEMM_SMEM>>>(bo, q_mask, out);
}

// round 16
// speedup vs baseline: 4.5283x; 1.4075x over previous
#include <cuda_runtime.h>
#include <cuda_fp16.h>
#include <cstdint>

// Problem constants
#define BB 4
#define SS 2048
#define DD 1024
#define HH 16
#define MM (BB*SS)          // 8192 rows

// Q pre-scale: 1/sqrt(64) * log2(e)  (softmax done in base-2)
#define QSCALE 0.18033688011112042f

// Scratch (device globals). fp16 interchange: A-side split (hi+lo),
// B-side truncated (hi only).
__device__ __half g_Aqhi[MM * DD];
__device__ __half g_Aqlo[MM * DD];
__device__ __half g_Akhi[MM * DD];
__device__ __half g_Aklo[MM * DD];
__device__ __half g_Avhi[MM * DD];
__device__ __half g_Avlo[MM * DD];
__device__ __half g_Wqh[DD * DD];   // transposed weights [N,K], hi only
__device__ __half g_Wkh[DD * DD];
__device__ __half g_Wvh[DD * DD];
__device__ __half g_Woh[DD * DD];
__device__ __half g_Qhi[MM * DD];   // [row][h*64+d], pre-scaled, split
__device__ __half g_Qlo[MM * DD];
__device__ __half g_Kh[MM * DD];    // hi only (B-side of QK^T)
__device__ __half g_Vth[MM * DD];   // transposed [(b*16+h)*64+d][S], hi only
__device__ __half g_Ohi[MM * DD];   // attention output, split (A-side of out)
__device__ __half g_Olo[MM * DD];

// ---------------------------------------------------------------------------
// Helpers
// ---------------------------------------------------------------------------
__device__ __forceinline__ uint32_t smem_u32(const void* p) {
    uint32_t a;
    asm("{ .reg .u64 t; cvta.to.shared.u64 t, %1; cvt.u32.u64 %0, t; }"
        : "=r"(a) : "l"(p));
    return a;
}

__device__ __forceinline__ void ldsm4(uint32_t* r, uint32_t addr) {
    asm volatile("ldmatrix.sync.aligned.m8n8.x4.shared.b16 {%0,%1,%2,%3}, [%4];"
        : "=r"(r[0]), "=r"(r[1]), "=r"(r[2]), "=r"(r[3]) : "r"(addr));
}

__device__ __forceinline__ void mma16816(float* c, const uint32_t* a,
                                         const uint32_t* b) {
    asm volatile(
        "mma.sync.aligned.m16n8k16.row.col.f32.f16.f16.f32 "
        "{%0,%1,%2,%3}, {%4,%5,%6,%7}, {%8,%9}, {%0,%1,%2,%3};"
        : "+f"(c[0]), "+f"(c[1]), "+f"(c[2]), "+f"(c[3])
        : "r"(a[0]), "r"(a[1]), "r"(a[2]), "r"(a[3]), "r"(b[0]), "r"(b[1]));
}

__device__ __forceinline__ void cp16(uint32_t saddr, const void* g) {
    asm volatile("cp.async.cg.shared.global [%0], [%1], 16;"
                 :: "r"(saddr), "l"(g) : "memory");
}
#define CP_COMMIT() asm volatile("cp.async.commit_group;" ::: "memory")
#define CP_WAIT0()  asm volatile("cp.async.wait_group 0;" ::: "memory")

// Swizzles: SW128 for 128B rows (attention), SW64 for 64B rows (GEMM)
#define SWZ(o)   ((o) ^ (((o) >> 3) & 0x70))
#define SWZ64(o) ((o) ^ (((o) >> 3) & 0x30))

// fp16 split: h = rn(v), l = rn(v - h); h+l accurate to ~2^-22
__device__ __forceinline__ void split_h(float v, uint16_t& h, uint16_t& l) {
    __half hb = __float2half_rn(v);
    __half lb = __float2half_rn(v - __half2float(hb));
    h = *(uint16_t*)&hb; l = *(uint16_t*)&lb;
}

// split+pack 2 floats -> packed hi f16x2 + lo f16x2
__device__ __forceinline__ void split_pack2h(float a, float b,
                                             uint32_t& hi2, uint32_t& lo2) {
    __half2 h = __floats2half2_rn(a, b);
    float2 hf = __half22float2(h);
    __half2 l = __floats2half2_rn(a - hf.x, b - hf.y);
    hi2 = *(uint32_t*)&h; lo2 = *(uint32_t*)&l;
}

__device__ __forceinline__ float ex2f(float x) {
    float y;
    asm("ex2.approx.f32 %0, %1;" : "=f"(y) : "f"(x));
    return y;
}

// ---------------------------------------------------------------------------
// Fused split of q,k,v inputs (A-side, hi+lo)
// ---------------------------------------------------------------------------
__global__ __launch_bounds__(256)
void split3_kernel(const float* __restrict__ x0, const float* __restrict__ x1,
                   const float* __restrict__ x2, int n4)
{
    int i = blockIdx.x * blockDim.x + threadIdx.x;
    if (i >= n4) return;
    const float* x;
    __half *hi, *lo;
    if (blockIdx.y == 0)      { x = x0; hi = g_Aqhi; lo = g_Aqlo; }
    else if (blockIdx.y == 1) { x = x1; hi = g_Akhi; lo = g_Aklo; }
    else                      { x = x2; hi = g_Avhi; lo = g_Avlo; }
    float4 v = ((const float4*)x)[i];
    uint32_t h0, l0, h1, l1;
    split_pack2h(v.x, v.y, h0, l0);
    split_pack2h(v.z, v.w, h1, l1);
    *(uint2*)(hi + (size_t)i * 4) = make_uint2(h0, h1);
    *(uint2*)(lo + (size_t)i * 4) = make_uint2(l0, l1);
}

// Fused W[K,N] fp32 -> Wh [N,K] fp16 (transposed, hi only), all 4 weights
__global__ __launch_bounds__(256)
void wsplit4_kernel(const float* __restrict__ W0, const float* __restrict__ W1,
                    const float* __restrict__ W2, const float* __restrict__ W3)
{
    __shared__ float t[32][33];
    const float* W;
    __half* hi;
    if (blockIdx.z == 0)      { W = W0; hi = g_Wqh; }
    else if (blockIdx.z == 1) { W = W1; hi = g_Wkh; }
    else if (blockIdx.z == 2) { W = W2; hi = g_Wvh; }
    else                      { W = W3; hi = g_Woh; }
    int tx = threadIdx.x & 31;
    int ty = threadIdx.x >> 5;
    int n0 = blockIdx.x * 32;
    int k0 = blockIdx.y * 32;
#pragma unroll
    for (int i = 0; i < 4; i++)
        t[ty + 8 * i][tx] = W[(size_t)(k0 + ty + 8 * i) * DD + n0 + tx];
    __syncthreads();
#pragma unroll
    for (int i = 0; i < 4; i++) {
        int n = ty + 8 * i;
        hi[(size_t)(n0 + n) * DD + k0 + tx] = __float2half_rn(t[tx][n]);
    }
}

// ---------------------------------------------------------------------------
// GEMM: CTA 128x128, warp tile 32x64, BK=32, 2-stage, 2 CTAs/SM.
// A split (hi+lo), B hi only: 2 MMA terms. Stage = 24KB.
// ---------------------------------------------------------------------------
#define BK 32
#define GA_H 0
#define GA_L 8192
#define GB_H 16384
#define G_STAGE 24576
#define GEMM_SMEM (2 * G_STAGE)   // 49152
#define NK (DD / BK)              // 32

#define GEMM_LOAD_STAGE(Ahi_, Alo_, Bh_, it, s)                                \
    do {                                                                       \
        const int kc_ = (it) * BK;                                             \
        const uint32_t stb_ = sbase + (s) * G_STAGE;                           \
        _Pragma("unroll")                                                      \
        for (int i_ = 0; i_ < 4; i_++) {                                       \
            int u_ = tid + i_ * 256;          /* 0..1023 */                    \
            int half_ = u_ >> 9;                                               \
            int rem_ = u_ & 511;                                               \
            int r_ = rem_ >> 2, c_ = rem_ & 3;                                 \
            const char* src_ = half_ ? (const char*)(Alo_) : (const char*)(Ahi_);\
            cp16(stb_ + (half_ ? GA_L : GA_H) + SWZ64((uint32_t)(r_ * 64 + c_ * 16)),\
                 src_ + ((size_t)(m0 + r_) * DD + kc_) * 2 + c_ * 16);         \
        }                                                                      \
        _Pragma("unroll")                                                      \
        for (int i_ = 0; i_ < 2; i_++) {                                       \
            int u_ = tid + i_ * 256;          /* 0..511 */                     \
            int r_ = u_ >> 2, c_ = u_ & 3;                                     \
            cp16(stb_ + GB_H + SWZ64((uint32_t)(r_ * 64 + c_ * 16)),           \
                 (const char*)(Bh_) + ((size_t)(n0 + r_) * DD + kc_) * 2 + c_ * 16);\
        }                                                                      \
    } while (0)

#define GEMM_MAINLOOP(Ahi_, Alo_, Bh_)                                         \
    GEMM_LOAD_STAGE(Ahi_, Alo_, Bh_, 0, 0);                                    \
    CP_COMMIT(); CP_WAIT0(); __syncthreads();                                  \
    for (int it = 0; it < NK; it++) {                                          \
        if (it + 1 < NK) {                                                     \
            GEMM_LOAD_STAGE(Ahi_, Alo_, Bh_, it + 1, (it + 1) & 1);            \
            CP_COMMIT();                                                       \
        }                                                                      \
        const uint32_t stb = sbase + (it & 1) * G_STAGE;                       \
        _Pragma("unroll")                                                      \
        for (int ks = 0; ks < 2; ks++) {                                       \
            uint32_t ah[2][4], al[2][4];                                       \
            _Pragma("unroll")                                                  \
            for (int mt = 0; mt < 2; mt++) {                                   \
                uint32_t off = (uint32_t)((a_row + mt * 16) * 64) +            \
                               (uint32_t)(ks * 32) + a_bc;                     \
                ldsm4(ah[mt], stb + GA_H + SWZ64(off));                        \
                ldsm4(al[mt], stb + GA_L + SWZ64(off));                        \
            }                                                                  \
            _Pragma("unroll")                                                  \
            for (int np = 0; np < 4; np++) {                                   \
                uint32_t bh[4];                                                \
                uint32_t off = (uint32_t)((b_row + np * 16) * 64) +            \
                               (uint32_t)(ks * 32) + b_bc;                     \
                ldsm4(bh, stb + GB_H + SWZ64(off));                            \
                _Pragma("unroll")                                              \
                for (int mt = 0; mt < 2; mt++) {                               \
                    mma16816(acc[mt][np * 2 + 0], ah[mt], bh);                 \
                    mma16816(acc[mt][np * 2 + 1], ah[mt], bh + 2);             \
                }                                                              \
                _Pragma("unroll")                                              \
                for (int mt = 0; mt < 2; mt++) {                               \
                    mma16816(acc[mt][np * 2 + 0], al[mt], bh);                 \
                    mma16816(acc[mt][np * 2 + 1], al[mt], bh + 2);             \
                }                                                              \
            }                                                                  \
        }                                                                      \
        CP_WAIT0();                                                            \
        __syncthreads();                                                       \
    }

// ---------------------------------------------------------------------------
// Merged Q/K/V projection GEMM (z: 0=Q split+prescale, 1=K hi, 2=V trans hi).
// ---------------------------------------------------------------------------
__global__ __launch_bounds__(256, 2)
void gemm_qkv(const float* __restrict__ bq, const float* __restrict__ bk,
              const float* __restrict__ bv)
{
    extern __shared__ char smc[];
    const uint32_t sbase = smem_u32(smc);

    const int tid  = threadIdx.x;
    const int lane = tid & 31;
    const int wid  = tid >> 5;
    const int wm   = wid & 3;
    const int wn   = wid >> 2;
    const int m0 = blockIdx.y * 128;
    const int n0 = blockIdx.x * 128;
    const int z  = blockIdx.z;

    const __half* Ahi = (z == 0) ? g_Aqhi : (z == 1) ? g_Akhi : g_Avhi;
    const __half* Alo = (z == 0) ? g_Aqlo : (z == 1) ? g_Aklo : g_Avlo;
    const __half* Bh  = (z == 0) ? g_Wqh  : (z == 1) ? g_Wkh  : g_Wvh;
    const float* bias = (z == 0) ? bq : (z == 1) ? bk : bv;

    float acc[2][8][4];
#pragma unroll
    for (int mt = 0; mt < 2; mt++)
#pragma unroll
        for (int nt = 0; nt < 8; nt++)
#pragma unroll
            for (int e = 0; e < 4; e++) acc[mt][nt][e] = 0.0f;

    const int a_row = wm * 32 + (lane & 15);
    const uint32_t a_bc = (uint32_t)((lane >> 4) << 4);
    const int b_row = wn * 64 + ((lane & 16) >> 1) + (lane & 7);
    const uint32_t b_bc = (uint32_t)((lane & 8) << 1);

    GEMM_MAINLOOP(Ahi, Alo, Bh);

    if (z == 2) {
        // V: transposed hi-only epilogue via two 64-column SMEM passes
        float* tb = (float*)smc;
#pragma unroll
        for (int pass = 0; pass < 2; pass++) {
            if (wn == pass) {
#pragma unroll
                for (int nt = 0; nt < 8; nt++) {
                    const int cl = ((lane & 3) << 1) + nt * 8;
                    const float b0 = bias[n0 + pass * 64 + cl];
                    const float b1 = bias[n0 + pass * 64 + cl + 1];
#pragma unroll
                    for (int mt = 0; mt < 2; mt++) {
                        int rl = wm * 32 + (lane >> 2) + mt * 16;
                        tb[cl * 132 + rl]           = acc[mt][nt][0] + b0;
                        tb[(cl + 1) * 132 + rl]     = acc[mt][nt][1] + b1;
                        tb[cl * 132 + rl + 8]       = acc[mt][nt][2] + b0;
                        tb[(cl + 1) * 132 + rl + 8] = acc[mt][nt][3] + b1;
                    }
                }
            }
            __syncthreads();
            const int cl = tid >> 2;
            const int qh4 = tid & 3;
            const float* src = tb + cl * 132 + qh4 * 32;
            const int col = n0 + pass * 64 + cl;
            const size_t base = ((size_t)(m0 >> 11) * 1024 + col) * SS +
                                (m0 & 2047) + qh4 * 32;
#pragma unroll
            for (int u = 0; u < 2; u++) {
                uint32_t hb[8];
#pragma unroll
                for (int i = 0; i < 8; i++) {
                    __half2 hp = __floats2half2_rn(src[u * 16 + 2 * i],
                                                   src[u * 16 + 2 * i + 1]);
                    hb[i] = *(uint32_t*)&hp;
                }
                *(uint4*)&g_Vth[base + u * 16] =
                    make_uint4(hb[0], hb[1], hb[2], hb[3]);
                *(uint4*)&g_Vth[base + u * 16 + 8] =
                    make_uint4(hb[4], hb[5], hb[6], hb[7]);
            }
            __syncthreads();
        }
        return;
    }

    const float sc = (z == 0) ? QSCALE : 1.0f;
    const int col_base = n0 + wn * 64 + ((lane & 3) << 1);
    const int row_base = m0 + wm * 32 + (lane >> 2);
#pragma unroll
    for (int nt = 0; nt < 8; nt++) {
        const int col = col_base + nt * 8;
        const float b0 = bias[col];
        const float b1 = bias[col + 1];
#pragma unroll
        for (int mt = 0; mt < 2; mt++) {
            int r0 = row_base + mt * 16;
            float v0 = (acc[mt][nt][0] + b0) * sc;
            float v1 = (acc[mt][nt][1] + b1) * sc;
            float v2 = (acc[mt][nt][2] + b0) * sc;
            float v3 = (acc[mt][nt][3] + b1) * sc;
            if (z == 0) {
                uint32_t h0, l0, h1, l1;
                split_pack2h(v0, v1, h0, l0);
                split_pack2h(v2, v3, h1, l1);
                *(uint32_t*)&g_Qhi[(size_t)r0 * DD + col] = h0;
                *(uint32_t*)&g_Qlo[(size_t)r0 * DD + col] = l0;
                *(uint32_t*)&g_Qhi[(size_t)(r0 + 8) * DD + col] = h1;
                *(uint32_t*)&g_Qlo[(size_t)(r0 + 8) * DD + col] = l1;
            } else {
                __half2 p0 = __floats2half2_rn(v0, v1);
                __half2 p1 = __floats2half2_rn(v2, v3);
                *(uint32_t*)&g_Kh[(size_t)r0 * DD + col] = *(uint32_t*)&p0;
                *(uint32_t*)&g_Kh[(size_t)(r0 + 8) * DD + col] = *(uint32_t*)&p1;
            }
        }
    }
}

// ---------------------------------------------------------------------------
// Output projection GEMM: A = O split, B = Woh; fp32 out + qmask.
// ---------------------------------------------------------------------------
__global__ __launch_bounds__(256, 2)
void gemm_out(const float* __restrict__ bias, const int* __restrict__ qmask,
              float* __restrict__ C)
{
    extern __shared__ char smc[];
    const uint32_t sbase = smem_u32(smc);

    const int tid  = threadIdx.x;
    const int lane = tid & 31;
    const int wid  = tid >> 5;
    const int wm   = wid & 3;
    const int wn   = wid >> 2;
    const int m0 = blockIdx.y * 128;
    const int n0 = blockIdx.x * 128;

    float acc[2][8][4];
#pragma unroll
    for (int mt = 0; mt < 2; mt++)
#pragma unroll
        for (int nt = 0; nt < 8; nt++)
#pragma unroll
            for (int e = 0; e < 4; e++) acc[mt][nt][e] = 0.0f;

    const int a_row = wm * 32 + (lane & 15);
    const uint32_t a_bc = (uint32_t)((lane >> 4) << 4);
    const int b_row = wn * 64 + ((lane & 16) >> 1) + (lane & 7);
    const uint32_t b_bc = (uint32_t)((lane & 8) << 1);

    GEMM_MAINLOOP(g_Ohi, g_Olo, g_Woh);

    const int col_base = n0 + wn * 64 + ((lane & 3) << 1);
    const int row_base = m0 + wm * 32 + (lane >> 2);
#pragma unroll
    for (int nt = 0; nt < 8; nt++) {
        const int col = col_base + nt * 8;
        const float b0 = bias[col];
        const float b1 = bias[col + 1];
#pragma unroll
        for (int mt = 0; mt < 2; mt++) {
            int r0 = row_base + mt * 16;
            float qm0 = (float)qmask[r0];
            float qm1 = (float)qmask[r0 + 8];
            *(float2*)&C[(size_t)r0 * DD + col] =
                make_float2((acc[mt][nt][0] + b0) * qm0,
                            (acc[mt][nt][1] + b1) * qm0);
            *(float2*)&C[(size_t)(r0 + 8) * DD + col] =
                make_float2((acc[mt][nt][2] + b0) * qm1,
                            (acc[mt][nt][3] + b1) * qm1);
        }
    }
}

// ---------------------------------------------------------------------------
// Tensor-core flash attention (fp16 2-term): Q split in registers, K/V hi
// only. 128 threads, q-tile 64, key-block 64, 3 CTAs/SM, Q overlaid stage1.
// ---------------------------------------------------------------------------
#define AQ_H 0
#define AQ_L 8192
#define SK_H 0
#define SV_H 8192
#define SVM  17408
#define STG_SZ 17664
#define STG1_BASE 0
#define STG0_BASE STG_SZ
#define AT_SMEM (2 * STG_SZ)   // 35328
#define VT_ROW 144

__global__ __launch_bounds__(128, 3)
void attn_mma(const int* __restrict__ v_mask)
{
    extern __shared__ char smc[];
    const uint32_t sb = smem_u32(smc);

    const int tid  = threadIdx.x;
    const int lane = tid & 31;
    const int w    = tid >> 5;
    const int bh = blockIdx.y;
    const int b  = bh >> 4;
    const int h  = bh & 15;
    const int qt = gridDim.x - 1 - blockIdx.x;
    const int q0 = qt * 64;

    // Q tile (64x64 fp16 hi+lo = 16KB) into the future stage-1 region
#pragma unroll
    for (int t = 0; t < 8; t++) {
        int idx = tid + t * 128;
        const char* src = (idx < 512) ? (const char*)g_Qhi : (const char*)g_Qlo;
        uint32_t dst = sb + ((idx < 512) ? AQ_H : AQ_L);
        int r = (idx >> 3) & 63;
        int c = idx & 7;
        const void* g = src + ((size_t)(b * SS + q0 + r) * DD + h * 64) * 2 + c * 16;
        cp16(dst + SWZ((uint32_t)(r * 128 + c * 16)), g);
    }

    auto load_stage = [&](int kt, int s) {
        const uint32_t stg = sb + (s ? STG1_BASE : STG0_BASE);
        // K hi (64x64 = 8KB)
#pragma unroll
        for (int t = 0; t < 4; t++) {
            int idx = tid + t * 128;         // 0..511
            int r = idx >> 3;
            int c = idx & 7;
            const void* g = (const char*)g_Kh +
                ((size_t)(b * SS + kt * 64 + r) * DD + h * 64) * 2 + c * 16;
            cp16(stg + SK_H + SWZ((uint32_t)(r * 128 + c * 16)), g);
        }
        // V hi transposed (64 d x 64 j, 144B rows)
#pragma unroll
        for (int t = 0; t < 4; t++) {
            int idx = tid + t * 128;
            int d = idx >> 3;
            int c = idx & 7;
            const void* g = (const char*)g_Vth +
                (((size_t)(b * 16 + h) * 64 + d) * SS + kt * 64) * 2 + c * 16;
            cp16(stg + SV_H + (uint32_t)(d * VT_ROW + c * 16), g);
        }
        if (tid < 64) {
            ((float*)(smc + (s ? STG1_BASE : STG0_BASE) + SVM))[tid] =
                v_mask[b * SS + kt * 64 + tid] ? 0.0f : -1e12f;
        }
    };

    load_stage(0, 0);
    CP_COMMIT();
    CP_WAIT0();
    __syncthreads();

    const int a_row = w * 16 + (lane & 15);
    const uint32_t a_bc = (uint32_t)((lane >> 4) << 4);
    const int b_rp  = ((lane & 16) >> 1) + (lane & 7);
    const uint32_t b_bc = (uint32_t)((lane & 8) << 1);

    uint32_t qh[4][4], ql[4][4];
#pragma unroll
    for (int ks = 0; ks < 4; ks++) {
        uint32_t off = SWZ((uint32_t)(a_row * 128 + ks * 32) + a_bc);
        ldsm4(qh[ks], sb + AQ_H + off);
        ldsm4(ql[ks], sb + AQ_L + off);
    }
    __syncthreads();   // Q consumed before stage1 overwrites it

    float o[8][4];
#pragma unroll
    for (int nt = 0; nt < 8; nt++)
#pragma unroll
        for (int e = 0; e < 4; e++) o[nt][e] = 0.0f;
    float m_lo = -1e30f, m_hi = -1e30f, l_lo = 0.0f, l_hi = 0.0f;

    const int r = lane >> 2;
    const int qi_lo = q0 + w * 16 + r;
    const int qi_hi = qi_lo + 8;
    const int jc = (lane & 3) * 2;

    const int nkt = qt + 1;
    for (int kt = 0; kt < nkt; kt++) {
        if (kt + 1 < nkt) { load_stage(kt + 1, (kt + 1) & 1); CP_COMMIT(); }

        const uint32_t stg = sb + ((kt & 1) ? STG1_BASE : STG0_BASE);

        // ---- S = Q K^T, 2-term (Qh+Ql)·Kh ----
        float s[8][4];
#pragma unroll
        for (int nt = 0; nt < 8; nt++)
#pragma unroll
            for (int e = 0; e < 4; e++) s[nt][e] = 0.0f;

#pragma unroll
        for (int ks = 0; ks < 4; ks++) {
#pragma unroll
            for (int npp = 0; npp < 2; npp++) {
                const int np0 = npp * 2, np1 = npp * 2 + 1;
                uint32_t kh0[4], kh1[4];
                ldsm4(kh0, stg + SK_H +
                      SWZ((uint32_t)((np0 * 16 + b_rp) * 128 + ks * 32) + b_bc));
                ldsm4(kh1, stg + SK_H +
                      SWZ((uint32_t)((np1 * 16 + b_rp) * 128 + ks * 32) + b_bc));
                float* s0 = s[npp * 4 + 0];
                float* s1 = s[npp * 4 + 1];
                float* s2 = s[npp * 4 + 2];
                float* s3 = s[npp * 4 + 3];
                mma16816(s0, qh[ks], kh0); mma16816(s1, qh[ks], kh0 + 2);
                mma16816(s2, qh[ks], kh1); mma16816(s3, qh[ks], kh1 + 2);
                mma16816(s0, ql[ks], kh0); mma16816(s1, ql[ks], kh0 + 2);
                mma16816(s2, ql[ks], kh1); mma16816(s3, ql[ks], kh1 + 2);
            }
        }

        // ---- mask + online softmax (base-2) ----
        const bool diag = (kt == qt);
        const float* mvm = (const float*)(smc + ((kt & 1) ? STG1_BASE : STG0_BASE) + SVM);
        float mx_lo = -1e30f, mx_hi = -1e30f;
#pragma unroll
        for (int nt = 0; nt < 8; nt++) {
            int jl = nt * 8 + jc;
            int jg = kt * 64 + jl;
            float2 av = *(const float2*)&mvm[jl];
            float v0 = s[nt][0] + av.x;
            float v1 = s[nt][1] + av.y;
            float v2 = s[nt][2] + av.x;
            float v3 = s[nt][3] + av.y;
            if (diag) {
                if (jg     > qi_lo) v0 = -1e12f;
                if (jg + 1 > qi_lo) v1 = -1e12f;
                if (jg     > qi_hi) v2 = -1e12f;
                if (jg + 1 > qi_hi) v3 = -1e12f;
            }
            s[nt][0] = v0; s[nt][1] = v1; s[nt][2] = v2; s[nt][3] = v3;
            mx_lo = fmaxf(mx_lo, fmaxf(v0, v1));
            mx_hi = fmaxf(mx_hi, fmaxf(v2, v3));
        }
        mx_lo = fmaxf(mx_lo, __shfl_xor_sync(0xffffffffu, mx_lo, 1));
        mx_lo = fmaxf(mx_lo, __shfl_xor_sync(0xffffffffu, mx_lo, 2));
        mx_hi = fmaxf(mx_hi, __shfl_xor_sync(0xffffffffu, mx_hi, 1));
        mx_hi = fmaxf(mx_hi, __shfl_xor_sync(0xffffffffu, mx_hi, 2));

        float mn_lo = fmaxf(m_lo, mx_lo);
        float mn_hi = fmaxf(m_hi, mx_hi);
        float corr_lo = ex2f(m_lo - mn_lo);
        float corr_hi = ex2f(m_hi - mn_hi);
        m_lo = mn_lo; m_hi = mn_hi;

        float sum_lo = 0.0f, sum_hi = 0.0f;
#pragma unroll
        for (int nt = 0; nt < 8; nt++) {
            float p0 = ex2f(s[nt][0] - mn_lo);
            float p1 = ex2f(s[nt][1] - mn_lo);
            float p2 = ex2f(s[nt][2] - mn_hi);
            float p3 = ex2f(s[nt][3] - mn_hi);
            s[nt][0] = p0; s[nt][1] = p1; s[nt][2] = p2; s[nt][3] = p3;
            sum_lo += p0 + p1;
            sum_hi += p2 + p3;
        }
        sum_lo += __shfl_xor_sync(0xffffffffu, sum_lo, 1);
        sum_lo += __shfl_xor_sync(0xffffffffu, sum_lo, 2);
        sum_hi += __shfl_xor_sync(0xffffffffu, sum_hi, 1);
        sum_hi += __shfl_xor_sync(0xffffffffu, sum_hi, 2);
        l_lo = l_lo * corr_lo + sum_lo;
        l_hi = l_hi * corr_hi + sum_hi;

#pragma unroll
        for (int nt = 0; nt < 8; nt++) {
            o[nt][0] *= corr_lo; o[nt][1] *= corr_lo;
            o[nt][2] *= corr_hi; o[nt][3] *= corr_hi;
        }

        // ---- O += P V, 2-term (Ph+Pl)·Vh ----
#pragma unroll
        for (int ks = 0; ks < 4; ks++) {
            uint32_t ah[4], al[4];
            split_pack2h(s[2*ks][0],   s[2*ks][1],   ah[0], al[0]);
            split_pack2h(s[2*ks][2],   s[2*ks][3],   ah[1], al[1]);
            split_pack2h(s[2*ks+1][0], s[2*ks+1][1], ah[2], al[2]);
            split_pack2h(s[2*ks+1][2], s[2*ks+1][3], ah[3], al[3]);
#pragma unroll
            for (int npp = 0; npp < 2; npp++) {
                const int np0 = npp * 2, np1 = npp * 2 + 1;
                uint32_t bh0[4], bh1[4];
                ldsm4(bh0, stg + SV_H +
                      (uint32_t)((np0 * 16 + b_rp) * VT_ROW + ks * 32) + b_bc);
                ldsm4(bh1, stg + SV_H +
                      (uint32_t)((np1 * 16 + b_rp) * VT_ROW + ks * 32) + b_bc);
                float* o0 = o[np0 * 2 + 0];
                float* o1 = o[np0 * 2 + 1];
                float* o2 = o[np1 * 2 + 0];
                float* o3 = o[np1 * 2 + 1];
                mma16816(o0, ah, bh0); mma16816(o1, ah, bh0 + 2);
                mma16816(o2, ah, bh1); mma16816(o3, ah, bh1 + 2);
                mma16816(o0, al, bh0); mma16816(o1, al, bh0 + 2);
                mma16816(o2, al, bh1); mma16816(o3, al, bh1 + 2);
            }
        }

        CP_WAIT0();
        __syncthreads();
    }

    // ---- normalize + split + store to g_Ohi/g_Olo ----
    float inv_lo = 1.0f / l_lo;
    float inv_hi = 1.0f / l_hi;
    const size_t row_lo = (size_t)(b * SS + q0 + w * 16 + r) * DD + h * 64;
    const size_t row_hi = row_lo + 8 * DD;
#pragma unroll
    for (int nt = 0; nt < 8; nt++) {
        int d0 = nt * 8 + jc;
        uint32_t hp, lp;
        split_pack2h(o[nt][0] * inv_lo, o[nt][1] * inv_lo, hp, lp);
        *(uint32_t*)&g_Ohi[row_lo + d0] = hp;
        *(uint32_t*)&g_Olo[row_lo + d0] = lp;
        split_pack2h(o[nt][2] * inv_hi, o[nt][3] * inv_hi, hp, lp);
        *(uint32_t*)&g_Ohi[row_hi + d0] = hp;
        *(uint32_t*)&g_Olo[row_hi + d0] = lp;
    }
}

// ---------------------------------------------------------------------------
// kernel_launch
// ---------------------------------------------------------------------------
extern "C" void kernel_launch(void* const* d_in, const int* in_sizes, int n_in,
                              void* d_out, int out_size)
{
    const float* q      = (const float*)d_in[0];
    const float* k      = (const float*)d_in[1];
    const float* v      = (const float*)d_in[2];
    const int*   q_mask = (const int*)  d_in[3];
    const int*   v_mask = (const int*)  d_in[4];
    const float* Wq     = (const float*)d_in[5];
    const float* bq     = (const float*)d_in[6];
    const float* Wk     = (const float*)d_in[7];
    const float* bk     = (const float*)d_in[8];
    const float* Wv     = (const float*)d_in[9];
    const float* bv     = (const float*)d_in[10];
    const float* Wo     = (const float*)d_in[11];
    const float* bo     = (const float*)d_in[12];
    float* out = (float*)d_out;

    cudaFuncSetAttribute(gemm_qkv,
                         cudaFuncAttributeMaxDynamicSharedMemorySize, GEMM_SMEM);
    cudaFuncSetAttribute(gemm_out,
                         cudaFuncAttributeMaxDynamicSharedMemorySize, GEMM_SMEM);
    cudaFuncSetAttribute(attn_mma,
                         cudaFuncAttributeMaxDynamicSharedMemorySize, AT_SMEM);

    const int n4 = MM * DD / 4;

    split3_kernel<<<dim3((n4 + 255) / 256, 3), 256>>>(q, k, v, n4);
    wsplit4_kernel<<<dim3(DD / 32, DD / 32, 4), 256>>>(Wq, Wk, Wv, Wo);

    gemm_qkv<<<dim3(DD / 128, MM / 128, 3), 256, GEMM_SMEM>>>(bq, bk, bv);

    attn_mma<<<dim3(SS / 64, BB * HH), 128, AT_SMEM>>>(v_mask);

    gemm_out<<<dim3(DD / 128, MM / 128), 256, GEMM_SMEM>>>(bo, q_mask, out);
}

// round 17
// speedup vs baseline: 4.5881x; 1.0132x over previous
#include <cuda_runtime.h>
#include <cuda_fp16.h>
#include <cstdint>

// Problem constants
#define BB 4
#define SS 2048
#define DD 1024
#define HH 16
#define MM (BB*SS)          // 8192 rows

// Q pre-scale: 1/sqrt(64) * log2(e)  (softmax done in base-2)
#define QSCALE 0.18033688011112042f

// Scratch (device globals). fp16 interchange: A-side split (hi+lo),
// B-side truncated (hi only).
__device__ __half g_Aqhi[MM * DD];
__device__ __half g_Aqlo[MM * DD];
__device__ __half g_Akhi[MM * DD];
__device__ __half g_Aklo[MM * DD];
__device__ __half g_Avhi[MM * DD];
__device__ __half g_Avlo[MM * DD];
__device__ __half g_Wqh[DD * DD];   // transposed weights [N,K], hi only
__device__ __half g_Wkh[DD * DD];
__device__ __half g_Wvh[DD * DD];
__device__ __half g_Woh[DD * DD];
__device__ __half g_Qhi[MM * DD];   // [row][h*64+d], pre-scaled, split
__device__ __half g_Qlo[MM * DD];
__device__ __half g_Kh[MM * DD];    // hi only (B-side of QK^T)
__device__ __half g_Vth[MM * DD];   // transposed [(b*16+h)*64+d][S], hi only
__device__ __half g_Ohi[MM * DD];   // attention output, split (A-side of out)
__device__ __half g_Olo[MM * DD];

// ---------------------------------------------------------------------------
// Helpers
// ---------------------------------------------------------------------------
__device__ __forceinline__ uint32_t smem_u32(const void* p) {
    uint32_t a;
    asm("{ .reg .u64 t; cvta.to.shared.u64 t, %1; cvt.u32.u64 %0, t; }"
        : "=r"(a) : "l"(p));
    return a;
}

__device__ __forceinline__ void ldsm4(uint32_t* r, uint32_t addr) {
    asm volatile("ldmatrix.sync.aligned.m8n8.x4.shared.b16 {%0,%1,%2,%3}, [%4];"
        : "=r"(r[0]), "=r"(r[1]), "=r"(r[2]), "=r"(r[3]) : "r"(addr));
}

__device__ __forceinline__ void mma16816(float* c, const uint32_t* a,
                                         const uint32_t* b) {
    asm volatile(
        "mma.sync.aligned.m16n8k16.row.col.f32.f16.f16.f32 "
        "{%0,%1,%2,%3}, {%4,%5,%6,%7}, {%8,%9}, {%0,%1,%2,%3};"
        : "+f"(c[0]), "+f"(c[1]), "+f"(c[2]), "+f"(c[3])
        : "r"(a[0]), "r"(a[1]), "r"(a[2]), "r"(a[3]), "r"(b[0]), "r"(b[1]));
}

__device__ __forceinline__ void cp16(uint32_t saddr, const void* g) {
    asm volatile("cp.async.cg.shared.global [%0], [%1], 16;"
                 :: "r"(saddr), "l"(g) : "memory");
}
#define CP_COMMIT() asm volatile("cp.async.commit_group;" ::: "memory")
#define CP_WAIT0()  asm volatile("cp.async.wait_group 0;" ::: "memory")

// Swizzles: SW128 for 128B rows (attention, GEMM)
#define SWZ(o)   ((o) ^ (((o) >> 3) & 0x70))

// split+pack 2 floats -> packed hi f16x2 + lo f16x2
__device__ __forceinline__ void split_pack2h(float a, float b,
                                             uint32_t& hi2, uint32_t& lo2) {
    __half2 h = __floats2half2_rn(a, b);
    float2 hf = __half22float2(h);
    __half2 l = __floats2half2_rn(a - hf.x, b - hf.y);
    hi2 = *(uint32_t*)&h; lo2 = *(uint32_t*)&l;
}

__device__ __forceinline__ float ex2f(float x) {
    float y;
    asm("ex2.approx.f32 %0, %1;" : "=f"(y) : "f"(x));
    return y;
}

// ---------------------------------------------------------------------------
// Fused split of q,k,v inputs (A-side, hi+lo)
// ---------------------------------------------------------------------------
__global__ __launch_bounds__(256)
void split3_kernel(const float* __restrict__ x0, const float* __restrict__ x1,
                   const float* __restrict__ x2, int n4)
{
    int i = blockIdx.x * blockDim.x + threadIdx.x;
    if (i >= n4) return;
    const float* x;
    __half *hi, *lo;
    if (blockIdx.y == 0)      { x = x0; hi = g_Aqhi; lo = g_Aqlo; }
    else if (blockIdx.y == 1) { x = x1; hi = g_Akhi; lo = g_Aklo; }
    else                      { x = x2; hi = g_Avhi; lo = g_Avlo; }
    float4 v = ((const float4*)x)[i];
    uint32_t h0, l0, h1, l1;
    split_pack2h(v.x, v.y, h0, l0);
    split_pack2h(v.z, v.w, h1, l1);
    *(uint2*)(hi + (size_t)i * 4) = make_uint2(h0, h1);
    *(uint2*)(lo + (size_t)i * 4) = make_uint2(l0, l1);
}

// Fused W[K,N] fp32 -> Wh [N,K] fp16 (transposed, hi only), all 4 weights
__global__ __launch_bounds__(256)
void wsplit4_kernel(const float* __restrict__ W0, const float* __restrict__ W1,
                    const float* __restrict__ W2, const float* __restrict__ W3)
{
    __shared__ float t[32][33];
    const float* W;
    __half* hi;
    if (blockIdx.z == 0)      { W = W0; hi = g_Wqh; }
    else if (blockIdx.z == 1) { W = W1; hi = g_Wkh; }
    else if (blockIdx.z == 2) { W = W2; hi = g_Wvh; }
    else                      { W = W3; hi = g_Woh; }
    int tx = threadIdx.x & 31;
    int ty = threadIdx.x >> 5;
    int n0 = blockIdx.x * 32;
    int k0 = blockIdx.y * 32;
#pragma unroll
    for (int i = 0; i < 4; i++)
        t[ty + 8 * i][tx] = W[(size_t)(k0 + ty + 8 * i) * DD + n0 + tx];
    __syncthreads();
#pragma unroll
    for (int i = 0; i < 4; i++) {
        int n = ty + 8 * i;
        hi[(size_t)(n0 + n) * DD + k0 + tx] = __float2half_rn(t[tx][n]);
    }
}

// ---------------------------------------------------------------------------
// GEMM: CTA 128x128, warp tile 32x64, BK=64, 2-stage, 2 CTAs/SM.
// A split (hi+lo), B hi only. Stage = 48KB (SW128, 128B rows).
// ---------------------------------------------------------------------------
#define BK 64
#define GA_H 0
#define GA_L 16384
#define GB_H 32768
#define G_STAGE 49152
#define GEMM_SMEM (2 * G_STAGE)   // 98304
#define NK (DD / BK)              // 16

#define GEMM_LOAD_STAGE(Ahi_, Alo_, Bh_, it, s)                                \
    do {                                                                       \
        const int kc_ = (it) * BK;                                             \
        const uint32_t stb_ = sbase + (s) * G_STAGE;                           \
        _Pragma("unroll")                                                      \
        for (int i_ = 0; i_ < 8; i_++) {                                       \
            int u_ = tid + i_ * 256;          /* 0..2047 */                    \
            int half_ = u_ >> 10;                                              \
            int rem_ = u_ & 1023;                                              \
            int r_ = rem_ >> 3, c_ = rem_ & 7;                                 \
            const char* src_ = half_ ? (const char*)(Alo_) : (const char*)(Ahi_);\
            cp16(stb_ + (half_ ? GA_L : GA_H) + SWZ((uint32_t)(r_ * 128 + c_ * 16)),\
                 src_ + ((size_t)(m0 + r_) * DD + kc_) * 2 + c_ * 16);         \
        }                                                                      \
        _Pragma("unroll")                                                      \
        for (int i_ = 0; i_ < 4; i_++) {                                       \
            int u_ = tid + i_ * 256;          /* 0..1023 */                    \
            int r_ = u_ >> 3, c_ = u_ & 7;                                     \
            cp16(stb_ + GB_H + SWZ((uint32_t)(r_ * 128 + c_ * 16)),            \
                 (const char*)(Bh_) + ((size_t)(n0 + r_) * DD + kc_) * 2 + c_ * 16);\
        }                                                                      \
    } while (0)

#define GEMM_MAINLOOP(Ahi_, Alo_, Bh_)                                         \
    GEMM_LOAD_STAGE(Ahi_, Alo_, Bh_, 0, 0);                                    \
    CP_COMMIT(); CP_WAIT0(); __syncthreads();                                  \
    for (int it = 0; it < NK; it++) {                                          \
        if (it + 1 < NK) {                                                     \
            GEMM_LOAD_STAGE(Ahi_, Alo_, Bh_, it + 1, (it + 1) & 1);            \
            CP_COMMIT();                                                       \
        }                                                                      \
        const uint32_t stb = sbase + (it & 1) * G_STAGE;                       \
        _Pragma("unroll")                                                      \
        for (int ks = 0; ks < 4; ks++) {                                       \
            uint32_t ah[2][4], al[2][4];                                       \
            _Pragma("unroll")                                                  \
            for (int mt = 0; mt < 2; mt++) {                                   \
                uint32_t off = (uint32_t)((a_row + mt * 16) * 128) +           \
                               (uint32_t)(ks * 32) + a_bc;                     \
                ldsm4(ah[mt], stb + GA_H + SWZ(off));                          \
                ldsm4(al[mt], stb + GA_L + SWZ(off));                          \
            }                                                                  \
            _Pragma("unroll")                                                  \
            for (int np = 0; np < 4; np++) {                                   \
                uint32_t bh[4];                                                \
                uint32_t off = (uint32_t)((b_row + np * 16) * 128) +           \
                               (uint32_t)(ks * 32) + b_bc;                     \
                ldsm4(bh, stb + GB_H + SWZ(off));                              \
                _Pragma("unroll")                                              \
                for (int mt = 0; mt < 2; mt++) {                               \
                    mma16816(acc[mt][np * 2 + 0], ah[mt], bh);                 \
                    mma16816(acc[mt][np * 2 + 1], ah[mt], bh + 2);             \
                }                                                              \
                _Pragma("unroll")                                              \
                for (int mt = 0; mt < 2; mt++) {                               \
                    mma16816(acc[mt][np * 2 + 0], al[mt], bh);                 \
                    mma16816(acc[mt][np * 2 + 1], al[mt], bh + 2);             \
                }                                                              \
            }                                                                  \
        }                                                                      \
        CP_WAIT0();                                                            \
        __syncthreads();                                                       \
    }

// ---------------------------------------------------------------------------
// Merged Q/K/V projection GEMM (z: 0=Q split+prescale, 1=K hi, 2=V trans hi).
// ---------------------------------------------------------------------------
__global__ __launch_bounds__(256, 2)
void gemm_qkv(const float* __restrict__ bq, const float* __restrict__ bk,
              const float* __restrict__ bv)
{
    extern __shared__ char smc[];
    const uint32_t sbase = smem_u32(smc);

    const int tid  = threadIdx.x;
    const int lane = tid & 31;
    const int wid  = tid >> 5;
    const int wm   = wid & 3;
    const int wn   = wid >> 2;
    const int m0 = blockIdx.y * 128;
    const int n0 = blockIdx.x * 128;
    const int z  = blockIdx.z;

    const __half* Ahi = (z == 0) ? g_Aqhi : (z == 1) ? g_Akhi : g_Avhi;
    const __half* Alo = (z == 0) ? g_Aqlo : (z == 1) ? g_Aklo : g_Avlo;
    const __half* Bh  = (z == 0) ? g_Wqh  : (z == 1) ? g_Wkh  : g_Wvh;
    const float* bias = (z == 0) ? bq : (z == 1) ? bk : bv;

    float acc[2][8][4];
#pragma unroll
    for (int mt = 0; mt < 2; mt++)
#pragma unroll
        for (int nt = 0; nt < 8; nt++)
#pragma unroll
            for (int e = 0; e < 4; e++) acc[mt][nt][e] = 0.0f;

    const int a_row = wm * 32 + (lane & 15);
    const uint32_t a_bc = (uint32_t)((lane >> 4) << 4);
    const int b_row = wn * 64 + ((lane & 16) >> 1) + (lane & 7);
    const uint32_t b_bc = (uint32_t)((lane & 8) << 1);

    GEMM_MAINLOOP(Ahi, Alo, Bh);

    if (z == 2) {
        // V: transposed hi-only epilogue via two 64-column SMEM passes
        float* tb = (float*)smc;
#pragma unroll
        for (int pass = 0; pass < 2; pass++) {
            if (wn == pass) {
#pragma unroll
                for (int nt = 0; nt < 8; nt++) {
                    const int cl = ((lane & 3) << 1) + nt * 8;
                    const float b0 = bias[n0 + pass * 64 + cl];
                    const float b1 = bias[n0 + pass * 64 + cl + 1];
#pragma unroll
                    for (int mt = 0; mt < 2; mt++) {
                        int rl = wm * 32 + (lane >> 2) + mt * 16;
                        tb[cl * 132 + rl]           = acc[mt][nt][0] + b0;
                        tb[(cl + 1) * 132 + rl]     = acc[mt][nt][1] + b1;
                        tb[cl * 132 + rl + 8]       = acc[mt][nt][2] + b0;
                        tb[(cl + 1) * 132 + rl + 8] = acc[mt][nt][3] + b1;
                    }
                }
            }
            __syncthreads();
            const int cl = tid >> 2;
            const int qh4 = tid & 3;
            const float* src = tb + cl * 132 + qh4 * 32;
            const int col = n0 + pass * 64 + cl;
            const size_t base = ((size_t)(m0 >> 11) * 1024 + col) * SS +
                                (m0 & 2047) + qh4 * 32;
#pragma unroll
            for (int u = 0; u < 2; u++) {
                uint32_t hb[8];
#pragma unroll
                for (int i = 0; i < 8; i++) {
                    __half2 hp = __floats2half2_rn(src[u * 16 + 2 * i],
                                                   src[u * 16 + 2 * i + 1]);
                    hb[i] = *(uint32_t*)&hp;
                }
                *(uint4*)&g_Vth[base + u * 16] =
                    make_uint4(hb[0], hb[1], hb[2], hb[3]);
                *(uint4*)&g_Vth[base + u * 16 + 8] =
                    make_uint4(hb[4], hb[5], hb[6], hb[7]);
            }
            __syncthreads();
        }
        return;
    }

    const float sc = (z == 0) ? QSCALE : 1.0f;
    const int col_base = n0 + wn * 64 + ((lane & 3) << 1);
    const int row_base = m0 + wm * 32 + (lane >> 2);
#pragma unroll
    for (int nt = 0; nt < 8; nt++) {
        const int col = col_base + nt * 8;
        const float b0 = bias[col];
        const float b1 = bias[col + 1];
#pragma unroll
        for (int mt = 0; mt < 2; mt++) {
            int r0 = row_base + mt * 16;
            float v0 = (acc[mt][nt][0] + b0) * sc;
            float v1 = (acc[mt][nt][1] + b1) * sc;
            float v2 = (acc[mt][nt][2] + b0) * sc;
            float v3 = (acc[mt][nt][3] + b1) * sc;
            if (z == 0) {
                uint32_t h0, l0, h1, l1;
                split_pack2h(v0, v1, h0, l0);
                split_pack2h(v2, v3, h1, l1);
                *(uint32_t*)&g_Qhi[(size_t)r0 * DD + col] = h0;
                *(uint32_t*)&g_Qlo[(size_t)r0 * DD + col] = l0;
                *(uint32_t*)&g_Qhi[(size_t)(r0 + 8) * DD + col] = h1;
                *(uint32_t*)&g_Qlo[(size_t)(r0 + 8) * DD + col] = l1;
            } else {
                __half2 p0 = __floats2half2_rn(v0, v1);
                __half2 p1 = __floats2half2_rn(v2, v3);
                *(uint32_t*)&g_Kh[(size_t)r0 * DD + col] = *(uint32_t*)&p0;
                *(uint32_t*)&g_Kh[(size_t)(r0 + 8) * DD + col] = *(uint32_t*)&p1;
            }
        }
    }
}

// ---------------------------------------------------------------------------
// Output projection GEMM: A = O split, B = Woh; fp32 out + qmask.
// ---------------------------------------------------------------------------
__global__ __launch_bounds__(256, 2)
void gemm_out(const float* __restrict__ bias, const int* __restrict__ qmask,
              float* __restrict__ C)
{
    extern __shared__ char smc[];
    const uint32_t sbase = smem_u32(smc);

    const int tid  = threadIdx.x;
    const int lane = tid & 31;
    const int wid  = tid >> 5;
    const int wm   = wid & 3;
    const int wn   = wid >> 2;
    const int m0 = blockIdx.y * 128;
    const int n0 = blockIdx.x * 128;

    float acc[2][8][4];
#pragma unroll
    for (int mt = 0; mt < 2; mt++)
#pragma unroll
        for (int nt = 0; nt < 8; nt++)
#pragma unroll
            for (int e = 0; e < 4; e++) acc[mt][nt][e] = 0.0f;

    const int a_row = wm * 32 + (lane & 15);
    const uint32_t a_bc = (uint32_t)((lane >> 4) << 4);
    const int b_row = wn * 64 + ((lane & 16) >> 1) + (lane & 7);
    const uint32_t b_bc = (uint32_t)((lane & 8) << 1);

    GEMM_MAINLOOP(g_Ohi, g_Olo, g_Woh);

    const int col_base = n0 + wn * 64 + ((lane & 3) << 1);
    const int row_base = m0 + wm * 32 + (lane >> 2);
#pragma unroll
    for (int nt = 0; nt < 8; nt++) {
        const int col = col_base + nt * 8;
        const float b0 = bias[col];
        const float b1 = bias[col + 1];
#pragma unroll
        for (int mt = 0; mt < 2; mt++) {
            int r0 = row_base + mt * 16;
            float qm0 = (float)qmask[r0];
            float qm1 = (float)qmask[r0 + 8];
            *(float2*)&C[(size_t)r0 * DD + col] =
                make_float2((acc[mt][nt][0] + b0) * qm0,
                            (acc[mt][nt][1] + b1) * qm0);
            *(float2*)&C[(size_t)(r0 + 8) * DD + col] =
                make_float2((acc[mt][nt][2] + b0) * qm1,
                            (acc[mt][nt][3] + b1) * qm1);
        }
    }
}

// ---------------------------------------------------------------------------
// Tensor-core flash attention (fp16 2-term, unchanged R16): 128 threads,
// q-tile 64, key-block 64, 3 CTAs/SM, Q overlaid on stage1.
// ---------------------------------------------------------------------------
#define AQ_H 0
#define AQ_L 8192
#define SK_H 0
#define SV_H 8192
#define SVM  17408
#define STG_SZ 17664
#define STG1_BASE 0
#define STG0_BASE STG_SZ
#define AT_SMEM (2 * STG_SZ)   // 35328
#define VT_ROW 144

__global__ __launch_bounds__(128, 3)
void attn_mma(const int* __restrict__ v_mask)
{
    extern __shared__ char smc[];
    const uint32_t sb = smem_u32(smc);

    const int tid  = threadIdx.x;
    const int lane = tid & 31;
    const int w    = tid >> 5;
    const int bh = blockIdx.y;
    const int b  = bh >> 4;
    const int h  = bh & 15;
    const int qt = gridDim.x - 1 - blockIdx.x;
    const int q0 = qt * 64;

#pragma unroll
    for (int t = 0; t < 8; t++) {
        int idx = tid + t * 128;
        const char* src = (idx < 512) ? (const char*)g_Qhi : (const char*)g_Qlo;
        uint32_t dst = sb + ((idx < 512) ? AQ_H : AQ_L);
        int r = (idx >> 3) & 63;
        int c = idx & 7;
        const void* g = src + ((size_t)(b * SS + q0 + r) * DD + h * 64) * 2 + c * 16;
        cp16(dst + SWZ((uint32_t)(r * 128 + c * 16)), g);
    }

    auto load_stage = [&](int kt, int s) {
        const uint32_t stg = sb + (s ? STG1_BASE : STG0_BASE);
#pragma unroll
        for (int t = 0; t < 4; t++) {
            int idx = tid + t * 128;
            int r = idx >> 3;
            int c = idx & 7;
            const void* g = (const char*)g_Kh +
                ((size_t)(b * SS + kt * 64 + r) * DD + h * 64) * 2 + c * 16;
            cp16(stg + SK_H + SWZ((uint32_t)(r * 128 + c * 16)), g);
        }
#pragma unroll
        for (int t = 0; t < 4; t++) {
            int idx = tid + t * 128;
            int d = idx >> 3;
            int c = idx & 7;
            const void* g = (const char*)g_Vth +
                (((size_t)(b * 16 + h) * 64 + d) * SS + kt * 64) * 2 + c * 16;
            cp16(stg + SV_H + (uint32_t)(d * VT_ROW + c * 16), g);
        }
        if (tid < 64) {
            ((float*)(smc + (s ? STG1_BASE : STG0_BASE) + SVM))[tid] =
                v_mask[b * SS + kt * 64 + tid] ? 0.0f : -1e12f;
        }
    };

    load_stage(0, 0);
    CP_COMMIT();
    CP_WAIT0();
    __syncthreads();

    const int a_row = w * 16 + (lane & 15);
    const uint32_t a_bc = (uint32_t)((lane >> 4) << 4);
    const int b_rp  = ((lane & 16) >> 1) + (lane & 7);
    const uint32_t b_bc = (uint32_t)((lane & 8) << 1);

    uint32_t qh[4][4], ql[4][4];
#pragma unroll
    for (int ks = 0; ks < 4; ks++) {
        uint32_t off = SWZ((uint32_t)(a_row * 128 + ks * 32) + a_bc);
        ldsm4(qh[ks], sb + AQ_H + off);
        ldsm4(ql[ks], sb + AQ_L + off);
    }
    __syncthreads();   // Q consumed before stage1 overwrites it

    float o[8][4];
#pragma unroll
    for (int nt = 0; nt < 8; nt++)
#pragma unroll
        for (int e = 0; e < 4; e++) o[nt][e] = 0.0f;
    float m_lo = -1e30f, m_hi = -1e30f, l_lo = 0.0f, l_hi = 0.0f;

    const int r = lane >> 2;
    const int qi_lo = q0 + w * 16 + r;
    const int qi_hi = qi_lo + 8;
    const int jc = (lane & 3) * 2;

    const int nkt = qt + 1;
    for (int kt = 0; kt < nkt; kt++) {
        if (kt + 1 < nkt) { load_stage(kt + 1, (kt + 1) & 1); CP_COMMIT(); }

        const uint32_t stg = sb + ((kt & 1) ? STG1_BASE : STG0_BASE);

        float s[8][4];
#pragma unroll
        for (int nt = 0; nt < 8; nt++)
#pragma unroll
            for (int e = 0; e < 4; e++) s[nt][e] = 0.0f;

#pragma unroll
        for (int ks = 0; ks < 4; ks++) {
#pragma unroll
            for (int npp = 0; npp < 2; npp++) {
                const int np0 = npp * 2, np1 = npp * 2 + 1;
                uint32_t kh0[4], kh1[4];
                ldsm4(kh0, stg + SK_H +
                      SWZ((uint32_t)((np0 * 16 + b_rp) * 128 + ks * 32) + b_bc));
                ldsm4(kh1, stg + SK_H +
                      SWZ((uint32_t)((np1 * 16 + b_rp) * 128 + ks * 32) + b_bc));
                float* s0 = s[npp * 4 + 0];
                float* s1 = s[npp * 4 + 1];
                float* s2 = s[npp * 4 + 2];
                float* s3 = s[npp * 4 + 3];
                mma16816(s0, qh[ks], kh0); mma16816(s1, qh[ks], kh0 + 2);
                mma16816(s2, qh[ks], kh1); mma16816(s3, qh[ks], kh1 + 2);
                mma16816(s0, ql[ks], kh0); mma16816(s1, ql[ks], kh0 + 2);
                mma16816(s2, ql[ks], kh1); mma16816(s3, ql[ks], kh1 + 2);
            }
        }

        const bool diag = (kt == qt);
        const float* mvm = (const float*)(smc + ((kt & 1) ? STG1_BASE : STG0_BASE) + SVM);
        float mx_lo = -1e30f, mx_hi = -1e30f;
#pragma unroll
        for (int nt = 0; nt < 8; nt++) {
            int jl = nt * 8 + jc;
            int jg = kt * 64 + jl;
            float2 av = *(const float2*)&mvm[jl];
            float v0 = s[nt][0] + av.x;
            float v1 = s[nt][1] + av.y;
            float v2 = s[nt][2] + av.x;
            float v3 = s[nt][3] + av.y;
            if (diag) {
                if (jg     > qi_lo) v0 = -1e12f;
                if (jg + 1 > qi_lo) v1 = -1e12f;
                if (jg     > qi_hi) v2 = -1e12f;
                if (jg + 1 > qi_hi) v3 = -1e12f;
            }
            s[nt][0] = v0; s[nt][1] = v1; s[nt][2] = v2; s[nt][3] = v3;
            mx_lo = fmaxf(mx_lo, fmaxf(v0, v1));
            mx_hi = fmaxf(mx_hi, fmaxf(v2, v3));
        }
        mx_lo = fmaxf(mx_lo, __shfl_xor_sync(0xffffffffu, mx_lo, 1));
        mx_lo = fmaxf(mx_lo, __shfl_xor_sync(0xffffffffu, mx_lo, 2));
        mx_hi = fmaxf(mx_hi, __shfl_xor_sync(0xffffffffu, mx_hi, 1));
        mx_hi = fmaxf(mx_hi, __shfl_xor_sync(0xffffffffu, mx_hi, 2));

        float mn_lo = fmaxf(m_lo, mx_lo);
        float mn_hi = fmaxf(m_hi, mx_hi);
        float corr_lo = ex2f(m_lo - mn_lo);
        float corr_hi = ex2f(m_hi - mn_hi);
        m_lo = mn_lo; m_hi = mn_hi;

        float sum_lo = 0.0f, sum_hi = 0.0f;
#pragma unroll
        for (int nt = 0; nt < 8; nt++) {
            float p0 = ex2f(s[nt][0] - mn_lo);
            float p1 = ex2f(s[nt][1] - mn_lo);
            float p2 = ex2f(s[nt][2] - mn_hi);
            float p3 = ex2f(s[nt][3] - mn_hi);
            s[nt][0] = p0; s[nt][1] = p1; s[nt][2] = p2; s[nt][3] = p3;
            sum_lo += p0 + p1;
            sum_hi += p2 + p3;
        }
        sum_lo += __shfl_xor_sync(0xffffffffu, sum_lo, 1);
        sum_lo += __shfl_xor_sync(0xffffffffu, sum_lo, 2);
        sum_hi += __shfl_xor_sync(0xffffffffu, sum_hi, 1);
        sum_hi += __shfl_xor_sync(0xffffffffu, sum_hi, 2);
        l_lo = l_lo * corr_lo + sum_lo;
        l_hi = l_hi * corr_hi + sum_hi;

#pragma unroll
        for (int nt = 0; nt < 8; nt++) {
            o[nt][0] *= corr_lo; o[nt][1] *= corr_lo;
            o[nt][2] *= corr_hi; o[nt][3] *= corr_hi;
        }

#pragma unroll
        for (int ks = 0; ks < 4; ks++) {
            uint32_t ah[4], al[4];
            split_pack2h(s[2*ks][0],   s[2*ks][1],   ah[0], al[0]);
            split_pack2h(s[2*ks][2],   s[2*ks][3],   ah[1], al[1]);
            split_pack2h(s[2*ks+1][0], s[2*ks+1][1], ah[2], al[2]);
            split_pack2h(s[2*ks+1][2], s[2*ks+1][3], ah[3], al[3]);
#pragma unroll
            for (int npp = 0; npp < 2; npp++) {
                const int np0 = npp * 2, np1 = npp * 2 + 1;
                uint32_t bh0[4], bh1[4];
                ldsm4(bh0, stg + SV_H +
                      (uint32_t)((np0 * 16 + b_rp) * VT_ROW + ks * 32) + b_bc);
                ldsm4(bh1, stg + SV_H +
                      (uint32_t)((np1 * 16 + b_rp) * VT_ROW + ks * 32) + b_bc);
                float* o0 = o[np0 * 2 + 0];
                float* o1 = o[np0 * 2 + 1];
                float* o2 = o[np1 * 2 + 0];
                float* o3 = o[np1 * 2 + 1];
                mma16816(o0, ah, bh0); mma16816(o1, ah, bh0 + 2);
                mma16816(o2, ah, bh1); mma16816(o3, ah, bh1 + 2);
                mma16816(o0, al, bh0); mma16816(o1, al, bh0 + 2);
                mma16816(o2, al, bh1); mma16816(o3, al, bh1 + 2);
            }
        }

        CP_WAIT0();
        __syncthreads();
    }

    float inv_lo = 1.0f / l_lo;
    float inv_hi = 1.0f / l_hi;
    const size_t row_lo = (size_t)(b * SS + q0 + w * 16 + r) * DD + h * 64;
    const size_t row_hi = row_lo + 8 * DD;
#pragma unroll
    for (int nt = 0; nt < 8; nt++) {
        int d0 = nt * 8 + jc;
        uint32_t hp, lp;
        split_pack2h(o[nt][0] * inv_lo, o[nt][1] * inv_lo, hp, lp);
        *(uint32_t*)&g_Ohi[row_lo + d0] = hp;
        *(uint32_t*)&g_Olo[row_lo + d0] = lp;
        split_pack2h(o[nt][2] * inv_hi, o[nt][3] * inv_hi, hp, lp);
        *(uint32_t*)&g_Ohi[row_hi + d0] = hp;
        *(uint32_t*)&g_Olo[row_hi + d0] = lp;
    }
}

// ---------------------------------------------------------------------------
// kernel_launch
// ---------------------------------------------------------------------------
extern "C" void kernel_launch(void* const* d_in, const int* in_sizes, int n_in,
                              void* d_out, int out_size)
{
    const float* q      = (const float*)d_in[0];
    const float* k      = (const float*)d_in[1];
    const float* v      = (const float*)d_in[2];
    const int*   q_mask = (const int*)  d_in[3];
    const int*   v_mask = (const int*)  d_in[4];
    const float* Wq     = (const float*)d_in[5];
    const float* bq     = (const float*)d_in[6];
    const float* Wk     = (const float*)d_in[7];
    const float* bk     = (const float*)d_in[8];
    const float* Wv     = (const float*)d_in[9];
    const float* bv     = (const float*)d_in[10];
    const float* Wo     = (const float*)d_in[11];
    const float* bo     = (const float*)d_in[12];
    float* out = (float*)d_out;

    cudaFuncSetAttribute(gemm_qkv,
                         cudaFuncAttributeMaxDynamicSharedMemorySize, GEMM_SMEM);
    cudaFuncSetAttribute(gemm_out,
                         cudaFuncAttributeMaxDynamicSharedMemorySize, GEMM_SMEM);
    cudaFuncSetAttribute(attn_mma,
                         cudaFuncAttributeMaxDynamicSharedMemorySize, AT_SMEM);

    const int n4 = MM * DD / 4;

    split3_kernel<<<dim3((n4 + 255) / 256, 3), 256>>>(q, k, v, n4);
    wsplit4_kernel<<<dim3(DD / 32, DD / 32, 4), 256>>>(Wq, Wk, Wv, Wo);

    gemm_qkv<<<dim3(DD / 128, MM / 128, 3), 256, GEMM_SMEM>>>(bq, bk, bv);

    attn_mma<<<dim3(SS / 64, BB * HH), 128, AT_SMEM>>>(v_mask);

    gemm_out<<<dim3(DD / 128, MM / 128), 256, GEMM_SMEM>>>(bo, q_mask, out);
}